// round 1
// baseline (speedup 1.0000x reference)
#include <cuda_runtime.h>
#include <math.h>

// ---------------------------------------------------------------------------
// Problem constants (fixed by the reference problem definition)
// ---------------------------------------------------------------------------
namespace {
constexpr int kD   = 256;
constexpr int kNH  = 8;
constexpr int kDH  = 32;
constexpr int kNL  = 4;
constexpr int kNP  = 4;
constexpr int kDFF = 1024;
constexpr int kBS  = 8;
constexpr int kNQ  = 300;
constexpr int kS   = 19947;          // total spatial size
constexpr int kMQ  = kBS * kNQ;      // 2400
constexpr int kMV  = kBS * kS;       // 159576

// scratch layout (in floats)
constexpr size_t OFF_QKADD = 0;
constexpr size_t OFF_QK    = OFF_QKADD + (size_t)kMQ * kD;        // q||k, 2*D per row
constexpr size_t OFF_V     = OFF_QK    + (size_t)kMQ * 2 * kD;
constexpr size_t OFF_ATTN  = OFF_V     + (size_t)kMQ * kD;
constexpr size_t OFF_SA    = OFF_ATTN  + (size_t)kMQ * kD;
constexpr size_t OFF_TGT1  = OFF_SA    + (size_t)kMQ * kD;
constexpr size_t OFF_QUERY = OFF_TGT1  + (size_t)kMQ * kD;
constexpr size_t OFF_OFFS  = OFF_QUERY + (size_t)kMQ * kD;
constexpr size_t OFF_AWL   = OFF_OFFS  + (size_t)kMQ * kD;
constexpr size_t OFF_MS    = OFF_AWL   + (size_t)kMQ * 128;
constexpr size_t OFF_T2    = OFF_MS    + (size_t)kMQ * kD;
constexpr size_t OFF_TGT2  = OFF_T2    + (size_t)kMQ * kD;
constexpr size_t OFF_HID   = OFF_TGT2  + (size_t)kMQ * kD;
constexpr size_t OFF_FFO   = OFF_HID   + (size_t)kMQ * kDFF;
constexpr size_t OFF_VAL   = OFF_FFO   + (size_t)kMQ * kD;
constexpr size_t SCRATCH_TOTAL = OFF_VAL + (size_t)kMV * kD;
} // namespace

__device__ float g_scratch[SCRATCH_TOTAL];

// ---------------------------------------------------------------------------
// Generic fp32 GEMM: C[M,N] = act(A[M,K] @ W[N,K]^T + bias[N])
// 64x64 tile, BK=16, 256 threads, 4x4 micro-tile per thread.
// ---------------------------------------------------------------------------
template <bool RELU>
__global__ void gemm_bias_kernel(const float* __restrict__ A,
                                 const float* __restrict__ W,
                                 const float* __restrict__ bias,
                                 float* __restrict__ C,
                                 int M, int N, int K) {
    constexpr int BM = 64, BN = 64, BK = 16;
    __shared__ float As[BK][BM + 4];
    __shared__ float Ws[BK][BN + 4];

    const int tid = threadIdx.x;          // 0..255
    const int tm  = blockIdx.y * BM;
    const int tn  = blockIdx.x * BN;
    const int tx  = tid & 15;             // col group
    const int ty  = tid >> 4;             // row group

    float acc[4][4] = {};

    for (int k0 = 0; k0 < K; k0 += BK) {
#pragma unroll
        for (int i = 0; i < (BM * BK) / 256; ++i) {
            int idx = tid + i * 256;
            int r = idx / BK, c = idx % BK;
            int gr = tm + r;
            As[c][r] = (gr < M) ? A[(size_t)gr * K + k0 + c] : 0.f;
        }
#pragma unroll
        for (int i = 0; i < (BN * BK) / 256; ++i) {
            int idx = tid + i * 256;
            int r = idx / BK, c = idx % BK;
            int gc = tn + r;
            Ws[c][r] = (gc < N) ? W[(size_t)gc * K + k0 + c] : 0.f;
        }
        __syncthreads();

#pragma unroll
        for (int k = 0; k < BK; ++k) {
            float a[4], b[4];
#pragma unroll
            for (int i = 0; i < 4; ++i) a[i] = As[k][ty * 4 + i];
#pragma unroll
            for (int j = 0; j < 4; ++j) b[j] = Ws[k][tx * 4 + j];
#pragma unroll
            for (int i = 0; i < 4; ++i)
#pragma unroll
                for (int j = 0; j < 4; ++j)
                    acc[i][j] = fmaf(a[i], b[j], acc[i][j]);
        }
        __syncthreads();
    }

#pragma unroll
    for (int i = 0; i < 4; ++i) {
        int gr = tm + ty * 4 + i;
        if (gr >= M) continue;
#pragma unroll
        for (int j = 0; j < 4; ++j) {
            int gc = tn + tx * 4 + j;
            if (gc >= N) continue;
            float v = acc[i][j] + bias[gc];
            if (RELU) v = fmaxf(v, 0.f);
            C[(size_t)gr * N + gc] = v;
        }
    }
}

// ---------------------------------------------------------------------------
// Elementwise add: out = a + b
// ---------------------------------------------------------------------------
__global__ void add_kernel(const float* __restrict__ a,
                           const float* __restrict__ b,
                           float* __restrict__ out, int n) {
    int i = blockIdx.x * blockDim.x + threadIdx.x;
    if (i < n) out[i] = a[i] + b[i];
}

// ---------------------------------------------------------------------------
// Residual + LayerNorm over 256 features. One block (256 thr) per row.
// out = (v - mean)/sqrt(var + eps) * g + b, v = x + r
// ---------------------------------------------------------------------------
__global__ void add_ln_kernel(const float* __restrict__ x,
                              const float* __restrict__ r,
                              const float* __restrict__ g,
                              const float* __restrict__ bta,
                              float* __restrict__ out) {
    const int row = blockIdx.x;
    const int t = threadIdx.x;
    const size_t base = (size_t)row * kD;
    float v = x[base + t] + r[base + t];

    __shared__ float sm[8];
    float s = v;
#pragma unroll
    for (int o = 16; o > 0; o >>= 1) s += __shfl_xor_sync(~0u, s, o);
    if ((t & 31) == 0) sm[t >> 5] = s;
    __syncthreads();
    float tot = 0.f;
#pragma unroll
    for (int i = 0; i < 8; ++i) tot += sm[i];
    const float mean = tot * (1.f / kD);
    const float d = v - mean;
    float s2 = d * d;
#pragma unroll
    for (int o = 16; o > 0; o >>= 1) s2 += __shfl_xor_sync(~0u, s2, o);
    __syncthreads();
    if ((t & 31) == 0) sm[t >> 5] = s2;
    __syncthreads();
    float tot2 = 0.f;
#pragma unroll
    for (int i = 0; i < 8; ++i) tot2 += sm[i];
    const float var = tot2 * (1.f / kD);
    out[base + t] = d * rsqrtf(var + 1e-5f) * g[t] + bta[t];
}

// ---------------------------------------------------------------------------
// Self attention. One warp per (b, h, q). qk buffer rows are [q(256) || k(256)].
// ---------------------------------------------------------------------------
__global__ void self_attn_kernel(const float* __restrict__ qk,
                                 const float* __restrict__ v,
                                 float* __restrict__ o) {
    const int w = threadIdx.x >> 5;
    const int lane = threadIdx.x & 31;
    const int q = blockIdx.x * 8 + w;
    const int h = blockIdx.y;
    const int b = blockIdx.z;
    __shared__ float s[8][kNQ];
    if (q >= kNQ) return;

    const float scale = 0.1767766952966369f;  // 1/sqrt(32)
    const float qv = qk[((size_t)(b * kNQ + q)) * 512 + h * kDH + lane];

    for (int k = 0; k < kNQ; ++k) {
        float kv = qk[((size_t)(b * kNQ + k)) * 512 + 256 + h * kDH + lane];
        float d = qv * kv;
#pragma unroll
        for (int off = 16; off > 0; off >>= 1) d += __shfl_xor_sync(~0u, d, off);
        if (lane == 0) s[w][k] = d * scale;
    }
    __syncwarp();

    float m = -INFINITY;
    for (int k = lane; k < kNQ; k += 32) m = fmaxf(m, s[w][k]);
#pragma unroll
    for (int off = 16; off > 0; off >>= 1) m = fmaxf(m, __shfl_xor_sync(~0u, m, off));
    float sum = 0.f;
    for (int k = lane; k < kNQ; k += 32) {
        float e = expf(s[w][k] - m);
        s[w][k] = e;
        sum += e;
    }
#pragma unroll
    for (int off = 16; off > 0; off >>= 1) sum += __shfl_xor_sync(~0u, sum, off);
    const float inv = 1.f / sum;
    __syncwarp();

    float acc = 0.f;
    for (int k = 0; k < kNQ; ++k)
        acc = fmaf(s[w][k], v[((size_t)(b * kNQ + k)) * kD + h * kDH + lane], acc);

    o[((size_t)(b * kNQ + q)) * kD + h * kDH + lane] = acc * inv;
}

// ---------------------------------------------------------------------------
// Multi-scale deformable attention sampling.
// One block (256 thr) per (b, q). warp = head, lane = channel.
// ---------------------------------------------------------------------------
__global__ void msdeform_kernel(const float* __restrict__ ref,
                                const float* __restrict__ off,
                                const float* __restrict__ awl,
                                const float* __restrict__ value,
                                float* __restrict__ out) {
    const int bq = blockIdx.x;            // 0..2399
    const int b = bq / kNQ;
    const int t = threadIdx.x;
    const int h = t >> 5;
    const int lane = t & 31;

    __shared__ float s_p[kNH][16];

    // softmax over 16 (l,p) attention logits for this head
    float lw = (lane < 16) ? awl[(size_t)bq * 128 + h * 16 + lane] : -INFINITY;
    float m = lw;
#pragma unroll
    for (int o = 8; o > 0; o >>= 1) m = fmaxf(m, __shfl_xor_sync(~0u, m, o, 16));
    float e = (lane < 16) ? expf(lw - m) : 0.f;
    float sum = e;
#pragma unroll
    for (int o = 8; o > 0; o >>= 1) sum += __shfl_xor_sync(~0u, sum, o, 16);
    if (lane < 16) s_p[h][lane] = e / sum;
    __syncwarp();

    const int cH[kNL]  = {100, 50, 25, 13};
    const int cW[kNL]  = {150, 75, 38, 19};
    const int cS0[kNL] = {0, 15000, 18750, 19700};

    float acc = 0.f;
#pragma unroll
    for (int l = 0; l < kNL; ++l) {
        const float rx = ref[((size_t)bq * kNL + l) * 2 + 0];
        const float ry = ref[((size_t)bq * kNL + l) * 2 + 1];
        const int Hl = cH[l], Wl = cW[l], s0 = cS0[l];
        const float fW = (float)Wl, fH = (float)Hl;
#pragma unroll
        for (int p = 0; p < kNP; ++p) {
            const size_t ob = (size_t)bq * 256 + (((h * kNL + l) * kNP + p) * 2);
            const float ox = off[ob + 0];
            const float oy = off[ob + 1];
            // replicate reference: (ref + off/norm)*dim - 0.5
            const float x = (rx + ox / fW) * fW - 0.5f;
            const float y = (ry + oy / fH) * fH - 0.5f;
            const float x0f = floorf(x), y0f = floorf(y);
            const float tx = x - x0f, ty = y - y0f;
            const int x0 = (int)x0f, y0 = (int)y0f;

            float samp = 0.f;
#pragma unroll
            for (int dy = 0; dy < 2; ++dy) {
#pragma unroll
                for (int dx = 0; dx < 2; ++dx) {
                    const int xi = x0 + dx, yi = y0 + dy;
                    const bool valid = (xi >= 0) & (xi < Wl) & (yi >= 0) & (yi < Hl);
                    if (valid) {
                        const float wgt = (dy ? ty : (1.f - ty)) * (dx ? tx : (1.f - tx));
                        const size_t vrow = (size_t)b * kS + s0 + yi * Wl + xi;
                        samp = fmaf(wgt, value[vrow * kD + h * kDH + lane], samp);
                    }
                }
            }
            acc = fmaf(s_p[h][l * kNP + p], samp, acc);
        }
    }
    out[(size_t)bq * kD + h * kDH + lane] = acc;
}

// ---------------------------------------------------------------------------
// Launch
// ---------------------------------------------------------------------------
static inline void launch_gemm(const float* A, const float* W, const float* b,
                               float* C, int M, int N, int K, bool relu) {
    dim3 grid((N + 63) / 64, (M + 63) / 64);
    if (relu)
        gemm_bias_kernel<true><<<grid, 256>>>(A, W, b, C, M, N, K);
    else
        gemm_bias_kernel<false><<<grid, 256>>>(A, W, b, C, M, N, K);
}

extern "C" void kernel_launch(void* const* d_in, const int* in_sizes, int n_in,
                              void* d_out, int out_size) {
    const float* tgt    = (const float*)d_in[0];
    const float* pos    = (const float*)d_in[1];
    const float* ref    = (const float*)d_in[2];
    const float* memory = (const float*)d_in[3];
    // d_in[4] padding mask: identically false in this problem -> no-op
    // d_in[5], d_in[6]: spatial shapes / level starts: compile-time constants
    const float* in_w  = (const float*)d_in[7];
    const float* in_b  = (const float*)d_in[8];
    const float* out_w = (const float*)d_in[9];
    const float* out_b = (const float*)d_in[10];
    const float* n1g = (const float*)d_in[11];
    const float* n1b = (const float*)d_in[12];
    const float* n2g = (const float*)d_in[13];
    const float* n2b = (const float*)d_in[14];
    const float* n3g = (const float*)d_in[15];
    const float* n3b = (const float*)d_in[16];
    const float* so_w = (const float*)d_in[17];
    const float* so_b = (const float*)d_in[18];
    const float* aw_w = (const float*)d_in[19];
    const float* aw_b = (const float*)d_in[20];
    const float* v_w  = (const float*)d_in[21];
    const float* v_b  = (const float*)d_in[22];
    const float* op_w = (const float*)d_in[23];
    const float* op_b = (const float*)d_in[24];
    const float* l1w  = (const float*)d_in[25];
    const float* l1b  = (const float*)d_in[26];
    const float* l2w  = (const float*)d_in[27];
    const float* l2b  = (const float*)d_in[28];

    float* scratch = nullptr;
    cudaGetSymbolAddress((void**)&scratch, g_scratch);

    float* s_qkadd = scratch + OFF_QKADD;
    float* s_qk    = scratch + OFF_QK;
    float* s_v     = scratch + OFF_V;
    float* s_attn  = scratch + OFF_ATTN;
    float* s_sa    = scratch + OFF_SA;
    float* s_tgt1  = scratch + OFF_TGT1;
    float* s_query = scratch + OFF_QUERY;
    float* s_offs  = scratch + OFF_OFFS;
    float* s_awl   = scratch + OFF_AWL;
    float* s_ms    = scratch + OFF_MS;
    float* s_t2    = scratch + OFF_T2;
    float* s_tgt2  = scratch + OFF_TGT2;
    float* s_hid   = scratch + OFF_HID;
    float* s_ffo   = scratch + OFF_FFO;
    float* s_val   = scratch + OFF_VAL;

    const int nQD = kMQ * kD;

    // ---- value projection (big GEMM, independent — launch first) ----
    launch_gemm(memory, v_w, v_b, s_val, kMV, kD, kD, false);

    // ---- self attention ----
    add_kernel<<<(nQD + 255) / 256, 256>>>(tgt, pos, s_qkadd, nQD);
    launch_gemm(s_qkadd, in_w, in_b, s_qk, kMQ, 2 * kD, kD, false);          // q||k
    launch_gemm(tgt, in_w + 512 * kD, in_b + 512, s_v, kMQ, kD, kD, false);  // v
    {
        dim3 grid((kNQ + 7) / 8, kNH, kBS);
        self_attn_kernel<<<grid, 256>>>(s_qk, s_v, s_attn);
    }
    launch_gemm(s_attn, out_w, out_b, s_sa, kMQ, kD, kD, false);
    add_ln_kernel<<<kMQ, 256>>>(tgt, s_sa, n2g, n2b, s_tgt1);

    // ---- MS deformable attention ----
    add_kernel<<<(nQD + 255) / 256, 256>>>(s_tgt1, pos, s_query, nQD);
    launch_gemm(s_query, so_w, so_b, s_offs, kMQ, kD, kD, false);
    launch_gemm(s_query, aw_w, aw_b, s_awl, kMQ, 128, kD, false);
    msdeform_kernel<<<kMQ, 256>>>(ref, s_offs, s_awl, s_val, s_ms);
    launch_gemm(s_ms, op_w, op_b, s_t2, kMQ, kD, kD, false);
    add_ln_kernel<<<kMQ, 256>>>(s_tgt1, s_t2, n1g, n1b, s_tgt2);

    // ---- FFN ----
    launch_gemm(s_tgt2, l1w, l1b, s_hid, kMQ, kDFF, kD, true);
    launch_gemm(s_hid, l2w, l2b, s_ffo, kMQ, kD, kDFF, false);
    add_ln_kernel<<<kMQ, 256>>>(s_tgt2, s_ffo, n3g, n3b, (float*)d_out);
}

// round 2
// speedup vs baseline: 2.2698x; 2.2698x over previous
#include <cuda_runtime.h>
#include <math.h>

// ---------------------------------------------------------------------------
// Problem constants (fixed by the reference problem definition)
// ---------------------------------------------------------------------------
namespace {
constexpr int kD   = 256;
constexpr int kNH  = 8;
constexpr int kDH  = 32;
constexpr int kNL  = 4;
constexpr int kNP  = 4;
constexpr int kDFF = 1024;
constexpr int kBS  = 8;
constexpr int kNQ  = 300;
constexpr int kS   = 19947;          // total spatial size
constexpr int kMQ  = kBS * kNQ;      // 2400
constexpr int kMV  = kBS * kS;       // 159576

// scratch layout (in floats)
constexpr size_t OFF_QKADD = 0;
constexpr size_t OFF_QK    = OFF_QKADD + (size_t)kMQ * kD;        // q||k, 2*D per row
constexpr size_t OFF_V     = OFF_QK    + (size_t)kMQ * 2 * kD;
constexpr size_t OFF_ATTN  = OFF_V     + (size_t)kMQ * kD;
constexpr size_t OFF_SA    = OFF_ATTN  + (size_t)kMQ * kD;
constexpr size_t OFF_TGT1  = OFF_SA    + (size_t)kMQ * kD;
constexpr size_t OFF_QUERY = OFF_TGT1  + (size_t)kMQ * kD;
constexpr size_t OFF_OFFS  = OFF_QUERY + (size_t)kMQ * kD;
constexpr size_t OFF_AWL   = OFF_OFFS  + (size_t)kMQ * kD;
constexpr size_t OFF_MS    = OFF_AWL   + (size_t)kMQ * 128;
constexpr size_t OFF_T2    = OFF_MS    + (size_t)kMQ * kD;
constexpr size_t OFF_TGT2  = OFF_T2    + (size_t)kMQ * kD;
constexpr size_t OFF_HID   = OFF_TGT2  + (size_t)kMQ * kD;
constexpr size_t OFF_FFO   = OFF_HID   + (size_t)kMQ * kDFF;
constexpr size_t OFF_VAL   = OFF_FFO   + (size_t)kMQ * kD;
constexpr size_t SCRATCH_TOTAL = OFF_VAL + (size_t)kMV * kD;
} // namespace

__device__ float g_scratch[SCRATCH_TOTAL];

// ---------------------------------------------------------------------------
// TF32 helpers
// ---------------------------------------------------------------------------
__device__ __forceinline__ unsigned f2tf32(float f) {
    unsigned r;
    asm("cvt.rna.tf32.f32 %0, %1;" : "=r"(r) : "f"(f));
    return r;
}

__device__ __forceinline__ void mma_tf32(float (&d)[4],
                                         const unsigned (&a)[4],
                                         const unsigned (&b)[2]) {
    asm volatile(
        "mma.sync.aligned.m16n8k8.row.col.f32.tf32.tf32.f32 "
        "{%0,%1,%2,%3}, {%4,%5,%6,%7}, {%8,%9}, {%0,%1,%2,%3};"
        : "+f"(d[0]), "+f"(d[1]), "+f"(d[2]), "+f"(d[3])
        : "r"(a[0]), "r"(a[1]), "r"(a[2]), "r"(a[3]),
          "r"(b[0]), "r"(b[1]));
}

// ---------------------------------------------------------------------------
// TF32 tensor-core GEMM: C[M,N] = act(A[M,K] @ W[N,K]^T + bias[N])
// Block tile 128x64, BK=32, 256 threads = 8 warps (4x2), warp tile 32x32.
// Requires: N % 64 == 0, K % 32 == 0 (all GEMMs in this problem qualify).
// SMEM row stride 36 words (== 4 mod 32) -> conflict-free fragment LDS.
// ---------------------------------------------------------------------------
template <bool RELU>
__global__ __launch_bounds__(256)
void gemm_tf32_kernel(const float* __restrict__ A,
                      const float* __restrict__ W,
                      const float* __restrict__ bias,
                      float* __restrict__ C,
                      int M, int N, int K) {
    constexpr int BM = 128, BN = 64, BK = 32;
    constexpr int LDA = BK + 4;   // 36
    constexpr int LDB = BK + 4;   // 36
    __shared__ unsigned As[BM * LDA];
    __shared__ unsigned Ws[BN * LDB];

    const int tid  = threadIdx.x;
    const int warp = tid >> 5;
    const int lane = tid & 31;
    const int g    = lane >> 2;   // group id (0..7)
    const int tg   = lane & 3;    // thread-in-group (0..3)
    const int tm   = blockIdx.y * BM;
    const int tn   = blockIdx.x * BN;
    const int wm   = (warp & 3) * 32;    // warp m offset in tile
    const int wn   = (warp >> 2) * 32;   // warp n offset in tile

    float acc[2][4][4] = {};             // [mtile][ntile][frag]

    unsigned a_pf[4][4];                 // prefetch regs (4 float4 worth)
    unsigned w_pf[2][4];

    auto load_gA = [&](int k0) {
#pragma unroll
        for (int i = 0; i < 4; ++i) {
            int idx = tid + i * 256;
            int r = idx >> 3, c4 = (idx & 7) * 4;
            int gr = tm + r;
            float4 v = make_float4(0.f, 0.f, 0.f, 0.f);
            if (gr < M) v = *(const float4*)(A + (size_t)gr * K + k0 + c4);
            a_pf[i][0] = f2tf32(v.x); a_pf[i][1] = f2tf32(v.y);
            a_pf[i][2] = f2tf32(v.z); a_pf[i][3] = f2tf32(v.w);
        }
    };
    auto load_gW = [&](int k0) {
#pragma unroll
        for (int i = 0; i < 2; ++i) {
            int idx = tid + i * 256;
            int r = idx >> 3, c4 = (idx & 7) * 4;
            float4 v = *(const float4*)(W + (size_t)(tn + r) * K + k0 + c4);
            w_pf[i][0] = f2tf32(v.x); w_pf[i][1] = f2tf32(v.y);
            w_pf[i][2] = f2tf32(v.z); w_pf[i][3] = f2tf32(v.w);
        }
    };
    auto store_s = [&]() {
#pragma unroll
        for (int i = 0; i < 4; ++i) {
            int idx = tid + i * 256;
            int r = idx >> 3, c4 = (idx & 7) * 4;
            *(uint4*)&As[r * LDA + c4] =
                make_uint4(a_pf[i][0], a_pf[i][1], a_pf[i][2], a_pf[i][3]);
        }
#pragma unroll
        for (int i = 0; i < 2; ++i) {
            int idx = tid + i * 256;
            int r = idx >> 3, c4 = (idx & 7) * 4;
            *(uint4*)&Ws[r * LDB + c4] =
                make_uint4(w_pf[i][0], w_pf[i][1], w_pf[i][2], w_pf[i][3]);
        }
    };

    load_gA(0);
    load_gW(0);
    store_s();
    __syncthreads();

    for (int k0 = 0; k0 < K; k0 += BK) {
        const bool more = (k0 + BK) < K;
        if (more) { load_gA(k0 + BK); load_gW(k0 + BK); }

#pragma unroll
        for (int ks = 0; ks < 4; ++ks) {
            const int kc = ks * 8 + tg;
            unsigned af[2][4], bf[4][2];
#pragma unroll
            for (int mt = 0; mt < 2; ++mt) {
                const int r = wm + mt * 16 + g;
                af[mt][0] = As[r * LDA + kc];
                af[mt][1] = As[(r + 8) * LDA + kc];
                af[mt][2] = As[r * LDA + kc + 4];
                af[mt][3] = As[(r + 8) * LDA + kc + 4];
            }
#pragma unroll
            for (int nt = 0; nt < 4; ++nt) {
                const int n = wn + nt * 8 + g;
                bf[nt][0] = Ws[n * LDB + kc];
                bf[nt][1] = Ws[n * LDB + kc + 4];
            }
#pragma unroll
            for (int mt = 0; mt < 2; ++mt)
#pragma unroll
                for (int nt = 0; nt < 4; ++nt)
                    mma_tf32(acc[mt][nt], af[mt], bf[nt]);
        }
        __syncthreads();
        if (more) { store_s(); __syncthreads(); }
    }

    // epilogue: c0,c1 -> row (g), cols tg*2, tg*2+1 ; c2,c3 -> row (g+8)
#pragma unroll
    for (int mt = 0; mt < 2; ++mt) {
        const int gr0 = tm + wm + mt * 16 + g;
        const int gr1 = gr0 + 8;
#pragma unroll
        for (int nt = 0; nt < 4; ++nt) {
            const int gc = tn + wn + nt * 8 + tg * 2;
            const float b0 = bias[gc], b1 = bias[gc + 1];
            if (gr0 < M) {
                float v0 = acc[mt][nt][0] + b0;
                float v1 = acc[mt][nt][1] + b1;
                if (RELU) { v0 = fmaxf(v0, 0.f); v1 = fmaxf(v1, 0.f); }
                *(float2*)(C + (size_t)gr0 * N + gc) = make_float2(v0, v1);
            }
            if (gr1 < M) {
                float v2 = acc[mt][nt][2] + b0;
                float v3 = acc[mt][nt][3] + b1;
                if (RELU) { v2 = fmaxf(v2, 0.f); v3 = fmaxf(v3, 0.f); }
                *(float2*)(C + (size_t)gr1 * N + gc) = make_float2(v2, v3);
            }
        }
    }
}

// ---------------------------------------------------------------------------
// Elementwise add: out = a + b
// ---------------------------------------------------------------------------
__global__ void add_kernel(const float* __restrict__ a,
                           const float* __restrict__ b,
                           float* __restrict__ out, int n) {
    int i = blockIdx.x * blockDim.x + threadIdx.x;
    if (i < n) out[i] = a[i] + b[i];
}

// ---------------------------------------------------------------------------
// Residual + LayerNorm over 256 features. One block (256 thr) per row.
// ---------------------------------------------------------------------------
__global__ void add_ln_kernel(const float* __restrict__ x,
                              const float* __restrict__ r,
                              const float* __restrict__ g,
                              const float* __restrict__ bta,
                              float* __restrict__ out) {
    const int row = blockIdx.x;
    const int t = threadIdx.x;
    const size_t base = (size_t)row * kD;
    float v = x[base + t] + r[base + t];

    __shared__ float sm[8];
    float s = v;
#pragma unroll
    for (int o = 16; o > 0; o >>= 1) s += __shfl_xor_sync(~0u, s, o);
    if ((t & 31) == 0) sm[t >> 5] = s;
    __syncthreads();
    float tot = 0.f;
#pragma unroll
    for (int i = 0; i < 8; ++i) tot += sm[i];
    const float mean = tot * (1.f / kD);
    const float d = v - mean;
    float s2 = d * d;
#pragma unroll
    for (int o = 16; o > 0; o >>= 1) s2 += __shfl_xor_sync(~0u, s2, o);
    __syncthreads();
    if ((t & 31) == 0) sm[t >> 5] = s2;
    __syncthreads();
    float tot2 = 0.f;
#pragma unroll
    for (int i = 0; i < 8; ++i) tot2 += sm[i];
    const float var = tot2 * (1.f / kD);
    out[base + t] = d * rsqrtf(var + 1e-5f) * g[t] + bta[t];
}

// ---------------------------------------------------------------------------
// Self attention. One warp per (b, h, q). qk rows are [q(256) || k(256)].
// ---------------------------------------------------------------------------
__global__ void self_attn_kernel(const float* __restrict__ qk,
                                 const float* __restrict__ v,
                                 float* __restrict__ o) {
    const int w = threadIdx.x >> 5;
    const int lane = threadIdx.x & 31;
    const int q = blockIdx.x * 8 + w;
    const int h = blockIdx.y;
    const int b = blockIdx.z;
    __shared__ float s[8][kNQ];
    if (q >= kNQ) return;

    const float scale = 0.1767766952966369f;  // 1/sqrt(32)
    const float qv = qk[((size_t)(b * kNQ + q)) * 512 + h * kDH + lane];

    for (int k = 0; k < kNQ; ++k) {
        float kv = qk[((size_t)(b * kNQ + k)) * 512 + 256 + h * kDH + lane];
        float d = qv * kv;
#pragma unroll
        for (int off = 16; off > 0; off >>= 1) d += __shfl_xor_sync(~0u, d, off);
        if (lane == 0) s[w][k] = d * scale;
    }
    __syncwarp();

    float m = -INFINITY;
    for (int k = lane; k < kNQ; k += 32) m = fmaxf(m, s[w][k]);
#pragma unroll
    for (int off = 16; off > 0; off >>= 1) m = fmaxf(m, __shfl_xor_sync(~0u, m, off));
    float sum = 0.f;
    for (int k = lane; k < kNQ; k += 32) {
        float e = expf(s[w][k] - m);
        s[w][k] = e;
        sum += e;
    }
#pragma unroll
    for (int off = 16; off > 0; off >>= 1) sum += __shfl_xor_sync(~0u, sum, off);
    const float inv = 1.f / sum;
    __syncwarp();

    float acc = 0.f;
    for (int k = 0; k < kNQ; ++k)
        acc = fmaf(s[w][k], v[((size_t)(b * kNQ + k)) * kD + h * kDH + lane], acc);

    o[((size_t)(b * kNQ + q)) * kD + h * kDH + lane] = acc * inv;
}

// ---------------------------------------------------------------------------
// Multi-scale deformable attention sampling.
// One block (256 thr) per (b, q). warp = head, lane = channel.
// ---------------------------------------------------------------------------
__global__ void msdeform_kernel(const float* __restrict__ ref,
                                const float* __restrict__ off,
                                const float* __restrict__ awl,
                                const float* __restrict__ value,
                                float* __restrict__ out) {
    const int bq = blockIdx.x;            // 0..2399
    const int b = bq / kNQ;
    const int t = threadIdx.x;
    const int h = t >> 5;
    const int lane = t & 31;

    __shared__ float s_p[kNH][16];

    float lw = (lane < 16) ? awl[(size_t)bq * 128 + h * 16 + lane] : -INFINITY;
    float m = lw;
#pragma unroll
    for (int o = 8; o > 0; o >>= 1) m = fmaxf(m, __shfl_xor_sync(~0u, m, o, 16));
    float e = (lane < 16) ? expf(lw - m) : 0.f;
    float sum = e;
#pragma unroll
    for (int o = 8; o > 0; o >>= 1) sum += __shfl_xor_sync(~0u, sum, o, 16);
    if (lane < 16) s_p[h][lane] = e / sum;
    __syncwarp();

    const int cH[kNL]  = {100, 50, 25, 13};
    const int cW[kNL]  = {150, 75, 38, 19};
    const int cS0[kNL] = {0, 15000, 18750, 19700};

    float acc = 0.f;
#pragma unroll
    for (int l = 0; l < kNL; ++l) {
        const float rx = ref[((size_t)bq * kNL + l) * 2 + 0];
        const float ry = ref[((size_t)bq * kNL + l) * 2 + 1];
        const int Hl = cH[l], Wl = cW[l], s0 = cS0[l];
        const float fW = (float)Wl, fH = (float)Hl;
#pragma unroll
        for (int p = 0; p < kNP; ++p) {
            const size_t ob = (size_t)bq * 256 + (((h * kNL + l) * kNP + p) * 2);
            const float ox = off[ob + 0];
            const float oy = off[ob + 1];
            const float x = (rx + ox / fW) * fW - 0.5f;
            const float y = (ry + oy / fH) * fH - 0.5f;
            const float x0f = floorf(x), y0f = floorf(y);
            const float tx = x - x0f, ty = y - y0f;
            const int x0 = (int)x0f, y0 = (int)y0f;

            float samp = 0.f;
#pragma unroll
            for (int dy = 0; dy < 2; ++dy) {
#pragma unroll
                for (int dx = 0; dx < 2; ++dx) {
                    const int xi = x0 + dx, yi = y0 + dy;
                    const bool valid = (xi >= 0) & (xi < Wl) & (yi >= 0) & (yi < Hl);
                    if (valid) {
                        const float wgt = (dy ? ty : (1.f - ty)) * (dx ? tx : (1.f - tx));
                        const size_t vrow = (size_t)b * kS + s0 + yi * Wl + xi;
                        samp = fmaf(wgt, value[vrow * kD + h * kDH + lane], samp);
                    }
                }
            }
            acc = fmaf(s_p[h][l * kNP + p], samp, acc);
        }
    }
    out[(size_t)bq * kD + h * kDH + lane] = acc;
}

// ---------------------------------------------------------------------------
// Launch
// ---------------------------------------------------------------------------
static inline void launch_gemm(const float* A, const float* W, const float* b,
                               float* C, int M, int N, int K, bool relu) {
    dim3 grid(N / 64, (M + 127) / 128);
    if (relu)
        gemm_tf32_kernel<true><<<grid, 256>>>(A, W, b, C, M, N, K);
    else
        gemm_tf32_kernel<false><<<grid, 256>>>(A, W, b, C, M, N, K);
}

extern "C" void kernel_launch(void* const* d_in, const int* in_sizes, int n_in,
                              void* d_out, int out_size) {
    const float* tgt    = (const float*)d_in[0];
    const float* pos    = (const float*)d_in[1];
    const float* ref    = (const float*)d_in[2];
    const float* memory = (const float*)d_in[3];
    const float* in_w  = (const float*)d_in[7];
    const float* in_b  = (const float*)d_in[8];
    const float* out_w = (const float*)d_in[9];
    const float* out_b = (const float*)d_in[10];
    const float* n1g = (const float*)d_in[11];
    const float* n1b = (const float*)d_in[12];
    const float* n2g = (const float*)d_in[13];
    const float* n2b = (const float*)d_in[14];
    const float* n3g = (const float*)d_in[15];
    const float* n3b = (const float*)d_in[16];
    const float* so_w = (const float*)d_in[17];
    const float* so_b = (const float*)d_in[18];
    const float* aw_w = (const float*)d_in[19];
    const float* aw_b = (const float*)d_in[20];
    const float* v_w  = (const float*)d_in[21];
    const float* v_b  = (const float*)d_in[22];
    const float* op_w = (const float*)d_in[23];
    const float* op_b = (const float*)d_in[24];
    const float* l1w  = (const float*)d_in[25];
    const float* l1b  = (const float*)d_in[26];
    const float* l2w  = (const float*)d_in[27];
    const float* l2b  = (const float*)d_in[28];

    float* scratch = nullptr;
    cudaGetSymbolAddress((void**)&scratch, g_scratch);

    float* s_qkadd = scratch + OFF_QKADD;
    float* s_qk    = scratch + OFF_QK;
    float* s_v     = scratch + OFF_V;
    float* s_attn  = scratch + OFF_ATTN;
    float* s_sa    = scratch + OFF_SA;
    float* s_tgt1  = scratch + OFF_TGT1;
    float* s_query = scratch + OFF_QUERY;
    float* s_offs  = scratch + OFF_OFFS;
    float* s_awl   = scratch + OFF_AWL;
    float* s_ms    = scratch + OFF_MS;
    float* s_t2    = scratch + OFF_T2;
    float* s_tgt2  = scratch + OFF_TGT2;
    float* s_hid   = scratch + OFF_HID;
    float* s_ffo   = scratch + OFF_FFO;
    float* s_val   = scratch + OFF_VAL;

    const int nQD = kMQ * kD;

    // ---- value projection (big GEMM, independent — launch first) ----
    launch_gemm(memory, v_w, v_b, s_val, kMV, kD, kD, false);

    // ---- self attention ----
    add_kernel<<<(nQD + 255) / 256, 256>>>(tgt, pos, s_qkadd, nQD);
    launch_gemm(s_qkadd, in_w, in_b, s_qk, kMQ, 2 * kD, kD, false);          // q||k
    launch_gemm(tgt, in_w + 512 * kD, in_b + 512, s_v, kMQ, kD, kD, false);  // v
    {
        dim3 grid((kNQ + 7) / 8, kNH, kBS);
        self_attn_kernel<<<grid, 256>>>(s_qk, s_v, s_attn);
    }
    launch_gemm(s_attn, out_w, out_b, s_sa, kMQ, kD, kD, false);
    add_ln_kernel<<<kMQ, 256>>>(tgt, s_sa, n2g, n2b, s_tgt1);

    // ---- MS deformable attention ----
    add_kernel<<<(nQD + 255) / 256, 256>>>(s_tgt1, pos, s_query, nQD);
    launch_gemm(s_query, so_w, so_b, s_offs, kMQ, kD, kD, false);
    launch_gemm(s_query, aw_w, aw_b, s_awl, kMQ, 128, kD, false);
    msdeform_kernel<<<kMQ, 256>>>(ref, s_offs, s_awl, s_val, s_ms);
    launch_gemm(s_ms, op_w, op_b, s_t2, kMQ, kD, kD, false);
    add_ln_kernel<<<kMQ, 256>>>(s_tgt1, s_t2, n1g, n1b, s_tgt2);

    // ---- FFN ----
    launch_gemm(s_tgt2, l1w, l1b, s_hid, kMQ, kDFF, kD, true);
    launch_gemm(s_hid, l2w, l2b, s_ffo, kMQ, kD, kDFF, false);
    add_ln_kernel<<<kMQ, 256>>>(s_tgt2, s_ffo, n3g, n3b, (float*)d_out);
}

// round 3
// speedup vs baseline: 2.7103x; 1.1941x over previous
#include <cuda_runtime.h>
#include <math.h>
#include <stdint.h>

// ---------------------------------------------------------------------------
// Problem constants
// ---------------------------------------------------------------------------
namespace {
constexpr int kD   = 256;
constexpr int kNH  = 8;
constexpr int kDH  = 32;
constexpr int kNL  = 4;
constexpr int kNP  = 4;
constexpr int kDFF = 1024;
constexpr int kBS  = 8;
constexpr int kNQ  = 300;
constexpr int kS   = 19947;
constexpr int kMQ  = kBS * kNQ;      // 2400
constexpr int kMV  = kBS * kS;       // 159576

constexpr size_t OFF_QKADD = 0;
constexpr size_t OFF_QK    = OFF_QKADD + (size_t)kMQ * kD;
constexpr size_t OFF_V     = OFF_QK    + (size_t)kMQ * 2 * kD;
constexpr size_t OFF_ATTN  = OFF_V     + (size_t)kMQ * kD;
constexpr size_t OFF_SA    = OFF_ATTN  + (size_t)kMQ * kD;
constexpr size_t OFF_TGT1  = OFF_SA    + (size_t)kMQ * kD;
constexpr size_t OFF_QUERY = OFF_TGT1  + (size_t)kMQ * kD;
constexpr size_t OFF_OFFS  = OFF_QUERY + (size_t)kMQ * kD;
constexpr size_t OFF_AWL   = OFF_OFFS  + (size_t)kMQ * kD;
constexpr size_t OFF_MS    = OFF_AWL   + (size_t)kMQ * 128;
constexpr size_t OFF_T2    = OFF_MS    + (size_t)kMQ * kD;
constexpr size_t OFF_TGT2  = OFF_T2    + (size_t)kMQ * kD;
constexpr size_t OFF_HID   = OFF_TGT2  + (size_t)kMQ * kD;
constexpr size_t OFF_FFO   = OFF_HID   + (size_t)kMQ * kDFF;
constexpr size_t OFF_VAL   = OFF_FFO   + (size_t)kMQ * kD;
constexpr size_t SCRATCH_TOTAL = OFF_VAL + (size_t)kMV * kD;
} // namespace

__device__ float g_scratch[SCRATCH_TOTAL];

// ---------------------------------------------------------------------------
// helpers
// ---------------------------------------------------------------------------
__device__ __forceinline__ uint32_t smem_u32(const void* p) {
    uint32_t a;
    asm("{ .reg .u64 t; cvta.to.shared.u64 t, %1; cvt.u32.u64 %0, t; }"
        : "=r"(a) : "l"(p));
    return a;
}

__device__ __forceinline__ void cp_async16(uint32_t dst, const void* src, bool pred) {
    int sz = pred ? 16 : 0;
    asm volatile("cp.async.cg.shared.global [%0], [%1], 16, %2;"
                 :: "r"(dst), "l"(src), "r"(sz));
}
__device__ __forceinline__ void cp_commit() {
    asm volatile("cp.async.commit_group;");
}
__device__ __forceinline__ void cp_wait_all() {
    asm volatile("cp.async.wait_group 0;");
}

__device__ __forceinline__ void mma_tf32(float (&d)[4],
                                         const uint32_t (&a)[4],
                                         const uint32_t (&b)[2]) {
    asm volatile(
        "mma.sync.aligned.m16n8k8.row.col.f32.tf32.tf32.f32 "
        "{%0,%1,%2,%3}, {%4,%5,%6,%7}, {%8,%9}, {%0,%1,%2,%3};"
        : "+f"(d[0]), "+f"(d[1]), "+f"(d[2]), "+f"(d[3])
        : "r"(a[0]), "r"(a[1]), "r"(a[2]), "r"(a[3]),
          "r"(b[0]), "r"(b[1]));
}

// ---------------------------------------------------------------------------
// TF32 tensor-core GEMM: C[M,N] = act(A[M,K] @ W[N,K]^T + bias[N])
// Template tiles BM x BN, BK=32, warp tile 32x32, cp.async double buffered.
// fp32 operands fed raw to HMMA (tf32 truncation). N%BN==0, K%32==0 required.
// ---------------------------------------------------------------------------
template <int BM, int BN, bool RELU>
__global__ __launch_bounds__((BM / 32) * (BN / 32) * 32)
void gemm_tf32_kernel(const float* __restrict__ A,
                      const float* __restrict__ W,
                      const float* __restrict__ bias,
                      float* __restrict__ C,
                      int M, int N, int K) {
    constexpr int BK  = 32;
    constexpr int LD  = BK + 4;                 // 36 words/row (conflict-free)
    constexpr int WM  = BM / 32;
    constexpr int WN  = BN / 32;
    constexpr int NWARP = WM * WN;
    constexpr int THREADS = NWARP * 32;
    constexpr int A_IT = (BM * BK / 4) / THREADS;
    constexpr int B_IT = (BN * BK / 4) / THREADS;

    __shared__ float As[2][BM * LD];
    __shared__ float Ws[2][BN * LD];

    const int tid  = threadIdx.x;
    const int warp = tid >> 5;
    const int lane = tid & 31;
    const int g    = lane >> 2;
    const int tg   = lane & 3;
    const int tm   = blockIdx.y * BM;
    const int tn   = blockIdx.x * BN;
    const int wm   = (warp % WM) * 32;
    const int wn   = (warp / WM) * 32;

    float acc[2][4][4] = {};

    auto issue_load = [&](int s, int k0) {
#pragma unroll
        for (int i = 0; i < A_IT; ++i) {
            int idx = tid + i * THREADS;
            int r = idx >> 3, c4 = (idx & 7) * 4;
            int gr = tm + r;
            uint32_t dst = smem_u32(&As[s][r * LD + c4]);
            cp_async16(dst, A + (size_t)gr * K + k0 + c4, gr < M);
        }
#pragma unroll
        for (int i = 0; i < B_IT; ++i) {
            int idx = tid + i * THREADS;
            int r = idx >> 3, c4 = (idx & 7) * 4;
            uint32_t dst = smem_u32(&Ws[s][r * LD + c4]);
            cp_async16(dst, W + (size_t)(tn + r) * K + k0 + c4, true);
        }
        cp_commit();
    };

    issue_load(0, 0);
    cp_wait_all();
    __syncthreads();

    int s = 0;
    for (int k0 = 0; k0 < K; k0 += BK) {
        const bool more = (k0 + BK) < K;
        if (more) issue_load(s ^ 1, k0 + BK);

#pragma unroll
        for (int ks = 0; ks < 4; ++ks) {
            const int kc = ks * 8 + tg;
            uint32_t af[2][4], bf[4][2];
#pragma unroll
            for (int mt = 0; mt < 2; ++mt) {
                const int r = wm + mt * 16 + g;
                af[mt][0] = __float_as_uint(As[s][r * LD + kc]);
                af[mt][1] = __float_as_uint(As[s][(r + 8) * LD + kc]);
                af[mt][2] = __float_as_uint(As[s][r * LD + kc + 4]);
                af[mt][3] = __float_as_uint(As[s][(r + 8) * LD + kc + 4]);
            }
#pragma unroll
            for (int nt = 0; nt < 4; ++nt) {
                const int n = wn + nt * 8 + g;
                bf[nt][0] = __float_as_uint(Ws[s][n * LD + kc]);
                bf[nt][1] = __float_as_uint(Ws[s][n * LD + kc + 4]);
            }
#pragma unroll
            for (int mt = 0; mt < 2; ++mt)
#pragma unroll
                for (int nt = 0; nt < 4; ++nt)
                    mma_tf32(acc[mt][nt], af[mt], bf[nt]);
        }
        if (more) {
            cp_wait_all();
            __syncthreads();
        }
        s ^= 1;
    }

#pragma unroll
    for (int mt = 0; mt < 2; ++mt) {
        const int gr0 = tm + wm + mt * 16 + g;
        const int gr1 = gr0 + 8;
#pragma unroll
        for (int nt = 0; nt < 4; ++nt) {
            const int gc = tn + wn + nt * 8 + tg * 2;
            const float b0 = bias[gc], b1 = bias[gc + 1];
            if (gr0 < M) {
                float v0 = acc[mt][nt][0] + b0;
                float v1 = acc[mt][nt][1] + b1;
                if (RELU) { v0 = fmaxf(v0, 0.f); v1 = fmaxf(v1, 0.f); }
                *(float2*)(C + (size_t)gr0 * N + gc) = make_float2(v0, v1);
            }
            if (gr1 < M) {
                float v2 = acc[mt][nt][2] + b0;
                float v3 = acc[mt][nt][3] + b1;
                if (RELU) { v2 = fmaxf(v2, 0.f); v3 = fmaxf(v3, 0.f); }
                *(float2*)(C + (size_t)gr1 * N + gc) = make_float2(v2, v3);
            }
        }
    }
}

// ---------------------------------------------------------------------------
// Elementwise add
// ---------------------------------------------------------------------------
__global__ void add_kernel(const float* __restrict__ a,
                           const float* __restrict__ b,
                           float* __restrict__ out, int n) {
    int i = blockIdx.x * blockDim.x + threadIdx.x;
    if (i < n) out[i] = a[i] + b[i];
}

// ---------------------------------------------------------------------------
// Residual + LayerNorm (256 features, one block per row)
// ---------------------------------------------------------------------------
__global__ void add_ln_kernel(const float* __restrict__ x,
                              const float* __restrict__ r,
                              const float* __restrict__ g,
                              const float* __restrict__ bta,
                              float* __restrict__ out) {
    const int row = blockIdx.x;
    const int t = threadIdx.x;
    const size_t base = (size_t)row * kD;
    float v = x[base + t] + r[base + t];

    __shared__ float sm[8];
    float s = v;
#pragma unroll
    for (int o = 16; o > 0; o >>= 1) s += __shfl_xor_sync(~0u, s, o);
    if ((t & 31) == 0) sm[t >> 5] = s;
    __syncthreads();
    float tot = 0.f;
#pragma unroll
    for (int i = 0; i < 8; ++i) tot += sm[i];
    const float mean = tot * (1.f / kD);
    const float d = v - mean;
    float s2 = d * d;
#pragma unroll
    for (int o = 16; o > 0; o >>= 1) s2 += __shfl_xor_sync(~0u, s2, o);
    __syncthreads();
    if ((t & 31) == 0) sm[t >> 5] = s2;
    __syncthreads();
    float tot2 = 0.f;
#pragma unroll
    for (int i = 0; i < 8; ++i) tot2 += sm[i];
    const float var = tot2 * (1.f / kD);
    out[base + t] = d * rsqrtf(var + 1e-5f) * g[t] + bta[t];
}

// ---------------------------------------------------------------------------
// Self attention. One warp per (b, h, q). qk rows are [q(256) || k(256)].
// Phase 1: lane-per-key scoring (32 keys/chunk), phase 2: softmax,
// phase 3: lane-per-channel weighted V accumulation.
// ---------------------------------------------------------------------------
__global__ void self_attn_kernel(const float* __restrict__ qk,
                                 const float* __restrict__ v,
                                 float* __restrict__ o) {
    const int w = threadIdx.x >> 5;
    const int lane = threadIdx.x & 31;
    const int q = blockIdx.x * 8 + w;
    const int h = blockIdx.y;
    const int b = blockIdx.z;
    __shared__ float s_p[8][320];
    __shared__ float s_q[8][32];
    if (q >= kNQ) return;

    const float scale = 0.1767766952966369f;  // 1/sqrt(32)
    s_q[w][lane] = qk[((size_t)(b * kNQ + q)) * 512 + h * kDH + lane];
    __syncwarp();

    float sc[10];
    float m = -INFINITY;
#pragma unroll
    for (int c = 0; c < 10; ++c) {
        const int k = c * 32 + lane;
        const bool valid = k < kNQ;
        const int kk = valid ? k : (kNQ - 1);
        const float4* kr =
            (const float4*)(qk + ((size_t)(b * kNQ + kk)) * 512 + 256 + h * kDH);
        float dot = 0.f;
#pragma unroll
        for (int j = 0; j < 8; ++j) {
            float4 kv = kr[j];
            dot = fmaf(s_q[w][j * 4 + 0], kv.x, dot);
            dot = fmaf(s_q[w][j * 4 + 1], kv.y, dot);
            dot = fmaf(s_q[w][j * 4 + 2], kv.z, dot);
            dot = fmaf(s_q[w][j * 4 + 3], kv.w, dot);
        }
        dot *= scale;
        if (!valid) dot = -INFINITY;
        sc[c] = dot;
        m = fmaxf(m, dot);
    }
#pragma unroll
    for (int off = 16; off > 0; off >>= 1)
        m = fmaxf(m, __shfl_xor_sync(~0u, m, off));

    float sum = 0.f;
#pragma unroll
    for (int c = 0; c < 10; ++c) {
        const int k = c * 32 + lane;
        float e = (k < kNQ) ? expf(sc[c] - m) : 0.f;
        if (k < 320) s_p[w][k] = e;
        sum += e;
    }
#pragma unroll
    for (int off = 16; off > 0; off >>= 1)
        sum += __shfl_xor_sync(~0u, sum, off);
    const float inv = 1.f / sum;
    __syncwarp();

    float acc = 0.f;
    for (int k = 0; k < kNQ; ++k)
        acc = fmaf(s_p[w][k], v[((size_t)(b * kNQ + k)) * kD + h * kDH + lane], acc);

    o[((size_t)(b * kNQ + q)) * kD + h * kDH + lane] = acc * inv;
}

// ---------------------------------------------------------------------------
// Multi-scale deformable attention sampling.
// ---------------------------------------------------------------------------
__global__ void msdeform_kernel(const float* __restrict__ ref,
                                const float* __restrict__ off,
                                const float* __restrict__ awl,
                                const float* __restrict__ value,
                                float* __restrict__ out) {
    const int bq = blockIdx.x;
    const int b = bq / kNQ;
    const int t = threadIdx.x;
    const int h = t >> 5;
    const int lane = t & 31;

    __shared__ float s_p[kNH][16];

    float lw = (lane < 16) ? awl[(size_t)bq * 128 + h * 16 + lane] : -INFINITY;
    float m = lw;
#pragma unroll
    for (int o = 8; o > 0; o >>= 1) m = fmaxf(m, __shfl_xor_sync(~0u, m, o, 16));
    float e = (lane < 16) ? expf(lw - m) : 0.f;
    float sum = e;
#pragma unroll
    for (int o = 8; o > 0; o >>= 1) sum += __shfl_xor_sync(~0u, sum, o, 16);
    if (lane < 16) s_p[h][lane] = e / sum;
    __syncwarp();

    const int cH[kNL]  = {100, 50, 25, 13};
    const int cW[kNL]  = {150, 75, 38, 19};
    const int cS0[kNL] = {0, 15000, 18750, 19700};

    float acc = 0.f;
#pragma unroll
    for (int l = 0; l < kNL; ++l) {
        const float rx = ref[((size_t)bq * kNL + l) * 2 + 0];
        const float ry = ref[((size_t)bq * kNL + l) * 2 + 1];
        const int Hl = cH[l], Wl = cW[l], s0 = cS0[l];
        const float fW = (float)Wl, fH = (float)Hl;
#pragma unroll
        for (int p = 0; p < kNP; ++p) {
            const size_t ob = (size_t)bq * 256 + (((h * kNL + l) * kNP + p) * 2);
            const float ox = off[ob + 0];
            const float oy = off[ob + 1];
            const float x = (rx + ox / fW) * fW - 0.5f;
            const float y = (ry + oy / fH) * fH - 0.5f;
            const float x0f = floorf(x), y0f = floorf(y);
            const float tx = x - x0f, ty = y - y0f;
            const int x0 = (int)x0f, y0 = (int)y0f;

            float samp = 0.f;
#pragma unroll
            for (int dy = 0; dy < 2; ++dy) {
#pragma unroll
                for (int dx = 0; dx < 2; ++dx) {
                    const int xi = x0 + dx, yi = y0 + dy;
                    const bool valid = (xi >= 0) & (xi < Wl) & (yi >= 0) & (yi < Hl);
                    if (valid) {
                        const float wgt = (dy ? ty : (1.f - ty)) * (dx ? tx : (1.f - tx));
                        const size_t vrow = (size_t)b * kS + s0 + yi * Wl + xi;
                        samp = fmaf(wgt, value[vrow * kD + h * kDH + lane], samp);
                    }
                }
            }
            acc = fmaf(s_p[h][l * kNP + p], samp, acc);
        }
    }
    out[(size_t)bq * kD + h * kDH + lane] = acc;
}

// ---------------------------------------------------------------------------
// Launch helpers
// ---------------------------------------------------------------------------
static inline void launch_gemm_big(const float* A, const float* W, const float* b,
                                   float* C, int M, int N, int K) {
    dim3 grid(N / 64, (M + 127) / 128);
    gemm_tf32_kernel<128, 64, false><<<grid, 256>>>(A, W, b, C, M, N, K);
}
static inline void launch_gemm_small(const float* A, const float* W, const float* b,
                                     float* C, int M, int N, int K, bool relu) {
    dim3 grid(N / 64, (M + 63) / 64);
    if (relu)
        gemm_tf32_kernel<64, 64, true><<<grid, 128>>>(A, W, b, C, M, N, K);
    else
        gemm_tf32_kernel<64, 64, false><<<grid, 128>>>(A, W, b, C, M, N, K);
}

extern "C" void kernel_launch(void* const* d_in, const int* in_sizes, int n_in,
                              void* d_out, int out_size) {
    const float* tgt    = (const float*)d_in[0];
    const float* pos    = (const float*)d_in[1];
    const float* ref    = (const float*)d_in[2];
    const float* memory = (const float*)d_in[3];
    const float* in_w  = (const float*)d_in[7];
    const float* in_b  = (const float*)d_in[8];
    const float* out_w = (const float*)d_in[9];
    const float* out_b = (const float*)d_in[10];
    const float* n1g = (const float*)d_in[11];
    const float* n1b = (const float*)d_in[12];
    const float* n2g = (const float*)d_in[13];
    const float* n2b = (const float*)d_in[14];
    const float* n3g = (const float*)d_in[15];
    const float* n3b = (const float*)d_in[16];
    const float* so_w = (const float*)d_in[17];
    const float* so_b = (const float*)d_in[18];
    const float* aw_w = (const float*)d_in[19];
    const float* aw_b = (const float*)d_in[20];
    const float* v_w  = (const float*)d_in[21];
    const float* v_b  = (const float*)d_in[22];
    const float* op_w = (const float*)d_in[23];
    const float* op_b = (const float*)d_in[24];
    const float* l1w  = (const float*)d_in[25];
    const float* l1b  = (const float*)d_in[26];
    const float* l2w  = (const float*)d_in[27];
    const float* l2b  = (const float*)d_in[28];

    float* scratch = nullptr;
    cudaGetSymbolAddress((void**)&scratch, g_scratch);

    float* s_qkadd = scratch + OFF_QKADD;
    float* s_qk    = scratch + OFF_QK;
    float* s_v     = scratch + OFF_V;
    float* s_attn  = scratch + OFF_ATTN;
    float* s_sa    = scratch + OFF_SA;
    float* s_tgt1  = scratch + OFF_TGT1;
    float* s_query = scratch + OFF_QUERY;
    float* s_offs  = scratch + OFF_OFFS;
    float* s_awl   = scratch + OFF_AWL;
    float* s_ms    = scratch + OFF_MS;
    float* s_t2    = scratch + OFF_T2;
    float* s_tgt2  = scratch + OFF_TGT2;
    float* s_hid   = scratch + OFF_HID;
    float* s_ffo   = scratch + OFF_FFO;
    float* s_val   = scratch + OFF_VAL;

    const int nQD = kMQ * kD;

    // ---- value projection (big GEMM, independent — launch first) ----
    launch_gemm_big(memory, v_w, v_b, s_val, kMV, kD, kD);

    // ---- self attention ----
    add_kernel<<<(nQD + 255) / 256, 256>>>(tgt, pos, s_qkadd, nQD);
    launch_gemm_small(s_qkadd, in_w, in_b, s_qk, kMQ, 2 * kD, kD, false);
    launch_gemm_small(tgt, in_w + 512 * kD, in_b + 512, s_v, kMQ, kD, kD, false);
    {
        dim3 grid((kNQ + 7) / 8, kNH, kBS);
        self_attn_kernel<<<grid, 256>>>(s_qk, s_v, s_attn);
    }
    launch_gemm_small(s_attn, out_w, out_b, s_sa, kMQ, kD, kD, false);
    add_ln_kernel<<<kMQ, 256>>>(tgt, s_sa, n2g, n2b, s_tgt1);

    // ---- MS deformable attention ----
    add_kernel<<<(nQD + 255) / 256, 256>>>(s_tgt1, pos, s_query, nQD);
    launch_gemm_small(s_query, so_w, so_b, s_offs, kMQ, kD, kD, false);
    launch_gemm_small(s_query, aw_w, aw_b, s_awl, kMQ, 128, kD, false);
    msdeform_kernel<<<kMQ, 256>>>(ref, s_offs, s_awl, s_val, s_ms);
    launch_gemm_small(s_ms, op_w, op_b, s_t2, kMQ, kD, kD, false);
    add_ln_kernel<<<kMQ, 256>>>(s_tgt1, s_t2, n1g, n1b, s_tgt2);

    // ---- FFN ----
    launch_gemm_small(s_tgt2, l1w, l1b, s_hid, kMQ, kDFF, kD, true);
    launch_gemm_small(s_hid, l2w, l2b, s_ffo, kMQ, kD, kDFF, false);
    add_ln_kernel<<<kMQ, 256>>>(s_tgt2, s_ffo, n3g, n3b, (float*)d_out);
}

// round 4
// speedup vs baseline: 2.9410x; 1.0851x over previous
#include <cuda_runtime.h>
#include <math.h>
#include <stdint.h>

// ---------------------------------------------------------------------------
// Problem constants
// ---------------------------------------------------------------------------
namespace {
constexpr int kD   = 256;
constexpr int kNH  = 8;
constexpr int kDH  = 32;
constexpr int kNL  = 4;
constexpr int kNP  = 4;
constexpr int kDFF = 1024;
constexpr int kBS  = 8;
constexpr int kNQ  = 300;
constexpr int kS   = 19947;
constexpr int kMQ  = kBS * kNQ;      // 2400
constexpr int kMV  = kBS * kS;       // 159576

constexpr size_t OFF_QKADD = 0;
constexpr size_t OFF_QK    = OFF_QKADD + (size_t)kMQ * kD;
constexpr size_t OFF_V     = OFF_QK    + (size_t)kMQ * 2 * kD;
constexpr size_t OFF_ATTN  = OFF_V     + (size_t)kMQ * kD;
constexpr size_t OFF_SA    = OFF_ATTN  + (size_t)kMQ * kD;
constexpr size_t OFF_TGT1  = OFF_SA    + (size_t)kMQ * kD;
constexpr size_t OFF_QUERY = OFF_TGT1  + (size_t)kMQ * kD;
constexpr size_t OFF_OFFS  = OFF_QUERY + (size_t)kMQ * kD;
constexpr size_t OFF_AWL   = OFF_OFFS  + (size_t)kMQ * kD;
constexpr size_t OFF_MS    = OFF_AWL   + (size_t)kMQ * 128;
constexpr size_t OFF_T2    = OFF_MS    + (size_t)kMQ * kD;
constexpr size_t OFF_TGT2  = OFF_T2    + (size_t)kMQ * kD;
constexpr size_t OFF_HID   = OFF_TGT2  + (size_t)kMQ * kD;
constexpr size_t OFF_FFO   = OFF_HID   + (size_t)kMQ * kDFF;
constexpr size_t OFF_VAL   = OFF_FFO   + (size_t)kMQ * kD;
constexpr size_t SCRATCH_TOTAL = OFF_VAL + (size_t)kMV * kD;
} // namespace

__device__ float g_scratch[SCRATCH_TOTAL];

// ---------------------------------------------------------------------------
// helpers
// ---------------------------------------------------------------------------
__device__ __forceinline__ uint32_t smem_u32(const void* p) {
    uint32_t a;
    asm("{ .reg .u64 t; cvta.to.shared.u64 t, %1; cvt.u32.u64 %0, t; }"
        : "=r"(a) : "l"(p));
    return a;
}

__device__ __forceinline__ void cp_async16(uint32_t dst, const void* src, bool pred) {
    int sz = pred ? 16 : 0;
    asm volatile("cp.async.cg.shared.global [%0], [%1], 16, %2;"
                 :: "r"(dst), "l"(src), "r"(sz));
}
__device__ __forceinline__ void cp_commit() {
    asm volatile("cp.async.commit_group;");
}
template <int N>
__device__ __forceinline__ void cp_wait() {
    asm volatile("cp.async.wait_group %0;" :: "n"(N));
}

__device__ __forceinline__ void mma_tf32(float (&d)[4],
                                         const uint32_t (&a)[4],
                                         const uint32_t (&b)[2]) {
    asm volatile(
        "mma.sync.aligned.m16n8k8.row.col.f32.tf32.tf32.f32 "
        "{%0,%1,%2,%3}, {%4,%5,%6,%7}, {%8,%9}, {%0,%1,%2,%3};"
        : "+f"(d[0]), "+f"(d[1]), "+f"(d[2]), "+f"(d[3])
        : "r"(a[0]), "r"(a[1]), "r"(a[2]), "r"(a[3]),
          "r"(b[0]), "r"(b[1]));
}

// ---------------------------------------------------------------------------
// TF32 tensor-core GEMM: C[M,N] = act(A[M,K] @ W[N,K]^T + bias[N])
// Block tile BM x BN, BK=32, WM x WN warps, warp tile (BM/WM) x (BN/WN).
// Multi-stage cp.async pipeline (STAGES), dynamic SMEM.
// Requires: N % BN == 0, K % 32 == 0.
// ---------------------------------------------------------------------------
template <int BM, int BN, int WM, int WN, int STAGES, bool RELU>
__global__ __launch_bounds__(WM * WN * 32, 2)
void gemm_tf32_kernel(const float* __restrict__ A,
                      const float* __restrict__ W,
                      const float* __restrict__ bias,
                      float* __restrict__ C,
                      int M, int N, int K) {
    constexpr int BK = 32;
    constexpr int LD = BK + 4;                 // 36 words/row
    constexpr int THREADS = WM * WN * 32;
    constexpr int WTM = BM / WM;
    constexpr int WTN = BN / WN;
    constexpr int MT = WTM / 16;
    constexpr int NT = WTN / 8;
    constexpr int A_IT = (BM * BK / 4) / THREADS;
    constexpr int B_IT = (BN * BK / 4) / THREADS;

    extern __shared__ float smem[];
    float* As = smem;                          // STAGES * BM * LD
    float* Ws = smem + (size_t)STAGES * BM * LD;

    const int tid  = threadIdx.x;
    const int warp = tid >> 5;
    const int lane = tid & 31;
    const int g    = lane >> 2;
    const int tg   = lane & 3;
    const int tm   = blockIdx.y * BM;
    const int tn   = blockIdx.x * BN;
    const int wm   = (warp % WM) * WTM;
    const int wn   = (warp / WM) * WTN;

    float acc[MT][NT][4] = {};
    const int NK = K / BK;

    auto issue = [&](int s, int kt) {
        if (kt < NK) {
            const int k0 = kt * BK;
#pragma unroll
            for (int i = 0; i < A_IT; ++i) {
                int idx = tid + i * THREADS;
                int r = idx >> 3, c4 = (idx & 7) * 4;
                int gr = tm + r;
                cp_async16(smem_u32(&As[(size_t)s * BM * LD + r * LD + c4]),
                           A + (size_t)gr * K + k0 + c4, gr < M);
            }
#pragma unroll
            for (int i = 0; i < B_IT; ++i) {
                int idx = tid + i * THREADS;
                int r = idx >> 3, c4 = (idx & 7) * 4;
                cp_async16(smem_u32(&Ws[(size_t)s * BN * LD + r * LD + c4]),
                           W + (size_t)(tn + r) * K + k0 + c4, true);
            }
        }
        cp_commit();
    };

    issue(0, 0);
    if (STAGES > 2) issue(1, 1);

    for (int kt = 0; kt < NK; ++kt) {
        const int s = kt % STAGES;
        cp_wait<STAGES - 2>();
        __syncthreads();
        issue((kt + STAGES - 1) % STAGES, kt + STAGES - 1);

        const float* as = &As[(size_t)s * BM * LD];
        const float* ws = &Ws[(size_t)s * BN * LD];
#pragma unroll
        for (int ks = 0; ks < 4; ++ks) {
            const int kc = ks * 8 + tg;
            uint32_t af[MT][4], bf[NT][2];
#pragma unroll
            for (int mt = 0; mt < MT; ++mt) {
                const int r = wm + mt * 16 + g;
                af[mt][0] = __float_as_uint(as[r * LD + kc]);
                af[mt][1] = __float_as_uint(as[(r + 8) * LD + kc]);
                af[mt][2] = __float_as_uint(as[r * LD + kc + 4]);
                af[mt][3] = __float_as_uint(as[(r + 8) * LD + kc + 4]);
            }
#pragma unroll
            for (int nt = 0; nt < NT; ++nt) {
                const int n = wn + nt * 8 + g;
                bf[nt][0] = __float_as_uint(ws[n * LD + kc]);
                bf[nt][1] = __float_as_uint(ws[n * LD + kc + 4]);
            }
#pragma unroll
            for (int mt = 0; mt < MT; ++mt)
#pragma unroll
                for (int nt = 0; nt < NT; ++nt)
                    mma_tf32(acc[mt][nt], af[mt], bf[nt]);
        }
        __syncthreads();
    }

#pragma unroll
    for (int mt = 0; mt < MT; ++mt) {
        const int gr0 = tm + wm + mt * 16 + g;
        const int gr1 = gr0 + 8;
#pragma unroll
        for (int nt = 0; nt < NT; ++nt) {
            const int gc = tn + wn + nt * 8 + tg * 2;
            const float b0 = bias[gc], b1 = bias[gc + 1];
            if (gr0 < M) {
                float v0 = acc[mt][nt][0] + b0;
                float v1 = acc[mt][nt][1] + b1;
                if (RELU) { v0 = fmaxf(v0, 0.f); v1 = fmaxf(v1, 0.f); }
                *(float2*)(C + (size_t)gr0 * N + gc) = make_float2(v0, v1);
            }
            if (gr1 < M) {
                float v2 = acc[mt][nt][2] + b0;
                float v3 = acc[mt][nt][3] + b1;
                if (RELU) { v2 = fmaxf(v2, 0.f); v3 = fmaxf(v3, 0.f); }
                *(float2*)(C + (size_t)gr1 * N + gc) = make_float2(v2, v3);
            }
        }
    }
}

// SMEM bytes for a config
template <int BM, int BN, int STAGES>
constexpr int gemm_smem_bytes() { return STAGES * (BM + BN) * 36 * 4; }

// ---------------------------------------------------------------------------
// Elementwise add
// ---------------------------------------------------------------------------
__global__ void add_kernel(const float* __restrict__ a,
                           const float* __restrict__ b,
                           float* __restrict__ out, int n) {
    int i = blockIdx.x * blockDim.x + threadIdx.x;
    if (i < n) out[i] = a[i] + b[i];
}

// ---------------------------------------------------------------------------
// Residual + LayerNorm (256 features, one block per row)
// ---------------------------------------------------------------------------
__global__ void add_ln_kernel(const float* __restrict__ x,
                              const float* __restrict__ r,
                              const float* __restrict__ g,
                              const float* __restrict__ bta,
                              float* __restrict__ out) {
    const int row = blockIdx.x;
    const int t = threadIdx.x;
    const size_t base = (size_t)row * kD;
    float v = x[base + t] + r[base + t];

    __shared__ float sm[8];
    float s = v;
#pragma unroll
    for (int o = 16; o > 0; o >>= 1) s += __shfl_xor_sync(~0u, s, o);
    if ((t & 31) == 0) sm[t >> 5] = s;
    __syncthreads();
    float tot = 0.f;
#pragma unroll
    for (int i = 0; i < 8; ++i) tot += sm[i];
    const float mean = tot * (1.f / kD);
    const float d = v - mean;
    float s2 = d * d;
#pragma unroll
    for (int o = 16; o > 0; o >>= 1) s2 += __shfl_xor_sync(~0u, s2, o);
    __syncthreads();
    if ((t & 31) == 0) sm[t >> 5] = s2;
    __syncthreads();
    float tot2 = 0.f;
#pragma unroll
    for (int i = 0; i < 8; ++i) tot2 += sm[i];
    const float var = tot2 * (1.f / kD);
    out[base + t] = d * rsqrtf(var + 1e-5f) * g[t] + bta[t];
}

// ---------------------------------------------------------------------------
// Self attention. One warp per (b, h, q).
// ---------------------------------------------------------------------------
__global__ void self_attn_kernel(const float* __restrict__ qk,
                                 const float* __restrict__ v,
                                 float* __restrict__ o) {
    const int w = threadIdx.x >> 5;
    const int lane = threadIdx.x & 31;
    const int q = blockIdx.x * 8 + w;
    const int h = blockIdx.y;
    const int b = blockIdx.z;
    __shared__ float s_p[8][320];
    __shared__ float s_q[8][32];
    if (q >= kNQ) return;

    const float scale = 0.1767766952966369f;  // 1/sqrt(32)
    s_q[w][lane] = qk[((size_t)(b * kNQ + q)) * 512 + h * kDH + lane];
    __syncwarp();

    float sc[10];
    float m = -INFINITY;
#pragma unroll
    for (int c = 0; c < 10; ++c) {
        const int k = c * 32 + lane;
        const bool valid = k < kNQ;
        const int kk = valid ? k : (kNQ - 1);
        const float4* kr =
            (const float4*)(qk + ((size_t)(b * kNQ + kk)) * 512 + 256 + h * kDH);
        float dot = 0.f;
#pragma unroll
        for (int j = 0; j < 8; ++j) {
            float4 kv = kr[j];
            dot = fmaf(s_q[w][j * 4 + 0], kv.x, dot);
            dot = fmaf(s_q[w][j * 4 + 1], kv.y, dot);
            dot = fmaf(s_q[w][j * 4 + 2], kv.z, dot);
            dot = fmaf(s_q[w][j * 4 + 3], kv.w, dot);
        }
        dot *= scale;
        if (!valid) dot = -INFINITY;
        sc[c] = dot;
        m = fmaxf(m, dot);
    }
#pragma unroll
    for (int off = 16; off > 0; off >>= 1)
        m = fmaxf(m, __shfl_xor_sync(~0u, m, off));

    float sum = 0.f;
#pragma unroll
    for (int c = 0; c < 10; ++c) {
        const int k = c * 32 + lane;
        float e = (k < kNQ) ? expf(sc[c] - m) : 0.f;
        if (k < 320) s_p[w][k] = e;
        sum += e;
    }
#pragma unroll
    for (int off = 16; off > 0; off >>= 1)
        sum += __shfl_xor_sync(~0u, sum, off);
    const float inv = 1.f / sum;
    __syncwarp();

    float acc = 0.f;
    for (int k = 0; k < kNQ; ++k)
        acc = fmaf(s_p[w][k], v[((size_t)(b * kNQ + k)) * kD + h * kDH + lane], acc);

    o[((size_t)(b * kNQ + q)) * kD + h * kDH + lane] = acc * inv;
}

// ---------------------------------------------------------------------------
// Multi-scale deformable attention sampling.
// ---------------------------------------------------------------------------
__global__ void msdeform_kernel(const float* __restrict__ ref,
                                const float* __restrict__ off,
                                const float* __restrict__ awl,
                                const float* __restrict__ value,
                                float* __restrict__ out) {
    const int bq = blockIdx.x;
    const int b = bq / kNQ;
    const int t = threadIdx.x;
    const int h = t >> 5;
    const int lane = t & 31;

    __shared__ float s_p[kNH][16];

    float lw = (lane < 16) ? awl[(size_t)bq * 128 + h * 16 + lane] : -INFINITY;
    float m = lw;
#pragma unroll
    for (int o = 8; o > 0; o >>= 1) m = fmaxf(m, __shfl_xor_sync(~0u, m, o, 16));
    float e = (lane < 16) ? expf(lw - m) : 0.f;
    float sum = e;
#pragma unroll
    for (int o = 8; o > 0; o >>= 1) sum += __shfl_xor_sync(~0u, sum, o, 16);
    if (lane < 16) s_p[h][lane] = e / sum;
    __syncwarp();

    const int cH[kNL]  = {100, 50, 25, 13};
    const int cW[kNL]  = {150, 75, 38, 19};
    const int cS0[kNL] = {0, 15000, 18750, 19700};

    float acc = 0.f;
#pragma unroll
    for (int l = 0; l < kNL; ++l) {
        const float rx = ref[((size_t)bq * kNL + l) * 2 + 0];
        const float ry = ref[((size_t)bq * kNL + l) * 2 + 1];
        const int Hl = cH[l], Wl = cW[l], s0 = cS0[l];
        const float fW = (float)Wl, fH = (float)Hl;
#pragma unroll
        for (int p = 0; p < kNP; ++p) {
            const size_t ob = (size_t)bq * 256 + (((h * kNL + l) * kNP + p) * 2);
            const float ox = off[ob + 0];
            const float oy = off[ob + 1];
            const float x = (rx + ox / fW) * fW - 0.5f;
            const float y = (ry + oy / fH) * fH - 0.5f;
            const float x0f = floorf(x), y0f = floorf(y);
            const float tx = x - x0f, ty = y - y0f;
            const int x0 = (int)x0f, y0 = (int)y0f;

            float samp = 0.f;
#pragma unroll
            for (int dy = 0; dy < 2; ++dy) {
#pragma unroll
                for (int dx = 0; dx < 2; ++dx) {
                    const int xi = x0 + dx, yi = y0 + dy;
                    const bool valid = (xi >= 0) & (xi < Wl) & (yi >= 0) & (yi < Hl);
                    if (valid) {
                        const float wgt = (dy ? ty : (1.f - ty)) * (dx ? tx : (1.f - tx));
                        const size_t vrow = (size_t)b * kS + s0 + yi * Wl + xi;
                        samp = fmaf(wgt, value[vrow * kD + h * kDH + lane], samp);
                    }
                }
            }
            acc = fmaf(s_p[h][l * kNP + p], samp, acc);
        }
    }
    out[(size_t)bq * kD + h * kDH + lane] = acc;
}

// ---------------------------------------------------------------------------
// Launch helpers
// ---------------------------------------------------------------------------
static inline void launch_gemm_big(const float* A, const float* W, const float* b,
                                   float* C, int M, int N, int K) {
    constexpr int SM = gemm_smem_bytes<128, 128, 3>();
    static bool attr_set = false;
    if (!attr_set) {
        cudaFuncSetAttribute((const void*)gemm_tf32_kernel<128, 128, 2, 4, 3, false>,
                             cudaFuncAttributeMaxDynamicSharedMemorySize, SM);
        attr_set = true;
    }
    dim3 grid(N / 128, (M + 127) / 128);
    gemm_tf32_kernel<128, 128, 2, 4, 3, false><<<grid, 256, SM>>>(A, W, b, C, M, N, K);
}

static inline void launch_gemm_small(const float* A, const float* W, const float* b,
                                     float* C, int M, int N, int K, bool relu) {
    constexpr int SM = gemm_smem_bytes<64, 64, 3>();
    static bool attr_set = false;
    if (!attr_set) {
        cudaFuncSetAttribute((const void*)gemm_tf32_kernel<64, 64, 2, 2, 3, false>,
                             cudaFuncAttributeMaxDynamicSharedMemorySize, SM);
        cudaFuncSetAttribute((const void*)gemm_tf32_kernel<64, 64, 2, 2, 3, true>,
                             cudaFuncAttributeMaxDynamicSharedMemorySize, SM);
        attr_set = true;
    }
    dim3 grid(N / 64, (M + 63) / 64);
    if (relu)
        gemm_tf32_kernel<64, 64, 2, 2, 3, true><<<grid, 128, SM>>>(A, W, b, C, M, N, K);
    else
        gemm_tf32_kernel<64, 64, 2, 2, 3, false><<<grid, 128, SM>>>(A, W, b, C, M, N, K);
}

extern "C" void kernel_launch(void* const* d_in, const int* in_sizes, int n_in,
                              void* d_out, int out_size) {
    const float* tgt    = (const float*)d_in[0];
    const float* pos    = (const float*)d_in[1];
    const float* ref    = (const float*)d_in[2];
    const float* memory = (const float*)d_in[3];
    const float* in_w  = (const float*)d_in[7];
    const float* in_b  = (const float*)d_in[8];
    const float* out_w = (const float*)d_in[9];
    const float* out_b = (const float*)d_in[10];
    const float* n1g = (const float*)d_in[11];
    const float* n1b = (const float*)d_in[12];
    const float* n2g = (const float*)d_in[13];
    const float* n2b = (const float*)d_in[14];
    const float* n3g = (const float*)d_in[15];
    const float* n3b = (const float*)d_in[16];
    const float* so_w = (const float*)d_in[17];
    const float* so_b = (const float*)d_in[18];
    const float* aw_w = (const float*)d_in[19];
    const float* aw_b = (const float*)d_in[20];
    const float* v_w  = (const float*)d_in[21];
    const float* v_b  = (const float*)d_in[22];
    const float* op_w = (const float*)d_in[23];
    const float* op_b = (const float*)d_in[24];
    const float* l1w  = (const float*)d_in[25];
    const float* l1b  = (const float*)d_in[26];
    const float* l2w  = (const float*)d_in[27];
    const float* l2b  = (const float*)d_in[28];

    float* scratch = nullptr;
    cudaGetSymbolAddress((void**)&scratch, g_scratch);

    float* s_qkadd = scratch + OFF_QKADD;
    float* s_qk    = scratch + OFF_QK;
    float* s_v     = scratch + OFF_V;
    float* s_attn  = scratch + OFF_ATTN;
    float* s_sa    = scratch + OFF_SA;
    float* s_tgt1  = scratch + OFF_TGT1;
    float* s_query = scratch + OFF_QUERY;
    float* s_offs  = scratch + OFF_OFFS;
    float* s_awl   = scratch + OFF_AWL;
    float* s_ms    = scratch + OFF_MS;
    float* s_t2    = scratch + OFF_T2;
    float* s_tgt2  = scratch + OFF_TGT2;
    float* s_hid   = scratch + OFF_HID;
    float* s_ffo   = scratch + OFF_FFO;
    float* s_val   = scratch + OFF_VAL;

    const int nQD = kMQ * kD;

    // ---- value projection (big GEMM, independent — launch first) ----
    launch_gemm_big(memory, v_w, v_b, s_val, kMV, kD, kD);

    // ---- self attention ----
    add_kernel<<<(nQD + 255) / 256, 256>>>(tgt, pos, s_qkadd, nQD);
    launch_gemm_small(s_qkadd, in_w, in_b, s_qk, kMQ, 2 * kD, kD, false);
    launch_gemm_small(tgt, in_w + 512 * kD, in_b + 512, s_v, kMQ, kD, kD, false);
    {
        dim3 grid((kNQ + 7) / 8, kNH, kBS);
        self_attn_kernel<<<grid, 256>>>(s_qk, s_v, s_attn);
    }
    launch_gemm_small(s_attn, out_w, out_b, s_sa, kMQ, kD, kD, false);
    add_ln_kernel<<<kMQ, 256>>>(tgt, s_sa, n2g, n2b, s_tgt1);

    // ---- MS deformable attention ----
    add_kernel<<<(nQD + 255) / 256, 256>>>(s_tgt1, pos, s_query, nQD);
    launch_gemm_small(s_query, so_w, so_b, s_offs, kMQ, kD, kD, false);
    launch_gemm_small(s_query, aw_w, aw_b, s_awl, kMQ, 128, kD, false);
    msdeform_kernel<<<kMQ, 256>>>(ref, s_offs, s_awl, s_val, s_ms);
    launch_gemm_small(s_ms, op_w, op_b, s_t2, kMQ, kD, kD, false);
    add_ln_kernel<<<kMQ, 256>>>(s_tgt1, s_t2, n1g, n1b, s_tgt2);

    // ---- FFN ----
    launch_gemm_small(s_tgt2, l1w, l1b, s_hid, kMQ, kDFF, kD, true);
    launch_gemm_small(s_hid, l2w, l2b, s_ffo, kMQ, kD, kDFF, false);
    add_ln_kernel<<<kMQ, 256>>>(s_tgt2, s_ffo, n3g, n3b, (float*)d_out);
}

// round 5
// speedup vs baseline: 3.2083x; 1.0909x over previous
#include <cuda_runtime.h>
#include <math.h>
#include <stdint.h>

// ---------------------------------------------------------------------------
// Problem constants
// ---------------------------------------------------------------------------
namespace {
constexpr int kD   = 256;
constexpr int kNH  = 8;
constexpr int kDH  = 32;
constexpr int kNL  = 4;
constexpr int kNP  = 4;
constexpr int kDFF = 1024;
constexpr int kBS  = 8;
constexpr int kNQ  = 300;
constexpr int kS   = 19947;
constexpr int kMQ  = kBS * kNQ;      // 2400
constexpr int kAK  = 2080;           // agg K: 8*256 + 8 bias + 24 pad (65*32)

constexpr size_t OFF_QKADD = 0;
constexpr size_t OFF_QK    = OFF_QKADD + (size_t)kMQ * kD;
constexpr size_t OFF_V     = OFF_QK    + (size_t)kMQ * 2 * kD;
constexpr size_t OFF_ATTN  = OFF_V     + (size_t)kMQ * kD;
constexpr size_t OFF_SA    = OFF_ATTN  + (size_t)kMQ * kD;
constexpr size_t OFF_TGT1  = OFF_SA    + (size_t)kMQ * kD;
constexpr size_t OFF_QUERY = OFF_TGT1  + (size_t)kMQ * kD;
constexpr size_t OFF_OFFS  = OFF_QUERY + (size_t)kMQ * kD;
constexpr size_t OFF_AWL   = OFF_OFFS  + (size_t)kMQ * kD;
constexpr size_t OFF_T2    = OFF_AWL   + (size_t)kMQ * 128;
constexpr size_t OFF_TGT2  = OFF_T2    + (size_t)kMQ * kD;
constexpr size_t OFF_HID   = OFF_TGT2  + (size_t)kMQ * kD;
constexpr size_t OFF_FFO   = OFF_HID   + (size_t)kMQ * kDFF;
constexpr size_t OFF_AGG   = OFF_FFO   + (size_t)kMQ * kD;
constexpr size_t OFF_WM    = OFF_AGG   + (size_t)kMQ * kAK;
constexpr size_t SCRATCH_TOTAL = OFF_WM + (size_t)kD * kAK;
} // namespace

__device__ float g_scratch[SCRATCH_TOTAL];

// ---------------------------------------------------------------------------
// helpers
// ---------------------------------------------------------------------------
__device__ __forceinline__ uint32_t smem_u32(const void* p) {
    uint32_t a;
    asm("{ .reg .u64 t; cvta.to.shared.u64 t, %1; cvt.u32.u64 %0, t; }"
        : "=r"(a) : "l"(p));
    return a;
}

__device__ __forceinline__ void cp_async16(uint32_t dst, const void* src, bool pred) {
    int sz = pred ? 16 : 0;
    asm volatile("cp.async.cg.shared.global [%0], [%1], 16, %2;"
                 :: "r"(dst), "l"(src), "r"(sz));
}
__device__ __forceinline__ void cp_commit() {
    asm volatile("cp.async.commit_group;");
}
template <int N>
__device__ __forceinline__ void cp_wait() {
    asm volatile("cp.async.wait_group %0;" :: "n"(N));
}

__device__ __forceinline__ void mma_tf32(float (&d)[4],
                                         const uint32_t (&a)[4],
                                         const uint32_t (&b)[2]) {
    asm volatile(
        "mma.sync.aligned.m16n8k8.row.col.f32.tf32.tf32.f32 "
        "{%0,%1,%2,%3}, {%4,%5,%6,%7}, {%8,%9}, {%0,%1,%2,%3};"
        : "+f"(d[0]), "+f"(d[1]), "+f"(d[2]), "+f"(d[3])
        : "r"(a[0]), "r"(a[1]), "r"(a[2]), "r"(a[3]),
          "r"(b[0]), "r"(b[1]));
}

// ---------------------------------------------------------------------------
// TF32 tensor-core GEMM: C[M,N] = act(A[M,K] @ W[N,K]^T + bias[N])
// Block tile BM x BN, BK=32, WM x WN warps, multi-stage cp.async.
// Requires N % BN == 0, K % 32 == 0.
// ---------------------------------------------------------------------------
template <int BM, int BN, int WM, int WN, int STAGES, bool RELU>
__global__ __launch_bounds__(WM * WN * 32, 2)
void gemm_tf32_kernel(const float* __restrict__ A,
                      const float* __restrict__ W,
                      const float* __restrict__ bias,
                      float* __restrict__ C,
                      int M, int N, int K) {
    constexpr int BK = 32;
    constexpr int LD = BK + 4;                 // 36 words/row
    constexpr int THREADS = WM * WN * 32;
    constexpr int WTM = BM / WM;
    constexpr int WTN = BN / WN;
    constexpr int MT = WTM / 16;
    constexpr int NT = WTN / 8;
    constexpr int A_IT = (BM * BK / 4) / THREADS;
    constexpr int B_IT = (BN * BK / 4) / THREADS;

    extern __shared__ float smem[];
    float* As = smem;                          // STAGES * BM * LD
    float* Ws = smem + (size_t)STAGES * BM * LD;

    const int tid  = threadIdx.x;
    const int warp = tid >> 5;
    const int lane = tid & 31;
    const int g    = lane >> 2;
    const int tg   = lane & 3;
    const int tm   = blockIdx.y * BM;
    const int tn   = blockIdx.x * BN;
    const int wm   = (warp % WM) * WTM;
    const int wn   = (warp / WM) * WTN;

    float acc[MT][NT][4] = {};
    const int NK = K / BK;

    auto issue = [&](int s, int kt) {
        if (kt < NK) {
            const int k0 = kt * BK;
#pragma unroll
            for (int i = 0; i < A_IT; ++i) {
                int idx = tid + i * THREADS;
                int r = idx >> 3, c4 = (idx & 7) * 4;
                int gr = tm + r;
                cp_async16(smem_u32(&As[(size_t)s * BM * LD + r * LD + c4]),
                           A + (size_t)gr * K + k0 + c4, gr < M);
            }
#pragma unroll
            for (int i = 0; i < B_IT; ++i) {
                int idx = tid + i * THREADS;
                int r = idx >> 3, c4 = (idx & 7) * 4;
                cp_async16(smem_u32(&Ws[(size_t)s * BN * LD + r * LD + c4]),
                           W + (size_t)(tn + r) * K + k0 + c4, true);
            }
        }
        cp_commit();
    };

    issue(0, 0);
    if (STAGES > 2) issue(1, 1);

    for (int kt = 0; kt < NK; ++kt) {
        const int s = kt % STAGES;
        cp_wait<STAGES - 2>();
        __syncthreads();
        issue((kt + STAGES - 1) % STAGES, kt + STAGES - 1);

        const float* as = &As[(size_t)s * BM * LD];
        const float* ws = &Ws[(size_t)s * BN * LD];
#pragma unroll
        for (int ks = 0; ks < 4; ++ks) {
            const int kc = ks * 8 + tg;
            uint32_t af[MT][4], bf[NT][2];
#pragma unroll
            for (int mt = 0; mt < MT; ++mt) {
                const int r = wm + mt * 16 + g;
                af[mt][0] = __float_as_uint(as[r * LD + kc]);
                af[mt][1] = __float_as_uint(as[(r + 8) * LD + kc]);
                af[mt][2] = __float_as_uint(as[r * LD + kc + 4]);
                af[mt][3] = __float_as_uint(as[(r + 8) * LD + kc + 4]);
            }
#pragma unroll
            for (int nt = 0; nt < NT; ++nt) {
                const int n = wn + nt * 8 + g;
                bf[nt][0] = __float_as_uint(ws[n * LD + kc]);
                bf[nt][1] = __float_as_uint(ws[n * LD + kc + 4]);
            }
#pragma unroll
            for (int mt = 0; mt < MT; ++mt)
#pragma unroll
                for (int nt = 0; nt < NT; ++nt)
                    mma_tf32(acc[mt][nt], af[mt], bf[nt]);
        }
        __syncthreads();
    }

#pragma unroll
    for (int mt = 0; mt < MT; ++mt) {
        const int gr0 = tm + wm + mt * 16 + g;
        const int gr1 = gr0 + 8;
#pragma unroll
        for (int nt = 0; nt < NT; ++nt) {
            const int gc = tn + wn + nt * 8 + tg * 2;
            const float b0 = bias[gc], b1 = bias[gc + 1];
            if (gr0 < M) {
                float v0 = acc[mt][nt][0] + b0;
                float v1 = acc[mt][nt][1] + b1;
                if (RELU) { v0 = fmaxf(v0, 0.f); v1 = fmaxf(v1, 0.f); }
                *(float2*)(C + (size_t)gr0 * N + gc) = make_float2(v0, v1);
            }
            if (gr1 < M) {
                float v2 = acc[mt][nt][2] + b0;
                float v3 = acc[mt][nt][3] + b1;
                if (RELU) { v2 = fmaxf(v2, 0.f); v3 = fmaxf(v3, 0.f); }
                *(float2*)(C + (size_t)gr1 * N + gc) = make_float2(v2, v3);
            }
        }
    }
}

template <int BM, int BN, int STAGES>
constexpr int gemm_smem_bytes() { return STAGES * (BM + BN) * 36 * 4; }

// ---------------------------------------------------------------------------
// Build Wm[256, 2080]: cols h*256+i = sum_j op_w[o,32h+j]*value_w[32h+j,i],
// col 2048+h = sum_j op_w[o,32h+j]*value_b[32h+j], cols 2056..2079 = 0.
// grid = (8 heads, 8 row-tiles of 32), block = 256.
// ---------------------------------------------------------------------------
__global__ void build_wm_kernel(const float* __restrict__ op_w,
                                const float* __restrict__ v_w,
                                const float* __restrict__ v_b,
                                float* __restrict__ wm) {
    const int h  = blockIdx.x;
    const int ot = blockIdx.y * 32;
    const int tid = threadIdx.x;
    __shared__ float vs[32][256];

    for (int idx = tid; idx < 32 * 256; idx += 256) {
        int r = idx >> 8, c = idx & 255;
        vs[r][c] = v_w[(size_t)(32 * h + r) * 256 + c];
    }
    __syncthreads();

    for (int oo = 0; oo < 32; ++oo) {
        const int o = ot + oo;
        const float* opr = op_w + (size_t)o * 256 + 32 * h;
        float s = 0.f;
#pragma unroll
        for (int j = 0; j < 32; ++j) s = fmaf(opr[j], vs[j][tid], s);
        wm[(size_t)o * kAK + h * 256 + tid] = s;
    }
    if (tid < 32) {
        const int o = ot + tid;
        const float* opr = op_w + (size_t)o * 256 + 32 * h;
        float s = 0.f;
#pragma unroll
        for (int j = 0; j < 32; ++j) s = fmaf(opr[j], v_b[32 * h + j], s);
        wm[(size_t)o * kAK + 2048 + h] = s;
        if (h == 0)
            for (int z = 2056; z < kAK; ++z) wm[(size_t)o * kAK + z] = 0.f;
    }
}

// ---------------------------------------------------------------------------
// Elementwise add
// ---------------------------------------------------------------------------
__global__ void add_kernel(const float* __restrict__ a,
                           const float* __restrict__ b,
                           float* __restrict__ out, int n) {
    int i = blockIdx.x * blockDim.x + threadIdx.x;
    if (i < n) out[i] = a[i] + b[i];
}

// ---------------------------------------------------------------------------
// Residual + LayerNorm (256 features, one block per row)
// ---------------------------------------------------------------------------
__global__ void add_ln_kernel(const float* __restrict__ x,
                              const float* __restrict__ r,
                              const float* __restrict__ g,
                              const float* __restrict__ bta,
                              float* __restrict__ out) {
    const int row = blockIdx.x;
    const int t = threadIdx.x;
    const size_t base = (size_t)row * kD;
    float v = x[base + t] + r[base + t];

    __shared__ float sm[8];
    float s = v;
#pragma unroll
    for (int o = 16; o > 0; o >>= 1) s += __shfl_xor_sync(~0u, s, o);
    if ((t & 31) == 0) sm[t >> 5] = s;
    __syncthreads();
    float tot = 0.f;
#pragma unroll
    for (int i = 0; i < 8; ++i) tot += sm[i];
    const float mean = tot * (1.f / kD);
    const float d = v - mean;
    float s2 = d * d;
#pragma unroll
    for (int o = 16; o > 0; o >>= 1) s2 += __shfl_xor_sync(~0u, s2, o);
    __syncthreads();
    if ((t & 31) == 0) sm[t >> 5] = s2;
    __syncthreads();
    float tot2 = 0.f;
#pragma unroll
    for (int i = 0; i < 8; ++i) tot2 += sm[i];
    const float var = tot2 * (1.f / kD);
    out[base + t] = d * rsqrtf(var + 1e-5f) * g[t] + bta[t];
}

// ---------------------------------------------------------------------------
// Self attention. One warp per (b, h, q).
// ---------------------------------------------------------------------------
__global__ void self_attn_kernel(const float* __restrict__ qk,
                                 const float* __restrict__ v,
                                 float* __restrict__ o) {
    const int w = threadIdx.x >> 5;
    const int lane = threadIdx.x & 31;
    const int q = blockIdx.x * 8 + w;
    const int h = blockIdx.y;
    const int b = blockIdx.z;
    __shared__ float s_p[8][320];
    __shared__ float s_q[8][32];
    if (q >= kNQ) return;

    const float scale = 0.1767766952966369f;  // 1/sqrt(32)
    s_q[w][lane] = qk[((size_t)(b * kNQ + q)) * 512 + h * kDH + lane];
    __syncwarp();

    float sc[10];
    float m = -INFINITY;
#pragma unroll
    for (int c = 0; c < 10; ++c) {
        const int k = c * 32 + lane;
        const bool valid = k < kNQ;
        const int kk = valid ? k : (kNQ - 1);
        const float4* kr =
            (const float4*)(qk + ((size_t)(b * kNQ + kk)) * 512 + 256 + h * kDH);
        float dot = 0.f;
#pragma unroll
        for (int j = 0; j < 8; ++j) {
            float4 kv = kr[j];
            dot = fmaf(s_q[w][j * 4 + 0], kv.x, dot);
            dot = fmaf(s_q[w][j * 4 + 1], kv.y, dot);
            dot = fmaf(s_q[w][j * 4 + 2], kv.z, dot);
            dot = fmaf(s_q[w][j * 4 + 3], kv.w, dot);
        }
        dot *= scale;
        if (!valid) dot = -INFINITY;
        sc[c] = dot;
        m = fmaxf(m, dot);
    }
#pragma unroll
    for (int off = 16; off > 0; off >>= 1)
        m = fmaxf(m, __shfl_xor_sync(~0u, m, off));

    float sum = 0.f;
#pragma unroll
    for (int c = 0; c < 10; ++c) {
        const int k = c * 32 + lane;
        float e = (k < kNQ) ? expf(sc[c] - m) : 0.f;
        if (k < 320) s_p[w][k] = e;
        sum += e;
    }
#pragma unroll
    for (int off = 16; off > 0; off >>= 1)
        sum += __shfl_xor_sync(~0u, sum, off);
    const float inv = 1.f / sum;
    __syncwarp();

    float acc = 0.f;
    for (int k = 0; k < kNQ; ++k)
        acc = fmaf(s_p[w][k], v[((size_t)(b * kNQ + k)) * kD + h * kDH + lane], acc);

    o[((size_t)(b * kNQ + q)) * kD + h * kDH + lane] = acc * inv;
}

// ---------------------------------------------------------------------------
// MS deformable aggregation over RAW memory rows.
// Block per (b,q), warp = head, lane owns 8 channels of the 256-ch aggregate.
// Writes agg[bq][h*256 + c] (per-head 256-vec) and agg[bq][2048+h] = bias sum.
// ---------------------------------------------------------------------------
__global__ void msdeform_agg_kernel(const float* __restrict__ ref,
                                    const float* __restrict__ off,
                                    const float* __restrict__ awl,
                                    const float* __restrict__ memory,
                                    float* __restrict__ agg) {
    const int bq = blockIdx.x;
    const int b = bq / kNQ;
    const int t = threadIdx.x;
    const int h = t >> 5;
    const int lane = t & 31;

    __shared__ float s_p[kNH][16];

    float lw = (lane < 16) ? awl[(size_t)bq * 128 + h * 16 + lane] : -INFINITY;
    float m = lw;
#pragma unroll
    for (int o = 8; o > 0; o >>= 1) m = fmaxf(m, __shfl_xor_sync(~0u, m, o, 16));
    float e = (lane < 16) ? expf(lw - m) : 0.f;
    float sum = e;
#pragma unroll
    for (int o = 8; o > 0; o >>= 1) sum += __shfl_xor_sync(~0u, sum, o, 16);
    if (lane < 16) s_p[h][lane] = e / sum;
    __syncwarp();

    const int cH[kNL]  = {100, 50, 25, 13};
    const int cW[kNL]  = {150, 75, 38, 19};
    const int cS0[kNL] = {0, 15000, 18750, 19700};

    float a0 = 0.f, a1 = 0.f, a2 = 0.f, a3 = 0.f;
    float a4 = 0.f, a5 = 0.f, a6 = 0.f, a7 = 0.f;
    float bsum = 0.f;

#pragma unroll
    for (int l = 0; l < kNL; ++l) {
        const float rx = ref[((size_t)bq * kNL + l) * 2 + 0];
        const float ry = ref[((size_t)bq * kNL + l) * 2 + 1];
        const int Hl = cH[l], Wl = cW[l], s0 = cS0[l];
        const float fW = (float)Wl, fH = (float)Hl;
#pragma unroll
        for (int p = 0; p < kNP; ++p) {
            const float aw = s_p[h][l * kNP + p];
            const size_t ob = (size_t)bq * 256 + (((h * kNL + l) * kNP + p) * 2);
            const float ox = off[ob + 0];
            const float oy = off[ob + 1];
            const float x = (rx + ox / fW) * fW - 0.5f;
            const float y = (ry + oy / fH) * fH - 0.5f;
            const float x0f = floorf(x), y0f = floorf(y);
            const float tx = x - x0f, ty = y - y0f;
            const int x0 = (int)x0f, y0 = (int)y0f;

#pragma unroll
            for (int dy = 0; dy < 2; ++dy) {
#pragma unroll
                for (int dx = 0; dx < 2; ++dx) {
                    const int xi = x0 + dx, yi = y0 + dy;
                    const bool valid = (xi >= 0) & (xi < Wl) & (yi >= 0) & (yi < Hl);
                    if (valid) {
                        const float w =
                            aw * (dy ? ty : (1.f - ty)) * (dx ? tx : (1.f - tx));
                        const float4* row = (const float4*)(
                            memory + ((size_t)b * kS + s0 + yi * Wl + xi) * kD +
                            lane * 8);
                        float4 v0 = row[0];
                        float4 v1 = row[1];
                        a0 = fmaf(w, v0.x, a0); a1 = fmaf(w, v0.y, a1);
                        a2 = fmaf(w, v0.z, a2); a3 = fmaf(w, v0.w, a3);
                        a4 = fmaf(w, v1.x, a4); a5 = fmaf(w, v1.y, a5);
                        a6 = fmaf(w, v1.z, a6); a7 = fmaf(w, v1.w, a7);
                        bsum += w;
                    }
                }
            }
        }
    }

    float4* dst = (float4*)(agg + (size_t)bq * kAK + h * 256 + lane * 8);
    dst[0] = make_float4(a0, a1, a2, a3);
    dst[1] = make_float4(a4, a5, a6, a7);
    if (lane == 0) agg[(size_t)bq * kAK + 2048 + h] = bsum;
    if (h == 0 && lane < 24) agg[(size_t)bq * kAK + 2056 + lane] = 0.f;
}

// ---------------------------------------------------------------------------
// Launch helpers
// ---------------------------------------------------------------------------
static inline void launch_gemm(const float* A, const float* W, const float* b,
                               float* C, int M, int N, int K, bool relu) {
    constexpr int SM = gemm_smem_bytes<64, 64, 3>();
    static bool attr_set = false;
    if (!attr_set) {
        cudaFuncSetAttribute((const void*)gemm_tf32_kernel<64, 64, 2, 4, 3, false>,
                             cudaFuncAttributeMaxDynamicSharedMemorySize, SM);
        cudaFuncSetAttribute((const void*)gemm_tf32_kernel<64, 64, 2, 4, 3, true>,
                             cudaFuncAttributeMaxDynamicSharedMemorySize, SM);
        attr_set = true;
    }
    dim3 grid(N / 64, (M + 63) / 64);
    if (relu)
        gemm_tf32_kernel<64, 64, 2, 4, 3, true><<<grid, 256, SM>>>(A, W, b, C, M, N, K);
    else
        gemm_tf32_kernel<64, 64, 2, 4, 3, false><<<grid, 256, SM>>>(A, W, b, C, M, N, K);
}

extern "C" void kernel_launch(void* const* d_in, const int* in_sizes, int n_in,
                              void* d_out, int out_size) {
    const float* tgt    = (const float*)d_in[0];
    const float* pos    = (const float*)d_in[1];
    const float* ref    = (const float*)d_in[2];
    const float* memory = (const float*)d_in[3];
    const float* in_w  = (const float*)d_in[7];
    const float* in_b  = (const float*)d_in[8];
    const float* out_w = (const float*)d_in[9];
    const float* out_b = (const float*)d_in[10];
    const float* n1g = (const float*)d_in[11];
    const float* n1b = (const float*)d_in[12];
    const float* n2g = (const float*)d_in[13];
    const float* n2b = (const float*)d_in[14];
    const float* n3g = (const float*)d_in[15];
    const float* n3b = (const float*)d_in[16];
    const float* so_w = (const float*)d_in[17];
    const float* so_b = (const float*)d_in[18];
    const float* aw_w = (const float*)d_in[19];
    const float* aw_b = (const float*)d_in[20];
    const float* v_w  = (const float*)d_in[21];
    const float* v_b  = (const float*)d_in[22];
    const float* op_w = (const float*)d_in[23];
    const float* op_b = (const float*)d_in[24];
    const float* l1w  = (const float*)d_in[25];
    const float* l1b  = (const float*)d_in[26];
    const float* l2w  = (const float*)d_in[27];
    const float* l2b  = (const float*)d_in[28];

    float* scratch = nullptr;
    cudaGetSymbolAddress((void**)&scratch, g_scratch);

    float* s_qkadd = scratch + OFF_QKADD;
    float* s_qk    = scratch + OFF_QK;
    float* s_v     = scratch + OFF_V;
    float* s_attn  = scratch + OFF_ATTN;
    float* s_sa    = scratch + OFF_SA;
    float* s_tgt1  = scratch + OFF_TGT1;
    float* s_query = scratch + OFF_QUERY;
    float* s_offs  = scratch + OFF_OFFS;
    float* s_awl   = scratch + OFF_AWL;
    float* s_t2    = scratch + OFF_T2;
    float* s_tgt2  = scratch + OFF_TGT2;
    float* s_hid   = scratch + OFF_HID;
    float* s_ffo   = scratch + OFF_FFO;
    float* s_agg   = scratch + OFF_AGG;
    float* s_wm    = scratch + OFF_WM;

    const int nQD = kMQ * kD;

    // ---- combined weight precompute (independent, launch first) ----
    {
        dim3 grid(kNH, kD / 32);
        build_wm_kernel<<<grid, 256>>>(op_w, v_w, v_b, s_wm);
    }

    // ---- self attention ----
    add_kernel<<<(nQD + 255) / 256, 256>>>(tgt, pos, s_qkadd, nQD);
    launch_gemm(s_qkadd, in_w, in_b, s_qk, kMQ, 2 * kD, kD, false);
    launch_gemm(tgt, in_w + 512 * kD, in_b + 512, s_v, kMQ, kD, kD, false);
    {
        dim3 grid((kNQ + 7) / 8, kNH, kBS);
        self_attn_kernel<<<grid, 256>>>(s_qk, s_v, s_attn);
    }
    launch_gemm(s_attn, out_w, out_b, s_sa, kMQ, kD, kD, false);
    add_ln_kernel<<<kMQ, 256>>>(tgt, s_sa, n2g, n2b, s_tgt1);

    // ---- MS deformable attention (value GEMM folded away) ----
    add_kernel<<<(nQD + 255) / 256, 256>>>(s_tgt1, pos, s_query, nQD);
    launch_gemm(s_query, so_w, so_b, s_offs, kMQ, kD, kD, false);
    launch_gemm(s_query, aw_w, aw_b, s_awl, kMQ, 128, kD, false);
    msdeform_agg_kernel<<<kMQ, 256>>>(ref, s_offs, s_awl, memory, s_agg);
    launch_gemm(s_agg, s_wm, op_b, s_t2, kMQ, kD, kAK, false);
    add_ln_kernel<<<kMQ, 256>>>(s_tgt1, s_t2, n1g, n1b, s_tgt2);

    // ---- FFN ----
    launch_gemm(s_tgt2, l1w, l1b, s_hid, kMQ, kDFF, kD, true);
    launch_gemm(s_hid, l2w, l2b, s_ffo, kMQ, kD, kDFF, false);
    add_ln_kernel<<<kMQ, 256>>>(s_tgt2, s_ffo, n3g, n3b, (float*)d_out);
}

// round 6
// speedup vs baseline: 3.2947x; 1.0269x over previous
#include <cuda_runtime.h>
#include <math.h>
#include <stdint.h>

// ---------------------------------------------------------------------------
// Problem constants
// ---------------------------------------------------------------------------
namespace {
constexpr int kD   = 256;
constexpr int kNH  = 8;
constexpr int kDH  = 32;
constexpr int kNL  = 4;
constexpr int kNP  = 4;
constexpr int kDFF = 1024;
constexpr int kBS  = 8;
constexpr int kNQ  = 300;
constexpr int kS   = 19947;
constexpr int kMQ  = kBS * kNQ;      // 2400
constexpr int kAK  = 2080;           // agg K: 8*256 + 8 bias + 24 pad (65*32)
constexpr int kOW  = 384;            // merged offs(256) + awl(128) width

constexpr size_t OFF_QKADD = 0;
constexpr size_t OFF_QKV   = OFF_QKADD + (size_t)kMQ * kD;   // [2400][768]
constexpr size_t OFF_ATTN  = OFF_QKV   + (size_t)kMQ * 768;
constexpr size_t OFF_SA    = OFF_ATTN  + (size_t)kMQ * kD;
constexpr size_t OFF_TGT1  = OFF_SA    + (size_t)kMQ * kD;
constexpr size_t OFF_QUERY = OFF_TGT1  + (size_t)kMQ * kD;
constexpr size_t OFF_OA    = OFF_QUERY + (size_t)kMQ * kD;   // [2400][384]
constexpr size_t OFF_T2    = OFF_OA    + (size_t)kMQ * kOW;
constexpr size_t OFF_TGT2  = OFF_T2    + (size_t)kMQ * kD;
constexpr size_t OFF_HID   = OFF_TGT2  + (size_t)kMQ * kD;
constexpr size_t OFF_FFO   = OFF_HID   + (size_t)kMQ * kDFF;
constexpr size_t OFF_AGG   = OFF_FFO   + (size_t)kMQ * kD;
constexpr size_t OFF_WM    = OFF_AGG   + (size_t)kMQ * kAK;
constexpr size_t OFF_WCAT  = OFF_WM    + (size_t)kD * kAK;   // [384][256]
constexpr size_t OFF_BCAT  = OFF_WCAT  + (size_t)kOW * kD;   // [384]
constexpr size_t SCRATCH_TOTAL = OFF_BCAT + kOW;
} // namespace

__device__ float g_scratch[SCRATCH_TOTAL];

// ---------------------------------------------------------------------------
// helpers
// ---------------------------------------------------------------------------
__device__ __forceinline__ uint32_t smem_u32(const void* p) {
    uint32_t a;
    asm("{ .reg .u64 t; cvta.to.shared.u64 t, %1; cvt.u32.u64 %0, t; }"
        : "=r"(a) : "l"(p));
    return a;
}

__device__ __forceinline__ void cp_async16(uint32_t dst, const void* src, bool pred) {
    int sz = pred ? 16 : 0;
    asm volatile("cp.async.cg.shared.global [%0], [%1], 16, %2;"
                 :: "r"(dst), "l"(src), "r"(sz));
}
__device__ __forceinline__ void cp_commit() {
    asm volatile("cp.async.commit_group;");
}
template <int N>
__device__ __forceinline__ void cp_wait() {
    asm volatile("cp.async.wait_group %0;" :: "n"(N));
}

__device__ __forceinline__ void mma_tf32(float (&d)[4],
                                         const uint32_t (&a)[4],
                                         const uint32_t (&b)[2]) {
    asm volatile(
        "mma.sync.aligned.m16n8k8.row.col.f32.tf32.tf32.f32 "
        "{%0,%1,%2,%3}, {%4,%5,%6,%7}, {%8,%9}, {%0,%1,%2,%3};"
        : "+f"(d[0]), "+f"(d[1]), "+f"(d[2]), "+f"(d[3])
        : "r"(a[0]), "r"(a[1]), "r"(a[2]), "r"(a[3]),
          "r"(b[0]), "r"(b[1]));
}

// ---------------------------------------------------------------------------
// TF32 tensor-core GEMM with per-n-region A select:
//   C[M,N] = act( Asel[M,K] @ W[N,K]^T + bias[N] ),
//   Asel = A1 for n-tile < n_split, else A2.
// Block tile 64x64, BK=32, 8 warps (WM=2,WN=4), STAGES-deep cp.async.
// Requires N % 64 == 0, K % 32 == 0.
// ---------------------------------------------------------------------------
template <int STAGES, bool RELU>
__global__ __launch_bounds__(256, 2)
void gemm_tf32_kernel(const float* __restrict__ A1,
                      const float* __restrict__ A2,
                      int n_split,
                      const float* __restrict__ W,
                      const float* __restrict__ bias,
                      float* __restrict__ C,
                      int M, int N, int K) {
    constexpr int BM = 64, BN = 64, BK = 32;
    constexpr int LD = BK + 4;                 // 36 words/row
    constexpr int THREADS = 256;
    constexpr int WM = 2, WN = 4;
    constexpr int MT = 2, NT = 2;              // warp tile 32x16? no: see below
    // warp tile: WTM = 32 (MT=2 m16 tiles), WTN = 16 (NT=2 n8 tiles)
    constexpr int A_IT = (BM * BK / 4) / THREADS;   // 2
    constexpr int B_IT = (BN * BK / 4) / THREADS;   // 2

    extern __shared__ float smem[];
    float* As = smem;                          // STAGES * BM * LD
    float* Ws = smem + (size_t)STAGES * BM * LD;

    const int tid  = threadIdx.x;
    const int warp = tid >> 5;
    const int lane = tid & 31;
    const int g    = lane >> 2;
    const int tg   = lane & 3;
    const int tm   = blockIdx.y * BM;
    const int tn   = blockIdx.x * BN;
    const int wm   = (warp % WM) * 32;
    const int wn   = (warp / WM) * 16;

    const float* A = (tn < n_split) ? A1 : A2;

    float acc[MT][NT][4] = {};
    const int NK = K / BK;

    auto issue = [&](int s, int kt) {
        if (kt < NK) {
            const int k0 = kt * BK;
#pragma unroll
            for (int i = 0; i < A_IT; ++i) {
                int idx = tid + i * THREADS;
                int r = idx >> 3, c4 = (idx & 7) * 4;
                int gr = tm + r;
                cp_async16(smem_u32(&As[(size_t)s * BM * LD + r * LD + c4]),
                           A + (size_t)gr * K + k0 + c4, gr < M);
            }
#pragma unroll
            for (int i = 0; i < B_IT; ++i) {
                int idx = tid + i * THREADS;
                int r = idx >> 3, c4 = (idx & 7) * 4;
                cp_async16(smem_u32(&Ws[(size_t)s * BN * LD + r * LD + c4]),
                           W + (size_t)(tn + r) * K + k0 + c4, true);
            }
        }
        cp_commit();
    };

    issue(0, 0);
#pragma unroll
    for (int p = 1; p < STAGES - 1; ++p) issue(p, p);

    for (int kt = 0; kt < NK; ++kt) {
        const int s = kt % STAGES;
        cp_wait<STAGES - 2>();
        __syncthreads();
        issue((kt + STAGES - 1) % STAGES, kt + STAGES - 1);

        const float* as = &As[(size_t)s * BM * LD];
        const float* ws = &Ws[(size_t)s * BN * LD];
#pragma unroll
        for (int ks = 0; ks < 4; ++ks) {
            const int kc = ks * 8 + tg;
            uint32_t af[MT][4], bf[NT][2];
#pragma unroll
            for (int mt = 0; mt < MT; ++mt) {
                const int r = wm + mt * 16 + g;
                af[mt][0] = __float_as_uint(as[r * LD + kc]);
                af[mt][1] = __float_as_uint(as[(r + 8) * LD + kc]);
                af[mt][2] = __float_as_uint(as[r * LD + kc + 4]);
                af[mt][3] = __float_as_uint(as[(r + 8) * LD + kc + 4]);
            }
#pragma unroll
            for (int nt = 0; nt < NT; ++nt) {
                const int n = wn + nt * 8 + g;
                bf[nt][0] = __float_as_uint(ws[n * LD + kc]);
                bf[nt][1] = __float_as_uint(ws[n * LD + kc + 4]);
            }
#pragma unroll
            for (int mt = 0; mt < MT; ++mt)
#pragma unroll
                for (int nt = 0; nt < NT; ++nt)
                    mma_tf32(acc[mt][nt], af[mt], bf[nt]);
        }
        __syncthreads();
    }

#pragma unroll
    for (int mt = 0; mt < MT; ++mt) {
        const int gr0 = tm + wm + mt * 16 + g;
        const int gr1 = gr0 + 8;
#pragma unroll
        for (int nt = 0; nt < NT; ++nt) {
            const int gc = tn + wn + nt * 8 + tg * 2;
            const float b0 = bias[gc], b1 = bias[gc + 1];
            if (gr0 < M) {
                float v0 = acc[mt][nt][0] + b0;
                float v1 = acc[mt][nt][1] + b1;
                if (RELU) { v0 = fmaxf(v0, 0.f); v1 = fmaxf(v1, 0.f); }
                *(float2*)(C + (size_t)gr0 * N + gc) = make_float2(v0, v1);
            }
            if (gr1 < M) {
                float v2 = acc[mt][nt][2] + b0;
                float v3 = acc[mt][nt][3] + b1;
                if (RELU) { v2 = fmaxf(v2, 0.f); v3 = fmaxf(v3, 0.f); }
                *(float2*)(C + (size_t)gr1 * N + gc) = make_float2(v2, v3);
            }
        }
    }
}

template <int STAGES>
constexpr int gemm_smem_bytes() { return STAGES * 128 * 36 * 4; }

// ---------------------------------------------------------------------------
// Precompute kernel. grid = (8, 9), block = 256.
//  y < 8 : build Wm[256][2080] head-block  (h = blockIdx.x, rows blockIdx.y*32)
//  y == 8: concat so_w/aw_w -> wcat[384][256] and so_b/aw_b -> bcat[384]
// ---------------------------------------------------------------------------
__global__ void precompute_kernel(const float* __restrict__ op_w,
                                  const float* __restrict__ v_w,
                                  const float* __restrict__ v_b,
                                  const float* __restrict__ so_w,
                                  const float* __restrict__ so_b,
                                  const float* __restrict__ aw_w,
                                  const float* __restrict__ aw_b,
                                  float* __restrict__ wm,
                                  float* __restrict__ wcat,
                                  float* __restrict__ bcat) {
    const int tid = threadIdx.x;
    if (blockIdx.y == 8) {
        // concat: 8 x-blocks, each handles 48 rows of 384
        const int r0 = blockIdx.x * 48;
        for (int r = r0; r < r0 + 48; ++r) {
            const float* src = (r < 256) ? (so_w + (size_t)r * 256)
                                         : (aw_w + (size_t)(r - 256) * 256);
            wcat[(size_t)r * 256 + tid] = src[tid];
        }
        if (tid < 48) {
            int r = r0 + tid;
            bcat[r] = (r < 256) ? so_b[r] : aw_b[r - 256];
        }
        return;
    }

    const int h  = blockIdx.x;
    const int ot = blockIdx.y * 32;
    __shared__ float vs[32][256];

    for (int idx = tid; idx < 32 * 256; idx += 256) {
        int r = idx >> 8, c = idx & 255;
        vs[r][c] = v_w[(size_t)(32 * h + r) * 256 + c];
    }
    __syncthreads();

    for (int oo = 0; oo < 32; ++oo) {
        const int o = ot + oo;
        const float* opr = op_w + (size_t)o * 256 + 32 * h;
        float s = 0.f;
#pragma unroll
        for (int j = 0; j < 32; ++j) s = fmaf(opr[j], vs[j][tid], s);
        wm[(size_t)o * kAK + h * 256 + tid] = s;
    }
    if (tid < 32) {
        const int o = ot + tid;
        const float* opr = op_w + (size_t)o * 256 + 32 * h;
        float s = 0.f;
#pragma unroll
        for (int j = 0; j < 32; ++j) s = fmaf(opr[j], v_b[32 * h + j], s);
        wm[(size_t)o * kAK + 2048 + h] = s;
        if (h == 0)
            for (int z = 2056; z < kAK; ++z) wm[(size_t)o * kAK + z] = 0.f;
    }
}

// ---------------------------------------------------------------------------
// Elementwise add
// ---------------------------------------------------------------------------
__global__ void add_kernel(const float* __restrict__ a,
                           const float* __restrict__ b,
                           float* __restrict__ out, int n) {
    int i = blockIdx.x * blockDim.x + threadIdx.x;
    if (i < n) out[i] = a[i] + b[i];
}

// ---------------------------------------------------------------------------
// Residual + LayerNorm (256 features, one block per row).
// Optionally also writes out2 = ln_out + pos (fused next-stage input).
// ---------------------------------------------------------------------------
template <bool WITH_POS>
__global__ void add_ln_kernel(const float* __restrict__ x,
                              const float* __restrict__ r,
                              const float* __restrict__ g,
                              const float* __restrict__ bta,
                              float* __restrict__ out,
                              const float* __restrict__ pos,
                              float* __restrict__ out2) {
    const int row = blockIdx.x;
    const int t = threadIdx.x;
    const size_t base = (size_t)row * kD;
    float v = x[base + t] + r[base + t];

    __shared__ float sm[8];
    float s = v;
#pragma unroll
    for (int o = 16; o > 0; o >>= 1) s += __shfl_xor_sync(~0u, s, o);
    if ((t & 31) == 0) sm[t >> 5] = s;
    __syncthreads();
    float tot = 0.f;
#pragma unroll
    for (int i = 0; i < 8; ++i) tot += sm[i];
    const float mean = tot * (1.f / kD);
    const float d = v - mean;
    float s2 = d * d;
#pragma unroll
    for (int o = 16; o > 0; o >>= 1) s2 += __shfl_xor_sync(~0u, s2, o);
    __syncthreads();
    if ((t & 31) == 0) sm[t >> 5] = s2;
    __syncthreads();
    float tot2 = 0.f;
#pragma unroll
    for (int i = 0; i < 8; ++i) tot2 += sm[i];
    const float var = tot2 * (1.f / kD);
    const float o1 = d * rsqrtf(var + 1e-5f) * g[t] + bta[t];
    out[base + t] = o1;
    if (WITH_POS) out2[base + t] = o1 + pos[base + t];
}

// ---------------------------------------------------------------------------
// Self attention. One warp per (b, h, q).
// qkv rows: [q(0..255) | k(256..511) | v(512..767)], stride 768.
// ---------------------------------------------------------------------------
__global__ void self_attn_kernel(const float* __restrict__ qkv,
                                 float* __restrict__ o) {
    const int w = threadIdx.x >> 5;
    const int lane = threadIdx.x & 31;
    const int q = blockIdx.x * 8 + w;
    const int h = blockIdx.y;
    const int b = blockIdx.z;
    __shared__ float s_p[8][320];
    __shared__ float s_q[8][32];
    if (q >= kNQ) return;

    const float scale = 0.1767766952966369f;  // 1/sqrt(32)
    s_q[w][lane] = qkv[((size_t)(b * kNQ + q)) * 768 + h * kDH + lane];
    __syncwarp();

    float sc[10];
    float m = -INFINITY;
#pragma unroll
    for (int c = 0; c < 10; ++c) {
        const int k = c * 32 + lane;
        const bool valid = k < kNQ;
        const int kk = valid ? k : (kNQ - 1);
        const float4* kr =
            (const float4*)(qkv + ((size_t)(b * kNQ + kk)) * 768 + 256 + h * kDH);
        float dot = 0.f;
#pragma unroll
        for (int j = 0; j < 8; ++j) {
            float4 kv = kr[j];
            dot = fmaf(s_q[w][j * 4 + 0], kv.x, dot);
            dot = fmaf(s_q[w][j * 4 + 1], kv.y, dot);
            dot = fmaf(s_q[w][j * 4 + 2], kv.z, dot);
            dot = fmaf(s_q[w][j * 4 + 3], kv.w, dot);
        }
        dot *= scale;
        if (!valid) dot = -INFINITY;
        sc[c] = dot;
        m = fmaxf(m, dot);
    }
#pragma unroll
    for (int off = 16; off > 0; off >>= 1)
        m = fmaxf(m, __shfl_xor_sync(~0u, m, off));

    float sum = 0.f;
#pragma unroll
    for (int c = 0; c < 10; ++c) {
        const int k = c * 32 + lane;
        float e = (k < kNQ) ? expf(sc[c] - m) : 0.f;
        if (k < 320) s_p[w][k] = e;
        sum += e;
    }
#pragma unroll
    for (int off = 16; off > 0; off >>= 1)
        sum += __shfl_xor_sync(~0u, sum, off);
    const float inv = 1.f / sum;
    __syncwarp();

    float acc = 0.f;
    for (int k = 0; k < kNQ; ++k)
        acc = fmaf(s_p[w][k],
                   qkv[((size_t)(b * kNQ + k)) * 768 + 512 + h * kDH + lane], acc);

    o[((size_t)(b * kNQ + q)) * kD + h * kDH + lane] = acc * inv;
}

// ---------------------------------------------------------------------------
// MS deformable aggregation over RAW memory rows.
// oa rows: [offsets(0..255) | logits(256..383)], stride 384.
// ---------------------------------------------------------------------------
__global__ void msdeform_agg_kernel(const float* __restrict__ ref,
                                    const float* __restrict__ oa,
                                    const float* __restrict__ memory,
                                    float* __restrict__ agg) {
    const int bq = blockIdx.x;
    const int b = bq / kNQ;
    const int t = threadIdx.x;
    const int h = t >> 5;
    const int lane = t & 31;

    __shared__ float s_p[kNH][16];

    float lw = (lane < 16) ? oa[(size_t)bq * kOW + 256 + h * 16 + lane] : -INFINITY;
    float m = lw;
#pragma unroll
    for (int o = 8; o > 0; o >>= 1) m = fmaxf(m, __shfl_xor_sync(~0u, m, o, 16));
    float e = (lane < 16) ? expf(lw - m) : 0.f;
    float sum = e;
#pragma unroll
    for (int o = 8; o > 0; o >>= 1) sum += __shfl_xor_sync(~0u, sum, o, 16);
    if (lane < 16) s_p[h][lane] = e / sum;
    __syncwarp();

    const int cH[kNL]  = {100, 50, 25, 13};
    const int cW[kNL]  = {150, 75, 38, 19};
    const int cS0[kNL] = {0, 15000, 18750, 19700};

    float a0 = 0.f, a1 = 0.f, a2 = 0.f, a3 = 0.f;
    float a4 = 0.f, a5 = 0.f, a6 = 0.f, a7 = 0.f;
    float bsum = 0.f;

#pragma unroll
    for (int l = 0; l < kNL; ++l) {
        const float rx = ref[((size_t)bq * kNL + l) * 2 + 0];
        const float ry = ref[((size_t)bq * kNL + l) * 2 + 1];
        const int Hl = cH[l], Wl = cW[l], s0 = cS0[l];
        const float fW = (float)Wl, fH = (float)Hl;
#pragma unroll
        for (int p = 0; p < kNP; ++p) {
            const float aw = s_p[h][l * kNP + p];
            const size_t ob = (size_t)bq * kOW + (((h * kNL + l) * kNP + p) * 2);
            const float ox = oa[ob + 0];
            const float oy = oa[ob + 1];
            const float x = (rx + ox / fW) * fW - 0.5f;
            const float y = (ry + oy / fH) * fH - 0.5f;
            const float x0f = floorf(x), y0f = floorf(y);
            const float tx = x - x0f, ty = y - y0f;
            const int x0 = (int)x0f, y0 = (int)y0f;

#pragma unroll
            for (int dy = 0; dy < 2; ++dy) {
#pragma unroll
                for (int dx = 0; dx < 2; ++dx) {
                    const int xi = x0 + dx, yi = y0 + dy;
                    const bool valid = (xi >= 0) & (xi < Wl) & (yi >= 0) & (yi < Hl);
                    if (valid) {
                        const float w =
                            aw * (dy ? ty : (1.f - ty)) * (dx ? tx : (1.f - tx));
                        const float4* row = (const float4*)(
                            memory + ((size_t)b * kS + s0 + yi * Wl + xi) * kD +
                            lane * 8);
                        float4 v0 = row[0];
                        float4 v1 = row[1];
                        a0 = fmaf(w, v0.x, a0); a1 = fmaf(w, v0.y, a1);
                        a2 = fmaf(w, v0.z, a2); a3 = fmaf(w, v0.w, a3);
                        a4 = fmaf(w, v1.x, a4); a5 = fmaf(w, v1.y, a5);
                        a6 = fmaf(w, v1.z, a6); a7 = fmaf(w, v1.w, a7);
                        bsum += w;
                    }
                }
            }
        }
    }

    float4* dst = (float4*)(agg + (size_t)bq * kAK + h * 256 + lane * 8);
    dst[0] = make_float4(a0, a1, a2, a3);
    dst[1] = make_float4(a4, a5, a6, a7);
    if (lane == 0) agg[(size_t)bq * kAK + 2048 + h] = bsum;
    if (h == 0 && lane < 24) agg[(size_t)bq * kAK + 2056 + lane] = 0.f;
}

// ---------------------------------------------------------------------------
// Launch helpers
// ---------------------------------------------------------------------------
static void ensure_attrs() {
    static bool done = false;
    if (done) return;
    cudaFuncSetAttribute((const void*)gemm_tf32_kernel<3, false>,
                         cudaFuncAttributeMaxDynamicSharedMemorySize,
                         gemm_smem_bytes<3>());
    cudaFuncSetAttribute((const void*)gemm_tf32_kernel<3, true>,
                         cudaFuncAttributeMaxDynamicSharedMemorySize,
                         gemm_smem_bytes<3>());
    cudaFuncSetAttribute((const void*)gemm_tf32_kernel<4, false>,
                         cudaFuncAttributeMaxDynamicSharedMemorySize,
                         gemm_smem_bytes<4>());
    done = true;
}

static inline void launch_gemm(const float* A, const float* W, const float* b,
                               float* C, int M, int N, int K, bool relu) {
    dim3 grid(N / 64, (M + 63) / 64);
    if (relu)
        gemm_tf32_kernel<3, true><<<grid, 256, gemm_smem_bytes<3>()>>>(
            A, A, N, W, b, C, M, N, K);
    else
        gemm_tf32_kernel<3, false><<<grid, 256, gemm_smem_bytes<3>()>>>(
            A, A, N, W, b, C, M, N, K);
}

extern "C" void kernel_launch(void* const* d_in, const int* in_sizes, int n_in,
                              void* d_out, int out_size) {
    const float* tgt    = (const float*)d_in[0];
    const float* pos    = (const float*)d_in[1];
    const float* ref    = (const float*)d_in[2];
    const float* memory = (const float*)d_in[3];
    const float* in_w  = (const float*)d_in[7];
    const float* in_b  = (const float*)d_in[8];
    const float* out_w = (const float*)d_in[9];
    const float* out_b = (const float*)d_in[10];
    const float* n1g = (const float*)d_in[11];
    const float* n1b = (const float*)d_in[12];
    const float* n2g = (const float*)d_in[13];
    const float* n2b = (const float*)d_in[14];
    const float* n3g = (const float*)d_in[15];
    const float* n3b = (const float*)d_in[16];
    const float* so_w = (const float*)d_in[17];
    const float* so_b = (const float*)d_in[18];
    const float* aw_w = (const float*)d_in[19];
    const float* aw_b = (const float*)d_in[20];
    const float* v_w  = (const float*)d_in[21];
    const float* v_b  = (const float*)d_in[22];
    const float* op_w = (const float*)d_in[23];
    const float* op_b = (const float*)d_in[24];
    const float* l1w  = (const float*)d_in[25];
    const float* l1b  = (const float*)d_in[26];
    const float* l2w  = (const float*)d_in[27];
    const float* l2b  = (const float*)d_in[28];

    float* scratch = nullptr;
    cudaGetSymbolAddress((void**)&scratch, g_scratch);
    ensure_attrs();

    float* s_qkadd = scratch + OFF_QKADD;
    float* s_qkv   = scratch + OFF_QKV;
    float* s_attn  = scratch + OFF_ATTN;
    float* s_sa    = scratch + OFF_SA;
    float* s_tgt1  = scratch + OFF_TGT1;
    float* s_query = scratch + OFF_QUERY;
    float* s_oa    = scratch + OFF_OA;
    float* s_t2    = scratch + OFF_T2;
    float* s_tgt2  = scratch + OFF_TGT2;
    float* s_hid   = scratch + OFF_HID;
    float* s_ffo   = scratch + OFF_FFO;
    float* s_agg   = scratch + OFF_AGG;
    float* s_wm    = scratch + OFF_WM;
    float* s_wcat  = scratch + OFF_WCAT;
    float* s_bcat  = scratch + OFF_BCAT;

    const int nQD = kMQ * kD;

    // ---- precompute (Wm, weight concat) + qkadd ----
    {
        dim3 grid(kNH, 9);
        precompute_kernel<<<grid, 256>>>(op_w, v_w, v_b, so_w, so_b, aw_w, aw_b,
                                         s_wm, s_wcat, s_bcat);
    }
    add_kernel<<<(nQD + 255) / 256, 256>>>(tgt, pos, s_qkadd, nQD);

    // ---- self attention: one merged QKV GEMM (A=qkadd for n<512, tgt for v) ----
    {
        dim3 grid(768 / 64, (kMQ + 63) / 64);
        gemm_tf32_kernel<3, false><<<grid, 256, gemm_smem_bytes<3>()>>>(
            s_qkadd, tgt, 512, in_w, in_b, s_qkv, kMQ, 768, kD);
    }
    {
        dim3 grid((kNQ + 7) / 8, kNH, kBS);
        self_attn_kernel<<<grid, 256>>>(s_qkv, s_attn);
    }
    launch_gemm(s_attn, out_w, out_b, s_sa, kMQ, kD, kD, false);
    add_ln_kernel<true><<<kMQ, 256>>>(tgt, s_sa, n2g, n2b, s_tgt1, pos, s_query);

    // ---- MS deformable attention (merged offs+awl GEMM; value GEMM folded) ----
    launch_gemm(s_query, s_wcat, s_bcat, s_oa, kMQ, kOW, kD, false);
    msdeform_agg_kernel<<<kMQ, 256>>>(ref, s_oa, memory, s_agg);
    {
        dim3 grid(kD / 64, (kMQ + 63) / 64);
        gemm_tf32_kernel<4, false><<<grid, 256, gemm_smem_bytes<4>()>>>(
            s_agg, s_agg, kD, s_wm, op_b, s_t2, kMQ, kD, kAK);
    }
    add_ln_kernel<false><<<kMQ, 256>>>(s_tgt1, s_t2, n1g, n1b, s_tgt2,
                                       nullptr, nullptr);

    // ---- FFN ----
    launch_gemm(s_tgt2, l1w, l1b, s_hid, kMQ, kDFF, kD, true);
    launch_gemm(s_hid, l2w, l2b, s_ffo, kMQ, kD, kDFF, false);
    add_ln_kernel<false><<<kMQ, 256>>>(s_tgt2, s_ffo, n3g, n3b, (float*)d_out,
                                       nullptr, nullptr);
}

// round 7
// speedup vs baseline: 4.4455x; 1.3493x over previous
#include <cuda_runtime.h>
#include <math.h>
#include <stdint.h>

// ---------------------------------------------------------------------------
// Problem constants
// ---------------------------------------------------------------------------
namespace {
constexpr int kD   = 256;
constexpr int kNH  = 8;
constexpr int kDH  = 32;
constexpr int kNL  = 4;
constexpr int kNP  = 4;
constexpr int kDFF = 1024;
constexpr int kBS  = 8;
constexpr int kNQ  = 300;
constexpr int kS   = 19947;
constexpr int kMQ  = kBS * kNQ;      // 2400
constexpr int kAK  = 2080;           // agg K: 8*256 + 8 bias + 24 pad (65*32)
constexpr int kOW  = 384;            // merged offs(256) + awl(128) width

constexpr size_t OFF_QKADD = 0;
constexpr size_t OFF_QKV   = OFF_QKADD + (size_t)kMQ * kD;   // [2400][768]
constexpr size_t OFF_ATTN  = OFF_QKV   + (size_t)kMQ * 768;
constexpr size_t OFF_SA    = OFF_ATTN  + (size_t)kMQ * kD;
constexpr size_t OFF_TGT1  = OFF_SA    + (size_t)kMQ * kD;
constexpr size_t OFF_QUERY = OFF_TGT1  + (size_t)kMQ * kD;
constexpr size_t OFF_OA    = OFF_QUERY + (size_t)kMQ * kD;   // [2400][384]
constexpr size_t OFF_T2    = OFF_OA    + (size_t)kMQ * kOW;
constexpr size_t OFF_TGT2  = OFF_T2    + (size_t)kMQ * kD;
constexpr size_t OFF_HID   = OFF_TGT2  + (size_t)kMQ * kD;
constexpr size_t OFF_FFO   = OFF_HID   + (size_t)kMQ * kDFF;
constexpr size_t OFF_AGG   = OFF_FFO   + (size_t)kMQ * kD;
constexpr size_t OFF_WM    = OFF_AGG   + (size_t)kMQ * kAK;
constexpr size_t OFF_WCAT  = OFF_WM    + (size_t)kD * kAK;   // [384][256]
constexpr size_t OFF_BCAT  = OFF_WCAT  + (size_t)kOW * kD;   // [384]
constexpr size_t SCRATCH_TOTAL = OFF_BCAT + kOW;
} // namespace

__device__ float g_scratch[SCRATCH_TOTAL];

// ---------------------------------------------------------------------------
// helpers
// ---------------------------------------------------------------------------
__device__ __forceinline__ uint32_t smem_u32(const void* p) {
    uint32_t a;
    asm("{ .reg .u64 t; cvta.to.shared.u64 t, %1; cvt.u32.u64 %0, t; }"
        : "=r"(a) : "l"(p));
    return a;
}

__device__ __forceinline__ void cp_async16(uint32_t dst, const void* src, bool pred) {
    int sz = pred ? 16 : 0;
    asm volatile("cp.async.cg.shared.global [%0], [%1], 16, %2;"
                 :: "r"(dst), "l"(src), "r"(sz));
}
__device__ __forceinline__ void cp_commit() {
    asm volatile("cp.async.commit_group;");
}
template <int N>
__device__ __forceinline__ void cp_wait() {
    asm volatile("cp.async.wait_group %0;" :: "n"(N));
}

__device__ __forceinline__ void mma_tf32(float (&d)[4],
                                         const uint32_t (&a)[4],
                                         const uint32_t (&b)[2]) {
    asm volatile(
        "mma.sync.aligned.m16n8k8.row.col.f32.tf32.tf32.f32 "
        "{%0,%1,%2,%3}, {%4,%5,%6,%7}, {%8,%9}, {%0,%1,%2,%3};"
        : "+f"(d[0]), "+f"(d[1]), "+f"(d[2]), "+f"(d[3])
        : "r"(a[0]), "r"(a[1]), "r"(a[2]), "r"(a[3]),
          "r"(b[0]), "r"(b[1]));
}

// ---------------------------------------------------------------------------
// TF32 tensor-core GEMM with per-n-region A select:
//   C[M,N] = act( Asel[M,K] @ W[N,K]^T + bias[N] )
// Block tile 64x64, BK=32, 8 warps (WM=2,WN=4), STAGES-deep cp.async.
// ---------------------------------------------------------------------------
template <int STAGES, bool RELU>
__global__ __launch_bounds__(256, 2)
void gemm_tf32_kernel(const float* __restrict__ A1,
                      const float* __restrict__ A2,
                      int n_split,
                      const float* __restrict__ W,
                      const float* __restrict__ bias,
                      float* __restrict__ C,
                      int M, int N, int K) {
    constexpr int BM = 64, BN = 64, BK = 32;
    constexpr int LD = BK + 4;                 // 36 words/row
    constexpr int THREADS = 256;
    constexpr int WM = 2;
    constexpr int MT = 2, NT = 2;
    constexpr int A_IT = (BM * BK / 4) / THREADS;   // 2
    constexpr int B_IT = (BN * BK / 4) / THREADS;   // 2

    extern __shared__ float smem[];
    float* As = smem;
    float* Ws = smem + (size_t)STAGES * BM * LD;

    const int tid  = threadIdx.x;
    const int warp = tid >> 5;
    const int lane = tid & 31;
    const int g    = lane >> 2;
    const int tg   = lane & 3;
    const int tm   = blockIdx.y * BM;
    const int tn   = blockIdx.x * BN;
    const int wm   = (warp % WM) * 32;
    const int wn   = (warp / WM) * 16;

    const float* A = (tn < n_split) ? A1 : A2;

    float acc[MT][NT][4] = {};
    const int NK = K / BK;

    auto issue = [&](int s, int kt) {
        if (kt < NK) {
            const int k0 = kt * BK;
#pragma unroll
            for (int i = 0; i < A_IT; ++i) {
                int idx = tid + i * THREADS;
                int r = idx >> 3, c4 = (idx & 7) * 4;
                int gr = tm + r;
                cp_async16(smem_u32(&As[(size_t)s * BM * LD + r * LD + c4]),
                           A + (size_t)gr * K + k0 + c4, gr < M);
            }
#pragma unroll
            for (int i = 0; i < B_IT; ++i) {
                int idx = tid + i * THREADS;
                int r = idx >> 3, c4 = (idx & 7) * 4;
                cp_async16(smem_u32(&Ws[(size_t)s * BN * LD + r * LD + c4]),
                           W + (size_t)(tn + r) * K + k0 + c4, true);
            }
        }
        cp_commit();
    };

    issue(0, 0);
#pragma unroll
    for (int p = 1; p < STAGES - 1; ++p) issue(p, p);

    for (int kt = 0; kt < NK; ++kt) {
        const int s = kt % STAGES;
        cp_wait<STAGES - 2>();
        __syncthreads();
        issue((kt + STAGES - 1) % STAGES, kt + STAGES - 1);

        const float* as = &As[(size_t)s * BM * LD];
        const float* ws = &Ws[(size_t)s * BN * LD];
#pragma unroll
        for (int ks = 0; ks < 4; ++ks) {
            const int kc = ks * 8 + tg;
            uint32_t af[MT][4], bf[NT][2];
#pragma unroll
            for (int mt = 0; mt < MT; ++mt) {
                const int r = wm + mt * 16 + g;
                af[mt][0] = __float_as_uint(as[r * LD + kc]);
                af[mt][1] = __float_as_uint(as[(r + 8) * LD + kc]);
                af[mt][2] = __float_as_uint(as[r * LD + kc + 4]);
                af[mt][3] = __float_as_uint(as[(r + 8) * LD + kc + 4]);
            }
#pragma unroll
            for (int nt = 0; nt < NT; ++nt) {
                const int n = wn + nt * 8 + g;
                bf[nt][0] = __float_as_uint(ws[n * LD + kc]);
                bf[nt][1] = __float_as_uint(ws[n * LD + kc + 4]);
            }
#pragma unroll
            for (int mt = 0; mt < MT; ++mt)
#pragma unroll
                for (int nt = 0; nt < NT; ++nt)
                    mma_tf32(acc[mt][nt], af[mt], bf[nt]);
        }
        __syncthreads();
    }

#pragma unroll
    for (int mt = 0; mt < MT; ++mt) {
        const int gr0 = tm + wm + mt * 16 + g;
        const int gr1 = gr0 + 8;
#pragma unroll
        for (int nt = 0; nt < NT; ++nt) {
            const int gc = tn + wn + nt * 8 + tg * 2;
            const float b0 = bias[gc], b1 = bias[gc + 1];
            if (gr0 < M) {
                float v0 = acc[mt][nt][0] + b0;
                float v1 = acc[mt][nt][1] + b1;
                if (RELU) { v0 = fmaxf(v0, 0.f); v1 = fmaxf(v1, 0.f); }
                *(float2*)(C + (size_t)gr0 * N + gc) = make_float2(v0, v1);
            }
            if (gr1 < M) {
                float v2 = acc[mt][nt][2] + b0;
                float v3 = acc[mt][nt][3] + b1;
                if (RELU) { v2 = fmaxf(v2, 0.f); v3 = fmaxf(v3, 0.f); }
                *(float2*)(C + (size_t)gr1 * N + gc) = make_float2(v2, v3);
            }
        }
    }
}

template <int STAGES>
constexpr int gemm_smem_bytes() { return STAGES * 128 * 36 * 4; }

// ---------------------------------------------------------------------------
// Precompute kernel. grid = (8, 9), block = 256.
// ---------------------------------------------------------------------------
__global__ void precompute_kernel(const float* __restrict__ op_w,
                                  const float* __restrict__ v_w,
                                  const float* __restrict__ v_b,
                                  const float* __restrict__ so_w,
                                  const float* __restrict__ so_b,
                                  const float* __restrict__ aw_w,
                                  const float* __restrict__ aw_b,
                                  float* __restrict__ wm,
                                  float* __restrict__ wcat,
                                  float* __restrict__ bcat) {
    const int tid = threadIdx.x;
    if (blockIdx.y == 8) {
        const int r0 = blockIdx.x * 48;
        for (int r = r0; r < r0 + 48; ++r) {
            const float* src = (r < 256) ? (so_w + (size_t)r * 256)
                                         : (aw_w + (size_t)(r - 256) * 256);
            wcat[(size_t)r * 256 + tid] = src[tid];
        }
        if (tid < 48) {
            int r = r0 + tid;
            bcat[r] = (r < 256) ? so_b[r] : aw_b[r - 256];
        }
        return;
    }

    const int h  = blockIdx.x;
    const int ot = blockIdx.y * 32;
    __shared__ float vs[32][256];

    for (int idx = tid; idx < 32 * 256; idx += 256) {
        int r = idx >> 8, c = idx & 255;
        vs[r][c] = v_w[(size_t)(32 * h + r) * 256 + c];
    }
    __syncthreads();

    for (int oo = 0; oo < 32; ++oo) {
        const int o = ot + oo;
        const float* opr = op_w + (size_t)o * 256 + 32 * h;
        float s = 0.f;
#pragma unroll
        for (int j = 0; j < 32; ++j) s = fmaf(opr[j], vs[j][tid], s);
        wm[(size_t)o * kAK + h * 256 + tid] = s;
    }
    if (tid < 32) {
        const int o = ot + tid;
        const float* opr = op_w + (size_t)o * 256 + 32 * h;
        float s = 0.f;
#pragma unroll
        for (int j = 0; j < 32; ++j) s = fmaf(opr[j], v_b[32 * h + j], s);
        wm[(size_t)o * kAK + 2048 + h] = s;
        if (h == 0)
            for (int z = 2056; z < kAK; ++z) wm[(size_t)o * kAK + z] = 0.f;
    }
}

// ---------------------------------------------------------------------------
// Elementwise add
// ---------------------------------------------------------------------------
__global__ void add_kernel(const float* __restrict__ a,
                           const float* __restrict__ b,
                           float* __restrict__ out, int n) {
    int i = blockIdx.x * blockDim.x + threadIdx.x;
    if (i < n) out[i] = a[i] + b[i];
}

// ---------------------------------------------------------------------------
// Residual + LayerNorm (256 features, one block per row).
// ---------------------------------------------------------------------------
template <bool WITH_POS>
__global__ void add_ln_kernel(const float* __restrict__ x,
                              const float* __restrict__ r,
                              const float* __restrict__ g,
                              const float* __restrict__ bta,
                              float* __restrict__ out,
                              const float* __restrict__ pos,
                              float* __restrict__ out2) {
    const int row = blockIdx.x;
    const int t = threadIdx.x;
    const size_t base = (size_t)row * kD;
    float v = x[base + t] + r[base + t];

    __shared__ float sm[8];
    float s = v;
#pragma unroll
    for (int o = 16; o > 0; o >>= 1) s += __shfl_xor_sync(~0u, s, o);
    if ((t & 31) == 0) sm[t >> 5] = s;
    __syncthreads();
    float tot = 0.f;
#pragma unroll
    for (int i = 0; i < 8; ++i) tot += sm[i];
    const float mean = tot * (1.f / kD);
    const float d = v - mean;
    float s2 = d * d;
#pragma unroll
    for (int o = 16; o > 0; o >>= 1) s2 += __shfl_xor_sync(~0u, s2, o);
    __syncthreads();
    if ((t & 31) == 0) sm[t >> 5] = s2;
    __syncthreads();
    float tot2 = 0.f;
#pragma unroll
    for (int i = 0; i < 8; ++i) tot2 += sm[i];
    const float var = tot2 * (1.f / kD);
    const float o1 = d * rsqrtf(var + 1e-5f) * g[t] + bta[t];
    out[base + t] = o1;
    if (WITH_POS) out2[base + t] = o1 + pos[base + t];
}

// ---------------------------------------------------------------------------
// Self attention with SMEM-cached K/V.
// grid = (5 qchunks of 60, NH, BS), block = 256 (8 warps).
// qkv rows: [q(0..255) | k(256..511) | v(512..767)], stride 768.
// SMEM: Ks[300][33] (lane-per-key conflict-free), Vs[300][32], ps[8][304].
// ---------------------------------------------------------------------------
namespace {
constexpr int kQC = 60;              // queries per block
constexpr int kKLD = 33;             // Ks row stride
constexpr int ATTN_SMEM =
    (kNQ * kKLD + kNQ * kDH + 8 * 304) * 4;   // 39600+38400+9728 = 87728 B
}

__global__ __launch_bounds__(256, 2)
void self_attn_kernel(const float* __restrict__ qkv,
                      float* __restrict__ o) {
    extern __shared__ float sm[];
    float* Ks = sm;                      // [300][33]
    float* Vs = sm + kNQ * kKLD;         // [300][32]
    float* ps = Vs + kNQ * kDH;          // [8][304]

    const int tid  = threadIdx.x;
    const int w    = tid >> 5;
    const int lane = tid & 31;
    const int h = blockIdx.y;
    const int b = blockIdx.z;
    const int q0 = blockIdx.x * kQC;

    // cooperative K/V load: idx over 300 rows x 8 float4-groups
    for (int idx = tid; idx < kNQ * 8; idx += 256) {
        const int r = idx >> 3, g4 = (idx & 7) * 4;
        const float* base = qkv + ((size_t)(b * kNQ + r)) * 768 + h * kDH + g4;
        float4 kv = *(const float4*)(base + 256);
        Ks[r * kKLD + g4 + 0] = kv.x;
        Ks[r * kKLD + g4 + 1] = kv.y;
        Ks[r * kKLD + g4 + 2] = kv.z;
        Ks[r * kKLD + g4 + 3] = kv.w;
        *(float4*)&Vs[r * kDH + g4] = *(const float4*)(base + 512);
    }
    __syncthreads();

    const float scale = 0.1767766952966369f;  // 1/sqrt(32)

    for (int q = q0 + w; q < q0 + kQC && q < kNQ; q += 8) {
        // q vector in registers (broadcast loads, L1-resident)
        float qreg[32];
        const float4* qr =
            (const float4*)(qkv + ((size_t)(b * kNQ + q)) * 768 + h * kDH);
#pragma unroll
        for (int j = 0; j < 8; ++j) {
            float4 v = qr[j];
            qreg[j * 4 + 0] = v.x; qreg[j * 4 + 1] = v.y;
            qreg[j * 4 + 2] = v.z; qreg[j * 4 + 3] = v.w;
        }

        // scores: lane-per-key
        float sc[10];
        float m = -INFINITY;
#pragma unroll
        for (int c = 0; c < 10; ++c) {
            const int k = c * 32 + lane;
            const float* kr = &Ks[(k < kNQ ? k : 0) * kKLD];
            float dot = 0.f;
#pragma unroll
            for (int j = 0; j < 32; ++j) dot = fmaf(kr[j], qreg[j], dot);
            dot *= scale;
            if (k >= kNQ) dot = -INFINITY;
            sc[c] = dot;
            m = fmaxf(m, dot);
        }
#pragma unroll
        for (int off = 16; off > 0; off >>= 1)
            m = fmaxf(m, __shfl_xor_sync(~0u, m, off));

        float sum = 0.f;
#pragma unroll
        for (int c = 0; c < 10; ++c) {
            const int k = c * 32 + lane;
            float e = (k < kNQ) ? expf(sc[c] - m) : 0.f;
            if (k < 304) ps[w * 304 + k] = e;
            sum += e;
        }
#pragma unroll
        for (int off = 16; off > 0; off >>= 1)
            sum += __shfl_xor_sync(~0u, sum, off);
        const float inv = 1.f / sum;
        __syncwarp();

        // PV: float4 p broadcast + conflict-free Vs reads
        float acc = 0.f;
#pragma unroll 5
        for (int c = 0; c < kNQ / 4; ++c) {
            float4 p4 = *(const float4*)&ps[w * 304 + c * 4];
            acc = fmaf(p4.x, Vs[(c * 4 + 0) * kDH + lane], acc);
            acc = fmaf(p4.y, Vs[(c * 4 + 1) * kDH + lane], acc);
            acc = fmaf(p4.z, Vs[(c * 4 + 2) * kDH + lane], acc);
            acc = fmaf(p4.w, Vs[(c * 4 + 3) * kDH + lane], acc);
        }
        __syncwarp();

        o[((size_t)(b * kNQ + q)) * kD + h * kDH + lane] = acc * inv;
    }
}

// ---------------------------------------------------------------------------
// MS deformable aggregation over RAW memory rows.
// ---------------------------------------------------------------------------
__global__ void msdeform_agg_kernel(const float* __restrict__ ref,
                                    const float* __restrict__ oa,
                                    const float* __restrict__ memory,
                                    float* __restrict__ agg) {
    const int bq = blockIdx.x;
    const int b = bq / kNQ;
    const int t = threadIdx.x;
    const int h = t >> 5;
    const int lane = t & 31;

    __shared__ float s_p[kNH][16];

    float lw = (lane < 16) ? oa[(size_t)bq * kOW + 256 + h * 16 + lane] : -INFINITY;
    float m = lw;
#pragma unroll
    for (int o = 8; o > 0; o >>= 1) m = fmaxf(m, __shfl_xor_sync(~0u, m, o, 16));
    float e = (lane < 16) ? expf(lw - m) : 0.f;
    float sum = e;
#pragma unroll
    for (int o = 8; o > 0; o >>= 1) sum += __shfl_xor_sync(~0u, sum, o, 16);
    if (lane < 16) s_p[h][lane] = e / sum;
    __syncwarp();

    const int cH[kNL]  = {100, 50, 25, 13};
    const int cW[kNL]  = {150, 75, 38, 19};
    const int cS0[kNL] = {0, 15000, 18750, 19700};

    float a0 = 0.f, a1 = 0.f, a2 = 0.f, a3 = 0.f;
    float a4 = 0.f, a5 = 0.f, a6 = 0.f, a7 = 0.f;
    float bsum = 0.f;

#pragma unroll
    for (int l = 0; l < kNL; ++l) {
        const float rx = ref[((size_t)bq * kNL + l) * 2 + 0];
        const float ry = ref[((size_t)bq * kNL + l) * 2 + 1];
        const int Hl = cH[l], Wl = cW[l], s0 = cS0[l];
        const float fW = (float)Wl, fH = (float)Hl;
#pragma unroll
        for (int p = 0; p < kNP; ++p) {
            const float aw = s_p[h][l * kNP + p];
            const size_t ob = (size_t)bq * kOW + (((h * kNL + l) * kNP + p) * 2);
            const float ox = oa[ob + 0];
            const float oy = oa[ob + 1];
            const float x = (rx + ox / fW) * fW - 0.5f;
            const float y = (ry + oy / fH) * fH - 0.5f;
            const float x0f = floorf(x), y0f = floorf(y);
            const float tx = x - x0f, ty = y - y0f;
            const int x0 = (int)x0f, y0 = (int)y0f;

#pragma unroll
            for (int dy = 0; dy < 2; ++dy) {
#pragma unroll
                for (int dx = 0; dx < 2; ++dx) {
                    const int xi = x0 + dx, yi = y0 + dy;
                    const bool valid = (xi >= 0) & (xi < Wl) & (yi >= 0) & (yi < Hl);
                    if (valid) {
                        const float w =
                            aw * (dy ? ty : (1.f - ty)) * (dx ? tx : (1.f - tx));
                        const float4* row = (const float4*)(
                            memory + ((size_t)b * kS + s0 + yi * Wl + xi) * kD +
                            lane * 8);
                        float4 v0 = row[0];
                        float4 v1 = row[1];
                        a0 = fmaf(w, v0.x, a0); a1 = fmaf(w, v0.y, a1);
                        a2 = fmaf(w, v0.z, a2); a3 = fmaf(w, v0.w, a3);
                        a4 = fmaf(w, v1.x, a4); a5 = fmaf(w, v1.y, a5);
                        a6 = fmaf(w, v1.z, a6); a7 = fmaf(w, v1.w, a7);
                        bsum += w;
                    }
                }
            }
        }
    }

    float4* dst = (float4*)(agg + (size_t)bq * kAK + h * 256 + lane * 8);
    dst[0] = make_float4(a0, a1, a2, a3);
    dst[1] = make_float4(a4, a5, a6, a7);
    if (lane == 0) agg[(size_t)bq * kAK + 2048 + h] = bsum;
    if (h == 0 && lane < 24) agg[(size_t)bq * kAK + 2056 + lane] = 0.f;
}

// ---------------------------------------------------------------------------
// Launch helpers
// ---------------------------------------------------------------------------
static void ensure_attrs() {
    static bool done = false;
    if (done) return;
    cudaFuncSetAttribute((const void*)gemm_tf32_kernel<3, false>,
                         cudaFuncAttributeMaxDynamicSharedMemorySize,
                         gemm_smem_bytes<3>());
    cudaFuncSetAttribute((const void*)gemm_tf32_kernel<3, true>,
                         cudaFuncAttributeMaxDynamicSharedMemorySize,
                         gemm_smem_bytes<3>());
    cudaFuncSetAttribute((const void*)gemm_tf32_kernel<4, false>,
                         cudaFuncAttributeMaxDynamicSharedMemorySize,
                         gemm_smem_bytes<4>());
    cudaFuncSetAttribute((const void*)self_attn_kernel,
                         cudaFuncAttributeMaxDynamicSharedMemorySize,
                         ATTN_SMEM);
    done = true;
}

static inline void launch_gemm(const float* A, const float* W, const float* b,
                               float* C, int M, int N, int K, bool relu) {
    dim3 grid(N / 64, (M + 63) / 64);
    if (relu)
        gemm_tf32_kernel<3, true><<<grid, 256, gemm_smem_bytes<3>()>>>(
            A, A, N, W, b, C, M, N, K);
    else
        gemm_tf32_kernel<3, false><<<grid, 256, gemm_smem_bytes<3>()>>>(
            A, A, N, W, b, C, M, N, K);
}

extern "C" void kernel_launch(void* const* d_in, const int* in_sizes, int n_in,
                              void* d_out, int out_size) {
    const float* tgt    = (const float*)d_in[0];
    const float* pos    = (const float*)d_in[1];
    const float* ref    = (const float*)d_in[2];
    const float* memory = (const float*)d_in[3];
    const float* in_w  = (const float*)d_in[7];
    const float* in_b  = (const float*)d_in[8];
    const float* out_w = (const float*)d_in[9];
    const float* out_b = (const float*)d_in[10];
    const float* n1g = (const float*)d_in[11];
    const float* n1b = (const float*)d_in[12];
    const float* n2g = (const float*)d_in[13];
    const float* n2b = (const float*)d_in[14];
    const float* n3g = (const float*)d_in[15];
    const float* n3b = (const float*)d_in[16];
    const float* so_w = (const float*)d_in[17];
    const float* so_b = (const float*)d_in[18];
    const float* aw_w = (const float*)d_in[19];
    const float* aw_b = (const float*)d_in[20];
    const float* v_w  = (const float*)d_in[21];
    const float* v_b  = (const float*)d_in[22];
    const float* op_w = (const float*)d_in[23];
    const float* op_b = (const float*)d_in[24];
    const float* l1w  = (const float*)d_in[25];
    const float* l1b  = (const float*)d_in[26];
    const float* l2w  = (const float*)d_in[27];
    const float* l2b  = (const float*)d_in[28];

    float* scratch = nullptr;
    cudaGetSymbolAddress((void**)&scratch, g_scratch);
    ensure_attrs();

    float* s_qkadd = scratch + OFF_QKADD;
    float* s_qkv   = scratch + OFF_QKV;
    float* s_attn  = scratch + OFF_ATTN;
    float* s_sa    = scratch + OFF_SA;
    float* s_tgt1  = scratch + OFF_TGT1;
    float* s_query = scratch + OFF_QUERY;
    float* s_oa    = scratch + OFF_OA;
    float* s_t2    = scratch + OFF_T2;
    float* s_tgt2  = scratch + OFF_TGT2;
    float* s_hid   = scratch + OFF_HID;
    float* s_ffo   = scratch + OFF_FFO;
    float* s_agg   = scratch + OFF_AGG;
    float* s_wm    = scratch + OFF_WM;
    float* s_wcat  = scratch + OFF_WCAT;
    float* s_bcat  = scratch + OFF_BCAT;

    const int nQD = kMQ * kD;

    // ---- precompute (Wm, weight concat) + qkadd ----
    {
        dim3 grid(kNH, 9);
        precompute_kernel<<<grid, 256>>>(op_w, v_w, v_b, so_w, so_b, aw_w, aw_b,
                                         s_wm, s_wcat, s_bcat);
    }
    add_kernel<<<(nQD + 255) / 256, 256>>>(tgt, pos, s_qkadd, nQD);

    // ---- self attention: merged QKV GEMM + SMEM-cached attention ----
    {
        dim3 grid(768 / 64, (kMQ + 63) / 64);
        gemm_tf32_kernel<3, false><<<grid, 256, gemm_smem_bytes<3>()>>>(
            s_qkadd, tgt, 512, in_w, in_b, s_qkv, kMQ, 768, kD);
    }
    {
        dim3 grid((kNQ + kQC - 1) / kQC, kNH, kBS);
        self_attn_kernel<<<grid, 256, ATTN_SMEM>>>(s_qkv, s_attn);
    }
    launch_gemm(s_attn, out_w, out_b, s_sa, kMQ, kD, kD, false);
    add_ln_kernel<true><<<kMQ, 256>>>(tgt, s_sa, n2g, n2b, s_tgt1, pos, s_query);

    // ---- MS deformable attention (merged offs+awl GEMM; value GEMM folded) ----
    launch_gemm(s_query, s_wcat, s_bcat, s_oa, kMQ, kOW, kD, false);
    msdeform_agg_kernel<<<kMQ, 256>>>(ref, s_oa, memory, s_agg);
    {
        dim3 grid(kD / 64, (kMQ + 63) / 64);
        gemm_tf32_kernel<4, false><<<grid, 256, gemm_smem_bytes<4>()>>>(
            s_agg, s_agg, kD, s_wm, op_b, s_t2, kMQ, kD, kAK);
    }
    add_ln_kernel<false><<<kMQ, 256>>>(s_tgt1, s_t2, n1g, n1b, s_tgt2,
                                       nullptr, nullptr);

    // ---- FFN ----
    launch_gemm(s_tgt2, l1w, l1b, s_hid, kMQ, kDFF, kD, true);
    launch_gemm(s_hid, l2w, l2b, s_ffo, kMQ, kD, kDFF, false);
    add_ln_kernel<false><<<kMQ, 256>>>(s_tgt2, s_ffo, n3g, n3b, (float*)d_out,
                                       nullptr, nullptr);
}

// round 8
// speedup vs baseline: 4.9362x; 1.1104x over previous
#include <cuda_runtime.h>
#include <math.h>
#include <stdint.h>

// ---------------------------------------------------------------------------
// Problem constants
// ---------------------------------------------------------------------------
namespace {
constexpr int kD   = 256;
constexpr int kNH  = 8;
constexpr int kDH  = 32;
constexpr int kNL  = 4;
constexpr int kNP  = 4;
constexpr int kDFF = 1024;
constexpr int kBS  = 8;
constexpr int kNQ  = 300;
constexpr int kS   = 19947;
constexpr int kMQ  = kBS * kNQ;      // 2400
constexpr int kAK  = 2080;           // agg K: 8*256 + 8 bias + 24 pad (65*32)
constexpr int kOW  = 384;            // merged offs(256) + awl(128) width

constexpr size_t OFF_QKADD = 0;
constexpr size_t OFF_QKV   = OFF_QKADD + (size_t)kMQ * kD;   // [2400][768]
constexpr size_t OFF_ATTN  = OFF_QKV   + (size_t)kMQ * 768;
constexpr size_t OFF_SA    = OFF_ATTN  + (size_t)kMQ * kD;
constexpr size_t OFF_TGT1  = OFF_SA    + (size_t)kMQ * kD;
constexpr size_t OFF_QUERY = OFF_TGT1  + (size_t)kMQ * kD;
constexpr size_t OFF_OA    = OFF_QUERY + (size_t)kMQ * kD;   // [2400][384]
constexpr size_t OFF_T2    = OFF_OA    + (size_t)kMQ * kOW;
constexpr size_t OFF_TGT2  = OFF_T2    + (size_t)kMQ * kD;
constexpr size_t OFF_HID   = OFF_TGT2  + (size_t)kMQ * kD;
constexpr size_t OFF_FFO   = OFF_HID   + (size_t)kMQ * kDFF;
constexpr size_t OFF_AGG   = OFF_FFO   + (size_t)kMQ * kD;
constexpr size_t OFF_WM    = OFF_AGG   + (size_t)kMQ * kAK;
constexpr size_t OFF_WCAT  = OFF_WM    + (size_t)kD * kAK;   // [384][256]
constexpr size_t OFF_BCAT  = OFF_WCAT  + (size_t)kOW * kD;   // [384]
constexpr size_t SCRATCH_TOTAL = OFF_BCAT + kOW;
} // namespace

__device__ float g_scratch[SCRATCH_TOTAL];

// ---------------------------------------------------------------------------
// helpers
// ---------------------------------------------------------------------------
__device__ __forceinline__ uint32_t smem_u32(const void* p) {
    uint32_t a;
    asm("{ .reg .u64 t; cvta.to.shared.u64 t, %1; cvt.u32.u64 %0, t; }"
        : "=r"(a) : "l"(p));
    return a;
}

__device__ __forceinline__ void cp_async16(uint32_t dst, const void* src, bool pred) {
    int sz = pred ? 16 : 0;
    asm volatile("cp.async.cg.shared.global [%0], [%1], 16, %2;"
                 :: "r"(dst), "l"(src), "r"(sz));
}
__device__ __forceinline__ void cp_commit() {
    asm volatile("cp.async.commit_group;");
}
template <int N>
__device__ __forceinline__ void cp_wait() {
    asm volatile("cp.async.wait_group %0;" :: "n"(N));
}

__device__ __forceinline__ void mma_tf32(float (&d)[4],
                                         const uint32_t (&a)[4],
                                         const uint32_t (&b)[2]) {
    asm volatile(
        "mma.sync.aligned.m16n8k8.row.col.f32.tf32.tf32.f32 "
        "{%0,%1,%2,%3}, {%4,%5,%6,%7}, {%8,%9}, {%0,%1,%2,%3};"
        : "+f"(d[0]), "+f"(d[1]), "+f"(d[2]), "+f"(d[3])
        : "r"(a[0]), "r"(a[1]), "r"(a[2]), "r"(a[3]),
          "r"(b[0]), "r"(b[1]));
}

// ---------------------------------------------------------------------------
// TF32 tensor-core GEMM with per-n-region A select:
//   C[M,N] = act( Asel[M,K] @ W[N,K]^T + bias[N] )
// Block tile 64x64, BK=32, 8 warps (WM=2,WN=4), STAGES-deep cp.async.
// ---------------------------------------------------------------------------
template <int STAGES, bool RELU>
__global__ __launch_bounds__(256, 2)
void gemm_tf32_kernel(const float* __restrict__ A1,
                      const float* __restrict__ A2,
                      int n_split,
                      const float* __restrict__ W,
                      const float* __restrict__ bias,
                      float* __restrict__ C,
                      int M, int N, int K) {
    constexpr int BM = 64, BN = 64, BK = 32;
    constexpr int LD = BK + 4;                 // 36 words/row
    constexpr int THREADS = 256;
    constexpr int WM = 2;
    constexpr int MT = 2, NT = 2;
    constexpr int A_IT = (BM * BK / 4) / THREADS;   // 2
    constexpr int B_IT = (BN * BK / 4) / THREADS;   // 2

    extern __shared__ float smem[];
    float* As = smem;
    float* Ws = smem + (size_t)STAGES * BM * LD;

    const int tid  = threadIdx.x;
    const int warp = tid >> 5;
    const int lane = tid & 31;
    const int g    = lane >> 2;
    const int tg   = lane & 3;
    const int tm   = blockIdx.y * BM;
    const int tn   = blockIdx.x * BN;
    const int wm   = (warp % WM) * 32;
    const int wn   = (warp / WM) * 16;

    const float* A = (tn < n_split) ? A1 : A2;

    float acc[MT][NT][4] = {};
    const int NK = K / BK;

    auto issue = [&](int s, int kt) {
        if (kt < NK) {
            const int k0 = kt * BK;
#pragma unroll
            for (int i = 0; i < A_IT; ++i) {
                int idx = tid + i * THREADS;
                int r = idx >> 3, c4 = (idx & 7) * 4;
                int gr = tm + r;
                cp_async16(smem_u32(&As[(size_t)s * BM * LD + r * LD + c4]),
                           A + (size_t)gr * K + k0 + c4, gr < M);
            }
#pragma unroll
            for (int i = 0; i < B_IT; ++i) {
                int idx = tid + i * THREADS;
                int r = idx >> 3, c4 = (idx & 7) * 4;
                cp_async16(smem_u32(&Ws[(size_t)s * BN * LD + r * LD + c4]),
                           W + (size_t)(tn + r) * K + k0 + c4, true);
            }
        }
        cp_commit();
    };

    issue(0, 0);
#pragma unroll
    for (int p = 1; p < STAGES - 1; ++p) issue(p, p);

    for (int kt = 0; kt < NK; ++kt) {
        const int s = kt % STAGES;
        cp_wait<STAGES - 2>();
        __syncthreads();
        issue((kt + STAGES - 1) % STAGES, kt + STAGES - 1);

        const float* as = &As[(size_t)s * BM * LD];
        const float* ws = &Ws[(size_t)s * BN * LD];
#pragma unroll
        for (int ks = 0; ks < 4; ++ks) {
            const int kc = ks * 8 + tg;
            uint32_t af[MT][4], bf[NT][2];
#pragma unroll
            for (int mt = 0; mt < MT; ++mt) {
                const int r = wm + mt * 16 + g;
                af[mt][0] = __float_as_uint(as[r * LD + kc]);
                af[mt][1] = __float_as_uint(as[(r + 8) * LD + kc]);
                af[mt][2] = __float_as_uint(as[r * LD + kc + 4]);
                af[mt][3] = __float_as_uint(as[(r + 8) * LD + kc + 4]);
            }
#pragma unroll
            for (int nt = 0; nt < NT; ++nt) {
                const int n = wn + nt * 8 + g;
                bf[nt][0] = __float_as_uint(ws[n * LD + kc]);
                bf[nt][1] = __float_as_uint(ws[n * LD + kc + 4]);
            }
#pragma unroll
            for (int mt = 0; mt < MT; ++mt)
#pragma unroll
                for (int nt = 0; nt < NT; ++nt)
                    mma_tf32(acc[mt][nt], af[mt], bf[nt]);
        }
        __syncthreads();
    }

#pragma unroll
    for (int mt = 0; mt < MT; ++mt) {
        const int gr0 = tm + wm + mt * 16 + g;
        const int gr1 = gr0 + 8;
#pragma unroll
        for (int nt = 0; nt < NT; ++nt) {
            const int gc = tn + wn + nt * 8 + tg * 2;
            const float b0 = bias[gc], b1 = bias[gc + 1];
            if (gr0 < M) {
                float v0 = acc[mt][nt][0] + b0;
                float v1 = acc[mt][nt][1] + b1;
                if (RELU) { v0 = fmaxf(v0, 0.f); v1 = fmaxf(v1, 0.f); }
                *(float2*)(C + (size_t)gr0 * N + gc) = make_float2(v0, v1);
            }
            if (gr1 < M) {
                float v2 = acc[mt][nt][2] + b0;
                float v3 = acc[mt][nt][3] + b1;
                if (RELU) { v2 = fmaxf(v2, 0.f); v3 = fmaxf(v3, 0.f); }
                *(float2*)(C + (size_t)gr1 * N + gc) = make_float2(v2, v3);
            }
        }
    }
}

template <int STAGES>
constexpr int gemm_smem_bytes() { return STAGES * 128 * 36 * 4; }

// ---------------------------------------------------------------------------
// Precompute kernel. grid = (8, 9), block = 256.
// ---------------------------------------------------------------------------
__global__ void precompute_kernel(const float* __restrict__ op_w,
                                  const float* __restrict__ v_w,
                                  const float* __restrict__ v_b,
                                  const float* __restrict__ so_w,
                                  const float* __restrict__ so_b,
                                  const float* __restrict__ aw_w,
                                  const float* __restrict__ aw_b,
                                  float* __restrict__ wm,
                                  float* __restrict__ wcat,
                                  float* __restrict__ bcat) {
    const int tid = threadIdx.x;
    if (blockIdx.y == 8) {
        const int r0 = blockIdx.x * 48;
        for (int r = r0; r < r0 + 48; ++r) {
            const float* src = (r < 256) ? (so_w + (size_t)r * 256)
                                         : (aw_w + (size_t)(r - 256) * 256);
            wcat[(size_t)r * 256 + tid] = src[tid];
        }
        if (tid < 48) {
            int r = r0 + tid;
            bcat[r] = (r < 256) ? so_b[r] : aw_b[r - 256];
        }
        return;
    }

    const int h  = blockIdx.x;
    const int ot = blockIdx.y * 32;
    __shared__ float vs[32][256];

    for (int idx = tid; idx < 32 * 256; idx += 256) {
        int r = idx >> 8, c = idx & 255;
        vs[r][c] = v_w[(size_t)(32 * h + r) * 256 + c];
    }
    __syncthreads();

    for (int oo = 0; oo < 32; ++oo) {
        const int o = ot + oo;
        const float* opr = op_w + (size_t)o * 256 + 32 * h;
        float s = 0.f;
#pragma unroll
        for (int j = 0; j < 32; ++j) s = fmaf(opr[j], vs[j][tid], s);
        wm[(size_t)o * kAK + h * 256 + tid] = s;
    }
    if (tid < 32) {
        const int o = ot + tid;
        const float* opr = op_w + (size_t)o * 256 + 32 * h;
        float s = 0.f;
#pragma unroll
        for (int j = 0; j < 32; ++j) s = fmaf(opr[j], v_b[32 * h + j], s);
        wm[(size_t)o * kAK + 2048 + h] = s;
        if (h == 0)
            for (int z = 2056; z < kAK; ++z) wm[(size_t)o * kAK + z] = 0.f;
    }
}

// ---------------------------------------------------------------------------
// Elementwise add
// ---------------------------------------------------------------------------
__global__ void add_kernel(const float* __restrict__ a,
                           const float* __restrict__ b,
                           float* __restrict__ out, int n) {
    int i = blockIdx.x * blockDim.x + threadIdx.x;
    if (i < n) out[i] = a[i] + b[i];
}

// ---------------------------------------------------------------------------
// Residual + LayerNorm (256 features, one block per row).
// ---------------------------------------------------------------------------
template <bool WITH_POS>
__global__ void add_ln_kernel(const float* __restrict__ x,
                              const float* __restrict__ r,
                              const float* __restrict__ g,
                              const float* __restrict__ bta,
                              float* __restrict__ out,
                              const float* __restrict__ pos,
                              float* __restrict__ out2) {
    const int row = blockIdx.x;
    const int t = threadIdx.x;
    const size_t base = (size_t)row * kD;
    float v = x[base + t] + r[base + t];

    __shared__ float sm[8];
    float s = v;
#pragma unroll
    for (int o = 16; o > 0; o >>= 1) s += __shfl_xor_sync(~0u, s, o);
    if ((t & 31) == 0) sm[t >> 5] = s;
    __syncthreads();
    float tot = 0.f;
#pragma unroll
    for (int i = 0; i < 8; ++i) tot += sm[i];
    const float mean = tot * (1.f / kD);
    const float d = v - mean;
    float s2 = d * d;
#pragma unroll
    for (int o = 16; o > 0; o >>= 1) s2 += __shfl_xor_sync(~0u, s2, o);
    __syncthreads();
    if ((t & 31) == 0) sm[t >> 5] = s2;
    __syncthreads();
    float tot2 = 0.f;
#pragma unroll
    for (int i = 0; i < 8; ++i) tot2 += sm[i];
    const float var = tot2 * (1.f / kD);
    const float o1 = d * rsqrtf(var + 1e-5f) * g[t] + bta[t];
    out[base + t] = o1;
    if (WITH_POS) out2[base + t] = o1 + pos[base + t];
}

// ---------------------------------------------------------------------------
// Self attention with SMEM-cached K/V, two queries per warp iteration.
// grid = (2 qchunks of 150, NH, BS), block = 256 (8 warps).
// qkv rows: [q(0..255) | k(256..511) | v(512..767)], stride 768.
// SMEM: Ks[300][33], Vs[300][32], ps[8][2][304].
// ---------------------------------------------------------------------------
namespace {
constexpr int kQC = 150;             // queries per block (even)
constexpr int kKLD = 33;             // Ks row stride
constexpr int ATTN_SMEM =
    (kNQ * kKLD + kNQ * kDH + 8 * 2 * 304) * 4;   // 39600+38400+19456 = 97456 B
}

__global__ __launch_bounds__(256, 2)
void self_attn_kernel(const float* __restrict__ qkv,
                      float* __restrict__ o) {
    extern __shared__ float sm[];
    float* Ks = sm;                      // [300][33]
    float* Vs = sm + kNQ * kKLD;         // [300][32]
    float* ps = Vs + kNQ * kDH;          // [8][2][304]

    const int tid  = threadIdx.x;
    const int w    = tid >> 5;
    const int lane = tid & 31;
    const int h = blockIdx.y;
    const int b = blockIdx.z;
    const int q0 = blockIdx.x * kQC;

    // cooperative K/V load
    for (int idx = tid; idx < kNQ * 8; idx += 256) {
        const int r = idx >> 3, g4 = (idx & 7) * 4;
        const float* base = qkv + ((size_t)(b * kNQ + r)) * 768 + h * kDH + g4;
        float4 kv = *(const float4*)(base + 256);
        Ks[r * kKLD + g4 + 0] = kv.x;
        Ks[r * kKLD + g4 + 1] = kv.y;
        Ks[r * kKLD + g4 + 2] = kv.z;
        Ks[r * kKLD + g4 + 3] = kv.w;
        *(float4*)&Vs[r * kDH + g4] = *(const float4*)(base + 512);
    }
    __syncthreads();

    const float scale = 0.1767766952966369f;  // 1/sqrt(32)
    float* ps0 = &ps[(w * 2 + 0) * 304];
    float* ps1 = &ps[(w * 2 + 1) * 304];

    // pairs (q, q+1); kQC even, so all pairs in-range
    for (int q = q0 + w * 2; q < q0 + kQC; q += 16) {
        float q0reg[32], q1reg[32];
        const float4* qr0 =
            (const float4*)(qkv + ((size_t)(b * kNQ + q)) * 768 + h * kDH);
        const float4* qr1 =
            (const float4*)(qkv + ((size_t)(b * kNQ + q + 1)) * 768 + h * kDH);
#pragma unroll
        for (int j = 0; j < 8; ++j) {
            float4 v0 = qr0[j], v1 = qr1[j];
            q0reg[j * 4 + 0] = v0.x; q0reg[j * 4 + 1] = v0.y;
            q0reg[j * 4 + 2] = v0.z; q0reg[j * 4 + 3] = v0.w;
            q1reg[j * 4 + 0] = v1.x; q1reg[j * 4 + 1] = v1.y;
            q1reg[j * 4 + 2] = v1.z; q1reg[j * 4 + 3] = v1.w;
        }

        // scores: lane-per-key, shared K read feeds both queries
        float sc0[10], sc1[10];
        float m0 = -INFINITY, m1 = -INFINITY;
#pragma unroll
        for (int c = 0; c < 10; ++c) {
            const int k = c * 32 + lane;
            const float* kr = &Ks[(k < kNQ ? k : 0) * kKLD];
            float d0 = 0.f, d1 = 0.f;
#pragma unroll
            for (int j = 0; j < 32; ++j) {
                const float kv = kr[j];
                d0 = fmaf(kv, q0reg[j], d0);
                d1 = fmaf(kv, q1reg[j], d1);
            }
            d0 *= scale; d1 *= scale;
            if (k >= kNQ) { d0 = -INFINITY; d1 = -INFINITY; }
            sc0[c] = d0; sc1[c] = d1;
            m0 = fmaxf(m0, d0); m1 = fmaxf(m1, d1);
        }
#pragma unroll
        for (int off = 16; off > 0; off >>= 1) {
            m0 = fmaxf(m0, __shfl_xor_sync(~0u, m0, off));
            m1 = fmaxf(m1, __shfl_xor_sync(~0u, m1, off));
        }

        float s0 = 0.f, s1 = 0.f;
#pragma unroll
        for (int c = 0; c < 10; ++c) {
            const int k = c * 32 + lane;
            float e0 = (k < kNQ) ? expf(sc0[c] - m0) : 0.f;
            float e1 = (k < kNQ) ? expf(sc1[c] - m1) : 0.f;
            if (k < 304) { ps0[k] = e0; ps1[k] = e1; }
            s0 += e0; s1 += e1;
        }
#pragma unroll
        for (int off = 16; off > 0; off >>= 1) {
            s0 += __shfl_xor_sync(~0u, s0, off);
            s1 += __shfl_xor_sync(~0u, s1, off);
        }
        const float inv0 = 1.f / s0, inv1 = 1.f / s1;
        __syncwarp();

        // PV: shared Vs reads feed both queries
        float a0 = 0.f, a1 = 0.f;
#pragma unroll 5
        for (int c = 0; c < kNQ / 4; ++c) {
            float4 p0 = *(const float4*)&ps0[c * 4];
            float4 p1 = *(const float4*)&ps1[c * 4];
            const float v0 = Vs[(c * 4 + 0) * kDH + lane];
            const float v1 = Vs[(c * 4 + 1) * kDH + lane];
            const float v2 = Vs[(c * 4 + 2) * kDH + lane];
            const float v3 = Vs[(c * 4 + 3) * kDH + lane];
            a0 = fmaf(p0.x, v0, a0); a1 = fmaf(p1.x, v0, a1);
            a0 = fmaf(p0.y, v1, a0); a1 = fmaf(p1.y, v1, a1);
            a0 = fmaf(p0.z, v2, a0); a1 = fmaf(p1.z, v2, a1);
            a0 = fmaf(p0.w, v3, a0); a1 = fmaf(p1.w, v3, a1);
        }
        __syncwarp();

        o[((size_t)(b * kNQ + q)) * kD + h * kDH + lane] = a0 * inv0;
        o[((size_t)(b * kNQ + q + 1)) * kD + h * kDH + lane] = a1 * inv1;
    }
}

// ---------------------------------------------------------------------------
// MS deformable aggregation over RAW memory rows.
// ---------------------------------------------------------------------------
__global__ void msdeform_agg_kernel(const float* __restrict__ ref,
                                    const float* __restrict__ oa,
                                    const float* __restrict__ memory,
                                    float* __restrict__ agg) {
    const int bq = blockIdx.x;
    const int b = bq / kNQ;
    const int t = threadIdx.x;
    const int h = t >> 5;
    const int lane = t & 31;

    __shared__ float s_p[kNH][16];

    float lw = (lane < 16) ? oa[(size_t)bq * kOW + 256 + h * 16 + lane] : -INFINITY;
    float m = lw;
#pragma unroll
    for (int o = 8; o > 0; o >>= 1) m = fmaxf(m, __shfl_xor_sync(~0u, m, o, 16));
    float e = (lane < 16) ? expf(lw - m) : 0.f;
    float sum = e;
#pragma unroll
    for (int o = 8; o > 0; o >>= 1) sum += __shfl_xor_sync(~0u, sum, o, 16);
    if (lane < 16) s_p[h][lane] = e / sum;
    __syncwarp();

    const int cH[kNL]  = {100, 50, 25, 13};
    const int cW[kNL]  = {150, 75, 38, 19};
    const int cS0[kNL] = {0, 15000, 18750, 19700};

    float a0 = 0.f, a1 = 0.f, a2 = 0.f, a3 = 0.f;
    float a4 = 0.f, a5 = 0.f, a6 = 0.f, a7 = 0.f;
    float bsum = 0.f;

#pragma unroll
    for (int l = 0; l < kNL; ++l) {
        const float rx = ref[((size_t)bq * kNL + l) * 2 + 0];
        const float ry = ref[((size_t)bq * kNL + l) * 2 + 1];
        const int Hl = cH[l], Wl = cW[l], s0 = cS0[l];
        const float fW = (float)Wl, fH = (float)Hl;
#pragma unroll
        for (int p = 0; p < kNP; ++p) {
            const float aw = s_p[h][l * kNP + p];
            const size_t ob = (size_t)bq * kOW + (((h * kNL + l) * kNP + p) * 2);
            const float ox = oa[ob + 0];
            const float oy = oa[ob + 1];
            const float x = (rx + ox / fW) * fW - 0.5f;
            const float y = (ry + oy / fH) * fH - 0.5f;
            const float x0f = floorf(x), y0f = floorf(y);
            const float tx = x - x0f, ty = y - y0f;
            const int x0 = (int)x0f, y0 = (int)y0f;

#pragma unroll
            for (int dy = 0; dy < 2; ++dy) {
#pragma unroll
                for (int dx = 0; dx < 2; ++dx) {
                    const int xi = x0 + dx, yi = y0 + dy;
                    const bool valid = (xi >= 0) & (xi < Wl) & (yi >= 0) & (yi < Hl);
                    if (valid) {
                        const float w =
                            aw * (dy ? ty : (1.f - ty)) * (dx ? tx : (1.f - tx));
                        const float4* row = (const float4*)(
                            memory + ((size_t)b * kS + s0 + yi * Wl + xi) * kD +
                            lane * 8);
                        float4 v0 = row[0];
                        float4 v1 = row[1];
                        a0 = fmaf(w, v0.x, a0); a1 = fmaf(w, v0.y, a1);
                        a2 = fmaf(w, v0.z, a2); a3 = fmaf(w, v0.w, a3);
                        a4 = fmaf(w, v1.x, a4); a5 = fmaf(w, v1.y, a5);
                        a6 = fmaf(w, v1.z, a6); a7 = fmaf(w, v1.w, a7);
                        bsum += w;
                    }
                }
            }
        }
    }

    float4* dst = (float4*)(agg + (size_t)bq * kAK + h * 256 + lane * 8);
    dst[0] = make_float4(a0, a1, a2, a3);
    dst[1] = make_float4(a4, a5, a6, a7);
    if (lane == 0) agg[(size_t)bq * kAK + 2048 + h] = bsum;
    if (h == 0 && lane < 24) agg[(size_t)bq * kAK + 2056 + lane] = 0.f;
}

// ---------------------------------------------------------------------------
// Launch helpers
// ---------------------------------------------------------------------------
static void ensure_attrs() {
    static bool done = false;
    if (done) return;
    cudaFuncSetAttribute((const void*)gemm_tf32_kernel<3, false>,
                         cudaFuncAttributeMaxDynamicSharedMemorySize,
                         gemm_smem_bytes<3>());
    cudaFuncSetAttribute((const void*)gemm_tf32_kernel<3, true>,
                         cudaFuncAttributeMaxDynamicSharedMemorySize,
                         gemm_smem_bytes<3>());
    cudaFuncSetAttribute((const void*)gemm_tf32_kernel<4, false>,
                         cudaFuncAttributeMaxDynamicSharedMemorySize,
                         gemm_smem_bytes<4>());
    cudaFuncSetAttribute((const void*)self_attn_kernel,
                         cudaFuncAttributeMaxDynamicSharedMemorySize,
                         ATTN_SMEM);
    done = true;
}

static inline void launch_gemm(const float* A, const float* W, const float* b,
                               float* C, int M, int N, int K, bool relu) {
    dim3 grid(N / 64, (M + 63) / 64);
    if (relu)
        gemm_tf32_kernel<3, true><<<grid, 256, gemm_smem_bytes<3>()>>>(
            A, A, N, W, b, C, M, N, K);
    else
        gemm_tf32_kernel<3, false><<<grid, 256, gemm_smem_bytes<3>()>>>(
            A, A, N, W, b, C, M, N, K);
}

extern "C" void kernel_launch(void* const* d_in, const int* in_sizes, int n_in,
                              void* d_out, int out_size) {
    const float* tgt    = (const float*)d_in[0];
    const float* pos    = (const float*)d_in[1];
    const float* ref    = (const float*)d_in[2];
    const float* memory = (const float*)d_in[3];
    const float* in_w  = (const float*)d_in[7];
    const float* in_b  = (const float*)d_in[8];
    const float* out_w = (const float*)d_in[9];
    const float* out_b = (const float*)d_in[10];
    const float* n1g = (const float*)d_in[11];
    const float* n1b = (const float*)d_in[12];
    const float* n2g = (const float*)d_in[13];
    const float* n2b = (const float*)d_in[14];
    const float* n3g = (const float*)d_in[15];
    const float* n3b = (const float*)d_in[16];
    const float* so_w = (const float*)d_in[17];
    const float* so_b = (const float*)d_in[18];
    const float* aw_w = (const float*)d_in[19];
    const float* aw_b = (const float*)d_in[20];
    const float* v_w  = (const float*)d_in[21];
    const float* v_b  = (const float*)d_in[22];
    const float* op_w = (const float*)d_in[23];
    const float* op_b = (const float*)d_in[24];
    const float* l1w  = (const float*)d_in[25];
    const float* l1b  = (const float*)d_in[26];
    const float* l2w  = (const float*)d_in[27];
    const float* l2b  = (const float*)d_in[28];

    float* scratch = nullptr;
    cudaGetSymbolAddress((void**)&scratch, g_scratch);
    ensure_attrs();

    float* s_qkadd = scratch + OFF_QKADD;
    float* s_qkv   = scratch + OFF_QKV;
    float* s_attn  = scratch + OFF_ATTN;
    float* s_sa    = scratch + OFF_SA;
    float* s_tgt1  = scratch + OFF_TGT1;
    float* s_query = scratch + OFF_QUERY;
    float* s_oa    = scratch + OFF_OA;
    float* s_t2    = scratch + OFF_T2;
    float* s_tgt2  = scratch + OFF_TGT2;
    float* s_hid   = scratch + OFF_HID;
    float* s_ffo   = scratch + OFF_FFO;
    float* s_agg   = scratch + OFF_AGG;
    float* s_wm    = scratch + OFF_WM;
    float* s_wcat  = scratch + OFF_WCAT;
    float* s_bcat  = scratch + OFF_BCAT;

    const int nQD = kMQ * kD;

    // ---- precompute (Wm, weight concat) + qkadd ----
    {
        dim3 grid(kNH, 9);
        precompute_kernel<<<grid, 256>>>(op_w, v_w, v_b, so_w, so_b, aw_w, aw_b,
                                         s_wm, s_wcat, s_bcat);
    }
    add_kernel<<<(nQD + 255) / 256, 256>>>(tgt, pos, s_qkadd, nQD);

    // ---- self attention: merged QKV GEMM + SMEM-cached attention ----
    {
        dim3 grid(768 / 64, (kMQ + 63) / 64);
        gemm_tf32_kernel<3, false><<<grid, 256, gemm_smem_bytes<3>()>>>(
            s_qkadd, tgt, 512, in_w, in_b, s_qkv, kMQ, 768, kD);
    }
    {
        dim3 grid(kNQ / kQC, kNH, kBS);
        self_attn_kernel<<<grid, 256, ATTN_SMEM>>>(s_qkv, s_attn);
    }
    launch_gemm(s_attn, out_w, out_b, s_sa, kMQ, kD, kD, false);
    add_ln_kernel<true><<<kMQ, 256>>>(tgt, s_sa, n2g, n2b, s_tgt1, pos, s_query);

    // ---- MS deformable attention (merged offs+awl GEMM; value GEMM folded) ----
    launch_gemm(s_query, s_wcat, s_bcat, s_oa, kMQ, kOW, kD, false);
    msdeform_agg_kernel<<<kMQ, 256>>>(ref, s_oa, memory, s_agg);
    {
        dim3 grid(kD / 64, (kMQ + 63) / 64);
        gemm_tf32_kernel<4, false><<<grid, 256, gemm_smem_bytes<4>()>>>(
            s_agg, s_agg, kD, s_wm, op_b, s_t2, kMQ, kD, kAK);
    }
    add_ln_kernel<false><<<kMQ, 256>>>(s_tgt1, s_t2, n1g, n1b, s_tgt2,
                                       nullptr, nullptr);

    // ---- FFN ----
    launch_gemm(s_tgt2, l1w, l1b, s_hid, kMQ, kDFF, kD, true);
    launch_gemm(s_hid, l2w, l2b, s_ffo, kMQ, kD, kDFF, false);
    add_ln_kernel<false><<<kMQ, 256>>>(s_tgt2, s_ffo, n3g, n3b, (float*)d_out,
                                       nullptr, nullptr);
}

// round 9
// speedup vs baseline: 4.9703x; 1.0069x over previous
#include <cuda_runtime.h>
#include <math.h>
#include <stdint.h>

// ---------------------------------------------------------------------------
// Problem constants
// ---------------------------------------------------------------------------
namespace {
constexpr int kD   = 256;
constexpr int kNH  = 8;
constexpr int kDH  = 32;
constexpr int kNL  = 4;
constexpr int kNP  = 4;
constexpr int kDFF = 1024;
constexpr int kBS  = 8;
constexpr int kNQ  = 300;
constexpr int kS   = 19947;
constexpr int kMQ  = kBS * kNQ;      // 2400
constexpr int kAK  = 2080;           // agg K: 8*256 + 8 bias + 24 pad (65*32)
constexpr int kOW  = 384;            // merged offs(256) + awl(128) width

constexpr size_t OFF_QKADD = 0;
constexpr size_t OFF_QKV   = OFF_QKADD + (size_t)kMQ * kD;   // [2400][768]
constexpr size_t OFF_ATTN  = OFF_QKV   + (size_t)kMQ * 768;
constexpr size_t OFF_SA    = OFF_ATTN  + (size_t)kMQ * kD;
constexpr size_t OFF_TGT1  = OFF_SA    + (size_t)kMQ * kD;
constexpr size_t OFF_QUERY = OFF_TGT1  + (size_t)kMQ * kD;
constexpr size_t OFF_OA    = OFF_QUERY + (size_t)kMQ * kD;   // [2400][384]
constexpr size_t OFF_T2    = OFF_OA    + (size_t)kMQ * kOW;
constexpr size_t OFF_TGT2  = OFF_T2    + (size_t)kMQ * kD;
constexpr size_t OFF_HID   = OFF_TGT2  + (size_t)kMQ * kD;
constexpr size_t OFF_FFO   = OFF_HID   + (size_t)kMQ * kDFF;
constexpr size_t OFF_AGG   = OFF_FFO   + (size_t)kMQ * kD;
constexpr size_t OFF_WM    = OFF_AGG   + (size_t)kMQ * kAK;
constexpr size_t OFF_WCAT  = OFF_WM    + (size_t)kD * kAK;   // [384][256]
constexpr size_t OFF_BCAT  = OFF_WCAT  + (size_t)kOW * kD;   // [384]
constexpr size_t SCRATCH_TOTAL = OFF_BCAT + kOW;
} // namespace

__device__ float g_scratch[SCRATCH_TOTAL];

// ---------------------------------------------------------------------------
// helpers
// ---------------------------------------------------------------------------
__device__ __forceinline__ uint32_t smem_u32(const void* p) {
    uint32_t a;
    asm("{ .reg .u64 t; cvta.to.shared.u64 t, %1; cvt.u32.u64 %0, t; }"
        : "=r"(a) : "l"(p));
    return a;
}

__device__ __forceinline__ void cp_async16(uint32_t dst, const void* src, bool pred) {
    int sz = pred ? 16 : 0;
    asm volatile("cp.async.cg.shared.global [%0], [%1], 16, %2;"
                 :: "r"(dst), "l"(src), "r"(sz));
}
__device__ __forceinline__ void cp_commit() {
    asm volatile("cp.async.commit_group;");
}
template <int N>
__device__ __forceinline__ void cp_wait() {
    asm volatile("cp.async.wait_group %0;" :: "n"(N));
}

__device__ __forceinline__ void mma_tf32(float (&d)[4],
                                         const uint32_t (&a)[4],
                                         const uint32_t (&b)[2]) {
    asm volatile(
        "mma.sync.aligned.m16n8k8.row.col.f32.tf32.tf32.f32 "
        "{%0,%1,%2,%3}, {%4,%5,%6,%7}, {%8,%9}, {%0,%1,%2,%3};"
        : "+f"(d[0]), "+f"(d[1]), "+f"(d[2]), "+f"(d[3])
        : "r"(a[0]), "r"(a[1]), "r"(a[2]), "r"(a[3]),
          "r"(b[0]), "r"(b[1]));
}

// ---------------------------------------------------------------------------
// TF32 tensor-core GEMM with per-n-region A select:
//   C[M,N] = act( Asel[M,K] @ W[N,K]^T + bias[N] )
// Block tile 64x64, BK=32, 8 warps (WM=2,WN=4), STAGES-deep cp.async.
// ---------------------------------------------------------------------------
template <int STAGES, bool RELU>
__global__ __launch_bounds__(256, 2)
void gemm_tf32_kernel(const float* __restrict__ A1,
                      const float* __restrict__ A2,
                      int n_split,
                      const float* __restrict__ W,
                      const float* __restrict__ bias,
                      float* __restrict__ C,
                      int M, int N, int K) {
    constexpr int BM = 64, BN = 64, BK = 32;
    constexpr int LD = BK + 4;                 // 36 words/row
    constexpr int THREADS = 256;
    constexpr int WM = 2;
    constexpr int MT = 2, NT = 2;
    constexpr int A_IT = (BM * BK / 4) / THREADS;   // 2
    constexpr int B_IT = (BN * BK / 4) / THREADS;   // 2

    extern __shared__ float smem[];
    float* As = smem;
    float* Ws = smem + (size_t)STAGES * BM * LD;

    const int tid  = threadIdx.x;
    const int warp = tid >> 5;
    const int lane = tid & 31;
    const int g    = lane >> 2;
    const int tg   = lane & 3;
    const int tm   = blockIdx.y * BM;
    const int tn   = blockIdx.x * BN;
    const int wm   = (warp % WM) * 32;
    const int wn   = (warp / WM) * 16;

    const float* A = (tn < n_split) ? A1 : A2;

    float acc[MT][NT][4] = {};
    const int NK = K / BK;

    auto issue = [&](int s, int kt) {
        if (kt < NK) {
            const int k0 = kt * BK;
#pragma unroll
            for (int i = 0; i < A_IT; ++i) {
                int idx = tid + i * THREADS;
                int r = idx >> 3, c4 = (idx & 7) * 4;
                int gr = tm + r;
                cp_async16(smem_u32(&As[(size_t)s * BM * LD + r * LD + c4]),
                           A + (size_t)gr * K + k0 + c4, gr < M);
            }
#pragma unroll
            for (int i = 0; i < B_IT; ++i) {
                int idx = tid + i * THREADS;
                int r = idx >> 3, c4 = (idx & 7) * 4;
                cp_async16(smem_u32(&Ws[(size_t)s * BN * LD + r * LD + c4]),
                           W + (size_t)(tn + r) * K + k0 + c4, true);
            }
        }
        cp_commit();
    };

    issue(0, 0);
#pragma unroll
    for (int p = 1; p < STAGES - 1; ++p) issue(p, p);

    for (int kt = 0; kt < NK; ++kt) {
        const int s = kt % STAGES;
        cp_wait<STAGES - 2>();
        __syncthreads();
        issue((kt + STAGES - 1) % STAGES, kt + STAGES - 1);

        const float* as = &As[(size_t)s * BM * LD];
        const float* ws = &Ws[(size_t)s * BN * LD];
#pragma unroll
        for (int ks = 0; ks < 4; ++ks) {
            const int kc = ks * 8 + tg;
            uint32_t af[MT][4], bf[NT][2];
#pragma unroll
            for (int mt = 0; mt < MT; ++mt) {
                const int r = wm + mt * 16 + g;
                af[mt][0] = __float_as_uint(as[r * LD + kc]);
                af[mt][1] = __float_as_uint(as[(r + 8) * LD + kc]);
                af[mt][2] = __float_as_uint(as[r * LD + kc + 4]);
                af[mt][3] = __float_as_uint(as[(r + 8) * LD + kc + 4]);
            }
#pragma unroll
            for (int nt = 0; nt < NT; ++nt) {
                const int n = wn + nt * 8 + g;
                bf[nt][0] = __float_as_uint(ws[n * LD + kc]);
                bf[nt][1] = __float_as_uint(ws[n * LD + kc + 4]);
            }
#pragma unroll
            for (int mt = 0; mt < MT; ++mt)
#pragma unroll
                for (int nt = 0; nt < NT; ++nt)
                    mma_tf32(acc[mt][nt], af[mt], bf[nt]);
        }
        __syncthreads();
    }

#pragma unroll
    for (int mt = 0; mt < MT; ++mt) {
        const int gr0 = tm + wm + mt * 16 + g;
        const int gr1 = gr0 + 8;
#pragma unroll
        for (int nt = 0; nt < NT; ++nt) {
            const int gc = tn + wn + nt * 8 + tg * 2;
            const float b0 = bias[gc], b1 = bias[gc + 1];
            if (gr0 < M) {
                float v0 = acc[mt][nt][0] + b0;
                float v1 = acc[mt][nt][1] + b1;
                if (RELU) { v0 = fmaxf(v0, 0.f); v1 = fmaxf(v1, 0.f); }
                *(float2*)(C + (size_t)gr0 * N + gc) = make_float2(v0, v1);
            }
            if (gr1 < M) {
                float v2 = acc[mt][nt][2] + b0;
                float v3 = acc[mt][nt][3] + b1;
                if (RELU) { v2 = fmaxf(v2, 0.f); v3 = fmaxf(v3, 0.f); }
                *(float2*)(C + (size_t)gr1 * N + gc) = make_float2(v2, v3);
            }
        }
    }
}

template <int STAGES>
constexpr int gemm_smem_bytes() { return STAGES * 128 * 36 * 4; }

// ---------------------------------------------------------------------------
// Precompute kernel. grid = (8, 9), block = 256.
// ---------------------------------------------------------------------------
__global__ void precompute_kernel(const float* __restrict__ op_w,
                                  const float* __restrict__ v_w,
                                  const float* __restrict__ v_b,
                                  const float* __restrict__ so_w,
                                  const float* __restrict__ so_b,
                                  const float* __restrict__ aw_w,
                                  const float* __restrict__ aw_b,
                                  float* __restrict__ wm,
                                  float* __restrict__ wcat,
                                  float* __restrict__ bcat) {
    const int tid = threadIdx.x;
    if (blockIdx.y == 8) {
        const int r0 = blockIdx.x * 48;
        for (int r = r0; r < r0 + 48; ++r) {
            const float* src = (r < 256) ? (so_w + (size_t)r * 256)
                                         : (aw_w + (size_t)(r - 256) * 256);
            wcat[(size_t)r * 256 + tid] = src[tid];
        }
        if (tid < 48) {
            int r = r0 + tid;
            bcat[r] = (r < 256) ? so_b[r] : aw_b[r - 256];
        }
        return;
    }

    const int h  = blockIdx.x;
    const int ot = blockIdx.y * 32;
    __shared__ float vs[32][256];

    for (int idx = tid; idx < 32 * 256; idx += 256) {
        int r = idx >> 8, c = idx & 255;
        vs[r][c] = v_w[(size_t)(32 * h + r) * 256 + c];
    }
    __syncthreads();

    for (int oo = 0; oo < 32; ++oo) {
        const int o = ot + oo;
        const float* opr = op_w + (size_t)o * 256 + 32 * h;
        float s = 0.f;
#pragma unroll
        for (int j = 0; j < 32; ++j) s = fmaf(opr[j], vs[j][tid], s);
        wm[(size_t)o * kAK + h * 256 + tid] = s;
    }
    if (tid < 32) {
        const int o = ot + tid;
        const float* opr = op_w + (size_t)o * 256 + 32 * h;
        float s = 0.f;
#pragma unroll
        for (int j = 0; j < 32; ++j) s = fmaf(opr[j], v_b[32 * h + j], s);
        wm[(size_t)o * kAK + 2048 + h] = s;
        if (h == 0)
            for (int z = 2056; z < kAK; ++z) wm[(size_t)o * kAK + z] = 0.f;
    }
}

// ---------------------------------------------------------------------------
// Elementwise add
// ---------------------------------------------------------------------------
__global__ void add_kernel(const float* __restrict__ a,
                           const float* __restrict__ b,
                           float* __restrict__ out, int n) {
    int i = blockIdx.x * blockDim.x + threadIdx.x;
    if (i < n) out[i] = a[i] + b[i];
}

// ---------------------------------------------------------------------------
// Residual + LayerNorm (256 features, one block per row).
// ---------------------------------------------------------------------------
template <bool WITH_POS>
__global__ void add_ln_kernel(const float* __restrict__ x,
                              const float* __restrict__ r,
                              const float* __restrict__ g,
                              const float* __restrict__ bta,
                              float* __restrict__ out,
                              const float* __restrict__ pos,
                              float* __restrict__ out2) {
    const int row = blockIdx.x;
    const int t = threadIdx.x;
    const size_t base = (size_t)row * kD;
    float v = x[base + t] + r[base + t];

    __shared__ float sm[8];
    float s = v;
#pragma unroll
    for (int o = 16; o > 0; o >>= 1) s += __shfl_xor_sync(~0u, s, o);
    if ((t & 31) == 0) sm[t >> 5] = s;
    __syncthreads();
    float tot = 0.f;
#pragma unroll
    for (int i = 0; i < 8; ++i) tot += sm[i];
    const float mean = tot * (1.f / kD);
    const float d = v - mean;
    float s2 = d * d;
#pragma unroll
    for (int o = 16; o > 0; o >>= 1) s2 += __shfl_xor_sync(~0u, s2, o);
    __syncthreads();
    if ((t & 31) == 0) sm[t >> 5] = s2;
    __syncthreads();
    float tot2 = 0.f;
#pragma unroll
    for (int i = 0; i < 8; ++i) tot2 += sm[i];
    const float var = tot2 * (1.f / kD);
    const float o1 = d * rsqrtf(var + 1e-5f) * g[t] + bta[t];
    out[base + t] = o1;
    if (WITH_POS) out2[base + t] = o1 + pos[base + t];
}

// ---------------------------------------------------------------------------
// Self attention with SMEM-cached K/V, two queries per warp iteration.
// grid = (4 qchunks of 76, NH, BS) = 256 blocks, block = 256 (8 warps).
// qkv rows: [q(0..255) | k(256..511) | v(512..767)], stride 768.
// SMEM: Ks[300][36] (float4-capable, conflict-free), Vs[300][32], ps[8][2][304].
// ---------------------------------------------------------------------------
namespace {
constexpr int kQC = 76;              // queries per block (even)
constexpr int kKLD = 36;             // Ks row stride (float4-aligned)
constexpr int ATTN_SMEM =
    (kNQ * kKLD + kNQ * kDH + 8 * 2 * 304) * 4;   // 43200+38400+19456 = 101056 B
}

__global__ __launch_bounds__(256, 2)
void self_attn_kernel(const float* __restrict__ qkv,
                      float* __restrict__ o) {
    extern __shared__ float sm[];
    float* Ks = sm;                      // [300][36]
    float* Vs = sm + kNQ * kKLD;         // [300][32]
    float* ps = Vs + kNQ * kDH;          // [8][2][304]

    const int tid  = threadIdx.x;
    const int w    = tid >> 5;
    const int lane = tid & 31;
    const int h = blockIdx.y;
    const int b = blockIdx.z;
    const int q0 = blockIdx.x * kQC;
    const int qend = (q0 + kQC < kNQ) ? (q0 + kQC) : kNQ;

    // cooperative K/V load
    for (int idx = tid; idx < kNQ * 8; idx += 256) {
        const int r = idx >> 3, g4 = (idx & 7) * 4;
        const float* base = qkv + ((size_t)(b * kNQ + r)) * 768 + h * kDH + g4;
        *(float4*)&Ks[r * kKLD + g4] = *(const float4*)(base + 256);
        *(float4*)&Vs[r * kDH + g4]  = *(const float4*)(base + 512);
    }
    __syncthreads();

    const float scale = 0.1767766952966369f;  // 1/sqrt(32)
    float* ps0 = &ps[(w * 2 + 0) * 304];
    float* ps1 = &ps[(w * 2 + 1) * 304];

    // pairs (q, q+1); q0 and qend even, so pairs stay in range
    for (int q = q0 + w * 2; q < qend; q += 16) {
        float q0reg[32], q1reg[32];
        const float4* qr0 =
            (const float4*)(qkv + ((size_t)(b * kNQ + q)) * 768 + h * kDH);
        const float4* qr1 =
            (const float4*)(qkv + ((size_t)(b * kNQ + q + 1)) * 768 + h * kDH);
#pragma unroll
        for (int j = 0; j < 8; ++j) {
            float4 v0 = qr0[j], v1 = qr1[j];
            q0reg[j * 4 + 0] = v0.x; q0reg[j * 4 + 1] = v0.y;
            q0reg[j * 4 + 2] = v0.z; q0reg[j * 4 + 3] = v0.w;
            q1reg[j * 4 + 0] = v1.x; q1reg[j * 4 + 1] = v1.y;
            q1reg[j * 4 + 2] = v1.z; q1reg[j * 4 + 3] = v1.w;
        }

        // scores: lane-per-key, float4 K reads feed both queries
        float sc0[10], sc1[10];
        float m0 = -INFINITY, m1 = -INFINITY;
#pragma unroll
        for (int c = 0; c < 10; ++c) {
            const int k = c * 32 + lane;
            const float* kr = &Ks[(k < kNQ ? k : 0) * kKLD];
            float d0 = 0.f, d1 = 0.f;
#pragma unroll
            for (int j4 = 0; j4 < 8; ++j4) {
                const float4 kv = *(const float4*)&kr[j4 * 4];
                d0 = fmaf(kv.x, q0reg[j4 * 4 + 0], d0);
                d1 = fmaf(kv.x, q1reg[j4 * 4 + 0], d1);
                d0 = fmaf(kv.y, q0reg[j4 * 4 + 1], d0);
                d1 = fmaf(kv.y, q1reg[j4 * 4 + 1], d1);
                d0 = fmaf(kv.z, q0reg[j4 * 4 + 2], d0);
                d1 = fmaf(kv.z, q1reg[j4 * 4 + 2], d1);
                d0 = fmaf(kv.w, q0reg[j4 * 4 + 3], d0);
                d1 = fmaf(kv.w, q1reg[j4 * 4 + 3], d1);
            }
            d0 *= scale; d1 *= scale;
            if (k >= kNQ) { d0 = -INFINITY; d1 = -INFINITY; }
            sc0[c] = d0; sc1[c] = d1;
            m0 = fmaxf(m0, d0); m1 = fmaxf(m1, d1);
        }
#pragma unroll
        for (int off = 16; off > 0; off >>= 1) {
            m0 = fmaxf(m0, __shfl_xor_sync(~0u, m0, off));
            m1 = fmaxf(m1, __shfl_xor_sync(~0u, m1, off));
        }

        float s0 = 0.f, s1 = 0.f;
#pragma unroll
        for (int c = 0; c < 10; ++c) {
            const int k = c * 32 + lane;
            float e0 = (k < kNQ) ? expf(sc0[c] - m0) : 0.f;
            float e1 = (k < kNQ) ? expf(sc1[c] - m1) : 0.f;
            if (k < 304) { ps0[k] = e0; ps1[k] = e1; }
            s0 += e0; s1 += e1;
        }
#pragma unroll
        for (int off = 16; off > 0; off >>= 1) {
            s0 += __shfl_xor_sync(~0u, s0, off);
            s1 += __shfl_xor_sync(~0u, s1, off);
        }
        const float inv0 = 1.f / s0, inv1 = 1.f / s1;
        __syncwarp();

        // PV: shared Vs reads feed both queries
        float a0 = 0.f, a1 = 0.f;
#pragma unroll 5
        for (int c = 0; c < kNQ / 4; ++c) {
            float4 p0 = *(const float4*)&ps0[c * 4];
            float4 p1 = *(const float4*)&ps1[c * 4];
            const float v0 = Vs[(c * 4 + 0) * kDH + lane];
            const float v1 = Vs[(c * 4 + 1) * kDH + lane];
            const float v2 = Vs[(c * 4 + 2) * kDH + lane];
            const float v3 = Vs[(c * 4 + 3) * kDH + lane];
            a0 = fmaf(p0.x, v0, a0); a1 = fmaf(p1.x, v0, a1);
            a0 = fmaf(p0.y, v1, a0); a1 = fmaf(p1.y, v1, a1);
            a0 = fmaf(p0.z, v2, a0); a1 = fmaf(p1.z, v2, a1);
            a0 = fmaf(p0.w, v3, a0); a1 = fmaf(p1.w, v3, a1);
        }
        __syncwarp();

        o[((size_t)(b * kNQ + q)) * kD + h * kDH + lane] = a0 * inv0;
        o[((size_t)(b * kNQ + q + 1)) * kD + h * kDH + lane] = a1 * inv1;
    }
}

// ---------------------------------------------------------------------------
// MS deformable aggregation over RAW memory rows.
// ---------------------------------------------------------------------------
__global__ void msdeform_agg_kernel(const float* __restrict__ ref,
                                    const float* __restrict__ oa,
                                    const float* __restrict__ memory,
                                    float* __restrict__ agg) {
    const int bq = blockIdx.x;
    const int b = bq / kNQ;
    const int t = threadIdx.x;
    const int h = t >> 5;
    const int lane = t & 31;

    __shared__ float s_p[kNH][16];

    float lw = (lane < 16) ? oa[(size_t)bq * kOW + 256 + h * 16 + lane] : -INFINITY;
    float m = lw;
#pragma unroll
    for (int o = 8; o > 0; o >>= 1) m = fmaxf(m, __shfl_xor_sync(~0u, m, o, 16));
    float e = (lane < 16) ? expf(lw - m) : 0.f;
    float sum = e;
#pragma unroll
    for (int o = 8; o > 0; o >>= 1) sum += __shfl_xor_sync(~0u, sum, o, 16);
    if (lane < 16) s_p[h][lane] = e / sum;
    __syncwarp();

    const int cH[kNL]  = {100, 50, 25, 13};
    const int cW[kNL]  = {150, 75, 38, 19};
    const int cS0[kNL] = {0, 15000, 18750, 19700};

    float a0 = 0.f, a1 = 0.f, a2 = 0.f, a3 = 0.f;
    float a4 = 0.f, a5 = 0.f, a6 = 0.f, a7 = 0.f;
    float bsum = 0.f;

#pragma unroll
    for (int l = 0; l < kNL; ++l) {
        const float rx = ref[((size_t)bq * kNL + l) * 2 + 0];
        const float ry = ref[((size_t)bq * kNL + l) * 2 + 1];
        const int Hl = cH[l], Wl = cW[l], s0 = cS0[l];
        const float fW = (float)Wl, fH = (float)Hl;
#pragma unroll
        for (int p = 0; p < kNP; ++p) {
            const float aw = s_p[h][l * kNP + p];
            const size_t ob = (size_t)bq * kOW + (((h * kNL + l) * kNP + p) * 2);
            const float ox = oa[ob + 0];
            const float oy = oa[ob + 1];
            const float x = (rx + ox / fW) * fW - 0.5f;
            const float y = (ry + oy / fH) * fH - 0.5f;
            const float x0f = floorf(x), y0f = floorf(y);
            const float tx = x - x0f, ty = y - y0f;
            const int x0 = (int)x0f, y0 = (int)y0f;

#pragma unroll
            for (int dy = 0; dy < 2; ++dy) {
#pragma unroll
                for (int dx = 0; dx < 2; ++dx) {
                    const int xi = x0 + dx, yi = y0 + dy;
                    const bool valid = (xi >= 0) & (xi < Wl) & (yi >= 0) & (yi < Hl);
                    if (valid) {
                        const float w =
                            aw * (dy ? ty : (1.f - ty)) * (dx ? tx : (1.f - tx));
                        const float4* row = (const float4*)(
                            memory + ((size_t)b * kS + s0 + yi * Wl + xi) * kD +
                            lane * 8);
                        float4 v0 = row[0];
                        float4 v1 = row[1];
                        a0 = fmaf(w, v0.x, a0); a1 = fmaf(w, v0.y, a1);
                        a2 = fmaf(w, v0.z, a2); a3 = fmaf(w, v0.w, a3);
                        a4 = fmaf(w, v1.x, a4); a5 = fmaf(w, v1.y, a5);
                        a6 = fmaf(w, v1.z, a6); a7 = fmaf(w, v1.w, a7);
                        bsum += w;
                    }
                }
            }
        }
    }

    float4* dst = (float4*)(agg + (size_t)bq * kAK + h * 256 + lane * 8);
    dst[0] = make_float4(a0, a1, a2, a3);
    dst[1] = make_float4(a4, a5, a6, a7);
    if (lane == 0) agg[(size_t)bq * kAK + 2048 + h] = bsum;
    if (h == 0 && lane < 24) agg[(size_t)bq * kAK + 2056 + lane] = 0.f;
}

// ---------------------------------------------------------------------------
// Launch helpers
// ---------------------------------------------------------------------------
static void ensure_attrs() {
    static bool done = false;
    if (done) return;
    cudaFuncSetAttribute((const void*)gemm_tf32_kernel<3, false>,
                         cudaFuncAttributeMaxDynamicSharedMemorySize,
                         gemm_smem_bytes<3>());
    cudaFuncSetAttribute((const void*)gemm_tf32_kernel<3, true>,
                         cudaFuncAttributeMaxDynamicSharedMemorySize,
                         gemm_smem_bytes<3>());
    cudaFuncSetAttribute((const void*)gemm_tf32_kernel<4, false>,
                         cudaFuncAttributeMaxDynamicSharedMemorySize,
                         gemm_smem_bytes<4>());
    cudaFuncSetAttribute((const void*)self_attn_kernel,
                         cudaFuncAttributeMaxDynamicSharedMemorySize,
                         ATTN_SMEM);
    done = true;
}

static inline void launch_gemm(const float* A, const float* W, const float* b,
                               float* C, int M, int N, int K, bool relu) {
    dim3 grid(N / 64, (M + 63) / 64);
    if (relu)
        gemm_tf32_kernel<3, true><<<grid, 256, gemm_smem_bytes<3>()>>>(
            A, A, N, W, b, C, M, N, K);
    else
        gemm_tf32_kernel<3, false><<<grid, 256, gemm_smem_bytes<3>()>>>(
            A, A, N, W, b, C, M, N, K);
}

extern "C" void kernel_launch(void* const* d_in, const int* in_sizes, int n_in,
                              void* d_out, int out_size) {
    const float* tgt    = (const float*)d_in[0];
    const float* pos    = (const float*)d_in[1];
    const float* ref    = (const float*)d_in[2];
    const float* memory = (const float*)d_in[3];
    const float* in_w  = (const float*)d_in[7];
    const float* in_b  = (const float*)d_in[8];
    const float* out_w = (const float*)d_in[9];
    const float* out_b = (const float*)d_in[10];
    const float* n1g = (const float*)d_in[11];
    const float* n1b = (const float*)d_in[12];
    const float* n2g = (const float*)d_in[13];
    const float* n2b = (const float*)d_in[14];
    const float* n3g = (const float*)d_in[15];
    const float* n3b = (const float*)d_in[16];
    const float* so_w = (const float*)d_in[17];
    const float* so_b = (const float*)d_in[18];
    const float* aw_w = (const float*)d_in[19];
    const float* aw_b = (const float*)d_in[20];
    const float* v_w  = (const float*)d_in[21];
    const float* v_b  = (const float*)d_in[22];
    const float* op_w = (const float*)d_in[23];
    const float* op_b = (const float*)d_in[24];
    const float* l1w  = (const float*)d_in[25];
    const float* l1b  = (const float*)d_in[26];
    const float* l2w  = (const float*)d_in[27];
    const float* l2b  = (const float*)d_in[28];

    float* scratch = nullptr;
    cudaGetSymbolAddress((void**)&scratch, g_scratch);
    ensure_attrs();

    float* s_qkadd = scratch + OFF_QKADD;
    float* s_qkv   = scratch + OFF_QKV;
    float* s_attn  = scratch + OFF_ATTN;
    float* s_sa    = scratch + OFF_SA;
    float* s_tgt1  = scratch + OFF_TGT1;
    float* s_query = scratch + OFF_QUERY;
    float* s_oa    = scratch + OFF_OA;
    float* s_t2    = scratch + OFF_T2;
    float* s_tgt2  = scratch + OFF_TGT2;
    float* s_hid   = scratch + OFF_HID;
    float* s_ffo   = scratch + OFF_FFO;
    float* s_agg   = scratch + OFF_AGG;
    float* s_wm    = scratch + OFF_WM;
    float* s_wcat  = scratch + OFF_WCAT;
    float* s_bcat  = scratch + OFF_BCAT;

    const int nQD = kMQ * kD;

    // ---- precompute (Wm, weight concat) + qkadd ----
    {
        dim3 grid(kNH, 9);
        precompute_kernel<<<grid, 256>>>(op_w, v_w, v_b, so_w, so_b, aw_w, aw_b,
                                         s_wm, s_wcat, s_bcat);
    }
    add_kernel<<<(nQD + 255) / 256, 256>>>(tgt, pos, s_qkadd, nQD);

    // ---- self attention: merged QKV GEMM + SMEM-cached attention ----
    {
        dim3 grid(768 / 64, (kMQ + 63) / 64);
        gemm_tf32_kernel<3, false><<<grid, 256, gemm_smem_bytes<3>()>>>(
            s_qkadd, tgt, 512, in_w, in_b, s_qkv, kMQ, 768, kD);
    }
    {
        dim3 grid((kNQ + kQC - 1) / kQC, kNH, kBS);
        self_attn_kernel<<<grid, 256, ATTN_SMEM>>>(s_qkv, s_attn);
    }
    launch_gemm(s_attn, out_w, out_b, s_sa, kMQ, kD, kD, false);
    add_ln_kernel<true><<<kMQ, 256>>>(tgt, s_sa, n2g, n2b, s_tgt1, pos, s_query);

    // ---- MS deformable attention (merged offs+awl GEMM; value GEMM folded) ----
    launch_gemm(s_query, s_wcat, s_bcat, s_oa, kMQ, kOW, kD, false);
    msdeform_agg_kernel<<<kMQ, 256>>>(ref, s_oa, memory, s_agg);
    {
        dim3 grid(kD / 64, (kMQ + 63) / 64);
        gemm_tf32_kernel<4, false><<<grid, 256, gemm_smem_bytes<4>()>>>(
            s_agg, s_agg, kD, s_wm, op_b, s_t2, kMQ, kD, kAK);
    }
    add_ln_kernel<false><<<kMQ, 256>>>(s_tgt1, s_t2, n1g, n1b, s_tgt2,
                                       nullptr, nullptr);

    // ---- FFN ----
    launch_gemm(s_tgt2, l1w, l1b, s_hid, kMQ, kDFF, kD, true);
    launch_gemm(s_hid, l2w, l2b, s_ffo, kMQ, kD, kDFF, false);
    add_ln_kernel<false><<<kMQ, 256>>>(s_tgt2, s_ffo, n3g, n3b, (float*)d_out,
                                       nullptr, nullptr);
}

// round 10
// speedup vs baseline: 5.0241x; 1.0108x over previous
#include <cuda_runtime.h>
#include <math.h>
#include <stdint.h>

// ---------------------------------------------------------------------------
// Problem constants
// ---------------------------------------------------------------------------
namespace {
constexpr int kD   = 256;
constexpr int kNH  = 8;
constexpr int kDH  = 32;
constexpr int kNL  = 4;
constexpr int kNP  = 4;
constexpr int kDFF = 1024;
constexpr int kBS  = 8;
constexpr int kNQ  = 300;
constexpr int kS   = 19947;
constexpr int kMQ  = kBS * kNQ;      // 2400
constexpr int kAK  = 2080;           // agg K: 8*256 + 8 bias + 24 pad (65*32)
constexpr int kOW  = 384;            // merged offs(256) + awl(128) width

constexpr size_t OFF_QKADD = 0;
constexpr size_t OFF_QKV   = OFF_QKADD + (size_t)kMQ * kD;   // [2400][768]
constexpr size_t OFF_ATTN  = OFF_QKV   + (size_t)kMQ * 768;
constexpr size_t OFF_SA    = OFF_ATTN  + (size_t)kMQ * kD;
constexpr size_t OFF_TGT1  = OFF_SA    + (size_t)kMQ * kD;
constexpr size_t OFF_QUERY = OFF_TGT1  + (size_t)kMQ * kD;
constexpr size_t OFF_OA    = OFF_QUERY + (size_t)kMQ * kD;   // [2400][384]
constexpr size_t OFF_T2    = OFF_OA    + (size_t)kMQ * kOW;
constexpr size_t OFF_TGT2  = OFF_T2    + (size_t)kMQ * kD;
constexpr size_t OFF_HID   = OFF_TGT2  + (size_t)kMQ * kD;
constexpr size_t OFF_FFO   = OFF_HID   + (size_t)kMQ * kDFF;
constexpr size_t OFF_AGG   = OFF_FFO   + (size_t)kMQ * kD;
constexpr size_t OFF_WM    = OFF_AGG   + (size_t)kMQ * kAK;
constexpr size_t OFF_WCAT  = OFF_WM    + (size_t)kD * kAK;   // [384][256]
constexpr size_t OFF_BCAT  = OFF_WCAT  + (size_t)kOW * kD;   // [384]
constexpr size_t SCRATCH_TOTAL = OFF_BCAT + kOW;
} // namespace

__device__ float g_scratch[SCRATCH_TOTAL];

// ---------------------------------------------------------------------------
// helpers
// ---------------------------------------------------------------------------
__device__ __forceinline__ uint32_t smem_u32(const void* p) {
    uint32_t a;
    asm("{ .reg .u64 t; cvta.to.shared.u64 t, %1; cvt.u32.u64 %0, t; }"
        : "=r"(a) : "l"(p));
    return a;
}

__device__ __forceinline__ void cp_async16(uint32_t dst, const void* src, bool pred) {
    int sz = pred ? 16 : 0;
    asm volatile("cp.async.cg.shared.global [%0], [%1], 16, %2;"
                 :: "r"(dst), "l"(src), "r"(sz));
}
__device__ __forceinline__ void cp_commit() {
    asm volatile("cp.async.commit_group;");
}
template <int N>
__device__ __forceinline__ void cp_wait() {
    asm volatile("cp.async.wait_group %0;" :: "n"(N));
}

__device__ __forceinline__ void mma_tf32(float (&d)[4],
                                         const uint32_t (&a)[4],
                                         const uint32_t (&b)[2]) {
    asm volatile(
        "mma.sync.aligned.m16n8k8.row.col.f32.tf32.tf32.f32 "
        "{%0,%1,%2,%3}, {%4,%5,%6,%7}, {%8,%9}, {%0,%1,%2,%3};"
        : "+f"(d[0]), "+f"(d[1]), "+f"(d[2]), "+f"(d[3])
        : "r"(a[0]), "r"(a[1]), "r"(a[2]), "r"(a[3]),
          "r"(b[0]), "r"(b[1]));
}

// ---------------------------------------------------------------------------
// TF32 tensor-core GEMM with per-n-region A select:
//   C[M,N] = act( Asel[M,K] @ W[N,K]^T + bias[N] )
// Block tile 64x64, BK=32, 8 warps (WM=2,WN=4), STAGES-deep cp.async.
// ---------------------------------------------------------------------------
template <int STAGES, bool RELU>
__global__ __launch_bounds__(256, 2)
void gemm_tf32_kernel(const float* __restrict__ A1,
                      const float* __restrict__ A2,
                      int n_split,
                      const float* __restrict__ W,
                      const float* __restrict__ bias,
                      float* __restrict__ C,
                      int M, int N, int K) {
    constexpr int BM = 64, BN = 64, BK = 32;
    constexpr int LD = BK + 4;                 // 36 words/row
    constexpr int THREADS = 256;
    constexpr int WM = 2;
    constexpr int MT = 2, NT = 2;
    constexpr int A_IT = (BM * BK / 4) / THREADS;   // 2
    constexpr int B_IT = (BN * BK / 4) / THREADS;   // 2

    extern __shared__ float smem[];
    float* As = smem;
    float* Ws = smem + (size_t)STAGES * BM * LD;

    const int tid  = threadIdx.x;
    const int warp = tid >> 5;
    const int lane = tid & 31;
    const int g    = lane >> 2;
    const int tg   = lane & 3;
    const int tm   = blockIdx.y * BM;
    const int tn   = blockIdx.x * BN;
    const int wm   = (warp % WM) * 32;
    const int wn   = (warp / WM) * 16;

    const float* A = (tn < n_split) ? A1 : A2;

    float acc[MT][NT][4] = {};
    const int NK = K / BK;

    auto issue = [&](int s, int kt) {
        if (kt < NK) {
            const int k0 = kt * BK;
#pragma unroll
            for (int i = 0; i < A_IT; ++i) {
                int idx = tid + i * THREADS;
                int r = idx >> 3, c4 = (idx & 7) * 4;
                int gr = tm + r;
                cp_async16(smem_u32(&As[(size_t)s * BM * LD + r * LD + c4]),
                           A + (size_t)gr * K + k0 + c4, gr < M);
            }
#pragma unroll
            for (int i = 0; i < B_IT; ++i) {
                int idx = tid + i * THREADS;
                int r = idx >> 3, c4 = (idx & 7) * 4;
                cp_async16(smem_u32(&Ws[(size_t)s * BN * LD + r * LD + c4]),
                           W + (size_t)(tn + r) * K + k0 + c4, true);
            }
        }
        cp_commit();
    };

    issue(0, 0);
#pragma unroll
    for (int p = 1; p < STAGES - 1; ++p) issue(p, p);

    for (int kt = 0; kt < NK; ++kt) {
        const int s = kt % STAGES;
        cp_wait<STAGES - 2>();
        __syncthreads();
        issue((kt + STAGES - 1) % STAGES, kt + STAGES - 1);

        const float* as = &As[(size_t)s * BM * LD];
        const float* ws = &Ws[(size_t)s * BN * LD];
#pragma unroll
        for (int ks = 0; ks < 4; ++ks) {
            const int kc = ks * 8 + tg;
            uint32_t af[MT][4], bf[NT][2];
#pragma unroll
            for (int mt = 0; mt < MT; ++mt) {
                const int r = wm + mt * 16 + g;
                af[mt][0] = __float_as_uint(as[r * LD + kc]);
                af[mt][1] = __float_as_uint(as[(r + 8) * LD + kc]);
                af[mt][2] = __float_as_uint(as[r * LD + kc + 4]);
                af[mt][3] = __float_as_uint(as[(r + 8) * LD + kc + 4]);
            }
#pragma unroll
            for (int nt = 0; nt < NT; ++nt) {
                const int n = wn + nt * 8 + g;
                bf[nt][0] = __float_as_uint(ws[n * LD + kc]);
                bf[nt][1] = __float_as_uint(ws[n * LD + kc + 4]);
            }
#pragma unroll
            for (int mt = 0; mt < MT; ++mt)
#pragma unroll
                for (int nt = 0; nt < NT; ++nt)
                    mma_tf32(acc[mt][nt], af[mt], bf[nt]);
        }
        __syncthreads();
    }

#pragma unroll
    for (int mt = 0; mt < MT; ++mt) {
        const int gr0 = tm + wm + mt * 16 + g;
        const int gr1 = gr0 + 8;
#pragma unroll
        for (int nt = 0; nt < NT; ++nt) {
            const int gc = tn + wn + nt * 8 + tg * 2;
            const float b0 = bias[gc], b1 = bias[gc + 1];
            if (gr0 < M) {
                float v0 = acc[mt][nt][0] + b0;
                float v1 = acc[mt][nt][1] + b1;
                if (RELU) { v0 = fmaxf(v0, 0.f); v1 = fmaxf(v1, 0.f); }
                *(float2*)(C + (size_t)gr0 * N + gc) = make_float2(v0, v1);
            }
            if (gr1 < M) {
                float v2 = acc[mt][nt][2] + b0;
                float v3 = acc[mt][nt][3] + b1;
                if (RELU) { v2 = fmaxf(v2, 0.f); v3 = fmaxf(v3, 0.f); }
                *(float2*)(C + (size_t)gr1 * N + gc) = make_float2(v2, v3);
            }
        }
    }
}

template <int STAGES>
constexpr int gemm_smem_bytes() { return STAGES * 128 * 36 * 4; }

// ---------------------------------------------------------------------------
// Precompute kernel. grid = (8, 9), block = 256.
// ---------------------------------------------------------------------------
__global__ void precompute_kernel(const float* __restrict__ op_w,
                                  const float* __restrict__ v_w,
                                  const float* __restrict__ v_b,
                                  const float* __restrict__ so_w,
                                  const float* __restrict__ so_b,
                                  const float* __restrict__ aw_w,
                                  const float* __restrict__ aw_b,
                                  float* __restrict__ wm,
                                  float* __restrict__ wcat,
                                  float* __restrict__ bcat) {
    const int tid = threadIdx.x;
    if (blockIdx.y == 8) {
        const int r0 = blockIdx.x * 48;
        for (int r = r0; r < r0 + 48; ++r) {
            const float* src = (r < 256) ? (so_w + (size_t)r * 256)
                                         : (aw_w + (size_t)(r - 256) * 256);
            wcat[(size_t)r * 256 + tid] = src[tid];
        }
        if (tid < 48) {
            int r = r0 + tid;
            bcat[r] = (r < 256) ? so_b[r] : aw_b[r - 256];
        }
        return;
    }

    const int h  = blockIdx.x;
    const int ot = blockIdx.y * 32;
    __shared__ float vs[32][256];

    for (int idx = tid; idx < 32 * 256; idx += 256) {
        int r = idx >> 8, c = idx & 255;
        vs[r][c] = v_w[(size_t)(32 * h + r) * 256 + c];
    }
    __syncthreads();

    for (int oo = 0; oo < 32; ++oo) {
        const int o = ot + oo;
        const float* opr = op_w + (size_t)o * 256 + 32 * h;
        float s = 0.f;
#pragma unroll
        for (int j = 0; j < 32; ++j) s = fmaf(opr[j], vs[j][tid], s);
        wm[(size_t)o * kAK + h * 256 + tid] = s;
    }
    if (tid < 32) {
        const int o = ot + tid;
        const float* opr = op_w + (size_t)o * 256 + 32 * h;
        float s = 0.f;
#pragma unroll
        for (int j = 0; j < 32; ++j) s = fmaf(opr[j], v_b[32 * h + j], s);
        wm[(size_t)o * kAK + 2048 + h] = s;
        if (h == 0)
            for (int z = 2056; z < kAK; ++z) wm[(size_t)o * kAK + z] = 0.f;
    }
}

// ---------------------------------------------------------------------------
// Elementwise add
// ---------------------------------------------------------------------------
__global__ void add_kernel(const float* __restrict__ a,
                           const float* __restrict__ b,
                           float* __restrict__ out, int n) {
    int i = blockIdx.x * blockDim.x + threadIdx.x;
    if (i < n) out[i] = a[i] + b[i];
}

// ---------------------------------------------------------------------------
// Residual + LayerNorm (256 features, one block per row).
// ---------------------------------------------------------------------------
template <bool WITH_POS>
__global__ void add_ln_kernel(const float* __restrict__ x,
                              const float* __restrict__ r,
                              const float* __restrict__ g,
                              const float* __restrict__ bta,
                              float* __restrict__ out,
                              const float* __restrict__ pos,
                              float* __restrict__ out2) {
    const int row = blockIdx.x;
    const int t = threadIdx.x;
    const size_t base = (size_t)row * kD;
    float v = x[base + t] + r[base + t];

    __shared__ float sm[8];
    float s = v;
#pragma unroll
    for (int o = 16; o > 0; o >>= 1) s += __shfl_xor_sync(~0u, s, o);
    if ((t & 31) == 0) sm[t >> 5] = s;
    __syncthreads();
    float tot = 0.f;
#pragma unroll
    for (int i = 0; i < 8; ++i) tot += sm[i];
    const float mean = tot * (1.f / kD);
    const float d = v - mean;
    float s2 = d * d;
#pragma unroll
    for (int o = 16; o > 0; o >>= 1) s2 += __shfl_xor_sync(~0u, s2, o);
    __syncthreads();
    if ((t & 31) == 0) sm[t >> 5] = s2;
    __syncthreads();
    float tot2 = 0.f;
#pragma unroll
    for (int i = 0; i < 8; ++i) tot2 += sm[i];
    const float var = tot2 * (1.f / kD);
    const float o1 = d * rsqrtf(var + 1e-5f) * g[t] + bta[t];
    out[base + t] = o1;
    if (WITH_POS) out2[base + t] = o1 + pos[base + t];
}

// ---------------------------------------------------------------------------
// Self attention with SMEM-cached K (key-major) and V (channel-major),
// two queries per warp iteration.
// grid = (4 qchunks of 76, NH, BS) = 256 blocks, block = 256 (8 warps).
// qkv rows: [q(0..255) | k(256..511) | v(512..767)], stride 768.
// SMEM: Ks[300][36], Vt[32][308] (transposed, float4 reads), ps[8][2][304].
// ---------------------------------------------------------------------------
namespace {
constexpr int kQC = 76;              // queries per block (even)
constexpr int kKLD = 36;             // Ks row stride (float4-aligned)
constexpr int kVLD = 308;            // Vt row stride (float4-aligned, 20 mod 32)
constexpr int ATTN_SMEM =
    (kNQ * kKLD + kDH * kVLD + 8 * 2 * 304) * 4;  // 43200+39424+19456 = 102080 B
}

__global__ __launch_bounds__(256, 2)
void self_attn_kernel(const float* __restrict__ qkv,
                      float* __restrict__ o) {
    extern __shared__ float sm[];
    float* Ks = sm;                      // [300][36]
    float* Vt = sm + kNQ * kKLD;         // [32][308]  Vt[ch][key]
    float* ps = Vt + kDH * kVLD;         // [8][2][304]

    const int tid  = threadIdx.x;
    const int w    = tid >> 5;
    const int lane = tid & 31;
    const int h = blockIdx.y;
    const int b = blockIdx.z;
    const int q0 = blockIdx.x * kQC;
    const int qend = (q0 + kQC < kNQ) ? (q0 + kQC) : kNQ;

    // cooperative K/V load: K key-major, V transposed to channel-major
    for (int idx = tid; idx < kNQ * 8; idx += 256) {
        const int r = idx >> 3, g4 = (idx & 7) * 4;
        const float* base = qkv + ((size_t)(b * kNQ + r)) * 768 + h * kDH + g4;
        *(float4*)&Ks[r * kKLD + g4] = *(const float4*)(base + 256);
        float4 v = *(const float4*)(base + 512);
        Vt[(g4 + 0) * kVLD + r] = v.x;
        Vt[(g4 + 1) * kVLD + r] = v.y;
        Vt[(g4 + 2) * kVLD + r] = v.z;
        Vt[(g4 + 3) * kVLD + r] = v.w;
    }
    // zero Vt tail keys 300..307 (ps is 0 there, but 0*garbage could be NaN)
    if (tid < kDH * 8) {
        const int ch = tid >> 3, k = kNQ + (tid & 7);
        Vt[ch * kVLD + k] = 0.f;
    }
    __syncthreads();

    const float scale = 0.1767766952966369f;  // 1/sqrt(32)
    float* ps0 = &ps[(w * 2 + 0) * 304];
    float* ps1 = &ps[(w * 2 + 1) * 304];
    const float* vrow = &Vt[lane * kVLD];

    // pairs (q, q+1); q0 and qend even, so pairs stay in range
    for (int q = q0 + w * 2; q < qend; q += 16) {
        float q0reg[32], q1reg[32];
        const float4* qr0 =
            (const float4*)(qkv + ((size_t)(b * kNQ + q)) * 768 + h * kDH);
        const float4* qr1 =
            (const float4*)(qkv + ((size_t)(b * kNQ + q + 1)) * 768 + h * kDH);
#pragma unroll
        for (int j = 0; j < 8; ++j) {
            float4 v0 = qr0[j], v1 = qr1[j];
            q0reg[j * 4 + 0] = v0.x; q0reg[j * 4 + 1] = v0.y;
            q0reg[j * 4 + 2] = v0.z; q0reg[j * 4 + 3] = v0.w;
            q1reg[j * 4 + 0] = v1.x; q1reg[j * 4 + 1] = v1.y;
            q1reg[j * 4 + 2] = v1.z; q1reg[j * 4 + 3] = v1.w;
        }

        // scores: lane-per-key, float4 K reads feed both queries
        float sc0[10], sc1[10];
        float m0 = -INFINITY, m1 = -INFINITY;
#pragma unroll
        for (int c = 0; c < 10; ++c) {
            const int k = c * 32 + lane;
            const float* kr = &Ks[(k < kNQ ? k : 0) * kKLD];
            float d0 = 0.f, d1 = 0.f;
#pragma unroll
            for (int j4 = 0; j4 < 8; ++j4) {
                const float4 kv = *(const float4*)&kr[j4 * 4];
                d0 = fmaf(kv.x, q0reg[j4 * 4 + 0], d0);
                d1 = fmaf(kv.x, q1reg[j4 * 4 + 0], d1);
                d0 = fmaf(kv.y, q0reg[j4 * 4 + 1], d0);
                d1 = fmaf(kv.y, q1reg[j4 * 4 + 1], d1);
                d0 = fmaf(kv.z, q0reg[j4 * 4 + 2], d0);
                d1 = fmaf(kv.z, q1reg[j4 * 4 + 2], d1);
                d0 = fmaf(kv.w, q0reg[j4 * 4 + 3], d0);
                d1 = fmaf(kv.w, q1reg[j4 * 4 + 3], d1);
            }
            d0 *= scale; d1 *= scale;
            if (k >= kNQ) { d0 = -INFINITY; d1 = -INFINITY; }
            sc0[c] = d0; sc1[c] = d1;
            m0 = fmaxf(m0, d0); m1 = fmaxf(m1, d1);
        }
#pragma unroll
        for (int off = 16; off > 0; off >>= 1) {
            m0 = fmaxf(m0, __shfl_xor_sync(~0u, m0, off));
            m1 = fmaxf(m1, __shfl_xor_sync(~0u, m1, off));
        }

        float s0 = 0.f, s1 = 0.f;
#pragma unroll
        for (int c = 0; c < 10; ++c) {
            const int k = c * 32 + lane;
            float e0 = (k < kNQ) ? expf(sc0[c] - m0) : 0.f;
            float e1 = (k < kNQ) ? expf(sc1[c] - m1) : 0.f;
            if (k < 304) { ps0[k] = e0; ps1[k] = e1; }
            s0 += e0; s1 += e1;
        }
#pragma unroll
        for (int off = 16; off > 0; off >>= 1) {
            s0 += __shfl_xor_sync(~0u, s0, off);
            s1 += __shfl_xor_sync(~0u, s1, off);
        }
        const float inv0 = 1.f / s0, inv1 = 1.f / s1;
        __syncwarp();

        // PV: all-float4 (p0, p1, V-transposed), 3 LDS.128 + 8 FMA per 4 keys
        float a0 = 0.f, a1 = 0.f;
#pragma unroll 5
        for (int c = 0; c < 304 / 4; ++c) {
            const float4 p0 = *(const float4*)&ps0[c * 4];
            const float4 p1 = *(const float4*)&ps1[c * 4];
            const float4 v  = *(const float4*)&vrow[c * 4];
            a0 = fmaf(p0.x, v.x, a0); a1 = fmaf(p1.x, v.x, a1);
            a0 = fmaf(p0.y, v.y, a0); a1 = fmaf(p1.y, v.y, a1);
            a0 = fmaf(p0.z, v.z, a0); a1 = fmaf(p1.z, v.z, a1);
            a0 = fmaf(p0.w, v.w, a0); a1 = fmaf(p1.w, v.w, a1);
        }
        __syncwarp();

        o[((size_t)(b * kNQ + q)) * kD + h * kDH + lane] = a0 * inv0;
        o[((size_t)(b * kNQ + q + 1)) * kD + h * kDH + lane] = a1 * inv1;
    }
}

// ---------------------------------------------------------------------------
// MS deformable aggregation over RAW memory rows.
// ---------------------------------------------------------------------------
__global__ void msdeform_agg_kernel(const float* __restrict__ ref,
                                    const float* __restrict__ oa,
                                    const float* __restrict__ memory,
                                    float* __restrict__ agg) {
    const int bq = blockIdx.x;
    const int b = bq / kNQ;
    const int t = threadIdx.x;
    const int h = t >> 5;
    const int lane = t & 31;

    __shared__ float s_p[kNH][16];

    float lw = (lane < 16) ? oa[(size_t)bq * kOW + 256 + h * 16 + lane] : -INFINITY;
    float m = lw;
#pragma unroll
    for (int o = 8; o > 0; o >>= 1) m = fmaxf(m, __shfl_xor_sync(~0u, m, o, 16));
    float e = (lane < 16) ? expf(lw - m) : 0.f;
    float sum = e;
#pragma unroll
    for (int o = 8; o > 0; o >>= 1) sum += __shfl_xor_sync(~0u, sum, o, 16);
    if (lane < 16) s_p[h][lane] = e / sum;
    __syncwarp();

    const int cH[kNL]  = {100, 50, 25, 13};
    const int cW[kNL]  = {150, 75, 38, 19};
    const int cS0[kNL] = {0, 15000, 18750, 19700};

    float a0 = 0.f, a1 = 0.f, a2 = 0.f, a3 = 0.f;
    float a4 = 0.f, a5 = 0.f, a6 = 0.f, a7 = 0.f;
    float bsum = 0.f;

#pragma unroll
    for (int l = 0; l < kNL; ++l) {
        const float rx = ref[((size_t)bq * kNL + l) * 2 + 0];
        const float ry = ref[((size_t)bq * kNL + l) * 2 + 1];
        const int Hl = cH[l], Wl = cW[l], s0 = cS0[l];
        const float fW = (float)Wl, fH = (float)Hl;
#pragma unroll
        for (int p = 0; p < kNP; ++p) {
            const float aw = s_p[h][l * kNP + p];
            const size_t ob = (size_t)bq * kOW + (((h * kNL + l) * kNP + p) * 2);
            const float ox = oa[ob + 0];
            const float oy = oa[ob + 1];
            const float x = (rx + ox / fW) * fW - 0.5f;
            const float y = (ry + oy / fH) * fH - 0.5f;
            const float x0f = floorf(x), y0f = floorf(y);
            const float tx = x - x0f, ty = y - y0f;
            const int x0 = (int)x0f, y0 = (int)y0f;

#pragma unroll
            for (int dy = 0; dy < 2; ++dy) {
#pragma unroll
                for (int dx = 0; dx < 2; ++dx) {
                    const int xi = x0 + dx, yi = y0 + dy;
                    const bool valid = (xi >= 0) & (xi < Wl) & (yi >= 0) & (yi < Hl);
                    if (valid) {
                        const float w =
                            aw * (dy ? ty : (1.f - ty)) * (dx ? tx : (1.f - tx));
                        const float4* row = (const float4*)(
                            memory + ((size_t)b * kS + s0 + yi * Wl + xi) * kD +
                            lane * 8);
                        float4 v0 = row[0];
                        float4 v1 = row[1];
                        a0 = fmaf(w, v0.x, a0); a1 = fmaf(w, v0.y, a1);
                        a2 = fmaf(w, v0.z, a2); a3 = fmaf(w, v0.w, a3);
                        a4 = fmaf(w, v1.x, a4); a5 = fmaf(w, v1.y, a5);
                        a6 = fmaf(w, v1.z, a6); a7 = fmaf(w, v1.w, a7);
                        bsum += w;
                    }
                }
            }
        }
    }

    float4* dst = (float4*)(agg + (size_t)bq * kAK + h * 256 + lane * 8);
    dst[0] = make_float4(a0, a1, a2, a3);
    dst[1] = make_float4(a4, a5, a6, a7);
    if (lane == 0) agg[(size_t)bq * kAK + 2048 + h] = bsum;
    if (h == 0 && lane < 24) agg[(size_t)bq * kAK + 2056 + lane] = 0.f;
}

// ---------------------------------------------------------------------------
// Launch helpers
// ---------------------------------------------------------------------------
static void ensure_attrs() {
    static bool done = false;
    if (done) return;
    cudaFuncSetAttribute((const void*)gemm_tf32_kernel<3, false>,
                         cudaFuncAttributeMaxDynamicSharedMemorySize,
                         gemm_smem_bytes<3>());
    cudaFuncSetAttribute((const void*)gemm_tf32_kernel<3, true>,
                         cudaFuncAttributeMaxDynamicSharedMemorySize,
                         gemm_smem_bytes<3>());
    cudaFuncSetAttribute((const void*)gemm_tf32_kernel<4, false>,
                         cudaFuncAttributeMaxDynamicSharedMemorySize,
                         gemm_smem_bytes<4>());
    cudaFuncSetAttribute((const void*)self_attn_kernel,
                         cudaFuncAttributeMaxDynamicSharedMemorySize,
                         ATTN_SMEM);
    done = true;
}

static inline void launch_gemm(const float* A, const float* W, const float* b,
                               float* C, int M, int N, int K, bool relu) {
    dim3 grid(N / 64, (M + 63) / 64);
    if (relu)
        gemm_tf32_kernel<3, true><<<grid, 256, gemm_smem_bytes<3>()>>>(
            A, A, N, W, b, C, M, N, K);
    else
        gemm_tf32_kernel<3, false><<<grid, 256, gemm_smem_bytes<3>()>>>(
            A, A, N, W, b, C, M, N, K);
}

extern "C" void kernel_launch(void* const* d_in, const int* in_sizes, int n_in,
                              void* d_out, int out_size) {
    const float* tgt    = (const float*)d_in[0];
    const float* pos    = (const float*)d_in[1];
    const float* ref    = (const float*)d_in[2];
    const float* memory = (const float*)d_in[3];
    const float* in_w  = (const float*)d_in[7];
    const float* in_b  = (const float*)d_in[8];
    const float* out_w = (const float*)d_in[9];
    const float* out_b = (const float*)d_in[10];
    const float* n1g = (const float*)d_in[11];
    const float* n1b = (const float*)d_in[12];
    const float* n2g = (const float*)d_in[13];
    const float* n2b = (const float*)d_in[14];
    const float* n3g = (const float*)d_in[15];
    const float* n3b = (const float*)d_in[16];
    const float* so_w = (const float*)d_in[17];
    const float* so_b = (const float*)d_in[18];
    const float* aw_w = (const float*)d_in[19];
    const float* aw_b = (const float*)d_in[20];
    const float* v_w  = (const float*)d_in[21];
    const float* v_b  = (const float*)d_in[22];
    const float* op_w = (const float*)d_in[23];
    const float* op_b = (const float*)d_in[24];
    const float* l1w  = (const float*)d_in[25];
    const float* l1b  = (const float*)d_in[26];
    const float* l2w  = (const float*)d_in[27];
    const float* l2b  = (const float*)d_in[28];

    float* scratch = nullptr;
    cudaGetSymbolAddress((void**)&scratch, g_scratch);
    ensure_attrs();

    float* s_qkadd = scratch + OFF_QKADD;
    float* s_qkv   = scratch + OFF_QKV;
    float* s_attn  = scratch + OFF_ATTN;
    float* s_sa    = scratch + OFF_SA;
    float* s_tgt1  = scratch + OFF_TGT1;
    float* s_query = scratch + OFF_QUERY;
    float* s_oa    = scratch + OFF_OA;
    float* s_t2    = scratch + OFF_T2;
    float* s_tgt2  = scratch + OFF_TGT2;
    float* s_hid   = scratch + OFF_HID;
    float* s_ffo   = scratch + OFF_FFO;
    float* s_agg   = scratch + OFF_AGG;
    float* s_wm    = scratch + OFF_WM;
    float* s_wcat  = scratch + OFF_WCAT;
    float* s_bcat  = scratch + OFF_BCAT;

    const int nQD = kMQ * kD;

    // ---- precompute (Wm, weight concat) + qkadd ----
    {
        dim3 grid(kNH, 9);
        precompute_kernel<<<grid, 256>>>(op_w, v_w, v_b, so_w, so_b, aw_w, aw_b,
                                         s_wm, s_wcat, s_bcat);
    }
    add_kernel<<<(nQD + 255) / 256, 256>>>(tgt, pos, s_qkadd, nQD);

    // ---- self attention: merged QKV GEMM + SMEM-cached attention ----
    {
        dim3 grid(768 / 64, (kMQ + 63) / 64);
        gemm_tf32_kernel<3, false><<<grid, 256, gemm_smem_bytes<3>()>>>(
            s_qkadd, tgt, 512, in_w, in_b, s_qkv, kMQ, 768, kD);
    }
    {
        dim3 grid((kNQ + kQC - 1) / kQC, kNH, kBS);
        self_attn_kernel<<<grid, 256, ATTN_SMEM>>>(s_qkv, s_attn);
    }
    launch_gemm(s_attn, out_w, out_b, s_sa, kMQ, kD, kD, false);
    add_ln_kernel<true><<<kMQ, 256>>>(tgt, s_sa, n2g, n2b, s_tgt1, pos, s_query);

    // ---- MS deformable attention (merged offs+awl GEMM; value GEMM folded) ----
    launch_gemm(s_query, s_wcat, s_bcat, s_oa, kMQ, kOW, kD, false);
    msdeform_agg_kernel<<<kMQ, 256>>>(ref, s_oa, memory, s_agg);
    {
        dim3 grid(kD / 64, (kMQ + 63) / 64);
        gemm_tf32_kernel<4, false><<<grid, 256, gemm_smem_bytes<4>()>>>(
            s_agg, s_agg, kD, s_wm, op_b, s_t2, kMQ, kD, kAK);
    }
    add_ln_kernel<false><<<kMQ, 256>>>(s_tgt1, s_t2, n1g, n1b, s_tgt2,
                                       nullptr, nullptr);

    // ---- FFN ----
    launch_gemm(s_tgt2, l1w, l1b, s_hid, kMQ, kDFF, kD, true);
    launch_gemm(s_hid, l2w, l2b, s_ffo, kMQ, kD, kDFF, false);
    add_ln_kernel<false><<<kMQ, 256>>>(s_tgt2, s_ffo, n3g, n3b, (float*)d_out,
                                       nullptr, nullptr);
}

// round 11
// speedup vs baseline: 5.0736x; 1.0099x over previous
#include <cuda_runtime.h>
#include <math.h>
#include <stdint.h>

// ---------------------------------------------------------------------------
// Problem constants
// ---------------------------------------------------------------------------
namespace {
constexpr int kD   = 256;
constexpr int kNH  = 8;
constexpr int kDH  = 32;
constexpr int kNL  = 4;
constexpr int kNP  = 4;
constexpr int kDFF = 1024;
constexpr int kBS  = 8;
constexpr int kNQ  = 300;
constexpr int kS   = 19947;
constexpr int kMQ  = kBS * kNQ;      // 2400
constexpr int kAK  = 2080;           // agg K: 8*256 + 8 bias + 24 pad (65*32)
constexpr int kOW  = 384;            // merged offs(256) + awl(128) width

constexpr size_t OFF_QKADD = 0;
constexpr size_t OFF_QKV   = OFF_QKADD + (size_t)kMQ * kD;   // [2400][768]
constexpr size_t OFF_ATTN  = OFF_QKV   + (size_t)kMQ * 768;
constexpr size_t OFF_SA    = OFF_ATTN  + (size_t)kMQ * kD;
constexpr size_t OFF_TGT1  = OFF_SA    + (size_t)kMQ * kD;
constexpr size_t OFF_QUERY = OFF_TGT1  + (size_t)kMQ * kD;
constexpr size_t OFF_OA    = OFF_QUERY + (size_t)kMQ * kD;   // [2400][384]
constexpr size_t OFF_T2    = OFF_OA    + (size_t)kMQ * kOW;
constexpr size_t OFF_TGT2  = OFF_T2    + (size_t)kMQ * kD;
constexpr size_t OFF_HID   = OFF_TGT2  + (size_t)kMQ * kD;
constexpr size_t OFF_FFO   = OFF_HID   + (size_t)kMQ * kDFF;
constexpr size_t OFF_AGG   = OFF_FFO   + (size_t)kMQ * kD;
constexpr size_t OFF_WM    = OFF_AGG   + (size_t)kMQ * kAK;
constexpr size_t OFF_WCAT  = OFF_WM    + (size_t)kD * kAK;   // [384][256]
constexpr size_t OFF_BCAT  = OFF_WCAT  + (size_t)kOW * kD;   // [384]
constexpr size_t SCRATCH_TOTAL = OFF_BCAT + kOW;
} // namespace

__device__ float g_scratch[SCRATCH_TOTAL];

// ---------------------------------------------------------------------------
// helpers
// ---------------------------------------------------------------------------
__device__ __forceinline__ uint32_t smem_u32(const void* p) {
    uint32_t a;
    asm("{ .reg .u64 t; cvta.to.shared.u64 t, %1; cvt.u32.u64 %0, t; }"
        : "=r"(a) : "l"(p));
    return a;
}

__device__ __forceinline__ void cp_async16(uint32_t dst, const void* src, bool pred) {
    int sz = pred ? 16 : 0;
    asm volatile("cp.async.cg.shared.global [%0], [%1], 16, %2;"
                 :: "r"(dst), "l"(src), "r"(sz));
}
__device__ __forceinline__ void cp_commit() {
    asm volatile("cp.async.commit_group;");
}
template <int N>
__device__ __forceinline__ void cp_wait() {
    asm volatile("cp.async.wait_group %0;" :: "n"(N));
}

__device__ __forceinline__ void mma_tf32(float (&d)[4],
                                         const uint32_t (&a)[4],
                                         const uint32_t (&b)[2]) {
    asm volatile(
        "mma.sync.aligned.m16n8k8.row.col.f32.tf32.tf32.f32 "
        "{%0,%1,%2,%3}, {%4,%5,%6,%7}, {%8,%9}, {%0,%1,%2,%3};"
        : "+f"(d[0]), "+f"(d[1]), "+f"(d[2]), "+f"(d[3])
        : "r"(a[0]), "r"(a[1]), "r"(a[2]), "r"(a[3]),
          "r"(b[0]), "r"(b[1]));
}

// ---------------------------------------------------------------------------
// TF32 tensor-core GEMM with per-n-region A select and optional split-K:
//   C[M,N] (+)= act( Asel[M,Krange] @ W[N,Krange]^T + bias[N] )
// Block tile 64x64, BK=32, 8 warps (WM=2,WN=4), STAGES-deep cp.async.
// SPLITK>1: blockIdx.z selects K-range; epilogue atomicAdd; C must be
// pre-zeroed; bias contributed only by split 0.
// ---------------------------------------------------------------------------
template <int STAGES, bool RELU, int SPLITK>
__global__ __launch_bounds__(256, 2)
void gemm_tf32_kernel(const float* __restrict__ A1,
                      const float* __restrict__ A2,
                      int n_split,
                      const float* __restrict__ W,
                      const float* __restrict__ bias,
                      float* __restrict__ C,
                      int M, int N, int K) {
    constexpr int BM = 64, BN = 64, BK = 32;
    constexpr int LD = BK + 4;                 // 36 words/row
    constexpr int THREADS = 256;
    constexpr int WM = 2;
    constexpr int MT = 2, NT = 2;
    constexpr int A_IT = (BM * BK / 4) / THREADS;   // 2
    constexpr int B_IT = (BN * BK / 4) / THREADS;   // 2

    extern __shared__ float smem[];
    float* As = smem;
    float* Ws = smem + (size_t)STAGES * BM * LD;

    const int tid  = threadIdx.x;
    const int warp = tid >> 5;
    const int lane = tid & 31;
    const int g    = lane >> 2;
    const int tg   = lane & 3;
    const int tm   = blockIdx.y * BM;
    const int tn   = blockIdx.x * BN;
    const int wm   = (warp % WM) * 32;
    const int wn   = (warp / WM) * 16;

    const float* A = (tn < n_split) ? A1 : A2;

    // split-K range (in BK-chunks)
    const int nk_all = K / BK;
    const int nk_per = (nk_all + SPLITK - 1) / SPLITK;
    const int k_lo   = (SPLITK > 1) ? blockIdx.z * nk_per : 0;
    const int k_hi   = (SPLITK > 1) ? ((k_lo + nk_per < nk_all) ? k_lo + nk_per
                                                                : nk_all)
                                    : nk_all;
    const int nk_this = k_hi - k_lo;

    float acc[MT][NT][4] = {};

    auto issue = [&](int s, int kt) {
        if (kt < nk_this) {
            const int k0 = (k_lo + kt) * BK;
#pragma unroll
            for (int i = 0; i < A_IT; ++i) {
                int idx = tid + i * THREADS;
                int r = idx >> 3, c4 = (idx & 7) * 4;
                int gr = tm + r;
                cp_async16(smem_u32(&As[(size_t)s * BM * LD + r * LD + c4]),
                           A + (size_t)gr * K + k0 + c4, gr < M);
            }
#pragma unroll
            for (int i = 0; i < B_IT; ++i) {
                int idx = tid + i * THREADS;
                int r = idx >> 3, c4 = (idx & 7) * 4;
                cp_async16(smem_u32(&Ws[(size_t)s * BN * LD + r * LD + c4]),
                           W + (size_t)(tn + r) * K + k0 + c4, true);
            }
        }
        cp_commit();
    };

    issue(0, 0);
#pragma unroll
    for (int p = 1; p < STAGES - 1; ++p) issue(p, p);

    for (int kt = 0; kt < nk_this; ++kt) {
        const int s = kt % STAGES;
        cp_wait<STAGES - 2>();
        __syncthreads();
        issue((kt + STAGES - 1) % STAGES, kt + STAGES - 1);

        const float* as = &As[(size_t)s * BM * LD];
        const float* ws = &Ws[(size_t)s * BN * LD];
#pragma unroll
        for (int ks = 0; ks < 4; ++ks) {
            const int kc = ks * 8 + tg;
            uint32_t af[MT][4], bf[NT][2];
#pragma unroll
            for (int mt = 0; mt < MT; ++mt) {
                const int r = wm + mt * 16 + g;
                af[mt][0] = __float_as_uint(as[r * LD + kc]);
                af[mt][1] = __float_as_uint(as[(r + 8) * LD + kc]);
                af[mt][2] = __float_as_uint(as[r * LD + kc + 4]);
                af[mt][3] = __float_as_uint(as[(r + 8) * LD + kc + 4]);
            }
#pragma unroll
            for (int nt = 0; nt < NT; ++nt) {
                const int n = wn + nt * 8 + g;
                bf[nt][0] = __float_as_uint(ws[n * LD + kc]);
                bf[nt][1] = __float_as_uint(ws[n * LD + kc + 4]);
            }
#pragma unroll
            for (int mt = 0; mt < MT; ++mt)
#pragma unroll
                for (int nt = 0; nt < NT; ++nt)
                    mma_tf32(acc[mt][nt], af[mt], bf[nt]);
        }
        __syncthreads();
    }

    const bool add_bias = (SPLITK == 1) || (blockIdx.z == 0);
#pragma unroll
    for (int mt = 0; mt < MT; ++mt) {
        const int gr0 = tm + wm + mt * 16 + g;
        const int gr1 = gr0 + 8;
#pragma unroll
        for (int nt = 0; nt < NT; ++nt) {
            const int gc = tn + wn + nt * 8 + tg * 2;
            const float b0 = add_bias ? bias[gc] : 0.f;
            const float b1 = add_bias ? bias[gc + 1] : 0.f;
            if (gr0 < M) {
                float v0 = acc[mt][nt][0] + b0;
                float v1 = acc[mt][nt][1] + b1;
                if (RELU) { v0 = fmaxf(v0, 0.f); v1 = fmaxf(v1, 0.f); }
                if (SPLITK == 1) {
                    *(float2*)(C + (size_t)gr0 * N + gc) = make_float2(v0, v1);
                } else {
                    atomicAdd(C + (size_t)gr0 * N + gc, v0);
                    atomicAdd(C + (size_t)gr0 * N + gc + 1, v1);
                }
            }
            if (gr1 < M) {
                float v2 = acc[mt][nt][2] + b0;
                float v3 = acc[mt][nt][3] + b1;
                if (RELU) { v2 = fmaxf(v2, 0.f); v3 = fmaxf(v3, 0.f); }
                if (SPLITK == 1) {
                    *(float2*)(C + (size_t)gr1 * N + gc) = make_float2(v2, v3);
                } else {
                    atomicAdd(C + (size_t)gr1 * N + gc, v2);
                    atomicAdd(C + (size_t)gr1 * N + gc + 1, v3);
                }
            }
        }
    }
}

template <int STAGES>
constexpr int gemm_smem_bytes() { return STAGES * 128 * 36 * 4; }

// ---------------------------------------------------------------------------
// Precompute kernel. grid = (8, 9), block = 256.
// ---------------------------------------------------------------------------
__global__ void precompute_kernel(const float* __restrict__ op_w,
                                  const float* __restrict__ v_w,
                                  const float* __restrict__ v_b,
                                  const float* __restrict__ so_w,
                                  const float* __restrict__ so_b,
                                  const float* __restrict__ aw_w,
                                  const float* __restrict__ aw_b,
                                  float* __restrict__ wm,
                                  float* __restrict__ wcat,
                                  float* __restrict__ bcat) {
    const int tid = threadIdx.x;
    if (blockIdx.y == 8) {
        const int r0 = blockIdx.x * 48;
        for (int r = r0; r < r0 + 48; ++r) {
            const float* src = (r < 256) ? (so_w + (size_t)r * 256)
                                         : (aw_w + (size_t)(r - 256) * 256);
            wcat[(size_t)r * 256 + tid] = src[tid];
        }
        if (tid < 48) {
            int r = r0 + tid;
            bcat[r] = (r < 256) ? so_b[r] : aw_b[r - 256];
        }
        return;
    }

    const int h  = blockIdx.x;
    const int ot = blockIdx.y * 32;
    __shared__ float vs[32][256];

    for (int idx = tid; idx < 32 * 256; idx += 256) {
        int r = idx >> 8, c = idx & 255;
        vs[r][c] = v_w[(size_t)(32 * h + r) * 256 + c];
    }
    __syncthreads();

    for (int oo = 0; oo < 32; ++oo) {
        const int o = ot + oo;
        const float* opr = op_w + (size_t)o * 256 + 32 * h;
        float s = 0.f;
#pragma unroll
        for (int j = 0; j < 32; ++j) s = fmaf(opr[j], vs[j][tid], s);
        wm[(size_t)o * kAK + h * 256 + tid] = s;
    }
    if (tid < 32) {
        const int o = ot + tid;
        const float* opr = op_w + (size_t)o * 256 + 32 * h;
        float s = 0.f;
#pragma unroll
        for (int j = 0; j < 32; ++j) s = fmaf(opr[j], v_b[32 * h + j], s);
        wm[(size_t)o * kAK + 2048 + h] = s;
        if (h == 0)
            for (int z = 2056; z < kAK; ++z) wm[(size_t)o * kAK + z] = 0.f;
    }
}

// ---------------------------------------------------------------------------
// Elementwise add
// ---------------------------------------------------------------------------
__global__ void add_kernel(const float* __restrict__ a,
                           const float* __restrict__ b,
                           float* __restrict__ out, int n) {
    int i = blockIdx.x * blockDim.x + threadIdx.x;
    if (i < n) out[i] = a[i] + b[i];
}

// ---------------------------------------------------------------------------
// Residual + LayerNorm (256 features, one block per row).
// ---------------------------------------------------------------------------
template <bool WITH_POS>
__global__ void add_ln_kernel(const float* __restrict__ x,
                              const float* __restrict__ r,
                              const float* __restrict__ g,
                              const float* __restrict__ bta,
                              float* __restrict__ out,
                              const float* __restrict__ pos,
                              float* __restrict__ out2) {
    const int row = blockIdx.x;
    const int t = threadIdx.x;
    const size_t base = (size_t)row * kD;
    float v = x[base + t] + r[base + t];

    __shared__ float sm[8];
    float s = v;
#pragma unroll
    for (int o = 16; o > 0; o >>= 1) s += __shfl_xor_sync(~0u, s, o);
    if ((t & 31) == 0) sm[t >> 5] = s;
    __syncthreads();
    float tot = 0.f;
#pragma unroll
    for (int i = 0; i < 8; ++i) tot += sm[i];
    const float mean = tot * (1.f / kD);
    const float d = v - mean;
    float s2 = d * d;
#pragma unroll
    for (int o = 16; o > 0; o >>= 1) s2 += __shfl_xor_sync(~0u, s2, o);
    __syncthreads();
    if ((t & 31) == 0) sm[t >> 5] = s2;
    __syncthreads();
    float tot2 = 0.f;
#pragma unroll
    for (int i = 0; i < 8; ++i) tot2 += sm[i];
    const float var = tot2 * (1.f / kD);
    const float o1 = d * rsqrtf(var + 1e-5f) * g[t] + bta[t];
    out[base + t] = o1;
    if (WITH_POS) out2[base + t] = o1 + pos[base + t];
}

// ---------------------------------------------------------------------------
// Self attention with SMEM-cached K (key-major) and V (channel-major),
// two queries per warp iteration.
// ---------------------------------------------------------------------------
namespace {
constexpr int kQC = 76;              // queries per block (even)
constexpr int kKLD = 36;             // Ks row stride (float4-aligned)
constexpr int kVLD = 308;            // Vt row stride (float4-aligned, 20 mod 32)
constexpr int ATTN_SMEM =
    (kNQ * kKLD + kDH * kVLD + 8 * 2 * 304) * 4;  // 102080 B
}

__global__ __launch_bounds__(256, 2)
void self_attn_kernel(const float* __restrict__ qkv,
                      float* __restrict__ o) {
    extern __shared__ float sm[];
    float* Ks = sm;                      // [300][36]
    float* Vt = sm + kNQ * kKLD;         // [32][308]  Vt[ch][key]
    float* ps = Vt + kDH * kVLD;         // [8][2][304]

    const int tid  = threadIdx.x;
    const int w    = tid >> 5;
    const int lane = tid & 31;
    const int h = blockIdx.y;
    const int b = blockIdx.z;
    const int q0 = blockIdx.x * kQC;
    const int qend = (q0 + kQC < kNQ) ? (q0 + kQC) : kNQ;

    for (int idx = tid; idx < kNQ * 8; idx += 256) {
        const int r = idx >> 3, g4 = (idx & 7) * 4;
        const float* base = qkv + ((size_t)(b * kNQ + r)) * 768 + h * kDH + g4;
        *(float4*)&Ks[r * kKLD + g4] = *(const float4*)(base + 256);
        float4 v = *(const float4*)(base + 512);
        Vt[(g4 + 0) * kVLD + r] = v.x;
        Vt[(g4 + 1) * kVLD + r] = v.y;
        Vt[(g4 + 2) * kVLD + r] = v.z;
        Vt[(g4 + 3) * kVLD + r] = v.w;
    }
    if (tid < kDH * 8) {
        const int ch = tid >> 3, k = kNQ + (tid & 7);
        Vt[ch * kVLD + k] = 0.f;
    }
    __syncthreads();

    const float scale = 0.1767766952966369f;  // 1/sqrt(32)
    float* ps0 = &ps[(w * 2 + 0) * 304];
    float* ps1 = &ps[(w * 2 + 1) * 304];
    const float* vrow = &Vt[lane * kVLD];

    for (int q = q0 + w * 2; q < qend; q += 16) {
        float q0reg[32], q1reg[32];
        const float4* qr0 =
            (const float4*)(qkv + ((size_t)(b * kNQ + q)) * 768 + h * kDH);
        const float4* qr1 =
            (const float4*)(qkv + ((size_t)(b * kNQ + q + 1)) * 768 + h * kDH);
#pragma unroll
        for (int j = 0; j < 8; ++j) {
            float4 v0 = qr0[j], v1 = qr1[j];
            q0reg[j * 4 + 0] = v0.x; q0reg[j * 4 + 1] = v0.y;
            q0reg[j * 4 + 2] = v0.z; q0reg[j * 4 + 3] = v0.w;
            q1reg[j * 4 + 0] = v1.x; q1reg[j * 4 + 1] = v1.y;
            q1reg[j * 4 + 2] = v1.z; q1reg[j * 4 + 3] = v1.w;
        }

        float sc0[10], sc1[10];
        float m0 = -INFINITY, m1 = -INFINITY;
#pragma unroll
        for (int c = 0; c < 10; ++c) {
            const int k = c * 32 + lane;
            const float* kr = &Ks[(k < kNQ ? k : 0) * kKLD];
            float d0 = 0.f, d1 = 0.f;
#pragma unroll
            for (int j4 = 0; j4 < 8; ++j4) {
                const float4 kv = *(const float4*)&kr[j4 * 4];
                d0 = fmaf(kv.x, q0reg[j4 * 4 + 0], d0);
                d1 = fmaf(kv.x, q1reg[j4 * 4 + 0], d1);
                d0 = fmaf(kv.y, q0reg[j4 * 4 + 1], d0);
                d1 = fmaf(kv.y, q1reg[j4 * 4 + 1], d1);
                d0 = fmaf(kv.z, q0reg[j4 * 4 + 2], d0);
                d1 = fmaf(kv.z, q1reg[j4 * 4 + 2], d1);
                d0 = fmaf(kv.w, q0reg[j4 * 4 + 3], d0);
                d1 = fmaf(kv.w, q1reg[j4 * 4 + 3], d1);
            }
            d0 *= scale; d1 *= scale;
            if (k >= kNQ) { d0 = -INFINITY; d1 = -INFINITY; }
            sc0[c] = d0; sc1[c] = d1;
            m0 = fmaxf(m0, d0); m1 = fmaxf(m1, d1);
        }
#pragma unroll
        for (int off = 16; off > 0; off >>= 1) {
            m0 = fmaxf(m0, __shfl_xor_sync(~0u, m0, off));
            m1 = fmaxf(m1, __shfl_xor_sync(~0u, m1, off));
        }

        float s0 = 0.f, s1 = 0.f;
#pragma unroll
        for (int c = 0; c < 10; ++c) {
            const int k = c * 32 + lane;
            float e0 = (k < kNQ) ? expf(sc0[c] - m0) : 0.f;
            float e1 = (k < kNQ) ? expf(sc1[c] - m1) : 0.f;
            if (k < 304) { ps0[k] = e0; ps1[k] = e1; }
            s0 += e0; s1 += e1;
        }
#pragma unroll
        for (int off = 16; off > 0; off >>= 1) {
            s0 += __shfl_xor_sync(~0u, s0, off);
            s1 += __shfl_xor_sync(~0u, s1, off);
        }
        const float inv0 = 1.f / s0, inv1 = 1.f / s1;
        __syncwarp();

        float a0 = 0.f, a1 = 0.f;
#pragma unroll 5
        for (int c = 0; c < 304 / 4; ++c) {
            const float4 p0 = *(const float4*)&ps0[c * 4];
            const float4 p1 = *(const float4*)&ps1[c * 4];
            const float4 v  = *(const float4*)&vrow[c * 4];
            a0 = fmaf(p0.x, v.x, a0); a1 = fmaf(p1.x, v.x, a1);
            a0 = fmaf(p0.y, v.y, a0); a1 = fmaf(p1.y, v.y, a1);
            a0 = fmaf(p0.z, v.z, a0); a1 = fmaf(p1.z, v.z, a1);
            a0 = fmaf(p0.w, v.w, a0); a1 = fmaf(p1.w, v.w, a1);
        }
        __syncwarp();

        o[((size_t)(b * kNQ + q)) * kD + h * kDH + lane] = a0 * inv0;
        o[((size_t)(b * kNQ + q + 1)) * kD + h * kDH + lane] = a1 * inv1;
    }
}

// ---------------------------------------------------------------------------
// MS deformable aggregation over RAW memory rows.
// ---------------------------------------------------------------------------
__global__ void msdeform_agg_kernel(const float* __restrict__ ref,
                                    const float* __restrict__ oa,
                                    const float* __restrict__ memory,
                                    float* __restrict__ agg) {
    const int bq = blockIdx.x;
    const int b = bq / kNQ;
    const int t = threadIdx.x;
    const int h = t >> 5;
    const int lane = t & 31;

    __shared__ float s_p[kNH][16];

    float lw = (lane < 16) ? oa[(size_t)bq * kOW + 256 + h * 16 + lane] : -INFINITY;
    float m = lw;
#pragma unroll
    for (int o = 8; o > 0; o >>= 1) m = fmaxf(m, __shfl_xor_sync(~0u, m, o, 16));
    float e = (lane < 16) ? expf(lw - m) : 0.f;
    float sum = e;
#pragma unroll
    for (int o = 8; o > 0; o >>= 1) sum += __shfl_xor_sync(~0u, sum, o, 16);
    if (lane < 16) s_p[h][lane] = e / sum;
    __syncwarp();

    const int cH[kNL]  = {100, 50, 25, 13};
    const int cW[kNL]  = {150, 75, 38, 19};
    const int cS0[kNL] = {0, 15000, 18750, 19700};

    float a0 = 0.f, a1 = 0.f, a2 = 0.f, a3 = 0.f;
    float a4 = 0.f, a5 = 0.f, a6 = 0.f, a7 = 0.f;
    float bsum = 0.f;

#pragma unroll
    for (int l = 0; l < kNL; ++l) {
        const float rx = ref[((size_t)bq * kNL + l) * 2 + 0];
        const float ry = ref[((size_t)bq * kNL + l) * 2 + 1];
        const int Hl = cH[l], Wl = cW[l], s0 = cS0[l];
        const float fW = (float)Wl, fH = (float)Hl;
#pragma unroll
        for (int p = 0; p < kNP; ++p) {
            const float aw = s_p[h][l * kNP + p];
            const size_t ob = (size_t)bq * kOW + (((h * kNL + l) * kNP + p) * 2);
            const float ox = oa[ob + 0];
            const float oy = oa[ob + 1];
            const float x = (rx + ox / fW) * fW - 0.5f;
            const float y = (ry + oy / fH) * fH - 0.5f;
            const float x0f = floorf(x), y0f = floorf(y);
            const float tx = x - x0f, ty = y - y0f;
            const int x0 = (int)x0f, y0 = (int)y0f;

#pragma unroll
            for (int dy = 0; dy < 2; ++dy) {
#pragma unroll
                for (int dx = 0; dx < 2; ++dx) {
                    const int xi = x0 + dx, yi = y0 + dy;
                    const bool valid = (xi >= 0) & (xi < Wl) & (yi >= 0) & (yi < Hl);
                    if (valid) {
                        const float w =
                            aw * (dy ? ty : (1.f - ty)) * (dx ? tx : (1.f - tx));
                        const float4* row = (const float4*)(
                            memory + ((size_t)b * kS + s0 + yi * Wl + xi) * kD +
                            lane * 8);
                        float4 v0 = row[0];
                        float4 v1 = row[1];
                        a0 = fmaf(w, v0.x, a0); a1 = fmaf(w, v0.y, a1);
                        a2 = fmaf(w, v0.z, a2); a3 = fmaf(w, v0.w, a3);
                        a4 = fmaf(w, v1.x, a4); a5 = fmaf(w, v1.y, a5);
                        a6 = fmaf(w, v1.z, a6); a7 = fmaf(w, v1.w, a7);
                        bsum += w;
                    }
                }
            }
        }
    }

    float4* dst = (float4*)(agg + (size_t)bq * kAK + h * 256 + lane * 8);
    dst[0] = make_float4(a0, a1, a2, a3);
    dst[1] = make_float4(a4, a5, a6, a7);
    if (lane == 0) agg[(size_t)bq * kAK + 2048 + h] = bsum;
    if (h == 0 && lane < 24) agg[(size_t)bq * kAK + 2056 + lane] = 0.f;
}

// ---------------------------------------------------------------------------
// Launch helpers
// ---------------------------------------------------------------------------
static void ensure_attrs() {
    static bool done = false;
    if (done) return;
    cudaFuncSetAttribute((const void*)gemm_tf32_kernel<3, false, 1>,
                         cudaFuncAttributeMaxDynamicSharedMemorySize,
                         gemm_smem_bytes<3>());
    cudaFuncSetAttribute((const void*)gemm_tf32_kernel<3, true, 1>,
                         cudaFuncAttributeMaxDynamicSharedMemorySize,
                         gemm_smem_bytes<3>());
    cudaFuncSetAttribute((const void*)gemm_tf32_kernel<3, false, 2>,
                         cudaFuncAttributeMaxDynamicSharedMemorySize,
                         gemm_smem_bytes<3>());
    cudaFuncSetAttribute((const void*)gemm_tf32_kernel<4, false, 2>,
                         cudaFuncAttributeMaxDynamicSharedMemorySize,
                         gemm_smem_bytes<4>());
    cudaFuncSetAttribute((const void*)self_attn_kernel,
                         cudaFuncAttributeMaxDynamicSharedMemorySize,
                         ATTN_SMEM);
    done = true;
}

static inline void launch_gemm(const float* A, const float* W, const float* b,
                               float* C, int M, int N, int K, bool relu) {
    dim3 grid(N / 64, (M + 63) / 64);
    if (relu)
        gemm_tf32_kernel<3, true, 1><<<grid, 256, gemm_smem_bytes<3>()>>>(
            A, A, N, W, b, C, M, N, K);
    else
        gemm_tf32_kernel<3, false, 1><<<grid, 256, gemm_smem_bytes<3>()>>>(
            A, A, N, W, b, C, M, N, K);
}

extern "C" void kernel_launch(void* const* d_in, const int* in_sizes, int n_in,
                              void* d_out, int out_size) {
    const float* tgt    = (const float*)d_in[0];
    const float* pos    = (const float*)d_in[1];
    const float* ref    = (const float*)d_in[2];
    const float* memory = (const float*)d_in[3];
    const float* in_w  = (const float*)d_in[7];
    const float* in_b  = (const float*)d_in[8];
    const float* out_w = (const float*)d_in[9];
    const float* out_b = (const float*)d_in[10];
    const float* n1g = (const float*)d_in[11];
    const float* n1b = (const float*)d_in[12];
    const float* n2g = (const float*)d_in[13];
    const float* n2b = (const float*)d_in[14];
    const float* n3g = (const float*)d_in[15];
    const float* n3b = (const float*)d_in[16];
    const float* so_w = (const float*)d_in[17];
    const float* so_b = (const float*)d_in[18];
    const float* aw_w = (const float*)d_in[19];
    const float* aw_b = (const float*)d_in[20];
    const float* v_w  = (const float*)d_in[21];
    const float* v_b  = (const float*)d_in[22];
    const float* op_w = (const float*)d_in[23];
    const float* op_b = (const float*)d_in[24];
    const float* l1w  = (const float*)d_in[25];
    const float* l1b  = (const float*)d_in[26];
    const float* l2w  = (const float*)d_in[27];
    const float* l2b  = (const float*)d_in[28];

    float* scratch = nullptr;
    cudaGetSymbolAddress((void**)&scratch, g_scratch);
    ensure_attrs();

    float* s_qkadd = scratch + OFF_QKADD;
    float* s_qkv   = scratch + OFF_QKV;
    float* s_attn  = scratch + OFF_ATTN;
    float* s_sa    = scratch + OFF_SA;
    float* s_tgt1  = scratch + OFF_TGT1;
    float* s_query = scratch + OFF_QUERY;
    float* s_oa    = scratch + OFF_OA;
    float* s_t2    = scratch + OFF_T2;
    float* s_tgt2  = scratch + OFF_TGT2;
    float* s_hid   = scratch + OFF_HID;
    float* s_ffo   = scratch + OFF_FFO;
    float* s_agg   = scratch + OFF_AGG;
    float* s_wm    = scratch + OFF_WM;
    float* s_wcat  = scratch + OFF_WCAT;
    float* s_bcat  = scratch + OFF_BCAT;

    const int nQD = kMQ * kD;

    // ---- zero split-K accumulation targets (graph-capturable memset nodes) ----
    cudaMemsetAsync(s_t2, 0, (size_t)kMQ * kD * sizeof(float));
    cudaMemsetAsync(s_ffo, 0, (size_t)kMQ * kD * sizeof(float));

    // ---- precompute (Wm, weight concat) + qkadd ----
    {
        dim3 grid(kNH, 9);
        precompute_kernel<<<grid, 256>>>(op_w, v_w, v_b, so_w, so_b, aw_w, aw_b,
                                         s_wm, s_wcat, s_bcat);
    }
    add_kernel<<<(nQD + 255) / 256, 256>>>(tgt, pos, s_qkadd, nQD);

    // ---- self attention: merged QKV GEMM + SMEM-cached attention ----
    {
        dim3 grid(768 / 64, (kMQ + 63) / 64);
        gemm_tf32_kernel<3, false, 1><<<grid, 256, gemm_smem_bytes<3>()>>>(
            s_qkadd, tgt, 512, in_w, in_b, s_qkv, kMQ, 768, kD);
    }
    {
        dim3 grid((kNQ + kQC - 1) / kQC, kNH, kBS);
        self_attn_kernel<<<grid, 256, ATTN_SMEM>>>(s_qkv, s_attn);
    }
    launch_gemm(s_attn, out_w, out_b, s_sa, kMQ, kD, kD, false);
    add_ln_kernel<true><<<kMQ, 256>>>(tgt, s_sa, n2g, n2b, s_tgt1, pos, s_query);

    // ---- MS deformable attention (merged offs+awl GEMM; value GEMM folded) ----
    launch_gemm(s_query, s_wcat, s_bcat, s_oa, kMQ, kOW, kD, false);
    msdeform_agg_kernel<<<kMQ, 256>>>(ref, s_oa, memory, s_agg);
    {
        // split-K=2 over K=2080 (33+32 iters), atomic accumulate into zeroed s_t2
        dim3 grid(kD / 64, (kMQ + 63) / 64, 2);
        gemm_tf32_kernel<4, false, 2><<<grid, 256, gemm_smem_bytes<4>()>>>(
            s_agg, s_agg, kD, s_wm, op_b, s_t2, kMQ, kD, kAK);
    }
    add_ln_kernel<false><<<kMQ, 256>>>(s_tgt1, s_t2, n1g, n1b, s_tgt2,
                                       nullptr, nullptr);

    // ---- FFN ----
    launch_gemm(s_tgt2, l1w, l1b, s_hid, kMQ, kDFF, kD, true);
    {
        // split-K=2 over K=1024 (16+16 iters), atomic accumulate into zeroed s_ffo
        dim3 grid(kD / 64, (kMQ + 63) / 64, 2);
        gemm_tf32_kernel<3, false, 2><<<grid, 256, gemm_smem_bytes<3>()>>>(
            s_hid, s_hid, kD, l2w, l2b, s_ffo, kMQ, kD, kDFF);
    }
    add_ln_kernel<false><<<kMQ, 256>>>(s_tgt2, s_ffo, n3g, n3b, (float*)d_out,
                                       nullptr, nullptr);
}

// round 12
// speedup vs baseline: 5.2583x; 1.0364x over previous
#include <cuda_runtime.h>
#include <math.h>
#include <stdint.h>

// ---------------------------------------------------------------------------
// Problem constants
// ---------------------------------------------------------------------------
namespace {
constexpr int kD   = 256;
constexpr int kNH  = 8;
constexpr int kDH  = 32;
constexpr int kNL  = 4;
constexpr int kNP  = 4;
constexpr int kDFF = 1024;
constexpr int kBS  = 8;
constexpr int kNQ  = 300;
constexpr int kS   = 19947;
constexpr int kMQ  = kBS * kNQ;      // 2400
constexpr int kAK  = 2080;           // agg K: 8*256 + 8 bias + 24 pad (65*32)
constexpr int kOW  = 384;            // merged offs(256) + awl(128) width

constexpr size_t OFF_QKADD = 0;
constexpr size_t OFF_QKV   = OFF_QKADD + (size_t)kMQ * kD;   // [2400][768]
constexpr size_t OFF_ATTN  = OFF_QKV   + (size_t)kMQ * 768;
constexpr size_t OFF_SA    = OFF_ATTN  + (size_t)kMQ * kD;
constexpr size_t OFF_TGT1  = OFF_SA    + (size_t)kMQ * kD;
constexpr size_t OFF_QUERY = OFF_TGT1  + (size_t)kMQ * kD;
constexpr size_t OFF_OA    = OFF_QUERY + (size_t)kMQ * kD;   // [2400][384]
constexpr size_t OFF_T2    = OFF_OA    + (size_t)kMQ * kOW;
constexpr size_t OFF_TGT2  = OFF_T2    + (size_t)kMQ * kD;
constexpr size_t OFF_HID   = OFF_TGT2  + (size_t)kMQ * kD;
constexpr size_t OFF_FFO   = OFF_HID   + (size_t)kMQ * kDFF;
constexpr size_t OFF_AGG   = OFF_FFO   + (size_t)kMQ * kD;
constexpr size_t OFF_WM    = OFF_AGG   + (size_t)kMQ * kAK;
constexpr size_t OFF_WCAT  = OFF_WM    + (size_t)kD * kAK;   // [384][256]
constexpr size_t OFF_BCAT  = OFF_WCAT  + (size_t)kOW * kD;   // [384]
constexpr size_t SCRATCH_TOTAL = OFF_BCAT + kOW;
} // namespace

__device__ float g_scratch[SCRATCH_TOTAL];

// ---------------------------------------------------------------------------
// helpers
// ---------------------------------------------------------------------------
__device__ __forceinline__ uint32_t smem_u32(const void* p) {
    uint32_t a;
    asm("{ .reg .u64 t; cvta.to.shared.u64 t, %1; cvt.u32.u64 %0, t; }"
        : "=r"(a) : "l"(p));
    return a;
}

__device__ __forceinline__ void cp_async16(uint32_t dst, const void* src, bool pred) {
    int sz = pred ? 16 : 0;
    asm volatile("cp.async.cg.shared.global [%0], [%1], 16, %2;"
                 :: "r"(dst), "l"(src), "r"(sz));
}
__device__ __forceinline__ void cp_commit() {
    asm volatile("cp.async.commit_group;");
}
template <int N>
__device__ __forceinline__ void cp_wait() {
    asm volatile("cp.async.wait_group %0;" :: "n"(N));
}

__device__ __forceinline__ void mma_tf32(float (&d)[4],
                                         const uint32_t (&a)[4],
                                         const uint32_t (&b)[2]) {
    asm volatile(
        "mma.sync.aligned.m16n8k8.row.col.f32.tf32.tf32.f32 "
        "{%0,%1,%2,%3}, {%4,%5,%6,%7}, {%8,%9}, {%0,%1,%2,%3};"
        : "+f"(d[0]), "+f"(d[1]), "+f"(d[2]), "+f"(d[3])
        : "r"(a[0]), "r"(a[1]), "r"(a[2]), "r"(a[3]),
          "r"(b[0]), "r"(b[1]));
}

// ---------------------------------------------------------------------------
// TF32 tensor-core GEMM with per-n-region A select and optional split-K.
// ---------------------------------------------------------------------------
template <int STAGES, bool RELU, int SPLITK>
__global__ __launch_bounds__(256, 2)
void gemm_tf32_kernel(const float* __restrict__ A1,
                      const float* __restrict__ A2,
                      int n_split,
                      const float* __restrict__ W,
                      const float* __restrict__ bias,
                      float* __restrict__ C,
                      int M, int N, int K) {
    constexpr int BM = 64, BN = 64, BK = 32;
    constexpr int LD = BK + 4;                 // 36 words/row
    constexpr int THREADS = 256;
    constexpr int WM = 2;
    constexpr int MT = 2, NT = 2;
    constexpr int A_IT = (BM * BK / 4) / THREADS;   // 2
    constexpr int B_IT = (BN * BK / 4) / THREADS;   // 2

    extern __shared__ float smem[];
    float* As = smem;
    float* Ws = smem + (size_t)STAGES * BM * LD;

    const int tid  = threadIdx.x;
    const int warp = tid >> 5;
    const int lane = tid & 31;
    const int g    = lane >> 2;
    const int tg   = lane & 3;
    const int tm   = blockIdx.y * BM;
    const int tn   = blockIdx.x * BN;
    const int wm   = (warp % WM) * 32;
    const int wn   = (warp / WM) * 16;

    const float* A = (tn < n_split) ? A1 : A2;

    const int nk_all = K / BK;
    const int nk_per = (nk_all + SPLITK - 1) / SPLITK;
    const int k_lo   = (SPLITK > 1) ? blockIdx.z * nk_per : 0;
    const int k_hi   = (SPLITK > 1) ? ((k_lo + nk_per < nk_all) ? k_lo + nk_per
                                                                : nk_all)
                                    : nk_all;
    const int nk_this = k_hi - k_lo;

    float acc[MT][NT][4] = {};

    auto issue = [&](int s, int kt) {
        if (kt < nk_this) {
            const int k0 = (k_lo + kt) * BK;
#pragma unroll
            for (int i = 0; i < A_IT; ++i) {
                int idx = tid + i * THREADS;
                int r = idx >> 3, c4 = (idx & 7) * 4;
                int gr = tm + r;
                cp_async16(smem_u32(&As[(size_t)s * BM * LD + r * LD + c4]),
                           A + (size_t)gr * K + k0 + c4, gr < M);
            }
#pragma unroll
            for (int i = 0; i < B_IT; ++i) {
                int idx = tid + i * THREADS;
                int r = idx >> 3, c4 = (idx & 7) * 4;
                cp_async16(smem_u32(&Ws[(size_t)s * BN * LD + r * LD + c4]),
                           W + (size_t)(tn + r) * K + k0 + c4, true);
            }
        }
        cp_commit();
    };

    issue(0, 0);
#pragma unroll
    for (int p = 1; p < STAGES - 1; ++p) issue(p, p);

    for (int kt = 0; kt < nk_this; ++kt) {
        const int s = kt % STAGES;
        cp_wait<STAGES - 2>();
        __syncthreads();
        issue((kt + STAGES - 1) % STAGES, kt + STAGES - 1);

        const float* as = &As[(size_t)s * BM * LD];
        const float* ws = &Ws[(size_t)s * BN * LD];
#pragma unroll
        for (int ks = 0; ks < 4; ++ks) {
            const int kc = ks * 8 + tg;
            uint32_t af[MT][4], bf[NT][2];
#pragma unroll
            for (int mt = 0; mt < MT; ++mt) {
                const int r = wm + mt * 16 + g;
                af[mt][0] = __float_as_uint(as[r * LD + kc]);
                af[mt][1] = __float_as_uint(as[(r + 8) * LD + kc]);
                af[mt][2] = __float_as_uint(as[r * LD + kc + 4]);
                af[mt][3] = __float_as_uint(as[(r + 8) * LD + kc + 4]);
            }
#pragma unroll
            for (int nt = 0; nt < NT; ++nt) {
                const int n = wn + nt * 8 + g;
                bf[nt][0] = __float_as_uint(ws[n * LD + kc]);
                bf[nt][1] = __float_as_uint(ws[n * LD + kc + 4]);
            }
#pragma unroll
            for (int mt = 0; mt < MT; ++mt)
#pragma unroll
                for (int nt = 0; nt < NT; ++nt)
                    mma_tf32(acc[mt][nt], af[mt], bf[nt]);
        }
        __syncthreads();
    }

    const bool add_bias = (SPLITK == 1) || (blockIdx.z == 0);
#pragma unroll
    for (int mt = 0; mt < MT; ++mt) {
        const int gr0 = tm + wm + mt * 16 + g;
        const int gr1 = gr0 + 8;
#pragma unroll
        for (int nt = 0; nt < NT; ++nt) {
            const int gc = tn + wn + nt * 8 + tg * 2;
            const float b0 = add_bias ? bias[gc] : 0.f;
            const float b1 = add_bias ? bias[gc + 1] : 0.f;
            if (gr0 < M) {
                float v0 = acc[mt][nt][0] + b0;
                float v1 = acc[mt][nt][1] + b1;
                if (RELU) { v0 = fmaxf(v0, 0.f); v1 = fmaxf(v1, 0.f); }
                if (SPLITK == 1) {
                    *(float2*)(C + (size_t)gr0 * N + gc) = make_float2(v0, v1);
                } else {
                    atomicAdd(C + (size_t)gr0 * N + gc, v0);
                    atomicAdd(C + (size_t)gr0 * N + gc + 1, v1);
                }
            }
            if (gr1 < M) {
                float v2 = acc[mt][nt][2] + b0;
                float v3 = acc[mt][nt][3] + b1;
                if (RELU) { v2 = fmaxf(v2, 0.f); v3 = fmaxf(v3, 0.f); }
                if (SPLITK == 1) {
                    *(float2*)(C + (size_t)gr1 * N + gc) = make_float2(v2, v3);
                } else {
                    atomicAdd(C + (size_t)gr1 * N + gc, v2);
                    atomicAdd(C + (size_t)gr1 * N + gc + 1, v3);
                }
            }
        }
    }
}

template <int STAGES>
constexpr int gemm_smem_bytes() { return STAGES * 128 * 36 * 4; }

// ---------------------------------------------------------------------------
// Precompute kernel. grid = (8, 9), block = 256.
// ---------------------------------------------------------------------------
__global__ void precompute_kernel(const float* __restrict__ op_w,
                                  const float* __restrict__ v_w,
                                  const float* __restrict__ v_b,
                                  const float* __restrict__ so_w,
                                  const float* __restrict__ so_b,
                                  const float* __restrict__ aw_w,
                                  const float* __restrict__ aw_b,
                                  float* __restrict__ wm,
                                  float* __restrict__ wcat,
                                  float* __restrict__ bcat) {
    const int tid = threadIdx.x;
    if (blockIdx.y == 8) {
        const int r0 = blockIdx.x * 48;
        for (int r = r0; r < r0 + 48; ++r) {
            const float* src = (r < 256) ? (so_w + (size_t)r * 256)
                                         : (aw_w + (size_t)(r - 256) * 256);
            wcat[(size_t)r * 256 + tid] = src[tid];
        }
        if (tid < 48) {
            int r = r0 + tid;
            bcat[r] = (r < 256) ? so_b[r] : aw_b[r - 256];
        }
        return;
    }

    const int h  = blockIdx.x;
    const int ot = blockIdx.y * 32;
    __shared__ float vs[32][256];

    for (int idx = tid; idx < 32 * 256; idx += 256) {
        int r = idx >> 8, c = idx & 255;
        vs[r][c] = v_w[(size_t)(32 * h + r) * 256 + c];
    }
    __syncthreads();

    for (int oo = 0; oo < 32; ++oo) {
        const int o = ot + oo;
        const float* opr = op_w + (size_t)o * 256 + 32 * h;
        float s = 0.f;
#pragma unroll
        for (int j = 0; j < 32; ++j) s = fmaf(opr[j], vs[j][tid], s);
        wm[(size_t)o * kAK + h * 256 + tid] = s;
    }
    if (tid < 32) {
        const int o = ot + tid;
        const float* opr = op_w + (size_t)o * 256 + 32 * h;
        float s = 0.f;
#pragma unroll
        for (int j = 0; j < 32; ++j) s = fmaf(opr[j], v_b[32 * h + j], s);
        wm[(size_t)o * kAK + 2048 + h] = s;
        if (h == 0)
            for (int z = 2056; z < kAK; ++z) wm[(size_t)o * kAK + z] = 0.f;
    }
}

// ---------------------------------------------------------------------------
// Elementwise add
// ---------------------------------------------------------------------------
__global__ void add_kernel(const float* __restrict__ a,
                           const float* __restrict__ b,
                           float* __restrict__ out, int n) {
    int i = blockIdx.x * blockDim.x + threadIdx.x;
    if (i < n) out[i] = a[i] + b[i];
}

// ---------------------------------------------------------------------------
// Residual + LayerNorm (256 features, one block per row).
// ---------------------------------------------------------------------------
template <bool WITH_POS>
__global__ void add_ln_kernel(const float* __restrict__ x,
                              const float* __restrict__ r,
                              const float* __restrict__ g,
                              const float* __restrict__ bta,
                              float* __restrict__ out,
                              const float* __restrict__ pos,
                              float* __restrict__ out2) {
    const int row = blockIdx.x;
    const int t = threadIdx.x;
    const size_t base = (size_t)row * kD;
    float v = x[base + t] + r[base + t];

    __shared__ float sm[8];
    float s = v;
#pragma unroll
    for (int o = 16; o > 0; o >>= 1) s += __shfl_xor_sync(~0u, s, o);
    if ((t & 31) == 0) sm[t >> 5] = s;
    __syncthreads();
    float tot = 0.f;
#pragma unroll
    for (int i = 0; i < 8; ++i) tot += sm[i];
    const float mean = tot * (1.f / kD);
    const float d = v - mean;
    float s2 = d * d;
#pragma unroll
    for (int o = 16; o > 0; o >>= 1) s2 += __shfl_xor_sync(~0u, s2, o);
    __syncthreads();
    if ((t & 31) == 0) sm[t >> 5] = s2;
    __syncthreads();
    float tot2 = 0.f;
#pragma unroll
    for (int i = 0; i < 8; ++i) tot2 += sm[i];
    const float var = tot2 * (1.f / kD);
    const float o1 = d * rsqrtf(var + 1e-5f) * g[t] + bta[t];
    out[base + t] = o1;
    if (WITH_POS) out2[base + t] = o1 + pos[base + t];
}

// ---------------------------------------------------------------------------
// Tensor-core self attention. Block = (qtile 64, h, b), 256 threads (8 warps).
// qkv rows: [q(0..255) | k(256..511) | v(512..767)], stride 768.
// Pass 1: S = scale * Q @ K^T via tf32 mma (K SMEM = natural col-major B).
// Softmax in SMEM (4 threads/row, __expf), Vt fill reuses dead K region.
// Pass 2: O = P @ V via tf32 mma, epilogue * 1/rowsum, masked stores.
// ---------------------------------------------------------------------------
namespace {
constexpr int kQT   = 64;
constexpr int kSLD  = 316;    // S stride: 28g+tg covers all banks in frag reads
constexpr int kKLD2 = 36;     // K stride (key-major)
constexpr int kVLD2 = 308;    // Vt stride (channel-major)
constexpr int S_FLOATS  = kQT * kSLD;    // 20224
constexpr int KV_FLOATS = kNQ * kKLD2;   // 10800 (>= 32*308 = 9856 for Vt)
constexpr int ATTN_SMEM = (S_FLOATS + KV_FLOATS + kQT) * 4;  // 124352 B
}

__global__ __launch_bounds__(256, 1)
void attn_tc_kernel(const float* __restrict__ qkv, float* __restrict__ o) {
    extern __shared__ float sm[];
    float* S    = sm;                    // [64][316]
    float* KV   = sm + S_FLOATS;         // Ks[300][36] then Vt[32][308]
    float* lrow = KV + KV_FLOATS;        // [64] inverse row sums

    const int tid  = threadIdx.x;
    const int w    = tid >> 5;
    const int lane = tid & 31;
    const int g    = lane >> 2;
    const int tg   = lane & 3;
    const int h  = blockIdx.y;
    const int b  = blockIdx.z;
    const int q0 = blockIdx.x * kQT;
    const float scale = 0.1767766952966369f;   // 1/sqrt(32)

    // ---- K into SMEM (key-major) ----
    for (int idx = tid; idx < kNQ * 8; idx += 256) {
        const int r = idx >> 3, c4 = (idx & 7) * 4;
        *(float4*)&KV[r * kKLD2 + c4] =
            *(const float4*)(qkv + ((size_t)(b * kNQ + r)) * 768 + 256 +
                             h * kDH + c4);
    }
    __syncthreads();

    // ---- pass 1: S = scale * Q @ K^T ----
    const int mstrip = w & 3;
    const int lr_g   = mstrip * 16 + g;          // local row of frag rows g
    uint32_t qf[4][4];
    {
        int grow0 = b * kNQ + q0 + lr_g;
        int grow1 = grow0 + 8;
        if (grow0 > kMQ - 1) grow0 = kMQ - 1;
        if (grow1 > kMQ - 1) grow1 = kMQ - 1;
        const float* q0p = qkv + (size_t)grow0 * 768 + h * kDH;
        const float* q1p = qkv + (size_t)grow1 * 768 + h * kDH;
#pragma unroll
        for (int ks = 0; ks < 4; ++ks) {
            qf[ks][0] = __float_as_uint(q0p[ks * 8 + tg]);
            qf[ks][1] = __float_as_uint(q1p[ks * 8 + tg]);
            qf[ks][2] = __float_as_uint(q0p[ks * 8 + tg + 4]);
            qf[ks][3] = __float_as_uint(q1p[ks * 8 + tg + 4]);
        }
    }
    const int khalf = w >> 2;
#pragma unroll 1
    for (int nt = 0; nt < 19; ++nt) {
        const int n0 = khalf * 152 + nt * 8;
        int kr = n0 + g;
        if (kr >= kNQ) kr = 0;                   // masked later
        float c[4] = {0.f, 0.f, 0.f, 0.f};
#pragma unroll
        for (int ks = 0; ks < 4; ++ks) {
            uint32_t bf[2];
            bf[0] = __float_as_uint(KV[kr * kKLD2 + ks * 8 + tg]);
            bf[1] = __float_as_uint(KV[kr * kKLD2 + ks * 8 + tg + 4]);
            mma_tf32(c, qf[ks], bf);
        }
        const int col = n0 + tg * 2;
        *(float2*)&S[lr_g * kSLD + col] =
            make_float2(c[0] * scale, c[1] * scale);
        *(float2*)&S[(lr_g + 8) * kSLD + col] =
            make_float2(c[2] * scale, c[3] * scale);
    }
    __syncthreads();

    // ---- Vt fill (overwrites dead Ks) + row softmax ----
    for (int idx = tid; idx < kNQ * 8; idx += 256) {
        const int r = idx >> 3, c4 = (idx & 7) * 4;
        float4 v = *(const float4*)(qkv + ((size_t)(b * kNQ + r)) * 768 + 512 +
                                    h * kDH + c4);
        KV[(c4 + 0) * kVLD2 + r] = v.x;
        KV[(c4 + 1) * kVLD2 + r] = v.y;
        KV[(c4 + 2) * kVLD2 + r] = v.z;
        KV[(c4 + 3) * kVLD2 + r] = v.w;
    }
    if (tid < kDH * 4) {                         // zero Vt keys 300..303
        const int ch = tid >> 2, k = kNQ + (tid & 3);
        KV[ch * kVLD2 + k] = 0.f;
    }

    {
        const int row  = tid >> 2;               // 0..63
        const int part = tid & 3;
        float* srow = &S[row * kSLD + part * 76];
        const int base_col = part * 76;
        float mx = -INFINITY;
#pragma unroll
        for (int i = 0; i < 19; ++i) {
            float4 v = *(const float4*)&srow[i * 4];
            const int c = base_col + i * 4;
            if (c + 0 < kNQ) mx = fmaxf(mx, v.x);
            if (c + 1 < kNQ) mx = fmaxf(mx, v.y);
            if (c + 2 < kNQ) mx = fmaxf(mx, v.z);
            if (c + 3 < kNQ) mx = fmaxf(mx, v.w);
        }
        mx = fmaxf(mx, __shfl_xor_sync(~0u, mx, 1));
        mx = fmaxf(mx, __shfl_xor_sync(~0u, mx, 2));
        float sum = 0.f;
#pragma unroll
        for (int i = 0; i < 19; ++i) {
            float4 v = *(const float4*)&srow[i * 4];
            const int c = base_col + i * 4;
            v.x = (c + 0 < kNQ) ? __expf(v.x - mx) : 0.f;
            v.y = (c + 1 < kNQ) ? __expf(v.y - mx) : 0.f;
            v.z = (c + 2 < kNQ) ? __expf(v.z - mx) : 0.f;
            v.w = (c + 3 < kNQ) ? __expf(v.w - mx) : 0.f;
            sum += (v.x + v.y) + (v.z + v.w);
            *(float4*)&srow[i * 4] = v;
        }
        sum += __shfl_xor_sync(~0u, sum, 1);
        sum += __shfl_xor_sync(~0u, sum, 2);
        if (part == 0) lrow[row] = 1.f / sum;
    }
    __syncthreads();

    // ---- pass 2: O = P @ V ----
    const int chhalf = w >> 2;
#pragma unroll
    for (int nt2 = 0; nt2 < 2; ++nt2) {
        const int n0 = chhalf * 16 + nt2 * 8;
        float c[4] = {0.f, 0.f, 0.f, 0.f};
#pragma unroll 2
        for (int kt = 0; kt < 38; ++kt) {
            const int k = kt * 8;
            uint32_t af[4], bf[2];
            af[0] = __float_as_uint(S[lr_g * kSLD + k + tg]);
            af[1] = __float_as_uint(S[(lr_g + 8) * kSLD + k + tg]);
            af[2] = __float_as_uint(S[lr_g * kSLD + k + tg + 4]);
            af[3] = __float_as_uint(S[(lr_g + 8) * kSLD + k + tg + 4]);
            bf[0] = __float_as_uint(KV[(n0 + g) * kVLD2 + k + tg]);
            bf[1] = __float_as_uint(KV[(n0 + g) * kVLD2 + k + tg + 4]);
            mma_tf32(c, af, bf);
        }
        const int qrow0 = q0 + lr_g, qrow1 = qrow0 + 8;
        const int col = n0 + tg * 2;
        if (qrow0 < kNQ) {
            const float inv = lrow[lr_g];
            *(float2*)(o + ((size_t)(b * kNQ + qrow0)) * kD + h * kDH + col) =
                make_float2(c[0] * inv, c[1] * inv);
        }
        if (qrow1 < kNQ) {
            const float inv = lrow[lr_g + 8];
            *(float2*)(o + ((size_t)(b * kNQ + qrow1)) * kD + h * kDH + col) =
                make_float2(c[2] * inv, c[3] * inv);
        }
    }
}

// ---------------------------------------------------------------------------
// MS deformable aggregation over RAW memory rows.
// ---------------------------------------------------------------------------
__global__ void msdeform_agg_kernel(const float* __restrict__ ref,
                                    const float* __restrict__ oa,
                                    const float* __restrict__ memory,
                                    float* __restrict__ agg) {
    const int bq = blockIdx.x;
    const int b = bq / kNQ;
    const int t = threadIdx.x;
    const int h = t >> 5;
    const int lane = t & 31;

    __shared__ float s_p[kNH][16];

    float lw = (lane < 16) ? oa[(size_t)bq * kOW + 256 + h * 16 + lane] : -INFINITY;
    float m = lw;
#pragma unroll
    for (int o = 8; o > 0; o >>= 1) m = fmaxf(m, __shfl_xor_sync(~0u, m, o, 16));
    float e = (lane < 16) ? expf(lw - m) : 0.f;
    float sum = e;
#pragma unroll
    for (int o = 8; o > 0; o >>= 1) sum += __shfl_xor_sync(~0u, sum, o, 16);
    if (lane < 16) s_p[h][lane] = e / sum;
    __syncwarp();

    const int cH[kNL]  = {100, 50, 25, 13};
    const int cW[kNL]  = {150, 75, 38, 19};
    const int cS0[kNL] = {0, 15000, 18750, 19700};

    float a0 = 0.f, a1 = 0.f, a2 = 0.f, a3 = 0.f;
    float a4 = 0.f, a5 = 0.f, a6 = 0.f, a7 = 0.f;
    float bsum = 0.f;

#pragma unroll
    for (int l = 0; l < kNL; ++l) {
        const float rx = ref[((size_t)bq * kNL + l) * 2 + 0];
        const float ry = ref[((size_t)bq * kNL + l) * 2 + 1];
        const int Hl = cH[l], Wl = cW[l], s0 = cS0[l];
        const float fW = (float)Wl, fH = (float)Hl;
#pragma unroll
        for (int p = 0; p < kNP; ++p) {
            const float aw = s_p[h][l * kNP + p];
            const size_t ob = (size_t)bq * kOW + (((h * kNL + l) * kNP + p) * 2);
            const float ox = oa[ob + 0];
            const float oy = oa[ob + 1];
            const float x = (rx + ox / fW) * fW - 0.5f;
            const float y = (ry + oy / fH) * fH - 0.5f;
            const float x0f = floorf(x), y0f = floorf(y);
            const float tx = x - x0f, ty = y - y0f;
            const int x0 = (int)x0f, y0 = (int)y0f;

#pragma unroll
            for (int dy = 0; dy < 2; ++dy) {
#pragma unroll
                for (int dx = 0; dx < 2; ++dx) {
                    const int xi = x0 + dx, yi = y0 + dy;
                    const bool valid = (xi >= 0) & (xi < Wl) & (yi >= 0) & (yi < Hl);
                    if (valid) {
                        const float w =
                            aw * (dy ? ty : (1.f - ty)) * (dx ? tx : (1.f - tx));
                        const float4* row = (const float4*)(
                            memory + ((size_t)b * kS + s0 + yi * Wl + xi) * kD +
                            lane * 8);
                        float4 v0 = row[0];
                        float4 v1 = row[1];
                        a0 = fmaf(w, v0.x, a0); a1 = fmaf(w, v0.y, a1);
                        a2 = fmaf(w, v0.z, a2); a3 = fmaf(w, v0.w, a3);
                        a4 = fmaf(w, v1.x, a4); a5 = fmaf(w, v1.y, a5);
                        a6 = fmaf(w, v1.z, a6); a7 = fmaf(w, v1.w, a7);
                        bsum += w;
                    }
                }
            }
        }
    }

    float4* dst = (float4*)(agg + (size_t)bq * kAK + h * 256 + lane * 8);
    dst[0] = make_float4(a0, a1, a2, a3);
    dst[1] = make_float4(a4, a5, a6, a7);
    if (lane == 0) agg[(size_t)bq * kAK + 2048 + h] = bsum;
    if (h == 0 && lane < 24) agg[(size_t)bq * kAK + 2056 + lane] = 0.f;
}

// ---------------------------------------------------------------------------
// Launch helpers
// ---------------------------------------------------------------------------
static void ensure_attrs() {
    static bool done = false;
    if (done) return;
    cudaFuncSetAttribute((const void*)gemm_tf32_kernel<3, false, 1>,
                         cudaFuncAttributeMaxDynamicSharedMemorySize,
                         gemm_smem_bytes<3>());
    cudaFuncSetAttribute((const void*)gemm_tf32_kernel<3, true, 1>,
                         cudaFuncAttributeMaxDynamicSharedMemorySize,
                         gemm_smem_bytes<3>());
    cudaFuncSetAttribute((const void*)gemm_tf32_kernel<3, false, 2>,
                         cudaFuncAttributeMaxDynamicSharedMemorySize,
                         gemm_smem_bytes<3>());
    cudaFuncSetAttribute((const void*)gemm_tf32_kernel<4, false, 2>,
                         cudaFuncAttributeMaxDynamicSharedMemorySize,
                         gemm_smem_bytes<4>());
    cudaFuncSetAttribute((const void*)attn_tc_kernel,
                         cudaFuncAttributeMaxDynamicSharedMemorySize,
                         ATTN_SMEM);
    done = true;
}

static inline void launch_gemm(const float* A, const float* W, const float* b,
                               float* C, int M, int N, int K, bool relu) {
    dim3 grid(N / 64, (M + 63) / 64);
    if (relu)
        gemm_tf32_kernel<3, true, 1><<<grid, 256, gemm_smem_bytes<3>()>>>(
            A, A, N, W, b, C, M, N, K);
    else
        gemm_tf32_kernel<3, false, 1><<<grid, 256, gemm_smem_bytes<3>()>>>(
            A, A, N, W, b, C, M, N, K);
}

extern "C" void kernel_launch(void* const* d_in, const int* in_sizes, int n_in,
                              void* d_out, int out_size) {
    const float* tgt    = (const float*)d_in[0];
    const float* pos    = (const float*)d_in[1];
    const float* ref    = (const float*)d_in[2];
    const float* memory = (const float*)d_in[3];
    const float* in_w  = (const float*)d_in[7];
    const float* in_b  = (const float*)d_in[8];
    const float* out_w = (const float*)d_in[9];
    const float* out_b = (const float*)d_in[10];
    const float* n1g = (const float*)d_in[11];
    const float* n1b = (const float*)d_in[12];
    const float* n2g = (const float*)d_in[13];
    const float* n2b = (const float*)d_in[14];
    const float* n3g = (const float*)d_in[15];
    const float* n3b = (const float*)d_in[16];
    const float* so_w = (const float*)d_in[17];
    const float* so_b = (const float*)d_in[18];
    const float* aw_w = (const float*)d_in[19];
    const float* aw_b = (const float*)d_in[20];
    const float* v_w  = (const float*)d_in[21];
    const float* v_b  = (const float*)d_in[22];
    const float* op_w = (const float*)d_in[23];
    const float* op_b = (const float*)d_in[24];
    const float* l1w  = (const float*)d_in[25];
    const float* l1b  = (const float*)d_in[26];
    const float* l2w  = (const float*)d_in[27];
    const float* l2b  = (const float*)d_in[28];

    float* scratch = nullptr;
    cudaGetSymbolAddress((void**)&scratch, g_scratch);
    ensure_attrs();

    float* s_qkadd = scratch + OFF_QKADD;
    float* s_qkv   = scratch + OFF_QKV;
    float* s_attn  = scratch + OFF_ATTN;
    float* s_sa    = scratch + OFF_SA;
    float* s_tgt1  = scratch + OFF_TGT1;
    float* s_query = scratch + OFF_QUERY;
    float* s_oa    = scratch + OFF_OA;
    float* s_t2    = scratch + OFF_T2;
    float* s_tgt2  = scratch + OFF_TGT2;
    float* s_hid   = scratch + OFF_HID;
    float* s_ffo   = scratch + OFF_FFO;
    float* s_agg   = scratch + OFF_AGG;
    float* s_wm    = scratch + OFF_WM;
    float* s_wcat  = scratch + OFF_WCAT;
    float* s_bcat  = scratch + OFF_BCAT;

    const int nQD = kMQ * kD;

    // ---- zero split-K accumulation targets (graph-capturable memsets) ----
    cudaMemsetAsync(s_t2, 0, (size_t)kMQ * kD * sizeof(float));
    cudaMemsetAsync(s_ffo, 0, (size_t)kMQ * kD * sizeof(float));

    // ---- precompute (Wm, weight concat) + qkadd ----
    {
        dim3 grid(kNH, 9);
        precompute_kernel<<<grid, 256>>>(op_w, v_w, v_b, so_w, so_b, aw_w, aw_b,
                                         s_wm, s_wcat, s_bcat);
    }
    add_kernel<<<(nQD + 255) / 256, 256>>>(tgt, pos, s_qkadd, nQD);

    // ---- self attention: merged QKV GEMM + tensor-core attention ----
    {
        dim3 grid(768 / 64, (kMQ + 63) / 64);
        gemm_tf32_kernel<3, false, 1><<<grid, 256, gemm_smem_bytes<3>()>>>(
            s_qkadd, tgt, 512, in_w, in_b, s_qkv, kMQ, 768, kD);
    }
    {
        dim3 grid((kNQ + kQT - 1) / kQT, kNH, kBS);
        attn_tc_kernel<<<grid, 256, ATTN_SMEM>>>(s_qkv, s_attn);
    }
    launch_gemm(s_attn, out_w, out_b, s_sa, kMQ, kD, kD, false);
    add_ln_kernel<true><<<kMQ, 256>>>(tgt, s_sa, n2g, n2b, s_tgt1, pos, s_query);

    // ---- MS deformable attention (merged offs+awl GEMM; value GEMM folded) ----
    launch_gemm(s_query, s_wcat, s_bcat, s_oa, kMQ, kOW, kD, false);
    msdeform_agg_kernel<<<kMQ, 256>>>(ref, s_oa, memory, s_agg);
    {
        dim3 grid(kD / 64, (kMQ + 63) / 64, 2);
        gemm_tf32_kernel<4, false, 2><<<grid, 256, gemm_smem_bytes<4>()>>>(
            s_agg, s_agg, kD, s_wm, op_b, s_t2, kMQ, kD, kAK);
    }
    add_ln_kernel<false><<<kMQ, 256>>>(s_tgt1, s_t2, n1g, n1b, s_tgt2,
                                       nullptr, nullptr);

    // ---- FFN ----
    launch_gemm(s_tgt2, l1w, l1b, s_hid, kMQ, kDFF, kD, true);
    {
        dim3 grid(kD / 64, (kMQ + 63) / 64, 2);
        gemm_tf32_kernel<3, false, 2><<<grid, 256, gemm_smem_bytes<3>()>>>(
            s_hid, s_hid, kD, l2w, l2b, s_ffo, kMQ, kD, kDFF);
    }
    add_ln_kernel<false><<<kMQ, 256>>>(s_tgt2, s_ffo, n3g, n3b, (float*)d_out,
                                       nullptr, nullptr);
}

// round 13
// speedup vs baseline: 5.3541x; 1.0182x over previous
#include <cuda_runtime.h>
#include <math.h>
#include <stdint.h>

// ---------------------------------------------------------------------------
// Problem constants
// ---------------------------------------------------------------------------
namespace {
constexpr int kD   = 256;
constexpr int kNH  = 8;
constexpr int kDH  = 32;
constexpr int kNL  = 4;
constexpr int kNP  = 4;
constexpr int kDFF = 1024;
constexpr int kBS  = 8;
constexpr int kNQ  = 300;
constexpr int kS   = 19947;
constexpr int kMQ  = kBS * kNQ;      // 2400
constexpr int kAK  = 2080;           // agg K: 8*256 + 8 bias + 24 pad (65*32)
constexpr int kOW  = 384;            // merged offs(256) + awl(128) width

constexpr size_t OFF_QKADD = 0;
constexpr size_t OFF_QKV   = OFF_QKADD + (size_t)kMQ * kD;   // [2400][768]
constexpr size_t OFF_ATTN  = OFF_QKV   + (size_t)kMQ * 768;
constexpr size_t OFF_SA    = OFF_ATTN  + (size_t)kMQ * kD;
constexpr size_t OFF_TGT1  = OFF_SA    + (size_t)kMQ * kD;
constexpr size_t OFF_QUERY = OFF_TGT1  + (size_t)kMQ * kD;
constexpr size_t OFF_OA    = OFF_QUERY + (size_t)kMQ * kD;   // [2400][384]
constexpr size_t OFF_T2    = OFF_OA    + (size_t)kMQ * kOW;
constexpr size_t OFF_TGT2  = OFF_T2    + (size_t)kMQ * kD;
constexpr size_t OFF_HID   = OFF_TGT2  + (size_t)kMQ * kD;
constexpr size_t OFF_FFO   = OFF_HID   + (size_t)kMQ * kDFF;
constexpr size_t OFF_AGG   = OFF_FFO   + (size_t)kMQ * kD;
constexpr size_t OFF_WM    = OFF_AGG   + (size_t)kMQ * kAK;
constexpr size_t OFF_WCAT  = OFF_WM    + (size_t)kD * kAK;   // [384][256]
constexpr size_t OFF_BCAT  = OFF_WCAT  + (size_t)kOW * kD;   // [384]
constexpr size_t SCRATCH_TOTAL = OFF_BCAT + kOW;
} // namespace

__device__ float g_scratch[SCRATCH_TOTAL];

// ---------------------------------------------------------------------------
// helpers
// ---------------------------------------------------------------------------
__device__ __forceinline__ uint32_t smem_u32(const void* p) {
    uint32_t a;
    asm("{ .reg .u64 t; cvta.to.shared.u64 t, %1; cvt.u32.u64 %0, t; }"
        : "=r"(a) : "l"(p));
    return a;
}

__device__ __forceinline__ void cp_async16(uint32_t dst, const void* src, bool pred) {
    int sz = pred ? 16 : 0;
    asm volatile("cp.async.cg.shared.global [%0], [%1], 16, %2;"
                 :: "r"(dst), "l"(src), "r"(sz));
}
__device__ __forceinline__ void cp_commit() {
    asm volatile("cp.async.commit_group;");
}
template <int N>
__device__ __forceinline__ void cp_wait() {
    asm volatile("cp.async.wait_group %0;" :: "n"(N));
}

__device__ __forceinline__ void mma_tf32(float (&d)[4],
                                         const uint32_t (&a)[4],
                                         const uint32_t (&b)[2]) {
    asm volatile(
        "mma.sync.aligned.m16n8k8.row.col.f32.tf32.tf32.f32 "
        "{%0,%1,%2,%3}, {%4,%5,%6,%7}, {%8,%9}, {%0,%1,%2,%3};"
        : "+f"(d[0]), "+f"(d[1]), "+f"(d[2]), "+f"(d[3])
        : "r"(a[0]), "r"(a[1]), "r"(a[2]), "r"(a[3]),
          "r"(b[0]), "r"(b[1]));
}

// ---------------------------------------------------------------------------
// TF32 tensor-core GEMM with per-n-region A select and optional split-K.
// ---------------------------------------------------------------------------
template <int STAGES, bool RELU, int SPLITK>
__global__ __launch_bounds__(256, 2)
void gemm_tf32_kernel(const float* __restrict__ A1,
                      const float* __restrict__ A2,
                      int n_split,
                      const float* __restrict__ W,
                      const float* __restrict__ bias,
                      float* __restrict__ C,
                      int M, int N, int K) {
    constexpr int BM = 64, BN = 64, BK = 32;
    constexpr int LD = BK + 4;                 // 36 words/row
    constexpr int THREADS = 256;
    constexpr int WM = 2;
    constexpr int MT = 2, NT = 2;
    constexpr int A_IT = (BM * BK / 4) / THREADS;   // 2
    constexpr int B_IT = (BN * BK / 4) / THREADS;   // 2

    extern __shared__ float smem[];
    float* As = smem;
    float* Ws = smem + (size_t)STAGES * BM * LD;

    const int tid  = threadIdx.x;
    const int warp = tid >> 5;
    const int lane = tid & 31;
    const int g    = lane >> 2;
    const int tg   = lane & 3;
    const int tm   = blockIdx.y * BM;
    const int tn   = blockIdx.x * BN;
    const int wm   = (warp % WM) * 32;
    const int wn   = (warp / WM) * 16;

    const float* A = (tn < n_split) ? A1 : A2;

    const int nk_all = K / BK;
    const int nk_per = (nk_all + SPLITK - 1) / SPLITK;
    const int k_lo   = (SPLITK > 1) ? blockIdx.z * nk_per : 0;
    const int k_hi   = (SPLITK > 1) ? ((k_lo + nk_per < nk_all) ? k_lo + nk_per
                                                                : nk_all)
                                    : nk_all;
    const int nk_this = k_hi - k_lo;

    float acc[MT][NT][4] = {};

    auto issue = [&](int s, int kt) {
        if (kt < nk_this) {
            const int k0 = (k_lo + kt) * BK;
#pragma unroll
            for (int i = 0; i < A_IT; ++i) {
                int idx = tid + i * THREADS;
                int r = idx >> 3, c4 = (idx & 7) * 4;
                int gr = tm + r;
                cp_async16(smem_u32(&As[(size_t)s * BM * LD + r * LD + c4]),
                           A + (size_t)gr * K + k0 + c4, gr < M);
            }
#pragma unroll
            for (int i = 0; i < B_IT; ++i) {
                int idx = tid + i * THREADS;
                int r = idx >> 3, c4 = (idx & 7) * 4;
                cp_async16(smem_u32(&Ws[(size_t)s * BN * LD + r * LD + c4]),
                           W + (size_t)(tn + r) * K + k0 + c4, true);
            }
        }
        cp_commit();
    };

    issue(0, 0);
#pragma unroll
    for (int p = 1; p < STAGES - 1; ++p) issue(p, p);

    for (int kt = 0; kt < nk_this; ++kt) {
        const int s = kt % STAGES;
        cp_wait<STAGES - 2>();
        __syncthreads();
        issue((kt + STAGES - 1) % STAGES, kt + STAGES - 1);

        const float* as = &As[(size_t)s * BM * LD];
        const float* ws = &Ws[(size_t)s * BN * LD];
#pragma unroll
        for (int ks = 0; ks < 4; ++ks) {
            const int kc = ks * 8 + tg;
            uint32_t af[MT][4], bf[NT][2];
#pragma unroll
            for (int mt = 0; mt < MT; ++mt) {
                const int r = wm + mt * 16 + g;
                af[mt][0] = __float_as_uint(as[r * LD + kc]);
                af[mt][1] = __float_as_uint(as[(r + 8) * LD + kc]);
                af[mt][2] = __float_as_uint(as[r * LD + kc + 4]);
                af[mt][3] = __float_as_uint(as[(r + 8) * LD + kc + 4]);
            }
#pragma unroll
            for (int nt = 0; nt < NT; ++nt) {
                const int n = wn + nt * 8 + g;
                bf[nt][0] = __float_as_uint(ws[n * LD + kc]);
                bf[nt][1] = __float_as_uint(ws[n * LD + kc + 4]);
            }
#pragma unroll
            for (int mt = 0; mt < MT; ++mt)
#pragma unroll
                for (int nt = 0; nt < NT; ++nt)
                    mma_tf32(acc[mt][nt], af[mt], bf[nt]);
        }
        __syncthreads();
    }

    const bool add_bias = (SPLITK == 1) || (blockIdx.z == 0);
#pragma unroll
    for (int mt = 0; mt < MT; ++mt) {
        const int gr0 = tm + wm + mt * 16 + g;
        const int gr1 = gr0 + 8;
#pragma unroll
        for (int nt = 0; nt < NT; ++nt) {
            const int gc = tn + wn + nt * 8 + tg * 2;
            const float b0 = add_bias ? bias[gc] : 0.f;
            const float b1 = add_bias ? bias[gc + 1] : 0.f;
            if (gr0 < M) {
                float v0 = acc[mt][nt][0] + b0;
                float v1 = acc[mt][nt][1] + b1;
                if (RELU) { v0 = fmaxf(v0, 0.f); v1 = fmaxf(v1, 0.f); }
                if (SPLITK == 1) {
                    *(float2*)(C + (size_t)gr0 * N + gc) = make_float2(v0, v1);
                } else {
                    atomicAdd(C + (size_t)gr0 * N + gc, v0);
                    atomicAdd(C + (size_t)gr0 * N + gc + 1, v1);
                }
            }
            if (gr1 < M) {
                float v2 = acc[mt][nt][2] + b0;
                float v3 = acc[mt][nt][3] + b1;
                if (RELU) { v2 = fmaxf(v2, 0.f); v3 = fmaxf(v3, 0.f); }
                if (SPLITK == 1) {
                    *(float2*)(C + (size_t)gr1 * N + gc) = make_float2(v2, v3);
                } else {
                    atomicAdd(C + (size_t)gr1 * N + gc, v2);
                    atomicAdd(C + (size_t)gr1 * N + gc + 1, v3);
                }
            }
        }
    }
}

template <int STAGES>
constexpr int gemm_smem_bytes() { return STAGES * 128 * 36 * 4; }

// ---------------------------------------------------------------------------
// Precompute kernel. grid = (8, 9), block = 256.
// ---------------------------------------------------------------------------
__global__ void precompute_kernel(const float* __restrict__ op_w,
                                  const float* __restrict__ v_w,
                                  const float* __restrict__ v_b,
                                  const float* __restrict__ so_w,
                                  const float* __restrict__ so_b,
                                  const float* __restrict__ aw_w,
                                  const float* __restrict__ aw_b,
                                  float* __restrict__ wm,
                                  float* __restrict__ wcat,
                                  float* __restrict__ bcat) {
    const int tid = threadIdx.x;
    if (blockIdx.y == 8) {
        const int r0 = blockIdx.x * 48;
        for (int r = r0; r < r0 + 48; ++r) {
            const float* src = (r < 256) ? (so_w + (size_t)r * 256)
                                         : (aw_w + (size_t)(r - 256) * 256);
            wcat[(size_t)r * 256 + tid] = src[tid];
        }
        if (tid < 48) {
            int r = r0 + tid;
            bcat[r] = (r < 256) ? so_b[r] : aw_b[r - 256];
        }
        return;
    }

    const int h  = blockIdx.x;
    const int ot = blockIdx.y * 32;
    __shared__ float vs[32][256];

    for (int idx = tid; idx < 32 * 256; idx += 256) {
        int r = idx >> 8, c = idx & 255;
        vs[r][c] = v_w[(size_t)(32 * h + r) * 256 + c];
    }
    __syncthreads();

    for (int oo = 0; oo < 32; ++oo) {
        const int o = ot + oo;
        const float* opr = op_w + (size_t)o * 256 + 32 * h;
        float s = 0.f;
#pragma unroll
        for (int j = 0; j < 32; ++j) s = fmaf(opr[j], vs[j][tid], s);
        wm[(size_t)o * kAK + h * 256 + tid] = s;
    }
    if (tid < 32) {
        const int o = ot + tid;
        const float* opr = op_w + (size_t)o * 256 + 32 * h;
        float s = 0.f;
#pragma unroll
        for (int j = 0; j < 32; ++j) s = fmaf(opr[j], v_b[32 * h + j], s);
        wm[(size_t)o * kAK + 2048 + h] = s;
        if (h == 0)
            for (int z = 2056; z < kAK; ++z) wm[(size_t)o * kAK + z] = 0.f;
    }
}

// ---------------------------------------------------------------------------
// Elementwise add
// ---------------------------------------------------------------------------
__global__ void add_kernel(const float* __restrict__ a,
                           const float* __restrict__ b,
                           float* __restrict__ out, int n) {
    int i = blockIdx.x * blockDim.x + threadIdx.x;
    if (i < n) out[i] = a[i] + b[i];
}

// ---------------------------------------------------------------------------
// Residual + LayerNorm (256 features, one block per row).
// ---------------------------------------------------------------------------
template <bool WITH_POS>
__global__ void add_ln_kernel(const float* __restrict__ x,
                              const float* __restrict__ r,
                              const float* __restrict__ g,
                              const float* __restrict__ bta,
                              float* __restrict__ out,
                              const float* __restrict__ pos,
                              float* __restrict__ out2) {
    const int row = blockIdx.x;
    const int t = threadIdx.x;
    const size_t base = (size_t)row * kD;
    float v = x[base + t] + r[base + t];

    __shared__ float sm[8];
    float s = v;
#pragma unroll
    for (int o = 16; o > 0; o >>= 1) s += __shfl_xor_sync(~0u, s, o);
    if ((t & 31) == 0) sm[t >> 5] = s;
    __syncthreads();
    float tot = 0.f;
#pragma unroll
    for (int i = 0; i < 8; ++i) tot += sm[i];
    const float mean = tot * (1.f / kD);
    const float d = v - mean;
    float s2 = d * d;
#pragma unroll
    for (int o = 16; o > 0; o >>= 1) s2 += __shfl_xor_sync(~0u, s2, o);
    __syncthreads();
    if ((t & 31) == 0) sm[t >> 5] = s2;
    __syncthreads();
    float tot2 = 0.f;
#pragma unroll
    for (int i = 0; i < 8; ++i) tot2 += sm[i];
    const float var = tot2 * (1.f / kD);
    const float o1 = d * rsqrtf(var + 1e-5f) * g[t] + bta[t];
    out[base + t] = o1;
    if (WITH_POS) out2[base + t] = o1 + pos[base + t];
}

// ---------------------------------------------------------------------------
// Tensor-core self attention, 32-query tile for 2 CTAs/SM.
// Block = (qtile 32, h, b) = 640 blocks, 256 threads (8 warps).
// Pass 1: warps = 2 m-strips x 4 col-quarters; S = scale * Q @ K^T.
// Softmax (4 thr/row, rows<32), Vt fill reuses dead Ks region.
// Pass 2: warps = 2 m-strips x 4 col-groups (8 ch each); O = P @ V.
// ---------------------------------------------------------------------------
namespace {
constexpr int kQT   = 32;
constexpr int kSLD  = 316;    // S stride: 28g mod 32 distinct for g=0..7
constexpr int kKLD2 = 36;     // K stride (key-major)
constexpr int kVLD2 = 308;    // Vt stride (channel-major, 20g mod 32 distinct)
constexpr int S_FLOATS  = kQT * kSLD;    // 10112
constexpr int KV_FLOATS = kNQ * kKLD2;   // 10800 (>= 32*308 = 9856 for Vt)
constexpr int ATTN_SMEM = (S_FLOATS + KV_FLOATS + kQT) * 4;  // 83776 B
}

__global__ __launch_bounds__(256, 2)
void attn_tc_kernel(const float* __restrict__ qkv, float* __restrict__ o) {
    extern __shared__ float sm[];
    float* S    = sm;                    // [32][316]
    float* KV   = sm + S_FLOATS;         // Ks[300][36] then Vt[32][308]
    float* lrow = KV + KV_FLOATS;        // [32] inverse row sums

    const int tid  = threadIdx.x;
    const int w    = tid >> 5;
    const int lane = tid & 31;
    const int g    = lane >> 2;
    const int tg   = lane & 3;
    const int h  = blockIdx.y;
    const int b  = blockIdx.z;
    const int q0 = blockIdx.x * kQT;
    const float scale = 0.1767766952966369f;   // 1/sqrt(32)

    // ---- K into SMEM (key-major) ----
    for (int idx = tid; idx < kNQ * 8; idx += 256) {
        const int r = idx >> 3, c4 = (idx & 7) * 4;
        *(float4*)&KV[r * kKLD2 + c4] =
            *(const float4*)(qkv + ((size_t)(b * kNQ + r)) * 768 + 256 +
                             h * kDH + c4);
    }
    __syncthreads();

    // ---- pass 1: S = scale * Q @ K^T ----
    const int mstrip = w & 1;
    const int lr_g   = mstrip * 16 + g;          // local row of frag rows g
    const int kq     = w >> 1;                   // col quarter 0..3
    uint32_t qf[4][4];
    {
        int grow0 = b * kNQ + q0 + lr_g;
        int grow1 = grow0 + 8;
        if (grow0 > kMQ - 1) grow0 = kMQ - 1;
        if (grow1 > kMQ - 1) grow1 = kMQ - 1;
        const float* q0p = qkv + (size_t)grow0 * 768 + h * kDH;
        const float* q1p = qkv + (size_t)grow1 * 768 + h * kDH;
#pragma unroll
        for (int ks = 0; ks < 4; ++ks) {
            qf[ks][0] = __float_as_uint(q0p[ks * 8 + tg]);
            qf[ks][1] = __float_as_uint(q1p[ks * 8 + tg]);
            qf[ks][2] = __float_as_uint(q0p[ks * 8 + tg + 4]);
            qf[ks][3] = __float_as_uint(q1p[ks * 8 + tg + 4]);
        }
    }
#pragma unroll 1
    for (int i = 0; i < 10; ++i) {
        const int n0 = (kq * 10 + i) * 8;
        if (n0 < 304) {
            int kr = n0 + g;
            if (kr >= kNQ) kr = 0;               // masked later
            float c[4] = {0.f, 0.f, 0.f, 0.f};
#pragma unroll
            for (int ks = 0; ks < 4; ++ks) {
                uint32_t bf[2];
                bf[0] = __float_as_uint(KV[kr * kKLD2 + ks * 8 + tg]);
                bf[1] = __float_as_uint(KV[kr * kKLD2 + ks * 8 + tg + 4]);
                mma_tf32(c, qf[ks], bf);
            }
            const int col = n0 + tg * 2;
            *(float2*)&S[lr_g * kSLD + col] =
                make_float2(c[0] * scale, c[1] * scale);
            *(float2*)&S[(lr_g + 8) * kSLD + col] =
                make_float2(c[2] * scale, c[3] * scale);
        }
    }
    __syncthreads();

    // ---- Vt fill (overwrites dead Ks) + row softmax ----
    for (int idx = tid; idx < kNQ * 8; idx += 256) {
        const int r = idx >> 3, c4 = (idx & 7) * 4;
        float4 v = *(const float4*)(qkv + ((size_t)(b * kNQ + r)) * 768 + 512 +
                                    h * kDH + c4);
        KV[(c4 + 0) * kVLD2 + r] = v.x;
        KV[(c4 + 1) * kVLD2 + r] = v.y;
        KV[(c4 + 2) * kVLD2 + r] = v.z;
        KV[(c4 + 3) * kVLD2 + r] = v.w;
    }
    if (tid < kDH * 4) {                         // zero Vt keys 300..303
        const int ch = tid >> 2, k = kNQ + (tid & 3);
        KV[ch * kVLD2 + k] = 0.f;
    }

    {
        const int row  = tid >> 2;               // 0..63; only row<32 active
        const int part = tid & 3;
        if (row < kQT) {
            float* srow = &S[row * kSLD + part * 76];
            const int base_col = part * 76;
            float mx = -INFINITY;
#pragma unroll
            for (int i = 0; i < 19; ++i) {
                float4 v = *(const float4*)&srow[i * 4];
                const int c = base_col + i * 4;
                if (c + 0 < kNQ) mx = fmaxf(mx, v.x);
                if (c + 1 < kNQ) mx = fmaxf(mx, v.y);
                if (c + 2 < kNQ) mx = fmaxf(mx, v.z);
                if (c + 3 < kNQ) mx = fmaxf(mx, v.w);
            }
            mx = fmaxf(mx, __shfl_xor_sync(~0u, mx, 1));
            mx = fmaxf(mx, __shfl_xor_sync(~0u, mx, 2));
            float sum = 0.f;
#pragma unroll
            for (int i = 0; i < 19; ++i) {
                float4 v = *(const float4*)&srow[i * 4];
                const int c = base_col + i * 4;
                v.x = (c + 0 < kNQ) ? __expf(v.x - mx) : 0.f;
                v.y = (c + 1 < kNQ) ? __expf(v.y - mx) : 0.f;
                v.z = (c + 2 < kNQ) ? __expf(v.z - mx) : 0.f;
                v.w = (c + 3 < kNQ) ? __expf(v.w - mx) : 0.f;
                sum += (v.x + v.y) + (v.z + v.w);
                *(float4*)&srow[i * 4] = v;
            }
            sum += __shfl_xor_sync(~0u, sum, 1);
            sum += __shfl_xor_sync(~0u, sum, 2);
            if (part == 0) lrow[row] = 1.f / sum;
        }
    }
    __syncthreads();

    // ---- pass 2: O = P @ V ----
    const int cgrp = w >> 1;                     // col group 0..3 (8 ch each)
    const int n0 = cgrp * 8;
    float c[4] = {0.f, 0.f, 0.f, 0.f};
#pragma unroll 2
    for (int kt = 0; kt < 38; ++kt) {
        const int k = kt * 8;
        uint32_t af[4], bf[2];
        af[0] = __float_as_uint(S[lr_g * kSLD + k + tg]);
        af[1] = __float_as_uint(S[(lr_g + 8) * kSLD + k + tg]);
        af[2] = __float_as_uint(S[lr_g * kSLD + k + tg + 4]);
        af[3] = __float_as_uint(S[(lr_g + 8) * kSLD + k + tg + 4]);
        bf[0] = __float_as_uint(KV[(n0 + g) * kVLD2 + k + tg]);
        bf[1] = __float_as_uint(KV[(n0 + g) * kVLD2 + k + tg + 4]);
        mma_tf32(c, af, bf);
    }
    {
        const int qrow0 = q0 + lr_g, qrow1 = qrow0 + 8;
        const int col = n0 + tg * 2;
        if (qrow0 < kNQ) {
            const float inv = lrow[lr_g];
            *(float2*)(o + ((size_t)(b * kNQ + qrow0)) * kD + h * kDH + col) =
                make_float2(c[0] * inv, c[1] * inv);
        }
        if (qrow1 < kNQ) {
            const float inv = lrow[lr_g + 8];
            *(float2*)(o + ((size_t)(b * kNQ + qrow1)) * kD + h * kDH + col) =
                make_float2(c[2] * inv, c[3] * inv);
        }
    }
}

// ---------------------------------------------------------------------------
// MS deformable aggregation over RAW memory rows.
// ---------------------------------------------------------------------------
__global__ void msdeform_agg_kernel(const float* __restrict__ ref,
                                    const float* __restrict__ oa,
                                    const float* __restrict__ memory,
                                    float* __restrict__ agg) {
    const int bq = blockIdx.x;
    const int b = bq / kNQ;
    const int t = threadIdx.x;
    const int h = t >> 5;
    const int lane = t & 31;

    __shared__ float s_p[kNH][16];

    float lw = (lane < 16) ? oa[(size_t)bq * kOW + 256 + h * 16 + lane] : -INFINITY;
    float m = lw;
#pragma unroll
    for (int o = 8; o > 0; o >>= 1) m = fmaxf(m, __shfl_xor_sync(~0u, m, o, 16));
    float e = (lane < 16) ? expf(lw - m) : 0.f;
    float sum = e;
#pragma unroll
    for (int o = 8; o > 0; o >>= 1) sum += __shfl_xor_sync(~0u, sum, o, 16);
    if (lane < 16) s_p[h][lane] = e / sum;
    __syncwarp();

    const int cH[kNL]  = {100, 50, 25, 13};
    const int cW[kNL]  = {150, 75, 38, 19};
    const int cS0[kNL] = {0, 15000, 18750, 19700};

    float a0 = 0.f, a1 = 0.f, a2 = 0.f, a3 = 0.f;
    float a4 = 0.f, a5 = 0.f, a6 = 0.f, a7 = 0.f;
    float bsum = 0.f;

#pragma unroll
    for (int l = 0; l < kNL; ++l) {
        const float rx = ref[((size_t)bq * kNL + l) * 2 + 0];
        const float ry = ref[((size_t)bq * kNL + l) * 2 + 1];
        const int Hl = cH[l], Wl = cW[l], s0 = cS0[l];
        const float fW = (float)Wl, fH = (float)Hl;
#pragma unroll
        for (int p = 0; p < kNP; ++p) {
            const float aw = s_p[h][l * kNP + p];
            const size_t ob = (size_t)bq * kOW + (((h * kNL + l) * kNP + p) * 2);
            const float ox = oa[ob + 0];
            const float oy = oa[ob + 1];
            const float x = (rx + ox / fW) * fW - 0.5f;
            const float y = (ry + oy / fH) * fH - 0.5f;
            const float x0f = floorf(x), y0f = floorf(y);
            const float tx = x - x0f, ty = y - y0f;
            const int x0 = (int)x0f, y0 = (int)y0f;

#pragma unroll
            for (int dy = 0; dy < 2; ++dy) {
#pragma unroll
                for (int dx = 0; dx < 2; ++dx) {
                    const int xi = x0 + dx, yi = y0 + dy;
                    const bool valid = (xi >= 0) & (xi < Wl) & (yi >= 0) & (yi < Hl);
                    if (valid) {
                        const float w =
                            aw * (dy ? ty : (1.f - ty)) * (dx ? tx : (1.f - tx));
                        const float4* row = (const float4*)(
                            memory + ((size_t)b * kS + s0 + yi * Wl + xi) * kD +
                            lane * 8);
                        float4 v0 = row[0];
                        float4 v1 = row[1];
                        a0 = fmaf(w, v0.x, a0); a1 = fmaf(w, v0.y, a1);
                        a2 = fmaf(w, v0.z, a2); a3 = fmaf(w, v0.w, a3);
                        a4 = fmaf(w, v1.x, a4); a5 = fmaf(w, v1.y, a5);
                        a6 = fmaf(w, v1.z, a6); a7 = fmaf(w, v1.w, a7);
                        bsum += w;
                    }
                }
            }
        }
    }

    float4* dst = (float4*)(agg + (size_t)bq * kAK + h * 256 + lane * 8);
    dst[0] = make_float4(a0, a1, a2, a3);
    dst[1] = make_float4(a4, a5, a6, a7);
    if (lane == 0) agg[(size_t)bq * kAK + 2048 + h] = bsum;
    if (h == 0 && lane < 24) agg[(size_t)bq * kAK + 2056 + lane] = 0.f;
}

// ---------------------------------------------------------------------------
// Launch helpers
// ---------------------------------------------------------------------------
static void ensure_attrs() {
    static bool done = false;
    if (done) return;
    cudaFuncSetAttribute((const void*)gemm_tf32_kernel<3, false, 1>,
                         cudaFuncAttributeMaxDynamicSharedMemorySize,
                         gemm_smem_bytes<3>());
    cudaFuncSetAttribute((const void*)gemm_tf32_kernel<3, true, 1>,
                         cudaFuncAttributeMaxDynamicSharedMemorySize,
                         gemm_smem_bytes<3>());
    cudaFuncSetAttribute((const void*)gemm_tf32_kernel<3, false, 2>,
                         cudaFuncAttributeMaxDynamicSharedMemorySize,
                         gemm_smem_bytes<3>());
    cudaFuncSetAttribute((const void*)gemm_tf32_kernel<4, false, 2>,
                         cudaFuncAttributeMaxDynamicSharedMemorySize,
                         gemm_smem_bytes<4>());
    cudaFuncSetAttribute((const void*)attn_tc_kernel,
                         cudaFuncAttributeMaxDynamicSharedMemorySize,
                         ATTN_SMEM);
    done = true;
}

static inline void launch_gemm(const float* A, const float* W, const float* b,
                               float* C, int M, int N, int K, bool relu) {
    dim3 grid(N / 64, (M + 63) / 64);
    if (relu)
        gemm_tf32_kernel<3, true, 1><<<grid, 256, gemm_smem_bytes<3>()>>>(
            A, A, N, W, b, C, M, N, K);
    else
        gemm_tf32_kernel<3, false, 1><<<grid, 256, gemm_smem_bytes<3>()>>>(
            A, A, N, W, b, C, M, N, K);
}

extern "C" void kernel_launch(void* const* d_in, const int* in_sizes, int n_in,
                              void* d_out, int out_size) {
    const float* tgt    = (const float*)d_in[0];
    const float* pos    = (const float*)d_in[1];
    const float* ref    = (const float*)d_in[2];
    const float* memory = (const float*)d_in[3];
    const float* in_w  = (const float*)d_in[7];
    const float* in_b  = (const float*)d_in[8];
    const float* out_w = (const float*)d_in[9];
    const float* out_b = (const float*)d_in[10];
    const float* n1g = (const float*)d_in[11];
    const float* n1b = (const float*)d_in[12];
    const float* n2g = (const float*)d_in[13];
    const float* n2b = (const float*)d_in[14];
    const float* n3g = (const float*)d_in[15];
    const float* n3b = (const float*)d_in[16];
    const float* so_w = (const float*)d_in[17];
    const float* so_b = (const float*)d_in[18];
    const float* aw_w = (const float*)d_in[19];
    const float* aw_b = (const float*)d_in[20];
    const float* v_w  = (const float*)d_in[21];
    const float* v_b  = (const float*)d_in[22];
    const float* op_w = (const float*)d_in[23];
    const float* op_b = (const float*)d_in[24];
    const float* l1w  = (const float*)d_in[25];
    const float* l1b  = (const float*)d_in[26];
    const float* l2w  = (const float*)d_in[27];
    const float* l2b  = (const float*)d_in[28];

    float* scratch = nullptr;
    cudaGetSymbolAddress((void**)&scratch, g_scratch);
    ensure_attrs();

    float* s_qkadd = scratch + OFF_QKADD;
    float* s_qkv   = scratch + OFF_QKV;
    float* s_attn  = scratch + OFF_ATTN;
    float* s_sa    = scratch + OFF_SA;
    float* s_tgt1  = scratch + OFF_TGT1;
    float* s_query = scratch + OFF_QUERY;
    float* s_oa    = scratch + OFF_OA;
    float* s_t2    = scratch + OFF_T2;
    float* s_tgt2  = scratch + OFF_TGT2;
    float* s_hid   = scratch + OFF_HID;
    float* s_ffo   = scratch + OFF_FFO;
    float* s_agg   = scratch + OFF_AGG;
    float* s_wm    = scratch + OFF_WM;
    float* s_wcat  = scratch + OFF_WCAT;
    float* s_bcat  = scratch + OFF_BCAT;

    const int nQD = kMQ * kD;

    // ---- zero split-K accumulation targets (graph-capturable memsets) ----
    cudaMemsetAsync(s_t2, 0, (size_t)kMQ * kD * sizeof(float));
    cudaMemsetAsync(s_ffo, 0, (size_t)kMQ * kD * sizeof(float));

    // ---- precompute (Wm, weight concat) + qkadd ----
    {
        dim3 grid(kNH, 9);
        precompute_kernel<<<grid, 256>>>(op_w, v_w, v_b, so_w, so_b, aw_w, aw_b,
                                         s_wm, s_wcat, s_bcat);
    }
    add_kernel<<<(nQD + 255) / 256, 256>>>(tgt, pos, s_qkadd, nQD);

    // ---- self attention: merged QKV GEMM + tensor-core attention ----
    {
        dim3 grid(768 / 64, (kMQ + 63) / 64);
        gemm_tf32_kernel<3, false, 1><<<grid, 256, gemm_smem_bytes<3>()>>>(
            s_qkadd, tgt, 512, in_w, in_b, s_qkv, kMQ, 768, kD);
    }
    {
        dim3 grid((kNQ + kQT - 1) / kQT, kNH, kBS);
        attn_tc_kernel<<<grid, 256, ATTN_SMEM>>>(s_qkv, s_attn);
    }
    launch_gemm(s_attn, out_w, out_b, s_sa, kMQ, kD, kD, false);
    add_ln_kernel<true><<<kMQ, 256>>>(tgt, s_sa, n2g, n2b, s_tgt1, pos, s_query);

    // ---- MS deformable attention (merged offs+awl GEMM; value GEMM folded) ----
    launch_gemm(s_query, s_wcat, s_bcat, s_oa, kMQ, kOW, kD, false);
    msdeform_agg_kernel<<<kMQ, 256>>>(ref, s_oa, memory, s_agg);
    {
        dim3 grid(kD / 64, (kMQ + 63) / 64, 2);
        gemm_tf32_kernel<4, false, 2><<<grid, 256, gemm_smem_bytes<4>()>>>(
            s_agg, s_agg, kD, s_wm, op_b, s_t2, kMQ, kD, kAK);
    }
    add_ln_kernel<false><<<kMQ, 256>>>(s_tgt1, s_t2, n1g, n1b, s_tgt2,
                                       nullptr, nullptr);

    // ---- FFN ----
    launch_gemm(s_tgt2, l1w, l1b, s_hid, kMQ, kDFF, kD, true);
    {
        dim3 grid(kD / 64, (kMQ + 63) / 64, 2);
        gemm_tf32_kernel<3, false, 2><<<grid, 256, gemm_smem_bytes<3>()>>>(
            s_hid, s_hid, kD, l2w, l2b, s_ffo, kMQ, kD, kDFF);
    }
    add_ln_kernel<false><<<kMQ, 256>>>(s_tgt2, s_ffo, n3g, n3b, (float*)d_out,
                                       nullptr, nullptr);
}

// round 14
// speedup vs baseline: 6.2487x; 1.1671x over previous
#include <cuda_runtime.h>
#include <math.h>
#include <stdint.h>

// ---------------------------------------------------------------------------
// Problem constants
// ---------------------------------------------------------------------------
namespace {
constexpr int kD   = 256;
constexpr int kNH  = 8;
constexpr int kDH  = 32;
constexpr int kNL  = 4;
constexpr int kNP  = 4;
constexpr int kDFF = 1024;
constexpr int kBS  = 8;
constexpr int kNQ  = 300;
constexpr int kS   = 19947;
constexpr int kMQ  = kBS * kNQ;      // 2400
constexpr int kHK  = 288;            // per-head agg K: 256 + bsum + 31 pad
constexpr int kAK2 = kNH * kHK;      // 2304 agg row width
constexpr int kOW  = 384;            // merged offs(256) + awl(128) width

constexpr size_t OFF_QKADD = 0;
constexpr size_t OFF_QKV   = OFF_QKADD + (size_t)kMQ * kD;   // [2400][768]
constexpr size_t OFF_ATTN  = OFF_QKV   + (size_t)kMQ * 768;
constexpr size_t OFF_SA    = OFF_ATTN  + (size_t)kMQ * kD;
constexpr size_t OFF_TGT1  = OFF_SA    + (size_t)kMQ * kD;
constexpr size_t OFF_QUERY = OFF_TGT1  + (size_t)kMQ * kD;
constexpr size_t OFF_OA    = OFF_QUERY + (size_t)kMQ * kD;   // [2400][384]
constexpr size_t OFF_T2    = OFF_OA    + (size_t)kMQ * kOW;
constexpr size_t OFF_TGT2  = OFF_T2    + (size_t)kMQ * kD;
constexpr size_t OFF_HID   = OFF_TGT2  + (size_t)kMQ * kD;
constexpr size_t OFF_FFO   = OFF_HID   + (size_t)kMQ * kDFF;
constexpr size_t OFF_Y     = OFF_FFO   + (size_t)kMQ * kD;   // [2400][256]
constexpr size_t OFF_AGG   = OFF_Y     + (size_t)kMQ * kD;   // [2400][2304]
constexpr size_t OFF_WV2   = OFF_AGG   + (size_t)kMQ * kAK2; // [8][32][288]
constexpr size_t OFF_WCAT  = OFF_WV2   + (size_t)kNH * 32 * kHK;
constexpr size_t OFF_BCAT  = OFF_WCAT  + (size_t)kOW * kD;   // [384]
constexpr size_t SCRATCH_TOTAL = OFF_BCAT + kOW;
} // namespace

__device__ float g_scratch[SCRATCH_TOTAL];

// ---------------------------------------------------------------------------
// helpers
// ---------------------------------------------------------------------------
__device__ __forceinline__ uint32_t smem_u32(const void* p) {
    uint32_t a;
    asm("{ .reg .u64 t; cvta.to.shared.u64 t, %1; cvt.u32.u64 %0, t; }"
        : "=r"(a) : "l"(p));
    return a;
}

__device__ __forceinline__ void cp_async16(uint32_t dst, const void* src, bool pred) {
    int sz = pred ? 16 : 0;
    asm volatile("cp.async.cg.shared.global [%0], [%1], 16, %2;"
                 :: "r"(dst), "l"(src), "r"(sz));
}
__device__ __forceinline__ void cp_commit() {
    asm volatile("cp.async.commit_group;");
}
template <int N>
__device__ __forceinline__ void cp_wait() {
    asm volatile("cp.async.wait_group %0;" :: "n"(N));
}

__device__ __forceinline__ void mma_tf32(float (&d)[4],
                                         const uint32_t (&a)[4],
                                         const uint32_t (&b)[2]) {
    asm volatile(
        "mma.sync.aligned.m16n8k8.row.col.f32.tf32.tf32.f32 "
        "{%0,%1,%2,%3}, {%4,%5,%6,%7}, {%8,%9}, {%0,%1,%2,%3};"
        : "+f"(d[0]), "+f"(d[1]), "+f"(d[2]), "+f"(d[3])
        : "r"(a[0]), "r"(a[1]), "r"(a[2]), "r"(a[3]),
          "r"(b[0]), "r"(b[1]));
}

// ---------------------------------------------------------------------------
// TF32 tensor-core GEMM with per-n-region A select and optional split-K.
// ---------------------------------------------------------------------------
template <int STAGES, bool RELU, int SPLITK>
__global__ __launch_bounds__(256, 2)
void gemm_tf32_kernel(const float* __restrict__ A1,
                      const float* __restrict__ A2,
                      int n_split,
                      const float* __restrict__ W,
                      const float* __restrict__ bias,
                      float* __restrict__ C,
                      int M, int N, int K) {
    constexpr int BM = 64, BN = 64, BK = 32;
    constexpr int LD = BK + 4;                 // 36 words/row
    constexpr int THREADS = 256;
    constexpr int WM = 2;
    constexpr int MT = 2, NT = 2;
    constexpr int A_IT = (BM * BK / 4) / THREADS;   // 2
    constexpr int B_IT = (BN * BK / 4) / THREADS;   // 2

    extern __shared__ float smem[];
    float* As = smem;
    float* Ws = smem + (size_t)STAGES * BM * LD;

    const int tid  = threadIdx.x;
    const int warp = tid >> 5;
    const int lane = tid & 31;
    const int g    = lane >> 2;
    const int tg   = lane & 3;
    const int tm   = blockIdx.y * BM;
    const int tn   = blockIdx.x * BN;
    const int wm   = (warp % WM) * 32;
    const int wn   = (warp / WM) * 16;

    const float* A = (tn < n_split) ? A1 : A2;

    const int nk_all = K / BK;
    const int nk_per = (nk_all + SPLITK - 1) / SPLITK;
    const int k_lo   = (SPLITK > 1) ? blockIdx.z * nk_per : 0;
    const int k_hi   = (SPLITK > 1) ? ((k_lo + nk_per < nk_all) ? k_lo + nk_per
                                                                : nk_all)
                                    : nk_all;
    const int nk_this = k_hi - k_lo;

    float acc[MT][NT][4] = {};

    auto issue = [&](int s, int kt) {
        if (kt < nk_this) {
            const int k0 = (k_lo + kt) * BK;
#pragma unroll
            for (int i = 0; i < A_IT; ++i) {
                int idx = tid + i * THREADS;
                int r = idx >> 3, c4 = (idx & 7) * 4;
                int gr = tm + r;
                cp_async16(smem_u32(&As[(size_t)s * BM * LD + r * LD + c4]),
                           A + (size_t)gr * K + k0 + c4, gr < M);
            }
#pragma unroll
            for (int i = 0; i < B_IT; ++i) {
                int idx = tid + i * THREADS;
                int r = idx >> 3, c4 = (idx & 7) * 4;
                cp_async16(smem_u32(&Ws[(size_t)s * BN * LD + r * LD + c4]),
                           W + (size_t)(tn + r) * K + k0 + c4, true);
            }
        }
        cp_commit();
    };

    issue(0, 0);
#pragma unroll
    for (int p = 1; p < STAGES - 1; ++p) issue(p, p);

    for (int kt = 0; kt < nk_this; ++kt) {
        const int s = kt % STAGES;
        cp_wait<STAGES - 2>();
        __syncthreads();
        issue((kt + STAGES - 1) % STAGES, kt + STAGES - 1);

        const float* as = &As[(size_t)s * BM * LD];
        const float* ws = &Ws[(size_t)s * BN * LD];
#pragma unroll
        for (int ks = 0; ks < 4; ++ks) {
            const int kc = ks * 8 + tg;
            uint32_t af[MT][4], bf[NT][2];
#pragma unroll
            for (int mt = 0; mt < MT; ++mt) {
                const int r = wm + mt * 16 + g;
                af[mt][0] = __float_as_uint(as[r * LD + kc]);
                af[mt][1] = __float_as_uint(as[(r + 8) * LD + kc]);
                af[mt][2] = __float_as_uint(as[r * LD + kc + 4]);
                af[mt][3] = __float_as_uint(as[(r + 8) * LD + kc + 4]);
            }
#pragma unroll
            for (int nt = 0; nt < NT; ++nt) {
                const int n = wn + nt * 8 + g;
                bf[nt][0] = __float_as_uint(ws[n * LD + kc]);
                bf[nt][1] = __float_as_uint(ws[n * LD + kc + 4]);
            }
#pragma unroll
            for (int mt = 0; mt < MT; ++mt)
#pragma unroll
                for (int nt = 0; nt < NT; ++nt)
                    mma_tf32(acc[mt][nt], af[mt], bf[nt]);
        }
        __syncthreads();
    }

    const bool add_bias = (SPLITK == 1) || (blockIdx.z == 0);
#pragma unroll
    for (int mt = 0; mt < MT; ++mt) {
        const int gr0 = tm + wm + mt * 16 + g;
        const int gr1 = gr0 + 8;
#pragma unroll
        for (int nt = 0; nt < NT; ++nt) {
            const int gc = tn + wn + nt * 8 + tg * 2;
            const float b0 = add_bias ? bias[gc] : 0.f;
            const float b1 = add_bias ? bias[gc + 1] : 0.f;
            if (gr0 < M) {
                float v0 = acc[mt][nt][0] + b0;
                float v1 = acc[mt][nt][1] + b1;
                if (RELU) { v0 = fmaxf(v0, 0.f); v1 = fmaxf(v1, 0.f); }
                if (SPLITK == 1) {
                    *(float2*)(C + (size_t)gr0 * N + gc) = make_float2(v0, v1);
                } else {
                    atomicAdd(C + (size_t)gr0 * N + gc, v0);
                    atomicAdd(C + (size_t)gr0 * N + gc + 1, v1);
                }
            }
            if (gr1 < M) {
                float v2 = acc[mt][nt][2] + b0;
                float v3 = acc[mt][nt][3] + b1;
                if (RELU) { v2 = fmaxf(v2, 0.f); v3 = fmaxf(v3, 0.f); }
                if (SPLITK == 1) {
                    *(float2*)(C + (size_t)gr1 * N + gc) = make_float2(v2, v3);
                } else {
                    atomicAdd(C + (size_t)gr1 * N + gc, v2);
                    atomicAdd(C + (size_t)gr1 * N + gc + 1, v3);
                }
            }
        }
    }
}

template <int STAGES>
constexpr int gemm_smem_bytes() { return STAGES * 128 * 36 * 4; }

// ---------------------------------------------------------------------------
// Stage-1 batched head GEMM: y[m][h*32+j] = agg[m][h*288..] @ Wv2[h][j][.]^T
// grid = (38 m-tiles, 8 heads), BM=64, BN=32, BK=32, 8 warps (warp tile 32x8).
// A row stride kAK2 (2304), W row-major [32][288], C row stride 256.
// ---------------------------------------------------------------------------
__global__ __launch_bounds__(256, 2)
void gemm_stage1_kernel(const float* __restrict__ agg,
                        const float* __restrict__ wv2,
                        float* __restrict__ y) {
    constexpr int BM = 64, BN = 32, BK = 32, STAGES = 3;
    constexpr int LD = BK + 4;
    constexpr int THREADS = 256;
    constexpr int NK = kHK / BK;                 // 9

    extern __shared__ float smem[];
    float* As = smem;                            // STAGES * 64 * 36
    float* Ws = smem + (size_t)STAGES * BM * LD; // STAGES * 32 * 36

    const int tid  = threadIdx.x;
    const int warp = tid >> 5;
    const int lane = tid & 31;
    const int g    = lane >> 2;
    const int tg   = lane & 3;
    const int tm   = blockIdx.x * BM;
    const int h    = blockIdx.y;
    const int wm   = (warp & 1) * 32;
    const int wn   = (warp >> 1) * 8;

    const float* A = agg + (size_t)h * kHK;      // column offset in 2304 row
    const float* W = wv2 + (size_t)h * 32 * kHK;

    float acc[2][4] = {};

    auto issue = [&](int s, int kt) {
        if (kt < NK) {
            const int k0 = kt * BK;
#pragma unroll
            for (int i = 0; i < 2; ++i) {
                int idx = tid + i * THREADS;
                int r = idx >> 3, c4 = (idx & 7) * 4;
                int gr = tm + r;
                cp_async16(smem_u32(&As[(size_t)s * BM * LD + r * LD + c4]),
                           A + (size_t)gr * kAK2 + k0 + c4, gr < kMQ);
            }
            {
                int r = tid >> 3, c4 = (tid & 7) * 4;
                cp_async16(smem_u32(&Ws[(size_t)s * BN * LD + r * LD + c4]),
                           W + (size_t)r * kHK + k0 + c4, true);
            }
        }
        cp_commit();
    };

    issue(0, 0);
    issue(1, 1);

    for (int kt = 0; kt < NK; ++kt) {
        const int s = kt % STAGES;
        cp_wait<1>();
        __syncthreads();
        issue((kt + 2) % STAGES, kt + 2);

        const float* as = &As[(size_t)s * BM * LD];
        const float* ws = &Ws[(size_t)s * BN * LD];
#pragma unroll
        for (int ks = 0; ks < 4; ++ks) {
            const int kc = ks * 8 + tg;
            uint32_t af[4], bf[2];
            const int r = wm + g;
            af[0] = __float_as_uint(as[r * LD + kc]);
            af[1] = __float_as_uint(as[(r + 8) * LD + kc]);
            af[2] = __float_as_uint(as[r * LD + kc + 4]);
            af[3] = __float_as_uint(as[(r + 8) * LD + kc + 4]);
            const int n = wn + g;
            bf[0] = __float_as_uint(ws[n * LD + kc]);
            bf[1] = __float_as_uint(ws[n * LD + kc + 4]);
            mma_tf32(acc[0], af, bf);
            const int r2 = r + 16;
            af[0] = __float_as_uint(as[r2 * LD + kc]);
            af[1] = __float_as_uint(as[(r2 + 8) * LD + kc]);
            af[2] = __float_as_uint(as[r2 * LD + kc + 4]);
            af[3] = __float_as_uint(as[(r2 + 8) * LD + kc + 4]);
            mma_tf32(acc[1], af, bf);
        }
        __syncthreads();
    }

#pragma unroll
    for (int mt = 0; mt < 2; ++mt) {
        const int gr0 = tm + wm + mt * 16 + g;
        const int gr1 = gr0 + 8;
        const int gc = h * 32 + wn + tg * 2;
        if (gr0 < kMQ)
            *(float2*)(y + (size_t)gr0 * kD + gc) =
                make_float2(acc[mt][0], acc[mt][1]);
        if (gr1 < kMQ)
            *(float2*)(y + (size_t)gr1 * kD + gc) =
                make_float2(acc[mt][2], acc[mt][3]);
    }
}

constexpr int stage1_smem_bytes() { return 3 * (64 + 32) * 36 * 4; }

// ---------------------------------------------------------------------------
// Precompute kernel. grid = (8, 9), block = 256.
//  y < 8 : build Wv2[h][32][288]: v_w rows, v_b at col 256, zeros after.
//  y == 8: concat so_w/aw_w -> wcat and so_b/aw_b -> bcat.
// ---------------------------------------------------------------------------
__global__ void precompute_kernel(const float* __restrict__ v_w,
                                  const float* __restrict__ v_b,
                                  const float* __restrict__ so_w,
                                  const float* __restrict__ so_b,
                                  const float* __restrict__ aw_w,
                                  const float* __restrict__ aw_b,
                                  float* __restrict__ wv2,
                                  float* __restrict__ wcat,
                                  float* __restrict__ bcat) {
    const int tid = threadIdx.x;
    if (blockIdx.y == 8) {
        const int r0 = blockIdx.x * 48;
        for (int r = r0; r < r0 + 48; ++r) {
            const float* src = (r < 256) ? (so_w + (size_t)r * 256)
                                         : (aw_w + (size_t)(r - 256) * 256);
            wcat[(size_t)r * 256 + tid] = src[tid];
        }
        if (tid < 48) {
            int r = r0 + tid;
            bcat[r] = (r < 256) ? so_b[r] : aw_b[r - 256];
        }
        return;
    }
    if (blockIdx.x > 0) return;                  // heads handled by y index
    const int h = blockIdx.y;
    float* dst = wv2 + (size_t)h * 32 * kHK;
    for (int idx = tid; idx < 32 * kHK; idx += 256) {
        const int j = idx / kHK, c = idx % kHK;
        float v = 0.f;
        if (c < 256)      v = v_w[(size_t)(32 * h + j) * 256 + c];
        else if (c == 256) v = v_b[32 * h + j];
        dst[idx] = v;
    }
}

// ---------------------------------------------------------------------------
// Elementwise add
// ---------------------------------------------------------------------------
__global__ void add_kernel(const float* __restrict__ a,
                           const float* __restrict__ b,
                           float* __restrict__ out, int n) {
    int i = blockIdx.x * blockDim.x + threadIdx.x;
    if (i < n) out[i] = a[i] + b[i];
}

// ---------------------------------------------------------------------------
// Residual + LayerNorm (256 features, one block per row).
// ---------------------------------------------------------------------------
template <bool WITH_POS>
__global__ void add_ln_kernel(const float* __restrict__ x,
                              const float* __restrict__ r,
                              const float* __restrict__ g,
                              const float* __restrict__ bta,
                              float* __restrict__ out,
                              const float* __restrict__ pos,
                              float* __restrict__ out2) {
    const int row = blockIdx.x;
    const int t = threadIdx.x;
    const size_t base = (size_t)row * kD;
    float v = x[base + t] + r[base + t];

    __shared__ float sm[8];
    float s = v;
#pragma unroll
    for (int o = 16; o > 0; o >>= 1) s += __shfl_xor_sync(~0u, s, o);
    if ((t & 31) == 0) sm[t >> 5] = s;
    __syncthreads();
    float tot = 0.f;
#pragma unroll
    for (int i = 0; i < 8; ++i) tot += sm[i];
    const float mean = tot * (1.f / kD);
    const float d = v - mean;
    float s2 = d * d;
#pragma unroll
    for (int o = 16; o > 0; o >>= 1) s2 += __shfl_xor_sync(~0u, s2, o);
    __syncthreads();
    if ((t & 31) == 0) sm[t >> 5] = s2;
    __syncthreads();
    float tot2 = 0.f;
#pragma unroll
    for (int i = 0; i < 8; ++i) tot2 += sm[i];
    const float var = tot2 * (1.f / kD);
    const float o1 = d * rsqrtf(var + 1e-5f) * g[t] + bta[t];
    out[base + t] = o1;
    if (WITH_POS) out2[base + t] = o1 + pos[base + t];
}

// ---------------------------------------------------------------------------
// Tensor-core self attention, 32-query tile for 2 CTAs/SM.
// ---------------------------------------------------------------------------
namespace {
constexpr int kQT   = 32;
constexpr int kSLD  = 316;
constexpr int kKLD2 = 36;
constexpr int kVLD2 = 308;
constexpr int S_FLOATS  = kQT * kSLD;
constexpr int KV_FLOATS = kNQ * kKLD2;
constexpr int ATTN_SMEM = (S_FLOATS + KV_FLOATS + kQT) * 4;  // 83776 B
}

__global__ __launch_bounds__(256, 2)
void attn_tc_kernel(const float* __restrict__ qkv, float* __restrict__ o) {
    extern __shared__ float sm[];
    float* S    = sm;
    float* KV   = sm + S_FLOATS;
    float* lrow = KV + KV_FLOATS;

    const int tid  = threadIdx.x;
    const int w    = tid >> 5;
    const int lane = tid & 31;
    const int g    = lane >> 2;
    const int tg   = lane & 3;
    const int h  = blockIdx.y;
    const int b  = blockIdx.z;
    const int q0 = blockIdx.x * kQT;
    const float scale = 0.1767766952966369f;

    for (int idx = tid; idx < kNQ * 8; idx += 256) {
        const int r = idx >> 3, c4 = (idx & 7) * 4;
        *(float4*)&KV[r * kKLD2 + c4] =
            *(const float4*)(qkv + ((size_t)(b * kNQ + r)) * 768 + 256 +
                             h * kDH + c4);
    }
    __syncthreads();

    const int mstrip = w & 1;
    const int lr_g   = mstrip * 16 + g;
    const int kq     = w >> 1;
    uint32_t qf[4][4];
    {
        int grow0 = b * kNQ + q0 + lr_g;
        int grow1 = grow0 + 8;
        if (grow0 > kMQ - 1) grow0 = kMQ - 1;
        if (grow1 > kMQ - 1) grow1 = kMQ - 1;
        const float* q0p = qkv + (size_t)grow0 * 768 + h * kDH;
        const float* q1p = qkv + (size_t)grow1 * 768 + h * kDH;
#pragma unroll
        for (int ks = 0; ks < 4; ++ks) {
            qf[ks][0] = __float_as_uint(q0p[ks * 8 + tg]);
            qf[ks][1] = __float_as_uint(q1p[ks * 8 + tg]);
            qf[ks][2] = __float_as_uint(q0p[ks * 8 + tg + 4]);
            qf[ks][3] = __float_as_uint(q1p[ks * 8 + tg + 4]);
        }
    }
#pragma unroll 1
    for (int i = 0; i < 10; ++i) {
        const int n0 = (kq * 10 + i) * 8;
        if (n0 < 304) {
            int kr = n0 + g;
            if (kr >= kNQ) kr = 0;
            float c[4] = {0.f, 0.f, 0.f, 0.f};
#pragma unroll
            for (int ks = 0; ks < 4; ++ks) {
                uint32_t bf[2];
                bf[0] = __float_as_uint(KV[kr * kKLD2 + ks * 8 + tg]);
                bf[1] = __float_as_uint(KV[kr * kKLD2 + ks * 8 + tg + 4]);
                mma_tf32(c, qf[ks], bf);
            }
            const int col = n0 + tg * 2;
            *(float2*)&S[lr_g * kSLD + col] =
                make_float2(c[0] * scale, c[1] * scale);
            *(float2*)&S[(lr_g + 8) * kSLD + col] =
                make_float2(c[2] * scale, c[3] * scale);
        }
    }
    __syncthreads();

    for (int idx = tid; idx < kNQ * 8; idx += 256) {
        const int r = idx >> 3, c4 = (idx & 7) * 4;
        float4 v = *(const float4*)(qkv + ((size_t)(b * kNQ + r)) * 768 + 512 +
                                    h * kDH + c4);
        KV[(c4 + 0) * kVLD2 + r] = v.x;
        KV[(c4 + 1) * kVLD2 + r] = v.y;
        KV[(c4 + 2) * kVLD2 + r] = v.z;
        KV[(c4 + 3) * kVLD2 + r] = v.w;
    }
    if (tid < kDH * 4) {
        const int ch = tid >> 2, k = kNQ + (tid & 3);
        KV[ch * kVLD2 + k] = 0.f;
    }

    {
        const int row  = tid >> 2;
        const int part = tid & 3;
        if (row < kQT) {
            float* srow = &S[row * kSLD + part * 76];
            const int base_col = part * 76;
            float mx = -INFINITY;
#pragma unroll
            for (int i = 0; i < 19; ++i) {
                float4 v = *(const float4*)&srow[i * 4];
                const int c = base_col + i * 4;
                if (c + 0 < kNQ) mx = fmaxf(mx, v.x);
                if (c + 1 < kNQ) mx = fmaxf(mx, v.y);
                if (c + 2 < kNQ) mx = fmaxf(mx, v.z);
                if (c + 3 < kNQ) mx = fmaxf(mx, v.w);
            }
            mx = fmaxf(mx, __shfl_xor_sync(~0u, mx, 1));
            mx = fmaxf(mx, __shfl_xor_sync(~0u, mx, 2));
            float sum = 0.f;
#pragma unroll
            for (int i = 0; i < 19; ++i) {
                float4 v = *(const float4*)&srow[i * 4];
                const int c = base_col + i * 4;
                v.x = (c + 0 < kNQ) ? __expf(v.x - mx) : 0.f;
                v.y = (c + 1 < kNQ) ? __expf(v.y - mx) : 0.f;
                v.z = (c + 2 < kNQ) ? __expf(v.z - mx) : 0.f;
                v.w = (c + 3 < kNQ) ? __expf(v.w - mx) : 0.f;
                sum += (v.x + v.y) + (v.z + v.w);
                *(float4*)&srow[i * 4] = v;
            }
            sum += __shfl_xor_sync(~0u, sum, 1);
            sum += __shfl_xor_sync(~0u, sum, 2);
            if (part == 0) lrow[row] = 1.f / sum;
        }
    }
    __syncthreads();

    const int cgrp = w >> 1;
    const int n0 = cgrp * 8;
    float c[4] = {0.f, 0.f, 0.f, 0.f};
#pragma unroll 2
    for (int kt = 0; kt < 38; ++kt) {
        const int k = kt * 8;
        uint32_t af[4], bf[2];
        af[0] = __float_as_uint(S[lr_g * kSLD + k + tg]);
        af[1] = __float_as_uint(S[(lr_g + 8) * kSLD + k + tg]);
        af[2] = __float_as_uint(S[lr_g * kSLD + k + tg + 4]);
        af[3] = __float_as_uint(S[(lr_g + 8) * kSLD + k + tg + 4]);
        bf[0] = __float_as_uint(KV[(n0 + g) * kVLD2 + k + tg]);
        bf[1] = __float_as_uint(KV[(n0 + g) * kVLD2 + k + tg + 4]);
        mma_tf32(c, af, bf);
    }
    {
        const int qrow0 = q0 + lr_g, qrow1 = qrow0 + 8;
        const int col = n0 + tg * 2;
        if (qrow0 < kNQ) {
            const float inv = lrow[lr_g];
            *(float2*)(o + ((size_t)(b * kNQ + qrow0)) * kD + h * kDH + col) =
                make_float2(c[0] * inv, c[1] * inv);
        }
        if (qrow1 < kNQ) {
            const float inv = lrow[lr_g + 8];
            *(float2*)(o + ((size_t)(b * kNQ + qrow1)) * kD + h * kDH + col) =
                make_float2(c[2] * inv, c[3] * inv);
        }
    }
}

// ---------------------------------------------------------------------------
// MS deformable aggregation over RAW memory rows. agg row = 8 x [256|bsum|31z].
// ---------------------------------------------------------------------------
__global__ void msdeform_agg_kernel(const float* __restrict__ ref,
                                    const float* __restrict__ oa,
                                    const float* __restrict__ memory,
                                    float* __restrict__ agg) {
    const int bq = blockIdx.x;
    const int b = bq / kNQ;
    const int t = threadIdx.x;
    const int h = t >> 5;
    const int lane = t & 31;

    __shared__ float s_p[kNH][16];

    float lw = (lane < 16) ? oa[(size_t)bq * kOW + 256 + h * 16 + lane] : -INFINITY;
    float m = lw;
#pragma unroll
    for (int o = 8; o > 0; o >>= 1) m = fmaxf(m, __shfl_xor_sync(~0u, m, o, 16));
    float e = (lane < 16) ? expf(lw - m) : 0.f;
    float sum = e;
#pragma unroll
    for (int o = 8; o > 0; o >>= 1) sum += __shfl_xor_sync(~0u, sum, o, 16);
    if (lane < 16) s_p[h][lane] = e / sum;
    __syncwarp();

    const int cH[kNL]  = {100, 50, 25, 13};
    const int cW[kNL]  = {150, 75, 38, 19};
    const int cS0[kNL] = {0, 15000, 18750, 19700};

    float a0 = 0.f, a1 = 0.f, a2 = 0.f, a3 = 0.f;
    float a4 = 0.f, a5 = 0.f, a6 = 0.f, a7 = 0.f;
    float bsum = 0.f;

#pragma unroll
    for (int l = 0; l < kNL; ++l) {
        const float rx = ref[((size_t)bq * kNL + l) * 2 + 0];
        const float ry = ref[((size_t)bq * kNL + l) * 2 + 1];
        const int Hl = cH[l], Wl = cW[l], s0 = cS0[l];
        const float fW = (float)Wl, fH = (float)Hl;
#pragma unroll
        for (int p = 0; p < kNP; ++p) {
            const float aw = s_p[h][l * kNP + p];
            const size_t ob = (size_t)bq * kOW + (((h * kNL + l) * kNP + p) * 2);
            const float ox = oa[ob + 0];
            const float oy = oa[ob + 1];
            const float x = (rx + ox / fW) * fW - 0.5f;
            const float y = (ry + oy / fH) * fH - 0.5f;
            const float x0f = floorf(x), y0f = floorf(y);
            const float tx = x - x0f, ty = y - y0f;
            const int x0 = (int)x0f, y0 = (int)y0f;

#pragma unroll
            for (int dy = 0; dy < 2; ++dy) {
#pragma unroll
                for (int dx = 0; dx < 2; ++dx) {
                    const int xi = x0 + dx, yi = y0 + dy;
                    const bool valid = (xi >= 0) & (xi < Wl) & (yi >= 0) & (yi < Hl);
                    if (valid) {
                        const float w =
                            aw * (dy ? ty : (1.f - ty)) * (dx ? tx : (1.f - tx));
                        const float4* row = (const float4*)(
                            memory + ((size_t)b * kS + s0 + yi * Wl + xi) * kD +
                            lane * 8);
                        float4 v0 = row[0];
                        float4 v1 = row[1];
                        a0 = fmaf(w, v0.x, a0); a1 = fmaf(w, v0.y, a1);
                        a2 = fmaf(w, v0.z, a2); a3 = fmaf(w, v0.w, a3);
                        a4 = fmaf(w, v1.x, a4); a5 = fmaf(w, v1.y, a5);
                        a6 = fmaf(w, v1.z, a6); a7 = fmaf(w, v1.w, a7);
                        bsum += w;
                    }
                }
            }
        }
    }

    float* hb = agg + (size_t)bq * kAK2 + h * kHK;
    float4* dst = (float4*)(hb + lane * 8);
    dst[0] = make_float4(a0, a1, a2, a3);
    dst[1] = make_float4(a4, a5, a6, a7);
    if (lane == 0) hb[256] = bsum;
    else hb[256 + lane] = 0.f;                   // zero pad cols 257..287
}

// ---------------------------------------------------------------------------
// Launch helpers
// ---------------------------------------------------------------------------
static void ensure_attrs() {
    static bool done = false;
    if (done) return;
    cudaFuncSetAttribute((const void*)gemm_tf32_kernel<3, false, 1>,
                         cudaFuncAttributeMaxDynamicSharedMemorySize,
                         gemm_smem_bytes<3>());
    cudaFuncSetAttribute((const void*)gemm_tf32_kernel<3, true, 1>,
                         cudaFuncAttributeMaxDynamicSharedMemorySize,
                         gemm_smem_bytes<3>());
    cudaFuncSetAttribute((const void*)gemm_tf32_kernel<3, false, 2>,
                         cudaFuncAttributeMaxDynamicSharedMemorySize,
                         gemm_smem_bytes<3>());
    cudaFuncSetAttribute((const void*)attn_tc_kernel,
                         cudaFuncAttributeMaxDynamicSharedMemorySize,
                         ATTN_SMEM);
    done = true;
}

static inline void launch_gemm(const float* A, const float* W, const float* b,
                               float* C, int M, int N, int K, bool relu) {
    dim3 grid(N / 64, (M + 63) / 64);
    if (relu)
        gemm_tf32_kernel<3, true, 1><<<grid, 256, gemm_smem_bytes<3>()>>>(
            A, A, N, W, b, C, M, N, K);
    else
        gemm_tf32_kernel<3, false, 1><<<grid, 256, gemm_smem_bytes<3>()>>>(
            A, A, N, W, b, C, M, N, K);
}

extern "C" void kernel_launch(void* const* d_in, const int* in_sizes, int n_in,
                              void* d_out, int out_size) {
    const float* tgt    = (const float*)d_in[0];
    const float* pos    = (const float*)d_in[1];
    const float* ref    = (const float*)d_in[2];
    const float* memory = (const float*)d_in[3];
    const float* in_w  = (const float*)d_in[7];
    const float* in_b  = (const float*)d_in[8];
    const float* out_w = (const float*)d_in[9];
    const float* out_b = (const float*)d_in[10];
    const float* n1g = (const float*)d_in[11];
    const float* n1b = (const float*)d_in[12];
    const float* n2g = (const float*)d_in[13];
    const float* n2b = (const float*)d_in[14];
    const float* n3g = (const float*)d_in[15];
    const float* n3b = (const float*)d_in[16];
    const float* so_w = (const float*)d_in[17];
    const float* so_b = (const float*)d_in[18];
    const float* aw_w = (const float*)d_in[19];
    const float* aw_b = (const float*)d_in[20];
    const float* v_w  = (const float*)d_in[21];
    const float* v_b  = (const float*)d_in[22];
    const float* op_w = (const float*)d_in[23];
    const float* op_b = (const float*)d_in[24];
    const float* l1w  = (const float*)d_in[25];
    const float* l1b  = (const float*)d_in[26];
    const float* l2w  = (const float*)d_in[27];
    const float* l2b  = (const float*)d_in[28];

    float* scratch = nullptr;
    cudaGetSymbolAddress((void**)&scratch, g_scratch);
    ensure_attrs();

    float* s_qkadd = scratch + OFF_QKADD;
    float* s_qkv   = scratch + OFF_QKV;
    float* s_attn  = scratch + OFF_ATTN;
    float* s_sa    = scratch + OFF_SA;
    float* s_tgt1  = scratch + OFF_TGT1;
    float* s_query = scratch + OFF_QUERY;
    float* s_oa    = scratch + OFF_OA;
    float* s_t2    = scratch + OFF_T2;
    float* s_tgt2  = scratch + OFF_TGT2;
    float* s_hid   = scratch + OFF_HID;
    float* s_ffo   = scratch + OFF_FFO;
    float* s_y     = scratch + OFF_Y;
    float* s_agg   = scratch + OFF_AGG;
    float* s_wv2   = scratch + OFF_WV2;
    float* s_wcat  = scratch + OFF_WCAT;
    float* s_bcat  = scratch + OFF_BCAT;

    const int nQD = kMQ * kD;

    // ---- zero split-K accumulation target (FFN2) ----
    cudaMemsetAsync(s_ffo, 0, (size_t)kMQ * kD * sizeof(float));

    // ---- precompute (Wv2, weight concat) + qkadd ----
    {
        dim3 grid(kNH, 9);
        precompute_kernel<<<grid, 256>>>(v_w, v_b, so_w, so_b, aw_w, aw_b,
                                         s_wv2, s_wcat, s_bcat);
    }
    add_kernel<<<(nQD + 255) / 256, 256>>>(tgt, pos, s_qkadd, nQD);

    // ---- self attention: merged QKV GEMM + tensor-core attention ----
    {
        dim3 grid(768 / 64, (kMQ + 63) / 64);
        gemm_tf32_kernel<3, false, 1><<<grid, 256, gemm_smem_bytes<3>()>>>(
            s_qkadd, tgt, 512, in_w, in_b, s_qkv, kMQ, 768, kD);
    }
    {
        dim3 grid((kNQ + kQT - 1) / kQT, kNH, kBS);
        attn_tc_kernel<<<grid, 256, ATTN_SMEM>>>(s_qkv, s_attn);
    }
    launch_gemm(s_attn, out_w, out_b, s_sa, kMQ, kD, kD, false);
    add_ln_kernel<true><<<kMQ, 256>>>(tgt, s_sa, n2g, n2b, s_tgt1, pos, s_query);

    // ---- MS deformable attention (factored rank-32 projection) ----
    launch_gemm(s_query, s_wcat, s_bcat, s_oa, kMQ, kOW, kD, false);
    msdeform_agg_kernel<<<kMQ, 256>>>(ref, s_oa, memory, s_agg);
    {
        dim3 grid((kMQ + 63) / 64, kNH);
        gemm_stage1_kernel<<<grid, 256, stage1_smem_bytes()>>>(s_agg, s_wv2, s_y);
    }
    launch_gemm(s_y, op_w, op_b, s_t2, kMQ, kD, kD, false);
    add_ln_kernel<false><<<kMQ, 256>>>(s_tgt1, s_t2, n1g, n1b, s_tgt2,
                                       nullptr, nullptr);

    // ---- FFN ----
    launch_gemm(s_tgt2, l1w, l1b, s_hid, kMQ, kDFF, kD, true);
    {
        dim3 grid(kD / 64, (kMQ + 63) / 64, 2);
        gemm_tf32_kernel<3, false, 2><<<grid, 256, gemm_smem_bytes<3>()>>>(
            s_hid, s_hid, kD, l2w, l2b, s_ffo, kMQ, kD, kDFF);
    }
    add_ln_kernel<false><<<kMQ, 256>>>(s_tgt2, s_ffo, n3g, n3b, (float*)d_out,
                                       nullptr, nullptr);
}

// round 15
// speedup vs baseline: 6.3450x; 1.0154x over previous
#include <cuda_runtime.h>
#include <math.h>
#include <stdint.h>

// ---------------------------------------------------------------------------
// Problem constants
// ---------------------------------------------------------------------------
namespace {
constexpr int kD   = 256;
constexpr int kNH  = 8;
constexpr int kDH  = 32;
constexpr int kNL  = 4;
constexpr int kNP  = 4;
constexpr int kDFF = 1024;
constexpr int kBS  = 8;
constexpr int kNQ  = 300;
constexpr int kS   = 19947;
constexpr int kMQ  = kBS * kNQ;      // 2400
constexpr int kHK  = 288;            // per-head agg K: 256 + bsum + 31 pad
constexpr int kAK2 = kNH * kHK;      // 2304 agg row width
constexpr int kOW  = 384;            // merged offs(256) + awl(128) width

constexpr size_t OFF_QKADD = 0;
constexpr size_t OFF_QKV   = OFF_QKADD + (size_t)kMQ * kD;   // [2400][768]
constexpr size_t OFF_ATTN  = OFF_QKV   + (size_t)kMQ * 768;
constexpr size_t OFF_SA    = OFF_ATTN  + (size_t)kMQ * kD;
constexpr size_t OFF_TGT1  = OFF_SA    + (size_t)kMQ * kD;
constexpr size_t OFF_QUERY = OFF_TGT1  + (size_t)kMQ * kD;
constexpr size_t OFF_OA    = OFF_QUERY + (size_t)kMQ * kD;   // [2400][384]
constexpr size_t OFF_T2    = OFF_OA    + (size_t)kMQ * kOW;
constexpr size_t OFF_TGT2  = OFF_T2    + (size_t)kMQ * kD;
constexpr size_t OFF_HID   = OFF_TGT2  + (size_t)kMQ * kD;
constexpr size_t OFF_FFO   = OFF_HID   + (size_t)kMQ * kDFF;
constexpr size_t OFF_Y     = OFF_FFO   + (size_t)kMQ * kD;   // [2400][256]
constexpr size_t OFF_AGG   = OFF_Y     + (size_t)kMQ * kD;   // [2400][2304]
constexpr size_t OFF_WV2   = OFF_AGG   + (size_t)kMQ * kAK2; // [8][32][288]
constexpr size_t OFF_WCAT  = OFF_WV2   + (size_t)kNH * 32 * kHK;
constexpr size_t OFF_BCAT  = OFF_WCAT  + (size_t)kOW * kD;   // [384]
constexpr size_t SCRATCH_TOTAL = OFF_BCAT + kOW;
} // namespace

__device__ float g_scratch[SCRATCH_TOTAL];

// ---------------------------------------------------------------------------
// helpers
// ---------------------------------------------------------------------------
__device__ __forceinline__ uint32_t smem_u32(const void* p) {
    uint32_t a;
    asm("{ .reg .u64 t; cvta.to.shared.u64 t, %1; cvt.u32.u64 %0, t; }"
        : "=r"(a) : "l"(p));
    return a;
}

__device__ __forceinline__ void cp_async16(uint32_t dst, const void* src, bool pred) {
    int sz = pred ? 16 : 0;
    asm volatile("cp.async.cg.shared.global [%0], [%1], 16, %2;"
                 :: "r"(dst), "l"(src), "r"(sz));
}
__device__ __forceinline__ void cp_commit() {
    asm volatile("cp.async.commit_group;");
}
template <int N>
__device__ __forceinline__ void cp_wait() {
    asm volatile("cp.async.wait_group %0;" :: "n"(N));
}

__device__ __forceinline__ void mma_tf32(float (&d)[4],
                                         const uint32_t (&a)[4],
                                         const uint32_t (&b)[2]) {
    asm volatile(
        "mma.sync.aligned.m16n8k8.row.col.f32.tf32.tf32.f32 "
        "{%0,%1,%2,%3}, {%4,%5,%6,%7}, {%8,%9}, {%0,%1,%2,%3};"
        : "+f"(d[0]), "+f"(d[1]), "+f"(d[2]), "+f"(d[3])
        : "r"(a[0]), "r"(a[1]), "r"(a[2]), "r"(a[3]),
          "r"(b[0]), "r"(b[1]));
}

// ---------------------------------------------------------------------------
// TF32 tensor-core GEMM with per-n-region A select and optional split-K.
// ---------------------------------------------------------------------------
template <int STAGES, bool RELU, int SPLITK>
__global__ __launch_bounds__(256, 2)
void gemm_tf32_kernel(const float* __restrict__ A1,
                      const float* __restrict__ A2,
                      int n_split,
                      const float* __restrict__ W,
                      const float* __restrict__ bias,
                      float* __restrict__ C,
                      int M, int N, int K) {
    constexpr int BM = 64, BN = 64, BK = 32;
    constexpr int LD = BK + 4;                 // 36 words/row
    constexpr int THREADS = 256;
    constexpr int WM = 2;
    constexpr int MT = 2, NT = 2;
    constexpr int A_IT = (BM * BK / 4) / THREADS;   // 2
    constexpr int B_IT = (BN * BK / 4) / THREADS;   // 2

    extern __shared__ float smem[];
    float* As = smem;
    float* Ws = smem + (size_t)STAGES * BM * LD;

    const int tid  = threadIdx.x;
    const int warp = tid >> 5;
    const int lane = tid & 31;
    const int g    = lane >> 2;
    const int tg   = lane & 3;
    const int tm   = blockIdx.y * BM;
    const int tn   = blockIdx.x * BN;
    const int wm   = (warp % WM) * 32;
    const int wn   = (warp / WM) * 16;

    const float* A = (tn < n_split) ? A1 : A2;

    const int nk_all = K / BK;
    const int nk_per = (nk_all + SPLITK - 1) / SPLITK;
    const int k_lo   = (SPLITK > 1) ? blockIdx.z * nk_per : 0;
    const int k_hi   = (SPLITK > 1) ? ((k_lo + nk_per < nk_all) ? k_lo + nk_per
                                                                : nk_all)
                                    : nk_all;
    const int nk_this = k_hi - k_lo;

    float acc[MT][NT][4] = {};

    auto issue = [&](int s, int kt) {
        if (kt < nk_this) {
            const int k0 = (k_lo + kt) * BK;
#pragma unroll
            for (int i = 0; i < A_IT; ++i) {
                int idx = tid + i * THREADS;
                int r = idx >> 3, c4 = (idx & 7) * 4;
                int gr = tm + r;
                cp_async16(smem_u32(&As[(size_t)s * BM * LD + r * LD + c4]),
                           A + (size_t)gr * K + k0 + c4, gr < M);
            }
#pragma unroll
            for (int i = 0; i < B_IT; ++i) {
                int idx = tid + i * THREADS;
                int r = idx >> 3, c4 = (idx & 7) * 4;
                cp_async16(smem_u32(&Ws[(size_t)s * BN * LD + r * LD + c4]),
                           W + (size_t)(tn + r) * K + k0 + c4, true);
            }
        }
        cp_commit();
    };

    issue(0, 0);
#pragma unroll
    for (int p = 1; p < STAGES - 1; ++p) issue(p, p);

    for (int kt = 0; kt < nk_this; ++kt) {
        const int s = kt % STAGES;
        cp_wait<STAGES - 2>();
        __syncthreads();
        issue((kt + STAGES - 1) % STAGES, kt + STAGES - 1);

        const float* as = &As[(size_t)s * BM * LD];
        const float* ws = &Ws[(size_t)s * BN * LD];
#pragma unroll
        for (int ks = 0; ks < 4; ++ks) {
            const int kc = ks * 8 + tg;
            uint32_t af[MT][4], bf[NT][2];
#pragma unroll
            for (int mt = 0; mt < MT; ++mt) {
                const int r = wm + mt * 16 + g;
                af[mt][0] = __float_as_uint(as[r * LD + kc]);
                af[mt][1] = __float_as_uint(as[(r + 8) * LD + kc]);
                af[mt][2] = __float_as_uint(as[r * LD + kc + 4]);
                af[mt][3] = __float_as_uint(as[(r + 8) * LD + kc + 4]);
            }
#pragma unroll
            for (int nt = 0; nt < NT; ++nt) {
                const int n = wn + nt * 8 + g;
                bf[nt][0] = __float_as_uint(ws[n * LD + kc]);
                bf[nt][1] = __float_as_uint(ws[n * LD + kc + 4]);
            }
#pragma unroll
            for (int mt = 0; mt < MT; ++mt)
#pragma unroll
                for (int nt = 0; nt < NT; ++nt)
                    mma_tf32(acc[mt][nt], af[mt], bf[nt]);
        }
        __syncthreads();
    }

    const bool add_bias = (SPLITK == 1) || (blockIdx.z == 0);
#pragma unroll
    for (int mt = 0; mt < MT; ++mt) {
        const int gr0 = tm + wm + mt * 16 + g;
        const int gr1 = gr0 + 8;
#pragma unroll
        for (int nt = 0; nt < NT; ++nt) {
            const int gc = tn + wn + nt * 8 + tg * 2;
            const float b0 = add_bias ? bias[gc] : 0.f;
            const float b1 = add_bias ? bias[gc + 1] : 0.f;
            if (gr0 < M) {
                float v0 = acc[mt][nt][0] + b0;
                float v1 = acc[mt][nt][1] + b1;
                if (RELU) { v0 = fmaxf(v0, 0.f); v1 = fmaxf(v1, 0.f); }
                if (SPLITK == 1) {
                    *(float2*)(C + (size_t)gr0 * N + gc) = make_float2(v0, v1);
                } else {
                    atomicAdd(C + (size_t)gr0 * N + gc, v0);
                    atomicAdd(C + (size_t)gr0 * N + gc + 1, v1);
                }
            }
            if (gr1 < M) {
                float v2 = acc[mt][nt][2] + b0;
                float v3 = acc[mt][nt][3] + b1;
                if (RELU) { v2 = fmaxf(v2, 0.f); v3 = fmaxf(v3, 0.f); }
                if (SPLITK == 1) {
                    *(float2*)(C + (size_t)gr1 * N + gc) = make_float2(v2, v3);
                } else {
                    atomicAdd(C + (size_t)gr1 * N + gc, v2);
                    atomicAdd(C + (size_t)gr1 * N + gc + 1, v3);
                }
            }
        }
    }
}

template <int STAGES>
constexpr int gemm_smem_bytes() { return STAGES * 128 * 36 * 4; }

// ---------------------------------------------------------------------------
// Stage-1 batched head GEMM: y[m][h*32+j] = agg[m][h*288..] @ Wv2[h][j][.]^T
// ---------------------------------------------------------------------------
__global__ __launch_bounds__(256, 2)
void gemm_stage1_kernel(const float* __restrict__ agg,
                        const float* __restrict__ wv2,
                        float* __restrict__ y) {
    constexpr int BM = 64, BN = 32, BK = 32, STAGES = 3;
    constexpr int LD = BK + 4;
    constexpr int THREADS = 256;
    constexpr int NK = kHK / BK;                 // 9

    extern __shared__ float smem[];
    float* As = smem;
    float* Ws = smem + (size_t)STAGES * BM * LD;

    const int tid  = threadIdx.x;
    const int warp = tid >> 5;
    const int lane = tid & 31;
    const int g    = lane >> 2;
    const int tg   = lane & 3;
    const int tm   = blockIdx.x * BM;
    const int h    = blockIdx.y;
    const int wm   = (warp & 1) * 32;
    const int wn   = (warp >> 1) * 8;

    const float* A = agg + (size_t)h * kHK;
    const float* W = wv2 + (size_t)h * 32 * kHK;

    float acc[2][4] = {};

    auto issue = [&](int s, int kt) {
        if (kt < NK) {
            const int k0 = kt * BK;
#pragma unroll
            for (int i = 0; i < 2; ++i) {
                int idx = tid + i * THREADS;
                int r = idx >> 3, c4 = (idx & 7) * 4;
                int gr = tm + r;
                cp_async16(smem_u32(&As[(size_t)s * BM * LD + r * LD + c4]),
                           A + (size_t)gr * kAK2 + k0 + c4, gr < kMQ);
            }
            {
                int r = tid >> 3, c4 = (tid & 7) * 4;
                cp_async16(smem_u32(&Ws[(size_t)s * BN * LD + r * LD + c4]),
                           W + (size_t)r * kHK + k0 + c4, true);
            }
        }
        cp_commit();
    };

    issue(0, 0);
    issue(1, 1);

    for (int kt = 0; kt < NK; ++kt) {
        const int s = kt % STAGES;
        cp_wait<1>();
        __syncthreads();
        issue((kt + 2) % STAGES, kt + 2);

        const float* as = &As[(size_t)s * BM * LD];
        const float* ws = &Ws[(size_t)s * BN * LD];
#pragma unroll
        for (int ks = 0; ks < 4; ++ks) {
            const int kc = ks * 8 + tg;
            uint32_t af[4], bf[2];
            const int r = wm + g;
            af[0] = __float_as_uint(as[r * LD + kc]);
            af[1] = __float_as_uint(as[(r + 8) * LD + kc]);
            af[2] = __float_as_uint(as[r * LD + kc + 4]);
            af[3] = __float_as_uint(as[(r + 8) * LD + kc + 4]);
            const int n = wn + g;
            bf[0] = __float_as_uint(ws[n * LD + kc]);
            bf[1] = __float_as_uint(ws[n * LD + kc + 4]);
            mma_tf32(acc[0], af, bf);
            const int r2 = r + 16;
            af[0] = __float_as_uint(as[r2 * LD + kc]);
            af[1] = __float_as_uint(as[(r2 + 8) * LD + kc]);
            af[2] = __float_as_uint(as[r2 * LD + kc + 4]);
            af[3] = __float_as_uint(as[(r2 + 8) * LD + kc + 4]);
            mma_tf32(acc[1], af, bf);
        }
        __syncthreads();
    }

#pragma unroll
    for (int mt = 0; mt < 2; ++mt) {
        const int gr0 = tm + wm + mt * 16 + g;
        const int gr1 = gr0 + 8;
        const int gc = h * 32 + wn + tg * 2;
        if (gr0 < kMQ)
            *(float2*)(y + (size_t)gr0 * kD + gc) =
                make_float2(acc[mt][0], acc[mt][1]);
        if (gr1 < kMQ)
            *(float2*)(y + (size_t)gr1 * kD + gc) =
                make_float2(acc[mt][2], acc[mt][3]);
    }
}

constexpr int stage1_smem_bytes() { return 3 * (64 + 32) * 36 * 4; }

// ---------------------------------------------------------------------------
// Precompute kernel. grid = (8, 9), block = 256.
// ---------------------------------------------------------------------------
__global__ void precompute_kernel(const float* __restrict__ v_w,
                                  const float* __restrict__ v_b,
                                  const float* __restrict__ so_w,
                                  const float* __restrict__ so_b,
                                  const float* __restrict__ aw_w,
                                  const float* __restrict__ aw_b,
                                  float* __restrict__ wv2,
                                  float* __restrict__ wcat,
                                  float* __restrict__ bcat) {
    const int tid = threadIdx.x;
    if (blockIdx.y == 8) {
        const int r0 = blockIdx.x * 48;
        for (int r = r0; r < r0 + 48; ++r) {
            const float* src = (r < 256) ? (so_w + (size_t)r * 256)
                                         : (aw_w + (size_t)(r - 256) * 256);
            wcat[(size_t)r * 256 + tid] = src[tid];
        }
        if (tid < 48) {
            int r = r0 + tid;
            bcat[r] = (r < 256) ? so_b[r] : aw_b[r - 256];
        }
        return;
    }
    if (blockIdx.x > 0) return;
    const int h = blockIdx.y;
    float* dst = wv2 + (size_t)h * 32 * kHK;
    for (int idx = tid; idx < 32 * kHK; idx += 256) {
        const int j = idx / kHK, c = idx % kHK;
        float v = 0.f;
        if (c < 256)      v = v_w[(size_t)(32 * h + j) * 256 + c];
        else if (c == 256) v = v_b[32 * h + j];
        dst[idx] = v;
    }
}

// ---------------------------------------------------------------------------
// Elementwise add
// ---------------------------------------------------------------------------
__global__ void add_kernel(const float* __restrict__ a,
                           const float* __restrict__ b,
                           float* __restrict__ out, int n) {
    int i = blockIdx.x * blockDim.x + threadIdx.x;
    if (i < n) out[i] = a[i] + b[i];
}

// ---------------------------------------------------------------------------
// Residual + LayerNorm (256 features, one block per row).
// ---------------------------------------------------------------------------
template <bool WITH_POS>
__global__ void add_ln_kernel(const float* __restrict__ x,
                              const float* __restrict__ r,
                              const float* __restrict__ g,
                              const float* __restrict__ bta,
                              float* __restrict__ out,
                              const float* __restrict__ pos,
                              float* __restrict__ out2) {
    const int row = blockIdx.x;
    const int t = threadIdx.x;
    const size_t base = (size_t)row * kD;
    float v = x[base + t] + r[base + t];

    __shared__ float sm[8];
    float s = v;
#pragma unroll
    for (int o = 16; o > 0; o >>= 1) s += __shfl_xor_sync(~0u, s, o);
    if ((t & 31) == 0) sm[t >> 5] = s;
    __syncthreads();
    float tot = 0.f;
#pragma unroll
    for (int i = 0; i < 8; ++i) tot += sm[i];
    const float mean = tot * (1.f / kD);
    const float d = v - mean;
    float s2 = d * d;
#pragma unroll
    for (int o = 16; o > 0; o >>= 1) s2 += __shfl_xor_sync(~0u, s2, o);
    __syncthreads();
    if ((t & 31) == 0) sm[t >> 5] = s2;
    __syncthreads();
    float tot2 = 0.f;
#pragma unroll
    for (int i = 0; i < 8; ++i) tot2 += sm[i];
    const float var = tot2 * (1.f / kD);
    const float o1 = d * rsqrtf(var + 1e-5f) * g[t] + bta[t];
    out[base + t] = o1;
    if (WITH_POS) out2[base + t] = o1 + pos[base + t];
}

// ---------------------------------------------------------------------------
// Tensor-core self attention, 32-query tile, software-pipelined fragments.
// ---------------------------------------------------------------------------
namespace {
constexpr int kQT   = 32;
constexpr int kSLD  = 316;
constexpr int kKLD2 = 36;
constexpr int kVLD2 = 308;
constexpr int S_FLOATS  = kQT * kSLD;
constexpr int KV_FLOATS = kNQ * kKLD2;
constexpr int ATTN_SMEM = (S_FLOATS + KV_FLOATS + kQT) * 4;  // 83776 B
}

__global__ __launch_bounds__(256, 2)
void attn_tc_kernel(const float* __restrict__ qkv, float* __restrict__ o) {
    extern __shared__ float sm[];
    float* S    = sm;
    float* KV   = sm + S_FLOATS;
    float* lrow = KV + KV_FLOATS;

    const int tid  = threadIdx.x;
    const int w    = tid >> 5;
    const int lane = tid & 31;
    const int g    = lane >> 2;
    const int tg   = lane & 3;
    const int h  = blockIdx.y;
    const int b  = blockIdx.z;
    const int q0 = blockIdx.x * kQT;
    const float scale = 0.1767766952966369f;

    for (int idx = tid; idx < kNQ * 8; idx += 256) {
        const int r = idx >> 3, c4 = (idx & 7) * 4;
        *(float4*)&KV[r * kKLD2 + c4] =
            *(const float4*)(qkv + ((size_t)(b * kNQ + r)) * 768 + 256 +
                             h * kDH + c4);
    }
    __syncthreads();

    const int mstrip = w & 1;
    const int lr_g   = mstrip * 16 + g;
    const int kq     = w >> 1;
    uint32_t qf[4][4];
    {
        int grow0 = b * kNQ + q0 + lr_g;
        int grow1 = grow0 + 8;
        if (grow0 > kMQ - 1) grow0 = kMQ - 1;
        if (grow1 > kMQ - 1) grow1 = kMQ - 1;
        const float* q0p = qkv + (size_t)grow0 * 768 + h * kDH;
        const float* q1p = qkv + (size_t)grow1 * 768 + h * kDH;
#pragma unroll
        for (int ks = 0; ks < 4; ++ks) {
            qf[ks][0] = __float_as_uint(q0p[ks * 8 + tg]);
            qf[ks][1] = __float_as_uint(q1p[ks * 8 + tg]);
            qf[ks][2] = __float_as_uint(q0p[ks * 8 + tg + 4]);
            qf[ks][3] = __float_as_uint(q1p[ks * 8 + tg + 4]);
        }
    }
#pragma unroll 2
    for (int i = 0; i < 10; ++i) {
        const int n0 = (kq * 10 + i) * 8;
        if (n0 < 304) {
            int kr = n0 + g;
            if (kr >= kNQ) kr = 0;
            float c[4] = {0.f, 0.f, 0.f, 0.f};
            // preload all 4 k-slices of B fragments, then MMA (breaks chains)
            uint32_t bf[4][2];
#pragma unroll
            for (int ks = 0; ks < 4; ++ks) {
                bf[ks][0] = __float_as_uint(KV[kr * kKLD2 + ks * 8 + tg]);
                bf[ks][1] = __float_as_uint(KV[kr * kKLD2 + ks * 8 + tg + 4]);
            }
#pragma unroll
            for (int ks = 0; ks < 4; ++ks)
                mma_tf32(c, qf[ks], bf[ks]);
            const int col = n0 + tg * 2;
            *(float2*)&S[lr_g * kSLD + col] =
                make_float2(c[0] * scale, c[1] * scale);
            *(float2*)&S[(lr_g + 8) * kSLD + col] =
                make_float2(c[2] * scale, c[3] * scale);
        }
    }
    __syncthreads();

    for (int idx = tid; idx < kNQ * 8; idx += 256) {
        const int r = idx >> 3, c4 = (idx & 7) * 4;
        float4 v = *(const float4*)(qkv + ((size_t)(b * kNQ + r)) * 768 + 512 +
                                    h * kDH + c4);
        KV[(c4 + 0) * kVLD2 + r] = v.x;
        KV[(c4 + 1) * kVLD2 + r] = v.y;
        KV[(c4 + 2) * kVLD2 + r] = v.z;
        KV[(c4 + 3) * kVLD2 + r] = v.w;
    }
    if (tid < kDH * 4) {
        const int ch = tid >> 2, k = kNQ + (tid & 3);
        KV[ch * kVLD2 + k] = 0.f;
    }

    {
        const int row  = tid >> 2;
        const int part = tid & 3;
        if (row < kQT) {
            float* srow = &S[row * kSLD + part * 76];
            const int base_col = part * 76;
            float mx = -INFINITY;
#pragma unroll
            for (int i = 0; i < 19; ++i) {
                float4 v = *(const float4*)&srow[i * 4];
                const int c = base_col + i * 4;
                if (c + 0 < kNQ) mx = fmaxf(mx, v.x);
                if (c + 1 < kNQ) mx = fmaxf(mx, v.y);
                if (c + 2 < kNQ) mx = fmaxf(mx, v.z);
                if (c + 3 < kNQ) mx = fmaxf(mx, v.w);
            }
            mx = fmaxf(mx, __shfl_xor_sync(~0u, mx, 1));
            mx = fmaxf(mx, __shfl_xor_sync(~0u, mx, 2));
            float sum = 0.f;
#pragma unroll
            for (int i = 0; i < 19; ++i) {
                float4 v = *(const float4*)&srow[i * 4];
                const int c = base_col + i * 4;
                v.x = (c + 0 < kNQ) ? __expf(v.x - mx) : 0.f;
                v.y = (c + 1 < kNQ) ? __expf(v.y - mx) : 0.f;
                v.z = (c + 2 < kNQ) ? __expf(v.z - mx) : 0.f;
                v.w = (c + 3 < kNQ) ? __expf(v.w - mx) : 0.f;
                sum += (v.x + v.y) + (v.z + v.w);
                *(float4*)&srow[i * 4] = v;
            }
            sum += __shfl_xor_sync(~0u, sum, 1);
            sum += __shfl_xor_sync(~0u, sum, 2);
            if (part == 0) lrow[row] = 1.f / sum;
        }
    }
    __syncthreads();

    // ---- pass 2: O = P @ V, software-pipelined double-buffered fragments ----
    const int cgrp = w >> 1;
    const int n0 = cgrp * 8;
    float c[4] = {0.f, 0.f, 0.f, 0.f};
    {
        const float* Srow0 = &S[lr_g * kSLD];
        const float* Srow1 = &S[(lr_g + 8) * kSLD];
        const float* Vrow  = &KV[(n0 + g) * kVLD2];
        uint32_t afb[2][4], bfb[2][2];
        // prologue: load kt = 0
        afb[0][0] = __float_as_uint(Srow0[tg]);
        afb[0][1] = __float_as_uint(Srow1[tg]);
        afb[0][2] = __float_as_uint(Srow0[tg + 4]);
        afb[0][3] = __float_as_uint(Srow1[tg + 4]);
        bfb[0][0] = __float_as_uint(Vrow[tg]);
        bfb[0][1] = __float_as_uint(Vrow[tg + 4]);
#pragma unroll
        for (int kt = 0; kt < 38; ++kt) {
            const int cur = kt & 1, nxt = cur ^ 1;
            if (kt < 37) {
                const int k = (kt + 1) * 8;
                afb[nxt][0] = __float_as_uint(Srow0[k + tg]);
                afb[nxt][1] = __float_as_uint(Srow1[k + tg]);
                afb[nxt][2] = __float_as_uint(Srow0[k + tg + 4]);
                afb[nxt][3] = __float_as_uint(Srow1[k + tg + 4]);
                bfb[nxt][0] = __float_as_uint(Vrow[k + tg]);
                bfb[nxt][1] = __float_as_uint(Vrow[k + tg + 4]);
            }
            mma_tf32(c, afb[cur], bfb[cur]);
        }
    }
    {
        const int qrow0 = q0 + lr_g, qrow1 = qrow0 + 8;
        const int col = n0 + tg * 2;
        if (qrow0 < kNQ) {
            const float inv = lrow[lr_g];
            *(float2*)(o + ((size_t)(b * kNQ + qrow0)) * kD + h * kDH + col) =
                make_float2(c[0] * inv, c[1] * inv);
        }
        if (qrow1 < kNQ) {
            const float inv = lrow[lr_g + 8];
            *(float2*)(o + ((size_t)(b * kNQ + qrow1)) * kD + h * kDH + col) =
                make_float2(c[2] * inv, c[3] * inv);
        }
    }
}

// ---------------------------------------------------------------------------
// MS deformable aggregation. Corner loads batched ahead of FMAs (MLP=8).
// ---------------------------------------------------------------------------
__global__ void msdeform_agg_kernel(const float* __restrict__ ref,
                                    const float* __restrict__ oa,
                                    const float* __restrict__ memory,
                                    float* __restrict__ agg) {
    const int bq = blockIdx.x;
    const int b = bq / kNQ;
    const int t = threadIdx.x;
    const int h = t >> 5;
    const int lane = t & 31;

    __shared__ float s_p[kNH][16];

    float lw = (lane < 16) ? oa[(size_t)bq * kOW + 256 + h * 16 + lane] : -INFINITY;
    float m = lw;
#pragma unroll
    for (int o = 8; o > 0; o >>= 1) m = fmaxf(m, __shfl_xor_sync(~0u, m, o, 16));
    float e = (lane < 16) ? expf(lw - m) : 0.f;
    float sum = e;
#pragma unroll
    for (int o = 8; o > 0; o >>= 1) sum += __shfl_xor_sync(~0u, sum, o, 16);
    if (lane < 16) s_p[h][lane] = e / sum;
    __syncwarp();

    const int cH[kNL]  = {100, 50, 25, 13};
    const int cW[kNL]  = {150, 75, 38, 19};
    const int cS0[kNL] = {0, 15000, 18750, 19700};

    float a0 = 0.f, a1 = 0.f, a2 = 0.f, a3 = 0.f;
    float a4 = 0.f, a5 = 0.f, a6 = 0.f, a7 = 0.f;
    float bsum = 0.f;

    const float* mbase = memory + (size_t)b * kS * kD + lane * 8;

#pragma unroll
    for (int l = 0; l < kNL; ++l) {
        const float rx = ref[((size_t)bq * kNL + l) * 2 + 0];
        const float ry = ref[((size_t)bq * kNL + l) * 2 + 1];
        const int Hl = cH[l], Wl = cW[l], s0 = cS0[l];
        const float fW = (float)Wl, fH = (float)Hl;
#pragma unroll
        for (int p = 0; p < kNP; ++p) {
            const float aw = s_p[h][l * kNP + p];
            const size_t ob = (size_t)bq * kOW + (((h * kNL + l) * kNP + p) * 2);
            const float ox = oa[ob + 0];
            const float oy = oa[ob + 1];
            const float x = (rx + ox / fW) * fW - 0.5f;
            const float y = (ry + oy / fH) * fH - 0.5f;
            const float x0f = floorf(x), y0f = floorf(y);
            const float tx = x - x0f, ty = y - y0f;
            const int x0 = (int)x0f, y0 = (int)y0f;

            // batch all corner loads (weight 0 + safe row for invalid corners)
            float wgt[4];
            const float4* rp[4];
#pragma unroll
            for (int cc = 0; cc < 4; ++cc) {
                const int dy = cc >> 1, dx = cc & 1;
                const int xi = x0 + dx, yi = y0 + dy;
                const bool valid =
                    (xi >= 0) & (xi < Wl) & (yi >= 0) & (yi < Hl);
                wgt[cc] = valid
                    ? aw * (dy ? ty : (1.f - ty)) * (dx ? tx : (1.f - tx))
                    : 0.f;
                const int row = valid ? (s0 + yi * Wl + xi) : s0;
                rp[cc] = (const float4*)(mbase + (size_t)row * kD);
            }
            float4 v0[4], v1[4];
#pragma unroll
            for (int cc = 0; cc < 4; ++cc) { v0[cc] = rp[cc][0]; v1[cc] = rp[cc][1]; }
#pragma unroll
            for (int cc = 0; cc < 4; ++cc) {
                const float wv = wgt[cc];
                a0 = fmaf(wv, v0[cc].x, a0); a1 = fmaf(wv, v0[cc].y, a1);
                a2 = fmaf(wv, v0[cc].z, a2); a3 = fmaf(wv, v0[cc].w, a3);
                a4 = fmaf(wv, v1[cc].x, a4); a5 = fmaf(wv, v1[cc].y, a5);
                a6 = fmaf(wv, v1[cc].z, a6); a7 = fmaf(wv, v1[cc].w, a7);
                bsum += wv;
            }
        }
    }

    float* hb = agg + (size_t)bq * kAK2 + h * kHK;
    float4* dst = (float4*)(hb + lane * 8);
    dst[0] = make_float4(a0, a1, a2, a3);
    dst[1] = make_float4(a4, a5, a6, a7);
    if (lane == 0) hb[256] = bsum;
    else hb[256 + lane] = 0.f;
}

// ---------------------------------------------------------------------------
// Launch helpers
// ---------------------------------------------------------------------------
static void ensure_attrs() {
    static bool done = false;
    if (done) return;
    cudaFuncSetAttribute((const void*)gemm_tf32_kernel<3, false, 1>,
                         cudaFuncAttributeMaxDynamicSharedMemorySize,
                         gemm_smem_bytes<3>());
    cudaFuncSetAttribute((const void*)gemm_tf32_kernel<3, true, 1>,
                         cudaFuncAttributeMaxDynamicSharedMemorySize,
                         gemm_smem_bytes<3>());
    cudaFuncSetAttribute((const void*)gemm_tf32_kernel<3, false, 2>,
                         cudaFuncAttributeMaxDynamicSharedMemorySize,
                         gemm_smem_bytes<3>());
    cudaFuncSetAttribute((const void*)attn_tc_kernel,
                         cudaFuncAttributeMaxDynamicSharedMemorySize,
                         ATTN_SMEM);
    done = true;
}

static inline void launch_gemm(const float* A, const float* W, const float* b,
                               float* C, int M, int N, int K, bool relu) {
    dim3 grid(N / 64, (M + 63) / 64);
    if (relu)
        gemm_tf32_kernel<3, true, 1><<<grid, 256, gemm_smem_bytes<3>()>>>(
            A, A, N, W, b, C, M, N, K);
    else
        gemm_tf32_kernel<3, false, 1><<<grid, 256, gemm_smem_bytes<3>()>>>(
            A, A, N, W, b, C, M, N, K);
}

extern "C" void kernel_launch(void* const* d_in, const int* in_sizes, int n_in,
                              void* d_out, int out_size) {
    const float* tgt    = (const float*)d_in[0];
    const float* pos    = (const float*)d_in[1];
    const float* ref    = (const float*)d_in[2];
    const float* memory = (const float*)d_in[3];
    const float* in_w  = (const float*)d_in[7];
    const float* in_b  = (const float*)d_in[8];
    const float* out_w = (const float*)d_in[9];
    const float* out_b = (const float*)d_in[10];
    const float* n1g = (const float*)d_in[11];
    const float* n1b = (const float*)d_in[12];
    const float* n2g = (const float*)d_in[13];
    const float* n2b = (const float*)d_in[14];
    const float* n3g = (const float*)d_in[15];
    const float* n3b = (const float*)d_in[16];
    const float* so_w = (const float*)d_in[17];
    const float* so_b = (const float*)d_in[18];
    const float* aw_w = (const float*)d_in[19];
    const float* aw_b = (const float*)d_in[20];
    const float* v_w  = (const float*)d_in[21];
    const float* v_b  = (const float*)d_in[22];
    const float* op_w = (const float*)d_in[23];
    const float* op_b = (const float*)d_in[24];
    const float* l1w  = (const float*)d_in[25];
    const float* l1b  = (const float*)d_in[26];
    const float* l2w  = (const float*)d_in[27];
    const float* l2b  = (const float*)d_in[28];

    float* scratch = nullptr;
    cudaGetSymbolAddress((void**)&scratch, g_scratch);
    ensure_attrs();

    float* s_qkadd = scratch + OFF_QKADD;
    float* s_qkv   = scratch + OFF_QKV;
    float* s_attn  = scratch + OFF_ATTN;
    float* s_sa    = scratch + OFF_SA;
    float* s_tgt1  = scratch + OFF_TGT1;
    float* s_query = scratch + OFF_QUERY;
    float* s_oa    = scratch + OFF_OA;
    float* s_t2    = scratch + OFF_T2;
    float* s_tgt2  = scratch + OFF_TGT2;
    float* s_hid   = scratch + OFF_HID;
    float* s_ffo   = scratch + OFF_FFO;
    float* s_y     = scratch + OFF_Y;
    float* s_agg   = scratch + OFF_AGG;
    float* s_wv2   = scratch + OFF_WV2;
    float* s_wcat  = scratch + OFF_WCAT;
    float* s_bcat  = scratch + OFF_BCAT;

    const int nQD = kMQ * kD;

    // ---- zero split-K accumulation target (FFN2) ----
    cudaMemsetAsync(s_ffo, 0, (size_t)kMQ * kD * sizeof(float));

    // ---- precompute (Wv2, weight concat) + qkadd ----
    {
        dim3 grid(kNH, 9);
        precompute_kernel<<<grid, 256>>>(v_w, v_b, so_w, so_b, aw_w, aw_b,
                                         s_wv2, s_wcat, s_bcat);
    }
    add_kernel<<<(nQD + 255) / 256, 256>>>(tgt, pos, s_qkadd, nQD);

    // ---- self attention: merged QKV GEMM + tensor-core attention ----
    {
        dim3 grid(768 / 64, (kMQ + 63) / 64);
        gemm_tf32_kernel<3, false, 1><<<grid, 256, gemm_smem_bytes<3>()>>>(
            s_qkadd, tgt, 512, in_w, in_b, s_qkv, kMQ, 768, kD);
    }
    {
        dim3 grid((kNQ + kQT - 1) / kQT, kNH, kBS);
        attn_tc_kernel<<<grid, 256, ATTN_SMEM>>>(s_qkv, s_attn);
    }
    launch_gemm(s_attn, out_w, out_b, s_sa, kMQ, kD, kD, false);
    add_ln_kernel<true><<<kMQ, 256>>>(tgt, s_sa, n2g, n2b, s_tgt1, pos, s_query);

    // ---- MS deformable attention (factored rank-32 projection) ----
    launch_gemm(s_query, s_wcat, s_bcat, s_oa, kMQ, kOW, kD, false);
    msdeform_agg_kernel<<<kMQ, 256>>>(ref, s_oa, memory, s_agg);
    {
        dim3 grid((kMQ + 63) / 64, kNH);
        gemm_stage1_kernel<<<grid, 256, stage1_smem_bytes()>>>(s_agg, s_wv2, s_y);
    }
    launch_gemm(s_y, op_w, op_b, s_t2, kMQ, kD, kD, false);
    add_ln_kernel<false><<<kMQ, 256>>>(s_tgt1, s_t2, n1g, n1b, s_tgt2,
                                       nullptr, nullptr);

    // ---- FFN ----
    launch_gemm(s_tgt2, l1w, l1b, s_hid, kMQ, kDFF, kD, true);
    {
        dim3 grid(kD / 64, (kMQ + 63) / 64, 2);
        gemm_tf32_kernel<3, false, 2><<<grid, 256, gemm_smem_bytes<3>()>>>(
            s_hid, s_hid, kD, l2w, l2b, s_ffo, kMQ, kD, kDFF);
    }
    add_ln_kernel<false><<<kMQ, 256>>>(s_tgt2, s_ffo, n3g, n3b, (float*)d_out,
                                       nullptr, nullptr);
}